// round 1
// baseline (speedup 1.0000x reference)
#include <cuda_runtime.h>
#include <cuda_bf16.h>
#include <math.h>

// ---------------------------------------------------------------------------
// Problem constants (fixed by the dataset)
// ---------------------------------------------------------------------------
#define NMAX 20000
#define EMAX 500000
#define CDIM 128

// ---------------------------------------------------------------------------
// Static device scratch (no dynamic allocation allowed)
// ---------------------------------------------------------------------------
__device__ float g_x   [NMAX * CDIM];    // drug_linear output
__device__ float g_xh  [NMAX * 640];     // per-head features (GAT1: 512, GAT2: 640)
__device__ float g_gat [NMAX * 640];     // GAT aggregation output (pre-bias)
__device__ float g_h1  [NMAX * CDIM];
__device__ float g_h2  [NMAX * CDIM];
__device__ float g_es  [NMAX * 5];
__device__ float g_ed  [NMAX * 5];
__device__ int   g_cnt   [NMAX];
__device__ int   g_rowptr[NMAX + 1];
__device__ int   g_cursor[NMAX];
__device__ int   g_csrc  [EMAX];
__device__ float g_hsum  [CDIM];
__device__ float g_small [1024];         // [0:384) v_, [384:768) hsumk, [768] hb
__device__ float g_logits[256 * CDIM];

// ---------------------------------------------------------------------------
// Kernel 0: zero the accumulators used this launch
// ---------------------------------------------------------------------------
__global__ void zero_kernel(int N) {
    int i = blockIdx.x * blockDim.x + threadIdx.x;
    if (i < N)   g_cnt[i] = 0;
    if (i < CDIM) g_hsum[i] = 0.f;
}

// ---------------------------------------------------------------------------
// CSR build: count -> scan -> fill  (skips self-edges; a single implicit
// self-loop per node is added inside the aggregation kernel)
// ---------------------------------------------------------------------------
__global__ void count_kernel(const int* __restrict__ ei, int E) {
    int e = blockIdx.x * blockDim.x + threadIdx.x;
    if (e < E) {
        int s = ei[e], d = ei[E + e];
        if (s != d) atomicAdd(&g_cnt[d], 1);
    }
}

__global__ void scan_kernel(int N) {
    __shared__ int sm[1024];
    __shared__ int carry_s;
    int tid = threadIdx.x;
    if (tid == 0) { carry_s = 0; g_rowptr[0] = 0; }
    __syncthreads();
    for (int base = 0; base < N; base += 1024) {
        int v = (base + tid < N) ? g_cnt[base + tid] : 0;
        sm[tid] = v;
        __syncthreads();
        for (int off = 1; off < 1024; off <<= 1) {
            int t = (tid >= off) ? sm[tid - off] : 0;
            __syncthreads();
            sm[tid] += t;
            __syncthreads();
        }
        int carry = carry_s;
        if (base + tid < N) {
            g_rowptr[base + tid + 1] = carry + sm[tid];
            g_cursor[base + tid]     = carry + sm[tid] - v;
        }
        __syncthreads();
        if (tid == 0) carry_s += sm[1023];
        __syncthreads();
    }
}

__global__ void fill_kernel(const int* __restrict__ ei, int E) {
    int e = blockIdx.x * blockDim.x + threadIdx.x;
    if (e < E) {
        int s = ei[e], d = ei[E + e];
        if (s != d) {
            int p = atomicAdd(&g_cursor[d], 1);
            g_csrc[p] = s;
        }
    }
}

// ---------------------------------------------------------------------------
// drug linear: x = float(triplets[:, :4]) @ Wd + bd
// ---------------------------------------------------------------------------
__global__ void drug_linear_kernel(const int* __restrict__ trip,
                                   const float* __restrict__ Wd,
                                   const float* __restrict__ bd, int N) {
    int idx = blockIdx.x * blockDim.x + threadIdx.x;
    if (idx >= N * CDIM) return;
    int n = idx >> 7, c = idx & 127;
    float a = bd[c];
#pragma unroll
    for (int i = 0; i < 4; i++) a += (float)trip[n * 4 + i] * Wd[i * CDIM + c];
    g_x[idx] = a;
}

// ---------------------------------------------------------------------------
// Generic 64x64 tiled fp32 GEMM:  C = A' @ B (+cbias), A' = elu(A + abias)?
// A: [M,K] row-major, B: [K,N] row-major, C: [M,N].
// Requires K % 16 == 0, N % 4 == 0.
// ---------------------------------------------------------------------------
__global__ void gemm64(const float* __restrict__ A, const float* __restrict__ Bm,
                       float* __restrict__ Cm, int M, int N, int K,
                       const float* __restrict__ abias, int aelu,
                       const float* __restrict__ cbias) {
    __shared__ float As[16][65];
    __shared__ float Bs[16][64];
    int t  = threadIdx.x;
    int tx = t & 15, ty = t >> 4;
    int m0 = blockIdx.y * 64, n0 = blockIdx.x * 64;
    int ar = t >> 2, ac = (t & 3) * 4;
    int br = t >> 4, bc = (t & 15) * 4;

    float acc[4][4];
#pragma unroll
    for (int i = 0; i < 4; i++)
#pragma unroll
        for (int j = 0; j < 4; j++) acc[i][j] = 0.f;

    for (int k0 = 0; k0 < K; k0 += 16) {
        float4 av = make_float4(0.f, 0.f, 0.f, 0.f);
        if (m0 + ar < M)
            av = *(const float4*)(A + (size_t)(m0 + ar) * K + k0 + ac);
        if (aelu) {
            float vv;
            vv = av.x + abias[k0 + ac + 0]; av.x = vv > 0.f ? vv : __expf(vv) - 1.f;
            vv = av.y + abias[k0 + ac + 1]; av.y = vv > 0.f ? vv : __expf(vv) - 1.f;
            vv = av.z + abias[k0 + ac + 2]; av.z = vv > 0.f ? vv : __expf(vv) - 1.f;
            vv = av.w + abias[k0 + ac + 3]; av.w = vv > 0.f ? vv : __expf(vv) - 1.f;
        }
        As[ac + 0][ar] = av.x;
        As[ac + 1][ar] = av.y;
        As[ac + 2][ar] = av.z;
        As[ac + 3][ar] = av.w;

        float4 bv = make_float4(0.f, 0.f, 0.f, 0.f);
        if (k0 + br < K && n0 + bc < N)
            bv = *(const float4*)(Bm + (size_t)(k0 + br) * N + n0 + bc);
        *(float4*)&Bs[br][bc] = bv;
        __syncthreads();

#pragma unroll
        for (int kk = 0; kk < 16; kk++) {
            float a[4], b[4];
#pragma unroll
            for (int i = 0; i < 4; i++) a[i] = As[kk][ty * 4 + i];
#pragma unroll
            for (int j = 0; j < 4; j++) b[j] = Bs[kk][tx * 4 + j];
#pragma unroll
            for (int i = 0; i < 4; i++)
#pragma unroll
                for (int j = 0; j < 4; j++) acc[i][j] += a[i] * b[j];
        }
        __syncthreads();
    }

#pragma unroll
    for (int i = 0; i < 4; i++) {
        int row = m0 + ty * 4 + i;
        if (row < M) {
#pragma unroll
            for (int j = 0; j < 4; j++) {
                int col = n0 + tx * 4 + j;
                if (col < N) {
                    float v = acc[i][j];
                    if (cbias) v += cbias[col];
                    Cm[(size_t)row * N + col] = v;
                }
            }
        }
    }
}

// ---------------------------------------------------------------------------
// attention coefficients: es[n,h] = <xh[n,h,:], a_s[h,:]>, ed likewise
// one warp per (n,h)
// ---------------------------------------------------------------------------
__global__ void esed_kernel(const float* __restrict__ xh,
                            const float* __restrict__ as_,
                            const float* __restrict__ ad_, int N, int H) {
    int gid  = blockIdx.x * blockDim.x + threadIdx.x;
    int w    = gid >> 5, lane = gid & 31;
    if (w >= N * H) return;
    int n = w / H, h = w - n * H;
    const float* row = xh + (size_t)n * H * CDIM + h * CDIM;
    float s1 = 0.f, s2 = 0.f;
    for (int i = lane; i < CDIM; i += 32) {
        float v = row[i];
        s1 += v * as_[h * CDIM + i];
        s2 += v * ad_[h * CDIM + i];
    }
    for (int o = 16; o; o >>= 1) {
        s1 += __shfl_xor_sync(0xffffffffu, s1, o);
        s2 += __shfl_xor_sync(0xffffffffu, s2, o);
    }
    if (lane == 0) { g_es[n * H + h] = s1; g_ed[n * H + h] = s2; }
}

// ---------------------------------------------------------------------------
// GAT softmax aggregation, one warp per destination node.
// 3 passes over incoming edges (+1 implicit self-loop): max, sum, gather.
// ---------------------------------------------------------------------------
template <int H>
__global__ void agg_kernel(const float* __restrict__ xh,
                           float* __restrict__ out, int N) {
    int warp = (blockIdx.x * blockDim.x + threadIdx.x) >> 5;
    int lane = threadIdx.x & 31;
    if (warp >= N) return;
    int n   = warp;
    int r0  = g_rowptr[n];
    int deg = g_rowptr[n + 1] - r0;
    int tot = deg + 1;  // + self loop

    float edv[H], m[H], sv[H];
#pragma unroll
    for (int h = 0; h < H; h++) {
        edv[h] = g_ed[n * H + h];
        m[h]   = -1e30f;
        sv[h]  = 0.f;
    }
    // pass 1: per-head max
    for (int i = lane; i < tot; i += 32) {
        int src = (i < deg) ? g_csrc[r0 + i] : n;
#pragma unroll
        for (int h = 0; h < H; h++) {
            float e = g_es[src * H + h] + edv[h];
            e = e > 0.f ? e : 0.2f * e;
            m[h] = fmaxf(m[h], e);
        }
    }
#pragma unroll
    for (int h = 0; h < H; h++)
        for (int o = 16; o; o >>= 1) m[h] = fmaxf(m[h], __shfl_xor_sync(0xffffffffu, m[h], o));
    // pass 2: per-head sum of exp
    for (int i = lane; i < tot; i += 32) {
        int src = (i < deg) ? g_csrc[r0 + i] : n;
#pragma unroll
        for (int h = 0; h < H; h++) {
            float e = g_es[src * H + h] + edv[h];
            e = e > 0.f ? e : 0.2f * e;
            sv[h] += __expf(e - m[h]);
        }
    }
#pragma unroll
    for (int h = 0; h < H; h++) {
        for (int o = 16; o; o >>= 1) sv[h] += __shfl_xor_sync(0xffffffffu, sv[h], o);
        sv[h] = 1.f / sv[h];
    }
    // pass 3: weighted gather (all lanes walk every edge, lanes = channels)
    float4 acc[H];
#pragma unroll
    for (int h = 0; h < H; h++) acc[h] = make_float4(0.f, 0.f, 0.f, 0.f);
    for (int i = 0; i < tot; i++) {
        int src = (i < deg) ? g_csrc[r0 + i] : n;
        const float4* row = (const float4*)(xh + (size_t)src * (H * CDIM));
#pragma unroll
        for (int h = 0; h < H; h++) {
            float e = g_es[src * H + h] + edv[h];
            e = e > 0.f ? e : 0.2f * e;
            float wv = __expf(e - m[h]) * sv[h];
            float4 v = row[h * 32 + lane];
            acc[h].x += v.x * wv;
            acc[h].y += v.y * wv;
            acc[h].z += v.z * wv;
            acc[h].w += v.w * wv;
        }
    }
    float4* orow = (float4*)(out + (size_t)n * (H * CDIM));
#pragma unroll
    for (int h = 0; h < H; h++) orow[h * 32 + lane] = acc[h];
}

// ---------------------------------------------------------------------------
// graph readout: hsum[c] += sum_n (h1[n,c] + h2[n,c])
// ---------------------------------------------------------------------------
__global__ void readout_kernel(int N) {
    int tid = threadIdx.x;  // 128 threads = channels
    float a = 0.f;
    for (int n = blockIdx.x; n < N; n += gridDim.x)
        a += g_h1[(size_t)n * CDIM + tid] + g_h2[(size_t)n * CDIM + tid];
    atomicAdd(&g_hsum[tid], a);
}

// ---------------------------------------------------------------------------
// tail 0 (single block, 384 threads): h -> hg -> v_, hsumk, hb
// ---------------------------------------------------------------------------
__global__ void tail0_kernel(const float* __restrict__ Wfc, const float* __restrict__ bfc,
                             const float* __restrict__ Whg, const float* __restrict__ bhg,
                             const float* __restrict__ Wv,  const float* __restrict__ bv,
                             const float* __restrict__ h_mat, const float* __restrict__ h_bias,
                             int N, int HOUT) {
    __shared__ float h[128];
    __shared__ float tm[256];
    __shared__ float hg[128];
    int tid = threadIdx.x;
    if (tid < 128) h[tid] = g_hsum[tid] / (float)N;
    __syncthreads();
    if (tid < 256) {
        float a = bfc[tid];
        for (int i = 0; i < 128; i++) a += h[i] * Wfc[i * 256 + tid];
        tm[tid] = a > 0.f ? a : 0.f;
    }
    __syncthreads();
    if (tid < 128) {
        float a = bhg[tid];
        for (int i = 0; i < 256; i++) a += tm[i] * Whg[i * 128 + tid];
        hg[tid] = a;
    }
    __syncthreads();
    if (tid < 384) {
        float a = bv[tid];
        for (int i = 0; i < 128; i++) a += hg[i] * Wv[i * 384 + tid];
        g_small[tid] = a > 0.f ? a : 0.f;
        float hs = 0.f;
        for (int hh = 0; hh < HOUT; hh++) hs += h_mat[hh * 384 + tid];
        g_small[384 + tid] = hs;
    }
    if (tid == 0) {
        float hb = 0.f;
        for (int i = 0; i < HOUT; i++) hb += h_bias[i];
        g_small[768] = hb;
    }
}

// ---------------------------------------------------------------------------
// tail 1: per batch row b: c -> q_ -> att_sum -> logits[b, :]
// ---------------------------------------------------------------------------
__global__ void tail1_kernel(const float* __restrict__ cell,
                             const float* __restrict__ Wc, const float* __restrict__ bc,
                             const float* __restrict__ Wq, const float* __restrict__ bq,
                             int CF) {
    __shared__ float sc[1024];
    __shared__ float crow[128];
    __shared__ float qrow[384];
    __shared__ float red[128];
    int b = blockIdx.x, tid = threadIdx.x;  // 128 threads
    for (int i = tid; i < CF; i += 128) sc[i] = cell[(size_t)b * CF + i];
    __syncthreads();
    {
        float a = bc[tid];
        for (int k = 0; k < CF; k++) a += sc[k] * Wc[k * 128 + tid];
        crow[tid] = a > 0.f ? a : 0.f;
    }
    __syncthreads();
    float part = 0.f;
    for (int mI = tid; mI < 384; mI += 128) {
        float q = bq[mI];
        for (int k = 0; k < 128; k++) q += crow[k] * Wq[k * 384 + mI];
        q = q > 0.f ? q : 0.f;
        qrow[mI] = q;
        part += g_small[384 + mI] * g_small[mI] * q;
    }
    red[tid] = part;
    __syncthreads();
    for (int o = 64; o; o >>= 1) {
        if (tid < o) red[tid] += red[tid + o];
        __syncthreads();
    }
    float att = red[0] + g_small[768];
    float l = 0.f;
#pragma unroll
    for (int j = 0; j < 3; j++) {
        int k = tid * 3 + j;
        l += g_small[k] * qrow[k];
    }
    g_logits[b * 128 + tid] = att * l;
}

// ---------------------------------------------------------------------------
// tail 2: batch norm over the B dim (one block per channel, B threads)
// ---------------------------------------------------------------------------
__global__ void tail2_kernel(const float* __restrict__ gamma,
                             const float* __restrict__ beta,
                             float* __restrict__ out, int B) {
    __shared__ float s1[256], s2[256];
    int c = blockIdx.x, b = threadIdx.x;
    float v = g_logits[b * 128 + c];
    s1[b] = v;
    s2[b] = v * v;
    __syncthreads();
    for (int o = B >> 1; o; o >>= 1) {
        if (b < o) { s1[b] += s1[b + o]; s2[b] += s2[b + o]; }
        __syncthreads();
    }
    float mu  = s1[0] / (float)B;
    float var = s2[0] / (float)B - mu * mu;
    out[b * 128 + c] = (v - mu) * rsqrtf(var + 1e-5f) * gamma[c] + beta[c];
}

// ---------------------------------------------------------------------------
// launch
// ---------------------------------------------------------------------------
extern "C" void kernel_launch(void* const* d_in, const int* in_sizes, int n_in,
                              void* d_out, int out_size) {
    const float* cell = (const float*)d_in[0];
    const float* Wd   = (const float*)d_in[1];
    const float* bd   = (const float*)d_in[2];
    const float* W1   = (const float*)d_in[3];
    const float* a1s  = (const float*)d_in[4];
    const float* a1d  = (const float*)d_in[5];
    const float* b1   = (const float*)d_in[6];
    const float* Wl1  = (const float*)d_in[7];
    const float* bl1  = (const float*)d_in[8];
    const float* W2   = (const float*)d_in[9];
    const float* a2s  = (const float*)d_in[10];
    const float* a2d  = (const float*)d_in[11];
    const float* b2   = (const float*)d_in[12];
    const float* Wl2  = (const float*)d_in[13];
    const float* bl2  = (const float*)d_in[14];
    const float* Wfc  = (const float*)d_in[15];
    const float* bfc  = (const float*)d_in[16];
    const float* Whg  = (const float*)d_in[17];
    const float* bhg  = (const float*)d_in[18];
    const float* Wc   = (const float*)d_in[19];
    const float* bc   = (const float*)d_in[20];
    const float* Wv   = (const float*)d_in[21];
    const float* bv   = (const float*)d_in[22];
    const float* Wq   = (const float*)d_in[23];
    const float* bq   = (const float*)d_in[24];
    const float* h_mat  = (const float*)d_in[25];
    const float* h_bias = (const float*)d_in[26];
    const float* gamma  = (const float*)d_in[27];
    const float* beta   = (const float*)d_in[28];
    const int*   trip   = (const int*)d_in[29];
    const int*   ei     = (const int*)d_in[30];

    int N  = in_sizes[29] / 4;
    int E  = in_sizes[30] / 2;
    int CF = in_sizes[19] / 128;
    int B  = in_sizes[0] / CF;
    int H1 = in_sizes[4] / 128;   // 4
    int H2 = in_sizes[10] / 128;  // 5
    int HOUT = in_sizes[26];
    if (N > NMAX) N = NMAX;
    if (E > EMAX) E = EMAX;
    float* out = (float*)d_out;

    void *px, *pxh, *pgat, *ph1, *ph2;
    cudaGetSymbolAddress(&px,   g_x);
    cudaGetSymbolAddress(&pxh,  g_xh);
    cudaGetSymbolAddress(&pgat, g_gat);
    cudaGetSymbolAddress(&ph1,  g_h1);
    cudaGetSymbolAddress(&ph2,  g_h2);

    int M1 = H1 * CDIM;  // 512
    int M2 = H2 * CDIM;  // 640

    // CSR build + accumulator zeroing
    zero_kernel<<<(N + 255) / 256, 256>>>(N);
    count_kernel<<<(E + 255) / 256, 256>>>(ei, E);
    scan_kernel<<<1, 1024>>>(N);
    fill_kernel<<<(E + 255) / 256, 256>>>(ei, E);

    // drug linear
    drug_linear_kernel<<<(N * CDIM + 255) / 256, 256>>>(trip, Wd, bd, N);

    int mblk = (N + 63) / 64;

    // ---- GAT layer 1 ----
    gemm64<<<dim3(M1 / 64, mblk), 256>>>((const float*)px, W1, (float*)pxh,
                                         N, M1, CDIM, nullptr, 0, nullptr);
    esed_kernel<<<(N * H1 * 32 + 255) / 256, 256>>>((const float*)pxh, a1s, a1d, N, H1);
    agg_kernel<4><<<(N * 32 + 255) / 256, 256>>>((const float*)pxh, (float*)pgat, N);
    gemm64<<<dim3(CDIM / 64, mblk), 256>>>((const float*)pgat, Wl1, (float*)ph1,
                                           N, CDIM, M1, b1, 1, bl1);

    // ---- GAT layer 2 ----
    gemm64<<<dim3(M2 / 64, mblk), 256>>>((const float*)ph1, W2, (float*)pxh,
                                         N, M2, CDIM, nullptr, 0, nullptr);
    esed_kernel<<<(N * H2 * 32 + 255) / 256, 256>>>((const float*)pxh, a2s, a2d, N, H2);
    agg_kernel<5><<<(N * 32 + 255) / 256, 256>>>((const float*)pxh, (float*)pgat, N);
    gemm64<<<dim3(CDIM / 64, mblk), 256>>>((const float*)pgat, Wl2, (float*)ph2,
                                           N, CDIM, M2, b2, 1, bl2);

    // readout + tail
    readout_kernel<<<256, 128>>>(N);
    tail0_kernel<<<1, 384>>>(Wfc, bfc, Whg, bhg, Wv, bv, h_mat, h_bias, N, HOUT);
    tail1_kernel<<<B, 128>>>(cell, Wc, bc, Wq, bq, CF);
    tail2_kernel<<<128, B>>>(gamma, beta, out, B);
}

// round 2
// speedup vs baseline: 1.0525x; 1.0525x over previous
#include <cuda_runtime.h>
#include <cuda_bf16.h>
#include <math.h>

// ---------------------------------------------------------------------------
// Problem constants (fixed by the dataset)
// ---------------------------------------------------------------------------
#define NMAX 20000
#define EMAX 500000
#define CDIM 128

// ---------------------------------------------------------------------------
// Static device scratch (no dynamic allocation allowed)
// ---------------------------------------------------------------------------
__device__ float g_xh  [NMAX * 640];     // per-head features (GAT1: 512, GAT2: 640)
__device__ float g_gat [NMAX * 640];     // GAT aggregation output (pre-bias)
__device__ float g_h1  [NMAX * CDIM];
__device__ float g_h2  [NMAX * CDIM];
__device__ float g_es  [NMAX * 5];
__device__ float g_ed  [NMAX * 5];
__device__ int   g_cnt   [NMAX];
__device__ int   g_rowptr[NMAX + 1];
__device__ int   g_cursor[NMAX];
__device__ int   g_csrc  [EMAX];
__device__ float g_hsum  [CDIM];
__device__ float g_small [1024];         // [0:384) v_, [384:768) hsumk, [768] hb
__device__ float g_logits[256 * CDIM];
__device__ float g_Wp  [4 * 640];        // folded Wd@W1
__device__ float g_bp  [640];            // folded bd@W1

// ---------------------------------------------------------------------------
// Kernel 0: zero the accumulators used this launch
// ---------------------------------------------------------------------------
__global__ void zero_kernel(int N) {
    int i = blockIdx.x * blockDim.x + threadIdx.x;
    if (i < N)   g_cnt[i] = 0;
    if (i < CDIM) g_hsum[i] = 0.f;
}

// ---------------------------------------------------------------------------
// CSR build: count -> scan -> fill  (skips self-edges; a single implicit
// self-loop per node is added inside the aggregation kernel)
// ---------------------------------------------------------------------------
__global__ void count_kernel(const int* __restrict__ ei, int E) {
    int e = blockIdx.x * blockDim.x + threadIdx.x;
    if (e < E) {
        int s = ei[e], d = ei[E + e];
        if (s != d) atomicAdd(&g_cnt[d], 1);
    }
}

__global__ void scan_kernel(int N) {
    __shared__ int sm[1024];
    __shared__ int carry_s;
    int tid = threadIdx.x;
    if (tid == 0) { carry_s = 0; g_rowptr[0] = 0; }
    __syncthreads();
    for (int base = 0; base < N; base += 1024) {
        int v = (base + tid < N) ? g_cnt[base + tid] : 0;
        sm[tid] = v;
        __syncthreads();
        for (int off = 1; off < 1024; off <<= 1) {
            int t = (tid >= off) ? sm[tid - off] : 0;
            __syncthreads();
            sm[tid] += t;
            __syncthreads();
        }
        int carry = carry_s;
        if (base + tid < N) {
            g_rowptr[base + tid + 1] = carry + sm[tid];
            g_cursor[base + tid]     = carry + sm[tid] - v;
        }
        __syncthreads();
        if (tid == 0) carry_s += sm[1023];
        __syncthreads();
    }
}

__global__ void fill_kernel(const int* __restrict__ ei, int E) {
    int e = blockIdx.x * blockDim.x + threadIdx.x;
    if (e < E) {
        int s = ei[e], d = ei[E + e];
        if (s != d) {
            int p = atomicAdd(&g_cursor[d], 1);
            g_csrc[p] = s;
        }
    }
}

// ---------------------------------------------------------------------------
// Fold drug_linear into GAT1's input GEMM:
//   xh1 = (trip4 @ Wd + bd) @ W1 = trip4 @ (Wd@W1) + (bd@W1)
// wprep computes Wp = Wd@W1 (4 x M1) and bp = bd@W1 (M1).
// ---------------------------------------------------------------------------
__global__ void wprep_kernel(const float* __restrict__ Wd,
                             const float* __restrict__ bd,
                             const float* __restrict__ W1, int M1) {
    int j = blockIdx.x * blockDim.x + threadIdx.x;
    if (j >= M1) return;
    float a0 = 0.f, a1 = 0.f, a2 = 0.f, a3 = 0.f, ab = 0.f;
#pragma unroll 4
    for (int k = 0; k < CDIM; k++) {
        float w = W1[k * M1 + j];
        a0 += Wd[0 * CDIM + k] * w;
        a1 += Wd[1 * CDIM + k] * w;
        a2 += Wd[2 * CDIM + k] * w;
        a3 += Wd[3 * CDIM + k] * w;
        ab += bd[k] * w;
    }
    g_Wp[0 * M1 + j] = a0;
    g_Wp[1 * M1 + j] = a1;
    g_Wp[2 * M1 + j] = a2;
    g_Wp[3 * M1 + j] = a3;
    g_bp[j] = ab;
}

// xh1[n, j] = bp[j] + sum_i trip[n,i] * Wp[i,j]  (rank-4, write-bound)
__global__ void xh1_kernel(const int* __restrict__ trip, int N, int M1) {
    int cols4 = M1 >> 2;
    int idx = blockIdx.x * blockDim.x + threadIdx.x;
    if (idx >= N * cols4) return;
    int n = idx / cols4;
    int j = (idx - n * cols4) << 2;
    int4 tv = *(const int4*)(trip + n * 4);
    float t0 = (float)tv.x, t1 = (float)tv.y, t2 = (float)tv.z, t3 = (float)tv.w;
    float4 w0 = *(const float4*)(g_Wp + 0 * M1 + j);
    float4 w1 = *(const float4*)(g_Wp + 1 * M1 + j);
    float4 w2 = *(const float4*)(g_Wp + 2 * M1 + j);
    float4 w3 = *(const float4*)(g_Wp + 3 * M1 + j);
    float4 b  = *(const float4*)(g_bp + j);
    float4 r;
    r.x = b.x + t0 * w0.x + t1 * w1.x + t2 * w2.x + t3 * w3.x;
    r.y = b.y + t0 * w0.y + t1 * w1.y + t2 * w2.y + t3 * w3.y;
    r.z = b.z + t0 * w0.z + t1 * w1.z + t2 * w2.z + t3 * w3.z;
    r.w = b.w + t0 * w0.w + t1 * w1.w + t2 * w2.w + t3 * w3.w;
    *(float4*)(g_xh + (size_t)n * M1 + j) = r;
}

// ---------------------------------------------------------------------------
// 128x64 tiled fp32 GEMM, double-buffered smem, 8x4 microtile:
//   C = A' @ B (+cbias), A' = elu(A + abias) when aelu
// A: [M,K] row-major, B: [K,N] row-major, C: [M,N]. K%16==0, N%64==0.
// ---------------------------------------------------------------------------
__global__ void __launch_bounds__(256, 2)
gemm128(const float* __restrict__ A, const float* __restrict__ Bm,
        float* __restrict__ Cm, int M, int N, int K,
        const float* __restrict__ abias, int aelu,
        const float* __restrict__ cbias) {
    __shared__ float As[2][16][132];
    __shared__ float Bs[2][16][64];
    int t  = threadIdx.x;
    int tx = t & 15, ty = t >> 4;
    int m0 = blockIdx.y * 128, n0 = blockIdx.x * 64;
    int ar = t >> 1;            // 0..127
    int ac = (t & 1) * 8;       // 0 or 8
    int br = t >> 4;            // 0..15
    int bc = (t & 15) * 4;

    float acc[8][4];
#pragma unroll
    for (int i = 0; i < 8; i++)
#pragma unroll
        for (int j = 0; j < 4; j++) acc[i][j] = 0.f;

    float4 pa0, pa1, pb;

#define LOAD_TILE(K0)                                                          \
    {                                                                          \
        pa0 = make_float4(0.f, 0.f, 0.f, 0.f);                                 \
        pa1 = pa0;                                                             \
        if (m0 + ar < M) {                                                     \
            const float* p = A + (size_t)(m0 + ar) * K + (K0) + ac;            \
            pa0 = *(const float4*)p;                                           \
            pa1 = *(const float4*)(p + 4);                                     \
        }                                                                      \
        if (aelu) {                                                            \
            const float* bb = abias + (K0) + ac;                               \
            float vv;                                                          \
            vv = pa0.x + bb[0]; pa0.x = vv > 0.f ? vv : __expf(vv) - 1.f;      \
            vv = pa0.y + bb[1]; pa0.y = vv > 0.f ? vv : __expf(vv) - 1.f;      \
            vv = pa0.z + bb[2]; pa0.z = vv > 0.f ? vv : __expf(vv) - 1.f;      \
            vv = pa0.w + bb[3]; pa0.w = vv > 0.f ? vv : __expf(vv) - 1.f;      \
            vv = pa1.x + bb[4]; pa1.x = vv > 0.f ? vv : __expf(vv) - 1.f;      \
            vv = pa1.y + bb[5]; pa1.y = vv > 0.f ? vv : __expf(vv) - 1.f;      \
            vv = pa1.z + bb[6]; pa1.z = vv > 0.f ? vv : __expf(vv) - 1.f;      \
            vv = pa1.w + bb[7]; pa1.w = vv > 0.f ? vv : __expf(vv) - 1.f;      \
        }                                                                      \
        pb = *(const float4*)(Bm + (size_t)((K0) + br) * N + n0 + bc);         \
    }

#define STORE_TILE(BUF)                                                        \
    {                                                                          \
        As[BUF][ac + 0][ar] = pa0.x;                                           \
        As[BUF][ac + 1][ar] = pa0.y;                                           \
        As[BUF][ac + 2][ar] = pa0.z;                                           \
        As[BUF][ac + 3][ar] = pa0.w;                                           \
        As[BUF][ac + 4][ar] = pa1.x;                                           \
        As[BUF][ac + 5][ar] = pa1.y;                                           \
        As[BUF][ac + 6][ar] = pa1.z;                                           \
        As[BUF][ac + 7][ar] = pa1.w;                                           \
        *(float4*)&Bs[BUF][br][bc] = pb;                                       \
    }

    LOAD_TILE(0)
    STORE_TILE(0)
    __syncthreads();

    int buf = 0;
    for (int k0 = 0; k0 < K; k0 += 16) {
        int kn = k0 + 16;
        if (kn < K) LOAD_TILE(kn)

#pragma unroll
        for (int kk = 0; kk < 16; kk++) {
            float a[8], b[4];
#pragma unroll
            for (int i = 0; i < 8; i++) a[i] = As[buf][kk][ty * 8 + i];
#pragma unroll
            for (int j = 0; j < 4; j++) b[j] = Bs[buf][kk][tx * 4 + j];
#pragma unroll
            for (int i = 0; i < 8; i++)
#pragma unroll
                for (int j = 0; j < 4; j++) acc[i][j] += a[i] * b[j];
        }
        if (kn < K) STORE_TILE(buf ^ 1)
        __syncthreads();
        buf ^= 1;
    }

    float cb[4] = {0.f, 0.f, 0.f, 0.f};
    if (cbias) {
#pragma unroll
        for (int j = 0; j < 4; j++) cb[j] = cbias[n0 + tx * 4 + j];
    }
#pragma unroll
    for (int i = 0; i < 8; i++) {
        int row = m0 + ty * 8 + i;
        if (row < M) {
            float4 v;
            v.x = acc[i][0] + cb[0];
            v.y = acc[i][1] + cb[1];
            v.z = acc[i][2] + cb[2];
            v.w = acc[i][3] + cb[3];
            *(float4*)(Cm + (size_t)row * N + n0 + tx * 4) = v;
        }
    }
#undef LOAD_TILE
#undef STORE_TILE
}

// ---------------------------------------------------------------------------
// attention coefficients: es[n,h] = <xh[n,h,:], a_s[h,:]>, ed likewise
// one warp per (n,h)
// ---------------------------------------------------------------------------
__global__ void esed_kernel(const float* __restrict__ xh,
                            const float* __restrict__ as_,
                            const float* __restrict__ ad_, int N, int H) {
    int gid  = blockIdx.x * blockDim.x + threadIdx.x;
    int w    = gid >> 5, lane = gid & 31;
    if (w >= N * H) return;
    int n = w / H, h = w - n * H;
    const float* row = xh + (size_t)n * H * CDIM + h * CDIM;
    float s1 = 0.f, s2 = 0.f;
    for (int i = lane; i < CDIM; i += 32) {
        float v = row[i];
        s1 += v * as_[h * CDIM + i];
        s2 += v * ad_[h * CDIM + i];
    }
    for (int o = 16; o; o >>= 1) {
        s1 += __shfl_xor_sync(0xffffffffu, s1, o);
        s2 += __shfl_xor_sync(0xffffffffu, s2, o);
    }
    if (lane == 0) { g_es[n * H + h] = s1; g_ed[n * H + h] = s2; }
}

// ---------------------------------------------------------------------------
// GAT softmax aggregation, one warp per destination node.
// 3 passes over incoming edges (+1 implicit self-loop): max, sum, gather.
// ---------------------------------------------------------------------------
template <int H>
__global__ void agg_kernel(const float* __restrict__ xh,
                           float* __restrict__ out, int N) {
    int warp = (blockIdx.x * blockDim.x + threadIdx.x) >> 5;
    int lane = threadIdx.x & 31;
    if (warp >= N) return;
    int n   = warp;
    int r0  = g_rowptr[n];
    int deg = g_rowptr[n + 1] - r0;
    int tot = deg + 1;  // + self loop

    float edv[H], m[H], sv[H];
#pragma unroll
    for (int h = 0; h < H; h++) {
        edv[h] = g_ed[n * H + h];
        m[h]   = -1e30f;
        sv[h]  = 0.f;
    }
    for (int i = lane; i < tot; i += 32) {
        int src = (i < deg) ? g_csrc[r0 + i] : n;
#pragma unroll
        for (int h = 0; h < H; h++) {
            float e = g_es[src * H + h] + edv[h];
            e = e > 0.f ? e : 0.2f * e;
            m[h] = fmaxf(m[h], e);
        }
    }
#pragma unroll
    for (int h = 0; h < H; h++)
        for (int o = 16; o; o >>= 1) m[h] = fmaxf(m[h], __shfl_xor_sync(0xffffffffu, m[h], o));
    for (int i = lane; i < tot; i += 32) {
        int src = (i < deg) ? g_csrc[r0 + i] : n;
#pragma unroll
        for (int h = 0; h < H; h++) {
            float e = g_es[src * H + h] + edv[h];
            e = e > 0.f ? e : 0.2f * e;
            sv[h] += __expf(e - m[h]);
        }
    }
#pragma unroll
    for (int h = 0; h < H; h++) {
        for (int o = 16; o; o >>= 1) sv[h] += __shfl_xor_sync(0xffffffffu, sv[h], o);
        sv[h] = 1.f / sv[h];
    }
    float4 acc[H];
#pragma unroll
    for (int h = 0; h < H; h++) acc[h] = make_float4(0.f, 0.f, 0.f, 0.f);
    for (int i = 0; i < tot; i++) {
        int src = (i < deg) ? g_csrc[r0 + i] : n;
        const float4* row = (const float4*)(xh + (size_t)src * (H * CDIM));
#pragma unroll
        for (int h = 0; h < H; h++) {
            float e = g_es[src * H + h] + edv[h];
            e = e > 0.f ? e : 0.2f * e;
            float wv = __expf(e - m[h]) * sv[h];
            float4 v = row[h * 32 + lane];
            acc[h].x += v.x * wv;
            acc[h].y += v.y * wv;
            acc[h].z += v.z * wv;
            acc[h].w += v.w * wv;
        }
    }
    float4* orow = (float4*)(out + (size_t)n * (H * CDIM));
#pragma unroll
    for (int h = 0; h < H; h++) orow[h * 32 + lane] = acc[h];
}

// ---------------------------------------------------------------------------
// graph readout: hsum[c] += sum_n (h1[n,c] + h2[n,c])
// ---------------------------------------------------------------------------
__global__ void readout_kernel(int N) {
    int tid = threadIdx.x;  // 128 threads = channels
    float a = 0.f;
    for (int n = blockIdx.x; n < N; n += gridDim.x)
        a += g_h1[(size_t)n * CDIM + tid] + g_h2[(size_t)n * CDIM + tid];
    atomicAdd(&g_hsum[tid], a);
}

// ---------------------------------------------------------------------------
// tail 0 (single block, 384 threads): h -> hg -> v_, hsumk, hb
// ---------------------------------------------------------------------------
__global__ void tail0_kernel(const float* __restrict__ Wfc, const float* __restrict__ bfc,
                             const float* __restrict__ Whg, const float* __restrict__ bhg,
                             const float* __restrict__ Wv,  const float* __restrict__ bv,
                             const float* __restrict__ h_mat, const float* __restrict__ h_bias,
                             int N, int HOUT) {
    __shared__ float h[128];
    __shared__ float tm[256];
    __shared__ float hg[128];
    int tid = threadIdx.x;
    if (tid < 128) h[tid] = g_hsum[tid] / (float)N;
    __syncthreads();
    if (tid < 256) {
        float a = bfc[tid];
        for (int i = 0; i < 128; i++) a += h[i] * Wfc[i * 256 + tid];
        tm[tid] = a > 0.f ? a : 0.f;
    }
    __syncthreads();
    if (tid < 128) {
        float a = bhg[tid];
        for (int i = 0; i < 256; i++) a += tm[i] * Whg[i * 128 + tid];
        hg[tid] = a;
    }
    __syncthreads();
    if (tid < 384) {
        float a = bv[tid];
        for (int i = 0; i < 128; i++) a += hg[i] * Wv[i * 384 + tid];
        g_small[tid] = a > 0.f ? a : 0.f;
        float hs = 0.f;
        for (int hh = 0; hh < HOUT; hh++) hs += h_mat[hh * 384 + tid];
        g_small[384 + tid] = hs;
    }
    if (tid == 0) {
        float hb = 0.f;
        for (int i = 0; i < HOUT; i++) hb += h_bias[i];
        g_small[768] = hb;
    }
}

// ---------------------------------------------------------------------------
// tail 1: per batch row b: c -> q_ -> att_sum -> logits[b, :]
// ---------------------------------------------------------------------------
__global__ void tail1_kernel(const float* __restrict__ cell,
                             const float* __restrict__ Wc, const float* __restrict__ bc,
                             const float* __restrict__ Wq, const float* __restrict__ bq,
                             int CF) {
    __shared__ float sc[1024];
    __shared__ float crow[128];
    __shared__ float qrow[384];
    __shared__ float red[128];
    int b = blockIdx.x, tid = threadIdx.x;  // 128 threads
    for (int i = tid; i < CF; i += 128) sc[i] = cell[(size_t)b * CF + i];
    __syncthreads();
    {
        float a = bc[tid];
        for (int k = 0; k < CF; k++) a += sc[k] * Wc[k * 128 + tid];
        crow[tid] = a > 0.f ? a : 0.f;
    }
    __syncthreads();
    float part = 0.f;
    for (int mI = tid; mI < 384; mI += 128) {
        float q = bq[mI];
        for (int k = 0; k < 128; k++) q += crow[k] * Wq[k * 384 + mI];
        q = q > 0.f ? q : 0.f;
        qrow[mI] = q;
        part += g_small[384 + mI] * g_small[mI] * q;
    }
    red[tid] = part;
    __syncthreads();
    for (int o = 64; o; o >>= 1) {
        if (tid < o) red[tid] += red[tid + o];
        __syncthreads();
    }
    float att = red[0] + g_small[768];
    float l = 0.f;
#pragma unroll
    for (int j = 0; j < 3; j++) {
        int k = tid * 3 + j;
        l += g_small[k] * qrow[k];
    }
    g_logits[b * 128 + tid] = att * l;
}

// ---------------------------------------------------------------------------
// tail 2: batch norm over the B dim (one block per channel, B threads)
// ---------------------------------------------------------------------------
__global__ void tail2_kernel(const float* __restrict__ gamma,
                             const float* __restrict__ beta,
                             float* __restrict__ out, int B) {
    __shared__ float s1[256], s2[256];
    int c = blockIdx.x, b = threadIdx.x;
    float v = g_logits[b * 128 + c];
    s1[b] = v;
    s2[b] = v * v;
    __syncthreads();
    for (int o = B >> 1; o; o >>= 1) {
        if (b < o) { s1[b] += s1[b + o]; s2[b] += s2[b + o]; }
        __syncthreads();
    }
    float mu  = s1[0] / (float)B;
    float var = s2[0] / (float)B - mu * mu;
    out[b * 128 + c] = (v - mu) * rsqrtf(var + 1e-5f) * gamma[c] + beta[c];
}

// ---------------------------------------------------------------------------
// launch
// ---------------------------------------------------------------------------
extern "C" void kernel_launch(void* const* d_in, const int* in_sizes, int n_in,
                              void* d_out, int out_size) {
    const float* cell = (const float*)d_in[0];
    const float* Wd   = (const float*)d_in[1];
    const float* bd   = (const float*)d_in[2];
    const float* W1   = (const float*)d_in[3];
    const float* a1s  = (const float*)d_in[4];
    const float* a1d  = (const float*)d_in[5];
    const float* b1   = (const float*)d_in[6];
    const float* Wl1  = (const float*)d_in[7];
    const float* bl1  = (const float*)d_in[8];
    const float* W2   = (const float*)d_in[9];
    const float* a2s  = (const float*)d_in[10];
    const float* a2d  = (const float*)d_in[11];
    const float* b2   = (const float*)d_in[12];
    const float* Wl2  = (const float*)d_in[13];
    const float* bl2  = (const float*)d_in[14];
    const float* Wfc  = (const float*)d_in[15];
    const float* bfc  = (const float*)d_in[16];
    const float* Whg  = (const float*)d_in[17];
    const float* bhg  = (const float*)d_in[18];
    const float* Wc   = (const float*)d_in[19];
    const float* bc   = (const float*)d_in[20];
    const float* Wv   = (const float*)d_in[21];
    const float* bv   = (const float*)d_in[22];
    const float* Wq   = (const float*)d_in[23];
    const float* bq   = (const float*)d_in[24];
    const float* h_mat  = (const float*)d_in[25];
    const float* h_bias = (const float*)d_in[26];
    const float* gamma  = (const float*)d_in[27];
    const float* beta   = (const float*)d_in[28];
    const int*   trip   = (const int*)d_in[29];
    const int*   ei     = (const int*)d_in[30];

    int N  = in_sizes[29] / 4;
    int E  = in_sizes[30] / 2;
    int CF = in_sizes[19] / 128;
    int B  = in_sizes[0] / CF;
    int H1 = in_sizes[4] / 128;   // 4
    int H2 = in_sizes[10] / 128;  // 5
    int HOUT = in_sizes[26];
    if (N > NMAX) N = NMAX;
    if (E > EMAX) E = EMAX;
    float* out = (float*)d_out;

    void *pxh, *pgat, *ph1, *ph2;
    cudaGetSymbolAddress(&pxh,  g_xh);
    cudaGetSymbolAddress(&pgat, g_gat);
    cudaGetSymbolAddress(&ph1,  g_h1);
    cudaGetSymbolAddress(&ph2,  g_h2);

    int M1 = H1 * CDIM;  // 512
    int M2 = H2 * CDIM;  // 640

    // CSR build + accumulator zeroing
    zero_kernel<<<(N + 255) / 256, 256>>>(N);
    count_kernel<<<(E + 255) / 256, 256>>>(ei, E);
    scan_kernel<<<1, 1024>>>(N);
    fill_kernel<<<(E + 255) / 256, 256>>>(ei, E);

    int mblk = (N + 127) / 128;

    // ---- GAT layer 1 (input GEMM folded through drug_linear: rank-4) ----
    wprep_kernel<<<(M1 + 127) / 128, 128>>>(Wd, bd, W1, M1);
    xh1_kernel<<<(N * (M1 / 4) + 255) / 256, 256>>>(trip, N, M1);
    esed_kernel<<<(N * H1 * 32 + 255) / 256, 256>>>((const float*)pxh, a1s, a1d, N, H1);
    agg_kernel<4><<<(N * 32 + 255) / 256, 256>>>((const float*)pxh, (float*)pgat, N);
    gemm128<<<dim3(CDIM / 64, mblk), 256>>>((const float*)pgat, Wl1, (float*)ph1,
                                            N, CDIM, M1, b1, 1, bl1);

    // ---- GAT layer 2 ----
    gemm128<<<dim3(M2 / 64, mblk), 256>>>((const float*)ph1, W2, (float*)pxh,
                                          N, M2, CDIM, nullptr, 0, nullptr);
    esed_kernel<<<(N * H2 * 32 + 255) / 256, 256>>>((const float*)pxh, a2s, a2d, N, H2);
    agg_kernel<5><<<(N * 32 + 255) / 256, 256>>>((const float*)pxh, (float*)pgat, N);
    gemm128<<<dim3(CDIM / 64, mblk), 256>>>((const float*)pgat, Wl2, (float*)ph2,
                                            N, CDIM, M2, b2, 1, bl2);

    // readout + tail
    readout_kernel<<<256, 128>>>(N);
    tail0_kernel<<<1, 384>>>(Wfc, bfc, Whg, bhg, Wv, bv, h_mat, h_bias, N, HOUT);
    tail1_kernel<<<B, 128>>>(cell, Wc, bc, Wq, bq, CF);
    tail2_kernel<<<128, B>>>(gamma, beta, out, B);
}

// round 3
// speedup vs baseline: 1.1384x; 1.0816x over previous
#include <cuda_runtime.h>
#include <cuda_bf16.h>
#include <math.h>

#define NMAX 20000
#define EMAX 500000
#define CDIM 128

// ---------------------------------------------------------------------------
// Static device scratch
// ---------------------------------------------------------------------------
__device__ float g_z2  [NMAX * 640];     // layer-2 aggregated features (pre-projection)
__device__ float g_gat [NMAX * 640];     // GAT conv outputs (pre-bias/elu)
__device__ float g_h1  [NMAX * CDIM];
__device__ float g_h2  [NMAX * CDIM];
__device__ float g_es  [NMAX * 5];
__device__ float g_ed  [NMAX * 5];
__device__ float g_tt  [NMAX * 16];      // layer-1 aggregated rank-4 coords [N, H1*4]
__device__ int   g_cnt   [NMAX];
__device__ int   g_rowptr[NMAX + 1];
__device__ int   g_cursor[NMAX];
__device__ int   g_csrc  [EMAX];
__device__ float g_hsum  [CDIM];
__device__ float g_small [1024];         // [0:384) v_, [384:768) hsumk, [768] hb
__device__ float g_logits[256 * CDIM];
__device__ float g_Wp  [4 * 512];        // folded Wd@W1
__device__ float g_bp  [512];            // folded bd@W1
__device__ float g_fold1[48];            // [0:16) vas, [16:32) vad, [32:36) vbs, [36:40) vbd
__device__ float g_fold2[128 * 10];      // [c][h(src 0..4), h(dst 5..9)]

// ---------------------------------------------------------------------------
__global__ void zero_kernel(int N) {
    int i = blockIdx.x * blockDim.x + threadIdx.x;
    if (i < N)   g_cnt[i] = 0;
    if (i < CDIM) g_hsum[i] = 0.f;
}

// ---------------------------------------------------------------------------
// CSR build
// ---------------------------------------------------------------------------
__global__ void count_kernel(const int* __restrict__ ei, int E) {
    int e = blockIdx.x * blockDim.x + threadIdx.x;
    if (e < E) {
        int s = ei[e], d = ei[E + e];
        if (s != d) atomicAdd(&g_cnt[d], 1);
    }
}

__global__ void scan_kernel(int N) {
    __shared__ int sm[1024];
    __shared__ int carry_s;
    int tid = threadIdx.x;
    if (tid == 0) { carry_s = 0; g_rowptr[0] = 0; }
    __syncthreads();
    for (int base = 0; base < N; base += 1024) {
        int v = (base + tid < N) ? g_cnt[base + tid] : 0;
        sm[tid] = v;
        __syncthreads();
        for (int off = 1; off < 1024; off <<= 1) {
            int t = (tid >= off) ? sm[tid - off] : 0;
            __syncthreads();
            sm[tid] += t;
            __syncthreads();
        }
        int carry = carry_s;
        if (base + tid < N) {
            g_rowptr[base + tid + 1] = carry + sm[tid];
            g_cursor[base + tid]     = carry + sm[tid] - v;
        }
        __syncthreads();
        if (tid == 0) carry_s += sm[1023];
        __syncthreads();
    }
}

__global__ void fill_kernel(const int* __restrict__ ei, int E) {
    int e = blockIdx.x * blockDim.x + threadIdx.x;
    if (e < E) {
        int s = ei[e], d = ei[E + e];
        if (s != d) {
            int p = atomicAdd(&g_cursor[d], 1);
            g_csrc[p] = s;
        }
    }
}

// ---------------------------------------------------------------------------
// Fold drug_linear into GAT1 input: Wp = Wd@W1 (4x512), bp = bd@W1 (512)
// ---------------------------------------------------------------------------
__global__ void wprep_kernel(const float* __restrict__ Wd,
                             const float* __restrict__ bd,
                             const float* __restrict__ W1, int M1) {
    int j = blockIdx.x * blockDim.x + threadIdx.x;
    if (j >= M1) return;
    float a0 = 0.f, a1 = 0.f, a2 = 0.f, a3 = 0.f, ab = 0.f;
#pragma unroll 4
    for (int k = 0; k < CDIM; k++) {
        float w = W1[k * M1 + j];
        a0 += Wd[0 * CDIM + k] * w;
        a1 += Wd[1 * CDIM + k] * w;
        a2 += Wd[2 * CDIM + k] * w;
        a3 += Wd[3 * CDIM + k] * w;
        ab += bd[k] * w;
    }
    g_Wp[0 * M1 + j] = a0;
    g_Wp[1 * M1 + j] = a1;
    g_Wp[2 * M1 + j] = a2;
    g_Wp[3 * M1 + j] = a3;
    g_bp[j] = ab;
}

// fold attention vectors through Wp/bp: vas[h,i] = <Wp[i, h-block], a1s[h]>, etc.
__global__ void wfold1_kernel(const float* __restrict__ a1s,
                              const float* __restrict__ a1d, int H, int M1) {
    int tid = threadIdx.x;
    int HG = H * 4;
    if (tid < HG) {                     // vas
        int h = tid >> 2, i = tid & 3;
        float s = 0.f;
        for (int k = 0; k < CDIM; k++) s += g_Wp[i * M1 + h * CDIM + k] * a1s[h * CDIM + k];
        g_fold1[tid] = s;
    } else if (tid < 2 * HG) {          // vad
        int t = tid - HG;
        int h = t >> 2, i = t & 3;
        float s = 0.f;
        for (int k = 0; k < CDIM; k++) s += g_Wp[i * M1 + h * CDIM + k] * a1d[h * CDIM + k];
        g_fold1[16 + t] = s;
    } else if (tid < 2 * HG + H) {      // vbs
        int h = tid - 2 * HG;
        float s = 0.f;
        for (int k = 0; k < CDIM; k++) s += g_bp[h * CDIM + k] * a1s[h * CDIM + k];
        g_fold1[32 + h] = s;
    } else if (tid < 2 * HG + 2 * H) {  // vbd
        int h = tid - 2 * HG - H;
        float s = 0.f;
        for (int k = 0; k < CDIM; k++) s += g_bp[h * CDIM + k] * a1d[h * CDIM + k];
        g_fold1[36 + h] = s;
    }
}

// es1[n,h] = trip4[n] . vas[h] + vbs[h]   (and ed1 with vad/vbd)
__global__ void es1_kernel(const int* __restrict__ trip, int N, int H) {
    int n = blockIdx.x * blockDim.x + threadIdx.x;
    if (n >= N) return;
    int4 tv = *(const int4*)(trip + n * 4);
    float t0 = (float)tv.x, t1 = (float)tv.y, t2 = (float)tv.z, t3 = (float)tv.w;
#pragma unroll
    for (int h = 0; h < 4; h++) {
        float s = g_fold1[32 + h] + t0 * g_fold1[h * 4 + 0] + t1 * g_fold1[h * 4 + 1]
                + t2 * g_fold1[h * 4 + 2] + t3 * g_fold1[h * 4 + 3];
        float d = g_fold1[36 + h] + t0 * g_fold1[16 + h * 4 + 0] + t1 * g_fold1[16 + h * 4 + 1]
                + t2 * g_fold1[16 + h * 4 + 2] + t3 * g_fold1[16 + h * 4 + 3];
        g_es[n * H + h] = s;
        g_ed[n * H + h] = d;
    }
}

// ---------------------------------------------------------------------------
// Layer-1 aggregation in rank-4 space: tt[n,h,0..3] = sum_e alpha_{e,h} trip4[src]
// one warp per destination node, lanes parallel over edges
// ---------------------------------------------------------------------------
template <int H>
__global__ void agg_rank4_kernel(const int* __restrict__ trip, int N) {
    int warp = (blockIdx.x * blockDim.x + threadIdx.x) >> 5;
    int lane = threadIdx.x & 31;
    if (warp >= N) return;
    int n   = warp;
    int r0  = g_rowptr[n];
    int deg = g_rowptr[n + 1] - r0;
    int tot = deg + 1;

    float edv[H], m[H], sv[H];
#pragma unroll
    for (int h = 0; h < H; h++) { edv[h] = g_ed[n * H + h]; m[h] = -1e30f; sv[h] = 0.f; }
    for (int i = lane; i < tot; i += 32) {
        int src = (i < deg) ? g_csrc[r0 + i] : n;
#pragma unroll
        for (int h = 0; h < H; h++) {
            float e = g_es[src * H + h] + edv[h];
            e = e > 0.f ? e : 0.2f * e;
            m[h] = fmaxf(m[h], e);
        }
    }
#pragma unroll
    for (int h = 0; h < H; h++)
        for (int o = 16; o; o >>= 1) m[h] = fmaxf(m[h], __shfl_xor_sync(0xffffffffu, m[h], o));
    for (int i = lane; i < tot; i += 32) {
        int src = (i < deg) ? g_csrc[r0 + i] : n;
#pragma unroll
        for (int h = 0; h < H; h++) {
            float e = g_es[src * H + h] + edv[h];
            e = e > 0.f ? e : 0.2f * e;
            sv[h] += __expf(e - m[h]);
        }
    }
#pragma unroll
    for (int h = 0; h < H; h++) {
        for (int o = 16; o; o >>= 1) sv[h] += __shfl_xor_sync(0xffffffffu, sv[h], o);
        sv[h] = 1.f / sv[h];
    }
    float4 acc[H];
#pragma unroll
    for (int h = 0; h < H; h++) acc[h] = make_float4(0.f, 0.f, 0.f, 0.f);
    for (int i = lane; i < tot; i += 32) {
        int src = (i < deg) ? g_csrc[r0 + i] : n;
        int4 tv = *(const int4*)(trip + src * 4);
        float4 tf = make_float4((float)tv.x, (float)tv.y, (float)tv.z, (float)tv.w);
#pragma unroll
        for (int h = 0; h < H; h++) {
            float e = g_es[src * H + h] + edv[h];
            e = e > 0.f ? e : 0.2f * e;
            float w = __expf(e - m[h]) * sv[h];
            acc[h].x += w * tf.x; acc[h].y += w * tf.y;
            acc[h].z += w * tf.z; acc[h].w += w * tf.w;
        }
    }
#pragma unroll
    for (int h = 0; h < H; h++) {
        for (int o = 16; o; o >>= 1) {
            acc[h].x += __shfl_xor_sync(0xffffffffu, acc[h].x, o);
            acc[h].y += __shfl_xor_sync(0xffffffffu, acc[h].y, o);
            acc[h].z += __shfl_xor_sync(0xffffffffu, acc[h].z, o);
            acc[h].w += __shfl_xor_sync(0xffffffffu, acc[h].w, o);
        }
    }
    if (lane == 0) {
#pragma unroll
        for (int h = 0; h < H; h++)
            *(float4*)(g_tt + n * 16 + h * 4) = acc[h];
    }
}

// out1[n, j] = bp[j] + sum_i tt[n, h*4+i] * Wp[i, j],  h = j>>7
__global__ void out1_kernel(int N, int M1) {
    int idx = blockIdx.x * blockDim.x + threadIdx.x;
    if (idx >= N * M1) return;
    int n = idx / M1, j = idx - n * M1;
    int h = j >> 7;
    float4 t = *(const float4*)(g_tt + n * 16 + h * 4);
    float v = g_bp[j] + t.x * g_Wp[0 * M1 + j] + t.y * g_Wp[1 * M1 + j]
            + t.z * g_Wp[2 * M1 + j] + t.w * g_Wp[3 * M1 + j];
    g_gat[(size_t)n * M1 + j] = v;
}

// ---------------------------------------------------------------------------
// 128x64 tiled fp32 GEMM, double-buffered, 8x4 microtile, strided + batched:
//   C = A' @ B (+cbias), A' = elu(A + abias) when aelu
// ---------------------------------------------------------------------------
__global__ void __launch_bounds__(256, 2)
gemm128(const float* __restrict__ A, int lda,
        const float* __restrict__ Bm, int ldb,
        float* __restrict__ Cm, int ldc,
        int M, int N, int K,
        const float* __restrict__ abias, int aelu,
        const float* __restrict__ cbias,
        int boa, int bob, int boc) {
    A  += (size_t)blockIdx.z * boa;
    Bm += (size_t)blockIdx.z * bob;
    Cm += (size_t)blockIdx.z * boc;
    __shared__ float As[2][16][132];
    __shared__ float Bs[2][16][64];
    int t  = threadIdx.x;
    int tx = t & 15, ty = t >> 4;
    int m0 = blockIdx.y * 128, n0 = blockIdx.x * 64;
    int ar = t >> 1;
    int ac = (t & 1) * 8;
    int br = t >> 4;
    int bc = (t & 15) * 4;

    float acc[8][4];
#pragma unroll
    for (int i = 0; i < 8; i++)
#pragma unroll
        for (int j = 0; j < 4; j++) acc[i][j] = 0.f;

    float4 pa0, pa1, pb;

#define LOAD_TILE(K0)                                                          \
    {                                                                          \
        pa0 = make_float4(0.f, 0.f, 0.f, 0.f);                                 \
        pa1 = pa0;                                                             \
        if (m0 + ar < M) {                                                     \
            const float* p = A + (size_t)(m0 + ar) * lda + (K0) + ac;          \
            pa0 = *(const float4*)p;                                           \
            pa1 = *(const float4*)(p + 4);                                     \
        }                                                                      \
        if (aelu) {                                                            \
            const float* bb = abias + (K0) + ac;                               \
            float vv;                                                          \
            vv = pa0.x + bb[0]; pa0.x = vv > 0.f ? vv : __expf(vv) - 1.f;      \
            vv = pa0.y + bb[1]; pa0.y = vv > 0.f ? vv : __expf(vv) - 1.f;      \
            vv = pa0.z + bb[2]; pa0.z = vv > 0.f ? vv : __expf(vv) - 1.f;      \
            vv = pa0.w + bb[3]; pa0.w = vv > 0.f ? vv : __expf(vv) - 1.f;      \
            vv = pa1.x + bb[4]; pa1.x = vv > 0.f ? vv : __expf(vv) - 1.f;      \
            vv = pa1.y + bb[5]; pa1.y = vv > 0.f ? vv : __expf(vv) - 1.f;      \
            vv = pa1.z + bb[6]; pa1.z = vv > 0.f ? vv : __expf(vv) - 1.f;      \
            vv = pa1.w + bb[7]; pa1.w = vv > 0.f ? vv : __expf(vv) - 1.f;      \
        }                                                                      \
        pb = *(const float4*)(Bm + (size_t)((K0) + br) * ldb + n0 + bc);       \
    }

#define STORE_TILE(BUF)                                                        \
    {                                                                          \
        As[BUF][ac + 0][ar] = pa0.x;                                           \
        As[BUF][ac + 1][ar] = pa0.y;                                           \
        As[BUF][ac + 2][ar] = pa0.z;                                           \
        As[BUF][ac + 3][ar] = pa0.w;                                           \
        As[BUF][ac + 4][ar] = pa1.x;                                           \
        As[BUF][ac + 5][ar] = pa1.y;                                           \
        As[BUF][ac + 6][ar] = pa1.z;                                           \
        As[BUF][ac + 7][ar] = pa1.w;                                           \
        *(float4*)&Bs[BUF][br][bc] = pb;                                       \
    }

    LOAD_TILE(0)
    STORE_TILE(0)
    __syncthreads();

    int buf = 0;
    for (int k0 = 0; k0 < K; k0 += 16) {
        int kn = k0 + 16;
        if (kn < K) LOAD_TILE(kn)
#pragma unroll
        for (int kk = 0; kk < 16; kk++) {
            float a[8], b[4];
#pragma unroll
            for (int i = 0; i < 8; i++) a[i] = As[buf][kk][ty * 8 + i];
#pragma unroll
            for (int j = 0; j < 4; j++) b[j] = Bs[buf][kk][tx * 4 + j];
#pragma unroll
            for (int i = 0; i < 8; i++)
#pragma unroll
                for (int j = 0; j < 4; j++) acc[i][j] += a[i] * b[j];
        }
        if (kn < K) STORE_TILE(buf ^ 1)
        __syncthreads();
        buf ^= 1;
    }

    float cb[4] = {0.f, 0.f, 0.f, 0.f};
    if (cbias) {
#pragma unroll
        for (int j = 0; j < 4; j++) cb[j] = cbias[n0 + tx * 4 + j];
    }
#pragma unroll
    for (int i = 0; i < 8; i++) {
        int row = m0 + ty * 8 + i;
        if (row < M) {
            float4 v;
            v.x = acc[i][0] + cb[0];
            v.y = acc[i][1] + cb[1];
            v.z = acc[i][2] + cb[2];
            v.w = acc[i][3] + cb[3];
            *(float4*)(Cm + (size_t)row * ldc + n0 + tx * 4) = v;
        }
    }
#undef LOAD_TILE
#undef STORE_TILE
}

// ---------------------------------------------------------------------------
// Layer-2 folded attention weights: wt[c, h] = <W2[c, h-block], a2s[h]> (and dst)
// ---------------------------------------------------------------------------
__global__ void wfold2_kernel(const float* __restrict__ W2,
                              const float* __restrict__ a2s,
                              const float* __restrict__ a2d, int H, int M2) {
    int tid = blockIdx.x * blockDim.x + threadIdx.x;
    if (tid >= CDIM * 2 * H) return;
    int c = tid / (2 * H), o = tid - c * (2 * H);
    int h = o % H;
    const float* av = (o < H) ? a2s : a2d;
    float s = 0.f;
    for (int k = 0; k < CDIM; k++) s += W2[c * M2 + h * CDIM + k] * av[h * CDIM + k];
    g_fold2[c * (2 * H) + o] = s;
}

// es2[n,h] = sum_c h1[n,c] * wt[c,h]; one warp per node
__global__ void es2_kernel(int N, int H) {
    __shared__ float wt[CDIM * 10];
    int tid = threadIdx.x;
    int TW = CDIM * 2 * H;
    for (int i = tid; i < TW; i += blockDim.x) wt[i] = g_fold2[i];
    __syncthreads();
    int warp = blockIdx.x * (blockDim.x >> 5) + (tid >> 5);
    int lane = tid & 31;
    if (warp >= N) return;
    float4 hv = *(const float4*)(g_h1 + (size_t)warp * CDIM + lane * 4);
    float s[10];
#pragma unroll
    for (int o = 0; o < 10; o++) s[o] = 0.f;
    float hvv[4] = {hv.x, hv.y, hv.z, hv.w};
#pragma unroll
    for (int j = 0; j < 4; j++) {
        int c = lane * 4 + j;
        for (int o = 0; o < 2 * H; o++) s[o] += hvv[j] * wt[c * (2 * H) + o];
    }
    for (int o = 0; o < 2 * H; o++)
        for (int off = 16; off; off >>= 1) s[o] += __shfl_xor_sync(0xffffffffu, s[o], off);
    if (lane < H)       g_es[warp * H + lane] = s[lane];
    else if (lane < 2 * H) g_ed[warp * H + lane - H] = s[lane];
}

// ---------------------------------------------------------------------------
// Layer-2 aggregation over 128-dim h1 features (pre-projection): z2[n,h,:]
// one warp per node; lanes = channels (float4 each); edges serial
// ---------------------------------------------------------------------------
template <int H>
__global__ void agg_feat_kernel(const float* __restrict__ feat,
                                float* __restrict__ outz, int N) {
    int warp = (blockIdx.x * blockDim.x + threadIdx.x) >> 5;
    int lane = threadIdx.x & 31;
    if (warp >= N) return;
    int n   = warp;
    int r0  = g_rowptr[n];
    int deg = g_rowptr[n + 1] - r0;
    int tot = deg + 1;

    float edv[H], m[H], sv[H];
#pragma unroll
    for (int h = 0; h < H; h++) { edv[h] = g_ed[n * H + h]; m[h] = -1e30f; sv[h] = 0.f; }
    for (int i = lane; i < tot; i += 32) {
        int src = (i < deg) ? g_csrc[r0 + i] : n;
#pragma unroll
        for (int h = 0; h < H; h++) {
            float e = g_es[src * H + h] + edv[h];
            e = e > 0.f ? e : 0.2f * e;
            m[h] = fmaxf(m[h], e);
        }
    }
#pragma unroll
    for (int h = 0; h < H; h++)
        for (int o = 16; o; o >>= 1) m[h] = fmaxf(m[h], __shfl_xor_sync(0xffffffffu, m[h], o));
    for (int i = lane; i < tot; i += 32) {
        int src = (i < deg) ? g_csrc[r0 + i] : n;
#pragma unroll
        for (int h = 0; h < H; h++) {
            float e = g_es[src * H + h] + edv[h];
            e = e > 0.f ? e : 0.2f * e;
            sv[h] += __expf(e - m[h]);
        }
    }
#pragma unroll
    for (int h = 0; h < H; h++) {
        for (int o = 16; o; o >>= 1) sv[h] += __shfl_xor_sync(0xffffffffu, sv[h], o);
        sv[h] = 1.f / sv[h];
    }
    float4 acc[H];
#pragma unroll
    for (int h = 0; h < H; h++) acc[h] = make_float4(0.f, 0.f, 0.f, 0.f);
    for (int i = 0; i < tot; i++) {
        int src = (i < deg) ? g_csrc[r0 + i] : n;
        float4 v = *(const float4*)(feat + (size_t)src * CDIM + lane * 4);
#pragma unroll
        for (int h = 0; h < H; h++) {
            float e = g_es[src * H + h] + edv[h];
            e = e > 0.f ? e : 0.2f * e;
            float w = __expf(e - m[h]) * sv[h];
            acc[h].x += w * v.x; acc[h].y += w * v.y;
            acc[h].z += w * v.z; acc[h].w += w * v.w;
        }
    }
#pragma unroll
    for (int h = 0; h < H; h++)
        *(float4*)(outz + (size_t)n * (H * CDIM) + h * CDIM + lane * 4) = acc[h];
}

// ---------------------------------------------------------------------------
// graph readout
// ---------------------------------------------------------------------------
__global__ void readout_kernel(int N) {
    int tid = threadIdx.x;
    float a = 0.f;
    for (int n = blockIdx.x; n < N; n += gridDim.x)
        a += g_h1[(size_t)n * CDIM + tid] + g_h2[(size_t)n * CDIM + tid];
    atomicAdd(&g_hsum[tid], a);
}

// ---------------------------------------------------------------------------
// tails (unchanged)
// ---------------------------------------------------------------------------
__global__ void tail0_kernel(const float* __restrict__ Wfc, const float* __restrict__ bfc,
                             const float* __restrict__ Whg, const float* __restrict__ bhg,
                             const float* __restrict__ Wv,  const float* __restrict__ bv,
                             const float* __restrict__ h_mat, const float* __restrict__ h_bias,
                             int N, int HOUT) {
    __shared__ float h[128];
    __shared__ float tm[256];
    __shared__ float hg[128];
    int tid = threadIdx.x;
    if (tid < 128) h[tid] = g_hsum[tid] / (float)N;
    __syncthreads();
    if (tid < 256) {
        float a = bfc[tid];
        for (int i = 0; i < 128; i++) a += h[i] * Wfc[i * 256 + tid];
        tm[tid] = a > 0.f ? a : 0.f;
    }
    __syncthreads();
    if (tid < 128) {
        float a = bhg[tid];
        for (int i = 0; i < 256; i++) a += tm[i] * Whg[i * 128 + tid];
        hg[tid] = a;
    }
    __syncthreads();
    if (tid < 384) {
        float a = bv[tid];
        for (int i = 0; i < 128; i++) a += hg[i] * Wv[i * 384 + tid];
        g_small[tid] = a > 0.f ? a : 0.f;
        float hs = 0.f;
        for (int hh = 0; hh < HOUT; hh++) hs += h_mat[hh * 384 + tid];
        g_small[384 + tid] = hs;
    }
    if (tid == 0) {
        float hb = 0.f;
        for (int i = 0; i < HOUT; i++) hb += h_bias[i];
        g_small[768] = hb;
    }
}

__global__ void tail1_kernel(const float* __restrict__ cell,
                             const float* __restrict__ Wc, const float* __restrict__ bc,
                             const float* __restrict__ Wq, const float* __restrict__ bq,
                             int CF) {
    __shared__ float sc[1024];
    __shared__ float crow[128];
    __shared__ float qrow[384];
    __shared__ float red[128];
    int b = blockIdx.x, tid = threadIdx.x;
    for (int i = tid; i < CF; i += 128) sc[i] = cell[(size_t)b * CF + i];
    __syncthreads();
    {
        float a = bc[tid];
        for (int k = 0; k < CF; k++) a += sc[k] * Wc[k * 128 + tid];
        crow[tid] = a > 0.f ? a : 0.f;
    }
    __syncthreads();
    float part = 0.f;
    for (int mI = tid; mI < 384; mI += 128) {
        float q = bq[mI];
        for (int k = 0; k < 128; k++) q += crow[k] * Wq[k * 384 + mI];
        q = q > 0.f ? q : 0.f;
        qrow[mI] = q;
        part += g_small[384 + mI] * g_small[mI] * q;
    }
    red[tid] = part;
    __syncthreads();
    for (int o = 64; o; o >>= 1) {
        if (tid < o) red[tid] += red[tid + o];
        __syncthreads();
    }
    float att = red[0] + g_small[768];
    float l = 0.f;
#pragma unroll
    for (int j = 0; j < 3; j++) {
        int k = tid * 3 + j;
        l += g_small[k] * qrow[k];
    }
    g_logits[b * 128 + tid] = att * l;
}

__global__ void tail2_kernel(const float* __restrict__ gamma,
                             const float* __restrict__ beta,
                             float* __restrict__ out, int B) {
    __shared__ float s1[256], s2[256];
    int c = blockIdx.x, b = threadIdx.x;
    float v = g_logits[b * 128 + c];
    s1[b] = v;
    s2[b] = v * v;
    __syncthreads();
    for (int o = B >> 1; o; o >>= 1) {
        if (b < o) { s1[b] += s1[b + o]; s2[b] += s2[b + o]; }
        __syncthreads();
    }
    float mu  = s1[0] / (float)B;
    float var = s2[0] / (float)B - mu * mu;
    out[b * 128 + c] = (v - mu) * rsqrtf(var + 1e-5f) * gamma[c] + beta[c];
}

// ---------------------------------------------------------------------------
// launch
// ---------------------------------------------------------------------------
extern "C" void kernel_launch(void* const* d_in, const int* in_sizes, int n_in,
                              void* d_out, int out_size) {
    const float* cell = (const float*)d_in[0];
    const float* Wd   = (const float*)d_in[1];
    const float* bd   = (const float*)d_in[2];
    const float* W1   = (const float*)d_in[3];
    const float* a1s  = (const float*)d_in[4];
    const float* a1d  = (const float*)d_in[5];
    const float* b1   = (const float*)d_in[6];
    const float* Wl1  = (const float*)d_in[7];
    const float* bl1  = (const float*)d_in[8];
    const float* W2   = (const float*)d_in[9];
    const float* a2s  = (const float*)d_in[10];
    const float* a2d  = (const float*)d_in[11];
    const float* b2   = (const float*)d_in[12];
    const float* Wl2  = (const float*)d_in[13];
    const float* bl2  = (const float*)d_in[14];
    const float* Wfc  = (const float*)d_in[15];
    const float* bfc  = (const float*)d_in[16];
    const float* Whg  = (const float*)d_in[17];
    const float* bhg  = (const float*)d_in[18];
    const float* Wc   = (const float*)d_in[19];
    const float* bc   = (const float*)d_in[20];
    const float* Wv   = (const float*)d_in[21];
    const float* bv   = (const float*)d_in[22];
    const float* Wq   = (const float*)d_in[23];
    const float* bq   = (const float*)d_in[24];
    const float* h_mat  = (const float*)d_in[25];
    const float* h_bias = (const float*)d_in[26];
    const float* gamma  = (const float*)d_in[27];
    const float* beta   = (const float*)d_in[28];
    const int*   trip   = (const int*)d_in[29];
    const int*   ei     = (const int*)d_in[30];

    int N  = in_sizes[29] / 4;
    int E  = in_sizes[30] / 2;
    int CF = in_sizes[19] / 128;
    int B  = in_sizes[0] / CF;
    int H1 = in_sizes[4] / 128;   // 4
    int H2 = in_sizes[10] / 128;  // 5
    int HOUT = in_sizes[26];
    if (N > NMAX) N = NMAX;
    if (E > EMAX) E = EMAX;
    float* out = (float*)d_out;

    void *pz2, *pgat, *ph1, *ph2;
    cudaGetSymbolAddress(&pz2,  g_z2);
    cudaGetSymbolAddress(&pgat, g_gat);
    cudaGetSymbolAddress(&ph1,  g_h1);
    cudaGetSymbolAddress(&ph2,  g_h2);

    int M1 = H1 * CDIM;  // 512
    int M2 = H2 * CDIM;  // 640
    int mblk = (N + 127) / 128;

    // CSR build + zero
    zero_kernel<<<(N + 255) / 256, 256>>>(N);
    count_kernel<<<(E + 255) / 256, 256>>>(ei, E);
    scan_kernel<<<1, 1024>>>(N);
    fill_kernel<<<(E + 255) / 256, 256>>>(ei, E);

    // ---- GAT layer 1 (fully rank-4 until projection) ----
    wprep_kernel<<<(M1 + 127) / 128, 128>>>(Wd, bd, W1, M1);
    wfold1_kernel<<<1, 64>>>(a1s, a1d, H1, M1);
    es1_kernel<<<(N + 255) / 256, 256>>>(trip, N, H1);
    agg_rank4_kernel<4><<<(N * 32 + 255) / 256, 256>>>(trip, N);
    out1_kernel<<<(N * M1 + 255) / 256, 256>>>(N, M1);
    gemm128<<<dim3(2, mblk), 256>>>((const float*)pgat, M1, Wl1, CDIM,
                                    (float*)ph1, CDIM, N, CDIM, M1, b1, 1, bl1, 0, 0, 0);

    // ---- GAT layer 2 (aggregate h1, then project per head) ----
    wfold2_kernel<<<(CDIM * 2 * H2 + 127) / 128, 128>>>(W2, a2s, a2d, H2, M2);
    es2_kernel<<<(N + 7) / 8, 256>>>(N, H2);
    agg_feat_kernel<5><<<(N * 32 + 255) / 256, 256>>>((const float*)ph1, (float*)pz2, N);
    // z2[:, h-block] @ W2[:, h-block] -> gat[:, h-block], batched over heads
    gemm128<<<dim3(2, mblk, H2), 256>>>((const float*)pz2, M2, W2, M2,
                                        (float*)pgat, M2, N, CDIM, CDIM,
                                        nullptr, 0, nullptr, CDIM, CDIM, CDIM);
    gemm128<<<dim3(2, mblk), 256>>>((const float*)pgat, M2, Wl2, CDIM,
                                    (float*)ph2, CDIM, N, CDIM, M2, b2, 1, bl2, 0, 0, 0);

    // readout + tail
    readout_kernel<<<256, 128>>>(N);
    tail0_kernel<<<1, 384>>>(Wfc, bfc, Whg, bhg, Wv, bv, h_mat, h_bias, N, HOUT);
    tail1_kernel<<<B, 128>>>(cell, Wc, bc, Wq, bq, CF);
    tail2_kernel<<<128, B>>>(gamma, beta, out, B);
}

// round 5
// speedup vs baseline: 1.2585x; 1.1055x over previous
#include <cuda_runtime.h>
#include <cuda_bf16.h>
#include <math.h>
#include <stdint.h>

#define NMAX 20000
#define EMAX 500000
#define CDIM 128

// ---------------------------------------------------------------------------
// Static device scratch
// ---------------------------------------------------------------------------
__device__ float g_z2  [NMAX * 640];     // layer-2 aggregated features (pre-projection)
__device__ float g_gat [NMAX * 640];     // GAT conv outputs (pre-bias/elu)
__device__ float g_h1  [NMAX * CDIM];
__device__ float g_h2  [NMAX * CDIM];
__device__ float g_es  [NMAX * 5];
__device__ float g_ed  [NMAX * 5];
__device__ float g_tt  [NMAX * 16];      // layer-1 aggregated rank-4 coords [N, H1*4]
__device__ int   g_cnt   [NMAX];
__device__ int   g_rowptr[NMAX + 1];
__device__ int   g_cursor[NMAX];
__device__ int   g_csrc  [EMAX];
__device__ float g_hsum  [CDIM];
__device__ float g_small [1024];
__device__ float g_logits[256 * CDIM];
__device__ float g_Wp  [4 * 512];        // folded Wd@W1
__device__ float g_bp  [512];            // folded bd@W1
__device__ float g_fold1[48];
__device__ float g_fold2[128 * 10];
// bf16 hi/lo transposed weights [128(N), K] K-major
__device__ __nv_bfloat16 g_bt1h[128 * 512], g_bt1l[128 * 512];         // Wl1
__device__ __nv_bfloat16 g_bt2h[5 * 128 * 128], g_bt2l[5 * 128 * 128]; // W2 per head
__device__ __nv_bfloat16 g_bt3h[128 * 640], g_bt3l[128 * 640];         // Wl2

// ---------------------------------------------------------------------------
// warp-MMA helpers (portable PTX: works on plain compute_103 target)
// ---------------------------------------------------------------------------
__device__ __forceinline__ uint32_t smem_u32(const void* p) {
    uint32_t a;
    asm("{ .reg .u64 t; cvta.to.shared.u64 t, %1; cvt.u32.u64 %0, t; }" : "=r"(a) : "l"(p));
    return a;
}
__device__ __forceinline__ void ldsm4(uint32_t* r, uint32_t addr) {
    asm volatile("ldmatrix.sync.aligned.m8n8.x4.shared.b16 {%0,%1,%2,%3}, [%4];"
                 : "=r"(r[0]), "=r"(r[1]), "=r"(r[2]), "=r"(r[3]) : "r"(addr));
}
__device__ __forceinline__ void mma16816(float* d, const uint32_t* a, const uint32_t* b) {
    asm volatile(
        "mma.sync.aligned.m16n8k16.row.col.f32.bf16.bf16.f32 "
        "{%0,%1,%2,%3}, {%4,%5,%6,%7}, {%8,%9}, {%0,%1,%2,%3};"
        : "+f"(d[0]), "+f"(d[1]), "+f"(d[2]), "+f"(d[3])
        : "r"(a[0]), "r"(a[1]), "r"(a[2]), "r"(a[3]), "r"(b[0]), "r"(b[1]));
}
__device__ __forceinline__ uint32_t pack_bf(__nv_bfloat16 a, __nv_bfloat16 b) {
    __nv_bfloat162 t;
    t.x = a; t.y = b;
    return *reinterpret_cast<uint32_t*>(&t);
}

// ---------------------------------------------------------------------------
__global__ void zero_kernel(int N) {
    int i = blockIdx.x * blockDim.x + threadIdx.x;
    if (i < N)   g_cnt[i] = 0;
    if (i < CDIM) g_hsum[i] = 0.f;
}

// ---------------------------------------------------------------------------
// CSR build
// ---------------------------------------------------------------------------
__global__ void count_kernel(const int* __restrict__ ei, int E) {
    int e = blockIdx.x * blockDim.x + threadIdx.x;
    if (e < E) {
        int s = ei[e], d = ei[E + e];
        if (s != d) atomicAdd(&g_cnt[d], 1);
    }
}

__global__ void scan_kernel(int N) {
    __shared__ int sm[1024];
    __shared__ int carry_s;
    int tid = threadIdx.x;
    if (tid == 0) { carry_s = 0; g_rowptr[0] = 0; }
    __syncthreads();
    for (int base = 0; base < N; base += 1024) {
        int v = (base + tid < N) ? g_cnt[base + tid] : 0;
        sm[tid] = v;
        __syncthreads();
        for (int off = 1; off < 1024; off <<= 1) {
            int t = (tid >= off) ? sm[tid - off] : 0;
            __syncthreads();
            sm[tid] += t;
            __syncthreads();
        }
        int carry = carry_s;
        if (base + tid < N) {
            g_rowptr[base + tid + 1] = carry + sm[tid];
            g_cursor[base + tid]     = carry + sm[tid] - v;
        }
        __syncthreads();
        if (tid == 0) carry_s += sm[1023];
        __syncthreads();
    }
}

__global__ void fill_kernel(const int* __restrict__ ei, int E) {
    int e = blockIdx.x * blockDim.x + threadIdx.x;
    if (e < E) {
        int s = ei[e], d = ei[E + e];
        if (s != d) {
            int p = atomicAdd(&g_cursor[d], 1);
            g_csrc[p] = s;
        }
    }
}

// ---------------------------------------------------------------------------
// weight prep
// ---------------------------------------------------------------------------
__global__ void wprep_kernel(const float* __restrict__ Wd,
                             const float* __restrict__ bd,
                             const float* __restrict__ W1, int M1) {
    int j = blockIdx.x * blockDim.x + threadIdx.x;
    if (j >= M1) return;
    float a0 = 0.f, a1 = 0.f, a2 = 0.f, a3 = 0.f, ab = 0.f;
#pragma unroll 4
    for (int k = 0; k < CDIM; k++) {
        float w = W1[k * M1 + j];
        a0 += Wd[0 * CDIM + k] * w;
        a1 += Wd[1 * CDIM + k] * w;
        a2 += Wd[2 * CDIM + k] * w;
        a3 += Wd[3 * CDIM + k] * w;
        ab += bd[k] * w;
    }
    g_Wp[0 * M1 + j] = a0;
    g_Wp[1 * M1 + j] = a1;
    g_Wp[2 * M1 + j] = a2;
    g_Wp[3 * M1 + j] = a3;
    g_bp[j] = ab;
}

// transpose B [K, 128] (row stride ldb, col offset blockIdx.y*128) -> bf16 hi/lo [128, K]
__global__ void btprep_kernel(const float* __restrict__ B, int ldb, int K,
                              __nv_bfloat16* __restrict__ oh,
                              __nv_bfloat16* __restrict__ ol) {
    int idx = blockIdx.x * blockDim.x + threadIdx.x;
    if (idx >= 128 * K) return;
    int j = idx / K, k = idx - j * K;
    float v = B[(size_t)k * ldb + blockIdx.y * 128 + j];
    __nv_bfloat16 h = __float2bfloat16(v);
    float r = v - __bfloat162float(h);
    size_t o = (size_t)blockIdx.y * 128 * K + idx;
    oh[o] = h;
    ol[o] = __float2bfloat16(r);
}

__global__ void wfold1_kernel(const float* __restrict__ a1s,
                              const float* __restrict__ a1d, int H, int M1) {
    int tid = threadIdx.x;
    int HG = H * 4;
    if (tid < HG) {
        int h = tid >> 2, i = tid & 3;
        float s = 0.f;
        for (int k = 0; k < CDIM; k++) s += g_Wp[i * M1 + h * CDIM + k] * a1s[h * CDIM + k];
        g_fold1[tid] = s;
    } else if (tid < 2 * HG) {
        int t = tid - HG;
        int h = t >> 2, i = t & 3;
        float s = 0.f;
        for (int k = 0; k < CDIM; k++) s += g_Wp[i * M1 + h * CDIM + k] * a1d[h * CDIM + k];
        g_fold1[16 + t] = s;
    } else if (tid < 2 * HG + H) {
        int h = tid - 2 * HG;
        float s = 0.f;
        for (int k = 0; k < CDIM; k++) s += g_bp[h * CDIM + k] * a1s[h * CDIM + k];
        g_fold1[32 + h] = s;
    } else if (tid < 2 * HG + 2 * H) {
        int h = tid - 2 * HG - H;
        float s = 0.f;
        for (int k = 0; k < CDIM; k++) s += g_bp[h * CDIM + k] * a1d[h * CDIM + k];
        g_fold1[36 + h] = s;
    }
}

__global__ void es1_kernel(const int* __restrict__ trip, int N, int H) {
    int n = blockIdx.x * blockDim.x + threadIdx.x;
    if (n >= N) return;
    int4 tv = *(const int4*)(trip + n * 4);
    float t0 = (float)tv.x, t1 = (float)tv.y, t2 = (float)tv.z, t3 = (float)tv.w;
#pragma unroll
    for (int h = 0; h < 4; h++) {
        float s = g_fold1[32 + h] + t0 * g_fold1[h * 4 + 0] + t1 * g_fold1[h * 4 + 1]
                + t2 * g_fold1[h * 4 + 2] + t3 * g_fold1[h * 4 + 3];
        float d = g_fold1[36 + h] + t0 * g_fold1[16 + h * 4 + 0] + t1 * g_fold1[16 + h * 4 + 1]
                + t2 * g_fold1[16 + h * 4 + 2] + t3 * g_fold1[16 + h * 4 + 3];
        g_es[n * H + h] = s;
        g_ed[n * H + h] = d;
    }
}

// ---------------------------------------------------------------------------
// Layer-1 aggregation in rank-4 space
// ---------------------------------------------------------------------------
template <int H>
__global__ void agg_rank4_kernel(const int* __restrict__ trip, int N) {
    int warp = (blockIdx.x * blockDim.x + threadIdx.x) >> 5;
    int lane = threadIdx.x & 31;
    if (warp >= N) return;
    int n   = warp;
    int r0  = g_rowptr[n];
    int deg = g_rowptr[n + 1] - r0;
    int tot = deg + 1;

    float edv[H], m[H], sv[H];
#pragma unroll
    for (int h = 0; h < H; h++) { edv[h] = g_ed[n * H + h]; m[h] = -1e30f; sv[h] = 0.f; }
    for (int i = lane; i < tot; i += 32) {
        int src = (i < deg) ? g_csrc[r0 + i] : n;
#pragma unroll
        for (int h = 0; h < H; h++) {
            float e = g_es[src * H + h] + edv[h];
            e = e > 0.f ? e : 0.2f * e;
            m[h] = fmaxf(m[h], e);
        }
    }
#pragma unroll
    for (int h = 0; h < H; h++)
        for (int o = 16; o; o >>= 1) m[h] = fmaxf(m[h], __shfl_xor_sync(0xffffffffu, m[h], o));
    for (int i = lane; i < tot; i += 32) {
        int src = (i < deg) ? g_csrc[r0 + i] : n;
#pragma unroll
        for (int h = 0; h < H; h++) {
            float e = g_es[src * H + h] + edv[h];
            e = e > 0.f ? e : 0.2f * e;
            sv[h] += __expf(e - m[h]);
        }
    }
#pragma unroll
    for (int h = 0; h < H; h++) {
        for (int o = 16; o; o >>= 1) sv[h] += __shfl_xor_sync(0xffffffffu, sv[h], o);
        sv[h] = 1.f / sv[h];
    }
    float4 acc[H];
#pragma unroll
    for (int h = 0; h < H; h++) acc[h] = make_float4(0.f, 0.f, 0.f, 0.f);
    for (int i = lane; i < tot; i += 32) {
        int src = (i < deg) ? g_csrc[r0 + i] : n;
        int4 tv = *(const int4*)(trip + src * 4);
        float4 tf = make_float4((float)tv.x, (float)tv.y, (float)tv.z, (float)tv.w);
#pragma unroll
        for (int h = 0; h < H; h++) {
            float e = g_es[src * H + h] + edv[h];
            e = e > 0.f ? e : 0.2f * e;
            float w = __expf(e - m[h]) * sv[h];
            acc[h].x += w * tf.x; acc[h].y += w * tf.y;
            acc[h].z += w * tf.z; acc[h].w += w * tf.w;
        }
    }
#pragma unroll
    for (int h = 0; h < H; h++) {
        for (int o = 16; o; o >>= 1) {
            acc[h].x += __shfl_xor_sync(0xffffffffu, acc[h].x, o);
            acc[h].y += __shfl_xor_sync(0xffffffffu, acc[h].y, o);
            acc[h].z += __shfl_xor_sync(0xffffffffu, acc[h].z, o);
            acc[h].w += __shfl_xor_sync(0xffffffffu, acc[h].w, o);
        }
    }
    if (lane == 0) {
#pragma unroll
        for (int h = 0; h < H; h++)
            *(float4*)(g_tt + n * 16 + h * 4) = acc[h];
    }
}

__global__ void out1_kernel(int N, int M1) {
    int idx = blockIdx.x * blockDim.x + threadIdx.x;
    if (idx >= N * M1) return;
    int n = idx / M1, j = idx - n * M1;
    int h = j >> 7;
    float4 t = *(const float4*)(g_tt + n * 16 + h * 4);
    float v = g_bp[j] + t.x * g_Wp[0 * M1 + j] + t.y * g_Wp[1 * M1 + j]
            + t.z * g_Wp[2 * M1 + j] + t.w * g_Wp[3 * M1 + j];
    g_gat[(size_t)n * M1 + j] = v;
}

// ---------------------------------------------------------------------------
// warp-MMA bf16 split GEMM: C[M,128] = elu?(A + abias) @ B (+cbias)
// A fp32 [M,K] (lda); B preconverted bf16 hi/lo [128, K] K-major (= col-major).
// CTA: 128x128 tile, 256 threads (8 warps of 32x64). K chunked by 32.
// smem row layout (128 B): [k0..31 hi | k0..31 lo] bf16, 16B-chunk xor swizzle.
// Accuracy: Ah*Bh + Al*Bh + Ah*Bl, fp32 accumulate (drop Al*Bl ~2^-16 rel).
// ---------------------------------------------------------------------------
__global__ void __launch_bounds__(256)
tgemm(const float* __restrict__ A, int lda, int boa,
      const __nv_bfloat16* __restrict__ Bth, const __nv_bfloat16* __restrict__ Btl, int bob,
      float* __restrict__ C, int ldc, int boc,
      int M, int K,
      const float* __restrict__ abias, int aelu, const float* __restrict__ cbias) {
    A   += (size_t)blockIdx.z * boa;
    Bth += (size_t)blockIdx.z * bob;
    Btl += (size_t)blockIdx.z * bob;
    C   += (size_t)blockIdx.z * boc;

    __shared__ __align__(16) __nv_bfloat16 sA[128 * 64];
    __shared__ __align__(16) __nv_bfloat16 sB[128 * 64];

    int tid  = threadIdx.x;
    int wid  = tid >> 5;
    int lane = tid & 31;
    int m0   = blockIdx.y * 128;
    int wm   = wid & 3;    // m quad: rows 32*wm
    int wn   = wid >> 2;   // n half: cols 64*wn

    float acc[2][8][4];
#pragma unroll
    for (int i = 0; i < 2; i++)
#pragma unroll
        for (int j = 0; j < 8; j++)
#pragma unroll
            for (int l = 0; l < 4; l++) acc[i][j][l] = 0.f;

    uint32_t sAu = smem_u32(sA);
    uint32_t sBu = smem_u32(sB);

    for (int kc = 0; kc < K; kc += 32) {
        // ---- stage A: 128 rows x 32 fp32 -> elu? -> bf16 hi/lo, swizzled
#pragma unroll
        for (int it = 0; it < 4; it++) {
            int idx = it * 256 + tid;      // 0..1023
            int row = idx >> 3;
            int c4  = (idx & 7) * 4;       // 0..28
            float4 v = make_float4(0.f, 0.f, 0.f, 0.f);
            int gr = m0 + row;
            if (gr < M) v = *(const float4*)(A + (size_t)gr * lda + kc + c4);
            if (aelu) {
                const float* bb = abias + kc + c4;
                float t;
                t = v.x + bb[0]; v.x = t > 0.f ? t : __expf(t) - 1.f;
                t = v.y + bb[1]; v.y = t > 0.f ? t : __expf(t) - 1.f;
                t = v.z + bb[2]; v.z = t > 0.f ? t : __expf(t) - 1.f;
                t = v.w + bb[3]; v.w = t > 0.f ? t : __expf(t) - 1.f;
            }
            __nv_bfloat16 hx = __float2bfloat16(v.x);
            __nv_bfloat16 hy = __float2bfloat16(v.y);
            __nv_bfloat16 hz = __float2bfloat16(v.z);
            __nv_bfloat16 hw = __float2bfloat16(v.w);
            uint2 hi2 = make_uint2(pack_bf(hx, hy), pack_bf(hz, hw));
            uint2 lo2 = make_uint2(
                pack_bf(__float2bfloat16(v.x - __bfloat162float(hx)),
                        __float2bfloat16(v.y - __bfloat162float(hy))),
                pack_bf(__float2bfloat16(v.z - __bfloat162float(hz)),
                        __float2bfloat16(v.w - __bfloat162float(hw))));
            int boff = c4 * 2;                 // byte offset in hi half: 0..56
            int ch   = boff >> 4;              // chunk 0..3
            int rem  = boff & 15;
            char* base = (char*)sA + row * 128;
            *(uint2*)(base + (((ch)     ^ (row & 7)) << 4) + rem) = hi2;
            *(uint2*)(base + (((ch + 4) ^ (row & 7)) << 4) + rem) = lo2;
        }
        // ---- stage B: 128 rows (n) x 32 bf16 hi + lo, swizzled
#pragma unroll
        for (int it = 0; it < 2; it++) {
            int idx = it * 256 + tid;      // 0..511
            int row = idx >> 2;
            int cg  = idx & 3;             // chunk 0..3
            uint4 vh = *(const uint4*)(Bth + (size_t)row * K + kc + cg * 8);
            uint4 vl = *(const uint4*)(Btl + (size_t)row * K + kc + cg * 8);
            char* base = (char*)sB + row * 128;
            *(uint4*)(base + (((cg)     ^ (row & 7)) << 4)) = vh;
            *(uint4*)(base + (((cg + 4) ^ (row & 7)) << 4)) = vl;
        }
        __syncthreads();

#pragma unroll
        for (int ks = 0; ks < 2; ks++) {
            uint32_t ah[2][4], al[2][4], bh[4][4], bl[4][4];
            // A fragments: mats (rows0-7 k0-7)(rows8-15 k0-7)(rows0-7 k8-15)(rows8-15 k8-15)
            int arow = (lane & 7) + ((lane >> 3) & 1) * 8;
            int akg  = 2 * ks + (lane >> 4);
#pragma unroll
            for (int mf = 0; mf < 2; mf++) {
                int r = 32 * wm + 16 * mf + arow;
                ldsm4(ah[mf], sAu + r * 128 + (((akg)     ^ (r & 7)) << 4));
                ldsm4(al[mf], sAu + r * 128 + (((akg + 4) ^ (r & 7)) << 4));
            }
            // B fragments: mats (n0-7 k0-7)(n0-7 k8-15)(n8-15 k0-7)(n8-15 k8-15)
            int brow = (lane & 7) + (lane >> 4) * 8;
            int bkg  = 2 * ks + ((lane >> 3) & 1);
#pragma unroll
            for (int q = 0; q < 4; q++) {
                int r = 64 * wn + 16 * q + brow;
                ldsm4(bh[q], sBu + r * 128 + (((bkg)     ^ (r & 7)) << 4));
                ldsm4(bl[q], sBu + r * 128 + (((bkg + 4) ^ (r & 7)) << 4));
            }
#pragma unroll
            for (int mf = 0; mf < 2; mf++) {
#pragma unroll
                for (int q = 0; q < 4; q++) {
                    mma16816(acc[mf][2 * q + 0], ah[mf], &bh[q][0]);
                    mma16816(acc[mf][2 * q + 1], ah[mf], &bh[q][2]);
                    mma16816(acc[mf][2 * q + 0], al[mf], &bh[q][0]);
                    mma16816(acc[mf][2 * q + 1], al[mf], &bh[q][2]);
                    mma16816(acc[mf][2 * q + 0], ah[mf], &bl[q][0]);
                    mma16816(acc[mf][2 * q + 1], ah[mf], &bl[q][2]);
                }
            }
        }
        __syncthreads();
    }

    // ---- epilogue: write fragments (+cbias)
#pragma unroll
    for (int mf = 0; mf < 2; mf++) {
        int r0 = m0 + 32 * wm + 16 * mf + (lane >> 2);
#pragma unroll
        for (int nf = 0; nf < 8; nf++) {
            int col = 64 * wn + 8 * nf + 2 * (lane & 3);
            float cb0 = 0.f, cb1 = 0.f;
            if (cbias) { cb0 = cbias[col]; cb1 = cbias[col + 1]; }
            if (r0 < M) {
                float2 v = make_float2(acc[mf][nf][0] + cb0, acc[mf][nf][1] + cb1);
                *(float2*)(C + (size_t)r0 * ldc + col) = v;
            }
            if (r0 + 8 < M) {
                float2 v = make_float2(acc[mf][nf][2] + cb0, acc[mf][nf][3] + cb1);
                *(float2*)(C + (size_t)(r0 + 8) * ldc + col) = v;
            }
        }
    }
}

// ---------------------------------------------------------------------------
// Layer-2 folded attention weights + logits
// ---------------------------------------------------------------------------
__global__ void wfold2_kernel(const float* __restrict__ W2,
                              const float* __restrict__ a2s,
                              const float* __restrict__ a2d, int H, int M2) {
    int tid = blockIdx.x * blockDim.x + threadIdx.x;
    if (tid >= CDIM * 2 * H) return;
    int c = tid / (2 * H), o = tid - c * (2 * H);
    int h = o % H;
    const float* av = (o < H) ? a2s : a2d;
    float s = 0.f;
    for (int k = 0; k < CDIM; k++) s += W2[c * M2 + h * CDIM + k] * av[h * CDIM + k];
    g_fold2[c * (2 * H) + o] = s;
}

__global__ void es2_kernel(int N, int H) {
    __shared__ float wt[CDIM * 10];
    int tid = threadIdx.x;
    int TW = CDIM * 2 * H;
    for (int i = tid; i < TW; i += blockDim.x) wt[i] = g_fold2[i];
    __syncthreads();
    int warp = blockIdx.x * (blockDim.x >> 5) + (tid >> 5);
    int lane = tid & 31;
    if (warp >= N) return;
    float4 hv = *(const float4*)(g_h1 + (size_t)warp * CDIM + lane * 4);
    float s[10];
#pragma unroll
    for (int o = 0; o < 10; o++) s[o] = 0.f;
    float hvv[4] = {hv.x, hv.y, hv.z, hv.w};
#pragma unroll
    for (int j = 0; j < 4; j++) {
        int c = lane * 4 + j;
        for (int o = 0; o < 2 * H; o++) s[o] += hvv[j] * wt[c * (2 * H) + o];
    }
    for (int o = 0; o < 2 * H; o++)
        for (int off = 16; off; off >>= 1) s[o] += __shfl_xor_sync(0xffffffffu, s[o], off);
    if (lane < H)          g_es[warp * H + lane] = s[lane];
    else if (lane < 2 * H) g_ed[warp * H + lane - H] = s[lane];
}

// ---------------------------------------------------------------------------
// Layer-2 aggregation over 128-dim h1 features
// ---------------------------------------------------------------------------
template <int H>
__global__ void agg_feat_kernel(const float* __restrict__ feat,
                                float* __restrict__ outz, int N) {
    int warp = (blockIdx.x * blockDim.x + threadIdx.x) >> 5;
    int lane = threadIdx.x & 31;
    if (warp >= N) return;
    int n   = warp;
    int r0  = g_rowptr[n];
    int deg = g_rowptr[n + 1] - r0;
    int tot = deg + 1;

    float edv[H], m[H], sv[H];
#pragma unroll
    for (int h = 0; h < H; h++) { edv[h] = g_ed[n * H + h]; m[h] = -1e30f; sv[h] = 0.f; }
    for (int i = lane; i < tot; i += 32) {
        int src = (i < deg) ? g_csrc[r0 + i] : n;
#pragma unroll
        for (int h = 0; h < H; h++) {
            float e = g_es[src * H + h] + edv[h];
            e = e > 0.f ? e : 0.2f * e;
            m[h] = fmaxf(m[h], e);
        }
    }
#pragma unroll
    for (int h = 0; h < H; h++)
        for (int o = 16; o; o >>= 1) m[h] = fmaxf(m[h], __shfl_xor_sync(0xffffffffu, m[h], o));
    for (int i = lane; i < tot; i += 32) {
        int src = (i < deg) ? g_csrc[r0 + i] : n;
#pragma unroll
        for (int h = 0; h < H; h++) {
            float e = g_es[src * H + h] + edv[h];
            e = e > 0.f ? e : 0.2f * e;
            sv[h] += __expf(e - m[h]);
        }
    }
#pragma unroll
    for (int h = 0; h < H; h++) {
        for (int o = 16; o; o >>= 1) sv[h] += __shfl_xor_sync(0xffffffffu, sv[h], o);
        sv[h] = 1.f / sv[h];
    }
    float4 acc[H];
#pragma unroll
    for (int h = 0; h < H; h++) acc[h] = make_float4(0.f, 0.f, 0.f, 0.f);
    for (int i = 0; i < tot; i++) {
        int src = (i < deg) ? g_csrc[r0 + i] : n;
        float4 v = *(const float4*)(feat + (size_t)src * CDIM + lane * 4);
#pragma unroll
        for (int h = 0; h < H; h++) {
            float e = g_es[src * H + h] + edv[h];
            e = e > 0.f ? e : 0.2f * e;
            float w = __expf(e - m[h]) * sv[h];
            acc[h].x += w * v.x; acc[h].y += w * v.y;
            acc[h].z += w * v.z; acc[h].w += w * v.w;
        }
    }
#pragma unroll
    for (int h = 0; h < H; h++)
        *(float4*)(outz + (size_t)n * (H * CDIM) + h * CDIM + lane * 4) = acc[h];
}

// ---------------------------------------------------------------------------
__global__ void readout_kernel(int N) {
    int tid = threadIdx.x;
    float a = 0.f;
    for (int n = blockIdx.x; n < N; n += gridDim.x)
        a += g_h1[(size_t)n * CDIM + tid] + g_h2[(size_t)n * CDIM + tid];
    atomicAdd(&g_hsum[tid], a);
}

__global__ void tail0_kernel(const float* __restrict__ Wfc, const float* __restrict__ bfc,
                             const float* __restrict__ Whg, const float* __restrict__ bhg,
                             const float* __restrict__ Wv,  const float* __restrict__ bv,
                             const float* __restrict__ h_mat, const float* __restrict__ h_bias,
                             int N, int HOUT) {
    __shared__ float h[128];
    __shared__ float tm[256];
    __shared__ float hg[128];
    int tid = threadIdx.x;
    if (tid < 128) h[tid] = g_hsum[tid] / (float)N;
    __syncthreads();
    if (tid < 256) {
        float a = bfc[tid];
        for (int i = 0; i < 128; i++) a += h[i] * Wfc[i * 256 + tid];
        tm[tid] = a > 0.f ? a : 0.f;
    }
    __syncthreads();
    if (tid < 128) {
        float a = bhg[tid];
        for (int i = 0; i < 256; i++) a += tm[i] * Whg[i * 128 + tid];
        hg[tid] = a;
    }
    __syncthreads();
    if (tid < 384) {
        float a = bv[tid];
        for (int i = 0; i < 128; i++) a += hg[i] * Wv[i * 384 + tid];
        g_small[tid] = a > 0.f ? a : 0.f;
        float hs = 0.f;
        for (int hh = 0; hh < HOUT; hh++) hs += h_mat[hh * 384 + tid];
        g_small[384 + tid] = hs;
    }
    if (tid == 0) {
        float hb = 0.f;
        for (int i = 0; i < HOUT; i++) hb += h_bias[i];
        g_small[768] = hb;
    }
}

__global__ void tail1_kernel(const float* __restrict__ cell,
                             const float* __restrict__ Wc, const float* __restrict__ bc,
                             const float* __restrict__ Wq, const float* __restrict__ bq,
                             int CF) {
    __shared__ float sc[1024];
    __shared__ float crow[128];
    __shared__ float qrow[384];
    __shared__ float red[128];
    int b = blockIdx.x, tid = threadIdx.x;
    for (int i = tid; i < CF; i += 128) sc[i] = cell[(size_t)b * CF + i];
    __syncthreads();
    {
        float a = bc[tid];
        for (int k = 0; k < CF; k++) a += sc[k] * Wc[k * 128 + tid];
        crow[tid] = a > 0.f ? a : 0.f;
    }
    __syncthreads();
    float part = 0.f;
    for (int mI = tid; mI < 384; mI += 128) {
        float q = bq[mI];
        for (int k = 0; k < 128; k++) q += crow[k] * Wq[k * 384 + mI];
        q = q > 0.f ? q : 0.f;
        qrow[mI] = q;
        part += g_small[384 + mI] * g_small[mI] * q;
    }
    red[tid] = part;
    __syncthreads();
    for (int o = 64; o; o >>= 1) {
        if (tid < o) red[tid] += red[tid + o];
        __syncthreads();
    }
    float att = red[0] + g_small[768];
    float l = 0.f;
#pragma unroll
    for (int j = 0; j < 3; j++) {
        int k = tid * 3 + j;
        l += g_small[k] * qrow[k];
    }
    g_logits[b * 128 + tid] = att * l;
}

__global__ void tail2_kernel(const float* __restrict__ gamma,
                             const float* __restrict__ beta,
                             float* __restrict__ out, int B) {
    __shared__ float s1[256], s2[256];
    int c = blockIdx.x, b = threadIdx.x;
    float v = g_logits[b * 128 + c];
    s1[b] = v;
    s2[b] = v * v;
    __syncthreads();
    for (int o = B >> 1; o; o >>= 1) {
        if (b < o) { s1[b] += s1[b + o]; s2[b] += s2[b + o]; }
        __syncthreads();
    }
    float mu  = s1[0] / (float)B;
    float var = s2[0] / (float)B - mu * mu;
    out[b * 128 + c] = (v - mu) * rsqrtf(var + 1e-5f) * gamma[c] + beta[c];
}

// ---------------------------------------------------------------------------
// launch
// ---------------------------------------------------------------------------
extern "C" void kernel_launch(void* const* d_in, const int* in_sizes, int n_in,
                              void* d_out, int out_size) {
    const float* cell = (const float*)d_in[0];
    const float* Wd   = (const float*)d_in[1];
    const float* bd   = (const float*)d_in[2];
    const float* W1   = (const float*)d_in[3];
    const float* a1s  = (const float*)d_in[4];
    const float* a1d  = (const float*)d_in[5];
    const float* b1   = (const float*)d_in[6];
    const float* Wl1  = (const float*)d_in[7];
    const float* bl1  = (const float*)d_in[8];
    const float* W2   = (const float*)d_in[9];
    const float* a2s  = (const float*)d_in[10];
    const float* a2d  = (const float*)d_in[11];
    const float* b2   = (const float*)d_in[12];
    const float* Wl2  = (const float*)d_in[13];
    const float* bl2  = (const float*)d_in[14];
    const float* Wfc  = (const float*)d_in[15];
    const float* bfc  = (const float*)d_in[16];
    const float* Whg  = (const float*)d_in[17];
    const float* bhg  = (const float*)d_in[18];
    const float* Wc   = (const float*)d_in[19];
    const float* bc   = (const float*)d_in[20];
    const float* Wv   = (const float*)d_in[21];
    const float* bv   = (const float*)d_in[22];
    const float* Wq   = (const float*)d_in[23];
    const float* bq   = (const float*)d_in[24];
    const float* h_mat  = (const float*)d_in[25];
    const float* h_bias = (const float*)d_in[26];
    const float* gamma  = (const float*)d_in[27];
    const float* beta   = (const float*)d_in[28];
    const int*   trip   = (const int*)d_in[29];
    const int*   ei     = (const int*)d_in[30];

    int N  = in_sizes[29] / 4;
    int E  = in_sizes[30] / 2;
    int CF = in_sizes[19] / 128;
    int B  = in_sizes[0] / CF;
    int H1 = in_sizes[4] / 128;   // 4
    int H2 = in_sizes[10] / 128;  // 5
    int HOUT = in_sizes[26];
    if (N > NMAX) N = NMAX;
    if (E > EMAX) E = EMAX;
    float* out = (float*)d_out;

    void *pz2, *pgat, *ph1, *ph2;
    void *pb1h, *pb1l, *pb2h, *pb2l, *pb3h, *pb3l;
    cudaGetSymbolAddress(&pz2,  g_z2);
    cudaGetSymbolAddress(&pgat, g_gat);
    cudaGetSymbolAddress(&ph1,  g_h1);
    cudaGetSymbolAddress(&ph2,  g_h2);
    cudaGetSymbolAddress(&pb1h, g_bt1h);
    cudaGetSymbolAddress(&pb1l, g_bt1l);
    cudaGetSymbolAddress(&pb2h, g_bt2h);
    cudaGetSymbolAddress(&pb2l, g_bt2l);
    cudaGetSymbolAddress(&pb3h, g_bt3h);
    cudaGetSymbolAddress(&pb3l, g_bt3l);

    int M1 = H1 * CDIM;  // 512
    int M2 = H2 * CDIM;  // 640
    int mt = (N + 127) / 128;

    // CSR build + zero
    zero_kernel<<<(N + 255) / 256, 256>>>(N);
    count_kernel<<<(E + 255) / 256, 256>>>(ei, E);
    scan_kernel<<<1, 1024>>>(N);
    fill_kernel<<<(E + 255) / 256, 256>>>(ei, E);

    // weight prep (bf16 transposed splits)
    btprep_kernel<<<dim3((128 * M1 + 255) / 256, 1), 256>>>(Wl1, 128, M1,
        (__nv_bfloat16*)pb1h, (__nv_bfloat16*)pb1l);
    btprep_kernel<<<dim3((128 * 128 + 255) / 256, H2), 256>>>(W2, M2, 128,
        (__nv_bfloat16*)pb2h, (__nv_bfloat16*)pb2l);
    btprep_kernel<<<dim3((128 * M2 + 255) / 256, 1), 256>>>(Wl2, 128, M2,
        (__nv_bfloat16*)pb3h, (__nv_bfloat16*)pb3l);

    // ---- GAT layer 1 (rank-4 until projection) ----
    wprep_kernel<<<(M1 + 127) / 128, 128>>>(Wd, bd, W1, M1);
    wfold1_kernel<<<1, 64>>>(a1s, a1d, H1, M1);
    es1_kernel<<<(N + 255) / 256, 256>>>(trip, N, H1);
    agg_rank4_kernel<4><<<(N * 32 + 255) / 256, 256>>>(trip, N);
    out1_kernel<<<(N * M1 + 255) / 256, 256>>>(N, M1);
    tgemm<<<dim3(1, mt, 1), 256>>>((const float*)pgat, M1, 0,
        (const __nv_bfloat16*)pb1h, (const __nv_bfloat16*)pb1l, 0,
        (float*)ph1, CDIM, 0, N, M1, b1, 1, bl1);

    // ---- GAT layer 2 ----
    wfold2_kernel<<<(CDIM * 2 * H2 + 127) / 128, 128>>>(W2, a2s, a2d, H2, M2);
    es2_kernel<<<(N + 7) / 8, 256>>>(N, H2);
    agg_feat_kernel<5><<<(N * 32 + 255) / 256, 256>>>((const float*)ph1, (float*)pz2, N);
    tgemm<<<dim3(1, mt, H2), 256>>>((const float*)pz2, M2, 128,
        (const __nv_bfloat16*)pb2h, (const __nv_bfloat16*)pb2l, 128 * 128,
        (float*)pgat, M2, 128, N, 128, nullptr, 0, nullptr);
    tgemm<<<dim3(1, mt, 1), 256>>>((const float*)pgat, M2, 0,
        (const __nv_bfloat16*)pb3h, (const __nv_bfloat16*)pb3l, 0,
        (float*)ph2, CDIM, 0, N, M2, b2, 1, bl2);

    // readout + tail
    readout_kernel<<<256, 128>>>(N);
    tail0_kernel<<<1, 384>>>(Wfc, bfc, Whg, bhg, Wv, bv, h_mat, h_bias, N, HOUT);
    tail1_kernel<<<B, 128>>>(cell, Wc, bc, Wq, bq, CF);
    tail2_kernel<<<128, B>>>(gamma, beta, out, B);
}

// round 6
// speedup vs baseline: 1.5660x; 1.2443x over previous
#include <cuda_runtime.h>
#include <cuda_bf16.h>
#include <math.h>
#include <stdint.h>

#define NMAX 20000
#define EMAX 500000
#define CDIM 128
#define NPAD (NMAX + 128)

// ---------------------------------------------------------------------------
// Static device scratch
// ---------------------------------------------------------------------------
__device__ float g_h1  [NMAX * CDIM];
__device__ float g_h2  [NMAX * CDIM];
__device__ float g_es  [NMAX * 5];
__device__ float g_ed  [NMAX * 5];
__device__ float g_tt  [NMAX * 16];      // layer-1 aggregated rank-4 coords
__device__ int   g_cnt   [NMAX];
__device__ int   g_rowptr[NMAX + 1];
__device__ int   g_cursor[NMAX];
__device__ int   g_csrc  [EMAX];
__device__ float g_ew    [EMAX * 5 + 8]; // per-edge softmax weights (5 heads)
__device__ float g_ewself[NMAX * 5];     // self-loop weights
__device__ float g_hsum  [CDIM];
__device__ float g_small [1024];
__device__ float g_logits[256 * CDIM];
__device__ float g_Wp  [4 * 512];
__device__ float g_bp  [512];
__device__ float g_fold1[48];
__device__ float g_fold2[128 * 10];
// bf16 hi/lo GEMM A operands (padded rows for tile overrun safety)
__device__ __nv_bfloat16 g_A1h[NPAD * 512], g_A1l[NPAD * 512];
__device__ __nv_bfloat16 g_A2h[NPAD * 640], g_A2l[NPAD * 640];
__device__ __nv_bfloat16 g_A3h[NPAD * 640], g_A3l[NPAD * 640];
// bf16 hi/lo transposed weights [128(N), K] K-major
__device__ __nv_bfloat16 g_bt1h[128 * 512], g_bt1l[128 * 512];
__device__ __nv_bfloat16 g_bt2h[5 * 128 * 128], g_bt2l[5 * 128 * 128];
__device__ __nv_bfloat16 g_bt3h[128 * 640], g_bt3l[128 * 640];

// ---------------------------------------------------------------------------
// helpers
// ---------------------------------------------------------------------------
__device__ __forceinline__ uint32_t smem_u32(const void* p) {
    uint32_t a;
    asm("{ .reg .u64 t; cvta.to.shared.u64 t, %1; cvt.u32.u64 %0, t; }" : "=r"(a) : "l"(p));
    return a;
}
__device__ __forceinline__ void ldsm4(uint32_t* r, uint32_t addr) {
    asm volatile("ldmatrix.sync.aligned.m8n8.x4.shared.b16 {%0,%1,%2,%3}, [%4];"
                 : "=r"(r[0]), "=r"(r[1]), "=r"(r[2]), "=r"(r[3]) : "r"(addr));
}
__device__ __forceinline__ void mma16816(float* d, const uint32_t* a, const uint32_t* b) {
    asm volatile(
        "mma.sync.aligned.m16n8k16.row.col.f32.bf16.bf16.f32 "
        "{%0,%1,%2,%3}, {%4,%5,%6,%7}, {%8,%9}, {%0,%1,%2,%3};"
        : "+f"(d[0]), "+f"(d[1]), "+f"(d[2]), "+f"(d[3])
        : "r"(a[0]), "r"(a[1]), "r"(a[2]), "r"(a[3]), "r"(b[0]), "r"(b[1]));
}
__device__ __forceinline__ uint32_t pack_bf(__nv_bfloat16 a, __nv_bfloat16 b) {
    __nv_bfloat162 t;
    t.x = a; t.y = b;
    return *reinterpret_cast<uint32_t*>(&t);
}
#define CPA(dst, src) \
    asm volatile("cp.async.cg.shared.global [%0], [%1], 16;" :: "r"(dst), "l"(src))

// ---------------------------------------------------------------------------
__global__ void zero_kernel(int N) {
    int i = blockIdx.x * blockDim.x + threadIdx.x;
    if (i < N)   g_cnt[i] = 0;
    if (i < CDIM) g_hsum[i] = 0.f;
}

// ---------------------------------------------------------------------------
// CSR build
// ---------------------------------------------------------------------------
__global__ void count_kernel(const int* __restrict__ ei, int E) {
    int e = blockIdx.x * blockDim.x + threadIdx.x;
    if (e < E) {
        int s = ei[e], d = ei[E + e];
        if (s != d) atomicAdd(&g_cnt[d], 1);
    }
}

__global__ void scan_kernel(int N) {
    __shared__ int sm[1024];
    __shared__ int carry_s;
    int tid = threadIdx.x;
    if (tid == 0) { carry_s = 0; g_rowptr[0] = 0; }
    __syncthreads();
    for (int base = 0; base < N; base += 1024) {
        int v = (base + tid < N) ? g_cnt[base + tid] : 0;
        sm[tid] = v;
        __syncthreads();
        for (int off = 1; off < 1024; off <<= 1) {
            int t = (tid >= off) ? sm[tid - off] : 0;
            __syncthreads();
            sm[tid] += t;
            __syncthreads();
        }
        int carry = carry_s;
        if (base + tid < N) {
            g_rowptr[base + tid + 1] = carry + sm[tid];
            g_cursor[base + tid]     = carry + sm[tid] - v;
        }
        __syncthreads();
        if (tid == 0) carry_s += sm[1023];
        __syncthreads();
    }
}

__global__ void fill_kernel(const int* __restrict__ ei, int E) {
    int e = blockIdx.x * blockDim.x + threadIdx.x;
    if (e < E) {
        int s = ei[e], d = ei[E + e];
        if (s != d) {
            int p = atomicAdd(&g_cursor[d], 1);
            g_csrc[p] = s;
        }
    }
}

// ---------------------------------------------------------------------------
// weight prep
// ---------------------------------------------------------------------------
__global__ void wprep_kernel(const float* __restrict__ Wd,
                             const float* __restrict__ bd,
                             const float* __restrict__ W1, int M1) {
    int j = blockIdx.x * blockDim.x + threadIdx.x;
    if (j >= M1) return;
    float a0 = 0.f, a1 = 0.f, a2 = 0.f, a3 = 0.f, ab = 0.f;
#pragma unroll 4
    for (int k = 0; k < CDIM; k++) {
        float w = W1[k * M1 + j];
        a0 += Wd[0 * CDIM + k] * w;
        a1 += Wd[1 * CDIM + k] * w;
        a2 += Wd[2 * CDIM + k] * w;
        a3 += Wd[3 * CDIM + k] * w;
        ab += bd[k] * w;
    }
    g_Wp[0 * M1 + j] = a0;
    g_Wp[1 * M1 + j] = a1;
    g_Wp[2 * M1 + j] = a2;
    g_Wp[3 * M1 + j] = a3;
    g_bp[j] = ab;
}

// transpose B [K, 128] -> bf16 hi/lo [128, K]
__global__ void btprep_kernel(const float* __restrict__ B, int ldb, int K,
                              __nv_bfloat16* __restrict__ oh,
                              __nv_bfloat16* __restrict__ ol) {
    int idx = blockIdx.x * blockDim.x + threadIdx.x;
    if (idx >= 128 * K) return;
    int j = idx / K, k = idx - j * K;
    float v = B[(size_t)k * ldb + blockIdx.y * 128 + j];
    __nv_bfloat16 h = __float2bfloat16(v);
    float r = v - __bfloat162float(h);
    size_t o = (size_t)blockIdx.y * 128 * K + idx;
    oh[o] = h;
    ol[o] = __float2bfloat16(r);
}

__global__ void wfold1_kernel(const float* __restrict__ a1s,
                              const float* __restrict__ a1d, int H, int M1) {
    int tid = threadIdx.x;
    int HG = H * 4;
    if (tid < HG) {
        int h = tid >> 2, i = tid & 3;
        float s = 0.f;
        for (int k = 0; k < CDIM; k++) s += g_Wp[i * M1 + h * CDIM + k] * a1s[h * CDIM + k];
        g_fold1[tid] = s;
    } else if (tid < 2 * HG) {
        int t = tid - HG;
        int h = t >> 2, i = t & 3;
        float s = 0.f;
        for (int k = 0; k < CDIM; k++) s += g_Wp[i * M1 + h * CDIM + k] * a1d[h * CDIM + k];
        g_fold1[16 + t] = s;
    } else if (tid < 2 * HG + H) {
        int h = tid - 2 * HG;
        float s = 0.f;
        for (int k = 0; k < CDIM; k++) s += g_bp[h * CDIM + k] * a1s[h * CDIM + k];
        g_fold1[32 + h] = s;
    } else if (tid < 2 * HG + 2 * H) {
        int h = tid - 2 * HG - H;
        float s = 0.f;
        for (int k = 0; k < CDIM; k++) s += g_bp[h * CDIM + k] * a1d[h * CDIM + k];
        g_fold1[36 + h] = s;
    }
}

__global__ void es1_kernel(const int* __restrict__ trip, int N, int H) {
    int n = blockIdx.x * blockDim.x + threadIdx.x;
    if (n >= N) return;
    int4 tv = *(const int4*)(trip + n * 4);
    float t0 = (float)tv.x, t1 = (float)tv.y, t2 = (float)tv.z, t3 = (float)tv.w;
#pragma unroll
    for (int h = 0; h < 4; h++) {
        float s = g_fold1[32 + h] + t0 * g_fold1[h * 4 + 0] + t1 * g_fold1[h * 4 + 1]
                + t2 * g_fold1[h * 4 + 2] + t3 * g_fold1[h * 4 + 3];
        float d = g_fold1[36 + h] + t0 * g_fold1[16 + h * 4 + 0] + t1 * g_fold1[16 + h * 4 + 1]
                + t2 * g_fold1[16 + h * 4 + 2] + t3 * g_fold1[16 + h * 4 + 3];
        g_es[n * H + h] = s;
        g_ed[n * H + h] = d;
    }
}

// ---------------------------------------------------------------------------
// Layer-1 aggregation in rank-4 space
// ---------------------------------------------------------------------------
template <int H>
__global__ void agg_rank4_kernel(const int* __restrict__ trip, int N) {
    int warp = (blockIdx.x * blockDim.x + threadIdx.x) >> 5;
    int lane = threadIdx.x & 31;
    if (warp >= N) return;
    int n   = warp;
    int r0  = g_rowptr[n];
    int deg = g_rowptr[n + 1] - r0;
    int tot = deg + 1;

    float edv[H], m[H], sv[H];
#pragma unroll
    for (int h = 0; h < H; h++) { edv[h] = g_ed[n * H + h]; m[h] = -1e30f; sv[h] = 0.f; }
    for (int i = lane; i < tot; i += 32) {
        int src = (i < deg) ? g_csrc[r0 + i] : n;
#pragma unroll
        for (int h = 0; h < H; h++) {
            float e = g_es[src * H + h] + edv[h];
            e = e > 0.f ? e : 0.2f * e;
            m[h] = fmaxf(m[h], e);
        }
    }
#pragma unroll
    for (int h = 0; h < H; h++)
        for (int o = 16; o; o >>= 1) m[h] = fmaxf(m[h], __shfl_xor_sync(0xffffffffu, m[h], o));
    for (int i = lane; i < tot; i += 32) {
        int src = (i < deg) ? g_csrc[r0 + i] : n;
#pragma unroll
        for (int h = 0; h < H; h++) {
            float e = g_es[src * H + h] + edv[h];
            e = e > 0.f ? e : 0.2f * e;
            sv[h] += __expf(e - m[h]);
        }
    }
#pragma unroll
    for (int h = 0; h < H; h++) {
        for (int o = 16; o; o >>= 1) sv[h] += __shfl_xor_sync(0xffffffffu, sv[h], o);
        sv[h] = 1.f / sv[h];
    }
    float4 acc[H];
#pragma unroll
    for (int h = 0; h < H; h++) acc[h] = make_float4(0.f, 0.f, 0.f, 0.f);
    for (int i = lane; i < tot; i += 32) {
        int src = (i < deg) ? g_csrc[r0 + i] : n;
        int4 tv = *(const int4*)(trip + src * 4);
        float4 tf = make_float4((float)tv.x, (float)tv.y, (float)tv.z, (float)tv.w);
#pragma unroll
        for (int h = 0; h < H; h++) {
            float e = g_es[src * H + h] + edv[h];
            e = e > 0.f ? e : 0.2f * e;
            float w = __expf(e - m[h]) * sv[h];
            acc[h].x += w * tf.x; acc[h].y += w * tf.y;
            acc[h].z += w * tf.z; acc[h].w += w * tf.w;
        }
    }
#pragma unroll
    for (int h = 0; h < H; h++) {
        for (int o = 16; o; o >>= 1) {
            acc[h].x += __shfl_xor_sync(0xffffffffu, acc[h].x, o);
            acc[h].y += __shfl_xor_sync(0xffffffffu, acc[h].y, o);
            acc[h].z += __shfl_xor_sync(0xffffffffu, acc[h].z, o);
            acc[h].w += __shfl_xor_sync(0xffffffffu, acc[h].w, o);
        }
    }
    if (lane == 0) {
#pragma unroll
        for (int h = 0; h < H; h++)
            *(float4*)(g_tt + n * 16 + h * 4) = acc[h];
    }
}

// out1: A1 = elu(tt@Wp + bp + b1), emitted as bf16 hi/lo. 2 elems/thread.
__global__ void out1_kernel(const float* __restrict__ b1, int N, int M1) {
    int half = M1 >> 1;
    int idx = blockIdx.x * blockDim.x + threadIdx.x;
    if (idx >= N * half) return;
    int n = idx / half, j = (idx - n * half) * 2;
    int h = j >> 7;
    float4 t = *(const float4*)(g_tt + n * 16 + h * 4);
    float v0 = g_bp[j] + b1[j] + t.x * g_Wp[0 * M1 + j] + t.y * g_Wp[1 * M1 + j]
             + t.z * g_Wp[2 * M1 + j] + t.w * g_Wp[3 * M1 + j];
    int j1 = j + 1;
    float v1 = g_bp[j1] + b1[j1] + t.x * g_Wp[0 * M1 + j1] + t.y * g_Wp[1 * M1 + j1]
             + t.z * g_Wp[2 * M1 + j1] + t.w * g_Wp[3 * M1 + j1];
    v0 = v0 > 0.f ? v0 : __expf(v0) - 1.f;
    v1 = v1 > 0.f ? v1 : __expf(v1) - 1.f;
    __nv_bfloat16 h0 = __float2bfloat16(v0);
    __nv_bfloat16 h1 = __float2bfloat16(v1);
    size_t o = (size_t)n * M1 + j;
    *(uint32_t*)(g_A1h + o) = pack_bf(h0, h1);
    *(uint32_t*)(g_A1l + o) = pack_bf(__float2bfloat16(v0 - __bfloat162float(h0)),
                                      __float2bfloat16(v1 - __bfloat162float(h1)));
}

// ---------------------------------------------------------------------------
// cp.async double-buffered warp-MMA bf16 split GEMM.
// A: bf16 hi/lo [M_pad, lda]; B: bf16 hi/lo [128, K] K-major.
// Out: fp32 (Cf) or bias+elu?+bf16 hi/lo (Ch/Cl).
// CTA 128x128 tile, 256 threads, K chunked by 32, 2-stage pipeline.
// ---------------------------------------------------------------------------
__global__ void __launch_bounds__(256)
tgemm(const __nv_bfloat16* __restrict__ Ah, const __nv_bfloat16* __restrict__ Al,
      int lda, int boa,
      const __nv_bfloat16* __restrict__ Bh, const __nv_bfloat16* __restrict__ Bl, int bob,
      float* __restrict__ Cf, __nv_bfloat16* __restrict__ Ch, __nv_bfloat16* __restrict__ Cl,
      int ldc, int boc,
      int M, int K, const float* __restrict__ cbias, int bocb, int celu) {
    Ah += (size_t)blockIdx.z * boa;
    Al += (size_t)blockIdx.z * boa;
    Bh += (size_t)blockIdx.z * bob;
    Bl += (size_t)blockIdx.z * bob;
    if (Cf) Cf += (size_t)blockIdx.z * boc;
    if (Ch) { Ch += (size_t)blockIdx.z * boc; Cl += (size_t)blockIdx.z * boc; }
    cbias += (size_t)blockIdx.z * bocb;

    extern __shared__ __align__(16) char dsm[];
    uint32_t sAu = smem_u32(dsm);            // A: 2 x 16KB
    uint32_t sBu = sAu + 32768;              // B: 2 x 16KB

    int tid  = threadIdx.x;
    int wid  = tid >> 5;
    int lane = tid & 31;
    int m0   = blockIdx.y * 128;
    int wm   = wid & 3;
    int wn   = wid >> 2;

    float acc[2][8][4];
#pragma unroll
    for (int i = 0; i < 2; i++)
#pragma unroll
        for (int j = 0; j < 8; j++)
#pragma unroll
            for (int l = 0; l < 4; l++) acc[i][j][l] = 0.f;

#define STAGE(BUF, KC)                                                         \
    {                                                                          \
        int _kc = (KC);                                                        \
        _Pragma("unroll")                                                      \
        for (int it = 0; it < 4; it++) {                                       \
            int idx = it * 256 + tid;                                          \
            int row = idx >> 3, ch = idx & 7;                                  \
            const __nv_bfloat16* gs = ((ch < 4) ? Ah : Al)                     \
                + (size_t)(m0 + row) * lda + _kc + (ch & 3) * 8;               \
            uint32_t dst = sAu + (BUF) * 16384 + row * 128                     \
                + ((ch ^ (row & 7)) << 4);                                     \
            CPA(dst, gs);                                                      \
        }                                                                      \
        _Pragma("unroll")                                                      \
        for (int it = 0; it < 4; it++) {                                       \
            int idx = it * 256 + tid;                                          \
            int row = idx >> 3, ch = idx & 7;                                  \
            const __nv_bfloat16* gs = ((ch < 4) ? Bh : Bl)                     \
                + (size_t)row * K + _kc + (ch & 3) * 8;                        \
            uint32_t dst = sBu + (BUF) * 16384 + row * 128                     \
                + ((ch ^ (row & 7)) << 4);                                     \
            CPA(dst, gs);                                                      \
        }                                                                      \
    }

    int nk = K >> 5;
    STAGE(0, 0)
    asm volatile("cp.async.commit_group;");

    for (int i = 0; i < nk; i++) {
        int buf = i & 1;
        if (i + 1 < nk) {
            STAGE(buf ^ 1, (i + 1) * 32)
            asm volatile("cp.async.commit_group;");
            asm volatile("cp.async.wait_group 1;");
        } else {
            asm volatile("cp.async.wait_group 0;");
        }
        __syncthreads();

        uint32_t a_base = sAu + buf * 16384;
        uint32_t b_base = sBu + buf * 16384;
#pragma unroll
        for (int ks = 0; ks < 2; ks++) {
            uint32_t ah[2][4], al[2][4], bh[4][4], bl[4][4];
            int arow = (lane & 7) + ((lane >> 3) & 1) * 8;
            int akg  = 2 * ks + (lane >> 4);
#pragma unroll
            for (int mf = 0; mf < 2; mf++) {
                int r = 32 * wm + 16 * mf + arow;
                ldsm4(ah[mf], a_base + r * 128 + (((akg)     ^ (r & 7)) << 4));
                ldsm4(al[mf], a_base + r * 128 + (((akg + 4) ^ (r & 7)) << 4));
            }
            int brow = (lane & 7) + (lane >> 4) * 8;
            int bkg  = 2 * ks + ((lane >> 3) & 1);
#pragma unroll
            for (int q = 0; q < 4; q++) {
                int r = 64 * wn + 16 * q + brow;
                ldsm4(bh[q], b_base + r * 128 + (((bkg)     ^ (r & 7)) << 4));
                ldsm4(bl[q], b_base + r * 128 + (((bkg + 4) ^ (r & 7)) << 4));
            }
#pragma unroll
            for (int mf = 0; mf < 2; mf++) {
#pragma unroll
                for (int q = 0; q < 4; q++) {
                    mma16816(acc[mf][2 * q + 0], ah[mf], &bh[q][0]);
                    mma16816(acc[mf][2 * q + 1], ah[mf], &bh[q][2]);
                    mma16816(acc[mf][2 * q + 0], al[mf], &bh[q][0]);
                    mma16816(acc[mf][2 * q + 1], al[mf], &bh[q][2]);
                    mma16816(acc[mf][2 * q + 0], ah[mf], &bl[q][0]);
                    mma16816(acc[mf][2 * q + 1], ah[mf], &bl[q][2]);
                }
            }
        }
        __syncthreads();
    }
#undef STAGE

    // epilogue
#pragma unroll
    for (int mf = 0; mf < 2; mf++) {
        int r0 = m0 + 32 * wm + 16 * mf + (lane >> 2);
#pragma unroll
        for (int nf = 0; nf < 8; nf++) {
            int col = 64 * wn + 8 * nf + 2 * (lane & 3);
            float cb0 = cbias[col], cb1 = cbias[col + 1];
#pragma unroll
            for (int rr = 0; rr < 2; rr++) {
                int r = r0 + rr * 8;
                if (r >= M) continue;
                float v0 = acc[mf][nf][2 * rr + 0] + cb0;
                float v1 = acc[mf][nf][2 * rr + 1] + cb1;
                if (Cf) {
                    *(float2*)(Cf + (size_t)r * ldc + col) = make_float2(v0, v1);
                } else {
                    if (celu) {
                        v0 = v0 > 0.f ? v0 : __expf(v0) - 1.f;
                        v1 = v1 > 0.f ? v1 : __expf(v1) - 1.f;
                    }
                    __nv_bfloat16 h0 = __float2bfloat16(v0);
                    __nv_bfloat16 h1 = __float2bfloat16(v1);
                    size_t o = (size_t)r * ldc + col;
                    *(uint32_t*)(Ch + o) = pack_bf(h0, h1);
                    *(uint32_t*)(Cl + o) =
                        pack_bf(__float2bfloat16(v0 - __bfloat162float(h0)),
                                __float2bfloat16(v1 - __bfloat162float(h1)));
                }
            }
        }
    }
}

// ---------------------------------------------------------------------------
// Layer-2 folded attention weights + logits
// ---------------------------------------------------------------------------
__global__ void wfold2_kernel(const float* __restrict__ W2,
                              const float* __restrict__ a2s,
                              const float* __restrict__ a2d, int H, int M2) {
    int tid = blockIdx.x * blockDim.x + threadIdx.x;
    if (tid >= CDIM * 2 * H) return;
    int c = tid / (2 * H), o = tid - c * (2 * H);
    int h = o % H;
    const float* av = (o < H) ? a2s : a2d;
    float s = 0.f;
    for (int k = 0; k < CDIM; k++) s += W2[c * M2 + h * CDIM + k] * av[h * CDIM + k];
    g_fold2[c * (2 * H) + o] = s;
}

__global__ void es2_kernel(int N, int H) {
    __shared__ float wt[CDIM * 10];
    int tid = threadIdx.x;
    int TW = CDIM * 2 * H;
    for (int i = tid; i < TW; i += blockDim.x) wt[i] = g_fold2[i];
    __syncthreads();
    int warp = blockIdx.x * (blockDim.x >> 5) + (tid >> 5);
    int lane = tid & 31;
    if (warp >= N) return;
    float4 hv = *(const float4*)(g_h1 + (size_t)warp * CDIM + lane * 4);
    float s[10];
#pragma unroll
    for (int o = 0; o < 10; o++) s[o] = 0.f;
    float hvv[4] = {hv.x, hv.y, hv.z, hv.w};
#pragma unroll
    for (int j = 0; j < 4; j++) {
        int c = lane * 4 + j;
        for (int o = 0; o < 2 * H; o++) s[o] += hvv[j] * wt[c * (2 * H) + o];
    }
    for (int o = 0; o < 2 * H; o++)
        for (int off = 16; off; off >>= 1) s[o] += __shfl_xor_sync(0xffffffffu, s[o], off);
    if (lane < H)          g_es[warp * H + lane] = s[lane];
    else if (lane < 2 * H) g_ed[warp * H + lane - H] = s[lane];
}

// ---------------------------------------------------------------------------
// Layer-2: precompute normalized softmax weights per (edge, head)
// ---------------------------------------------------------------------------
template <int H>
__global__ void aggw_kernel(int N) {
    int warp = (blockIdx.x * blockDim.x + threadIdx.x) >> 5;
    int lane = threadIdx.x & 31;
    if (warp >= N) return;
    int n   = warp;
    int r0  = g_rowptr[n];
    int deg = g_rowptr[n + 1] - r0;
    int tot = deg + 1;

    float edv[H], m[H], sv[H];
#pragma unroll
    for (int h = 0; h < H; h++) { edv[h] = g_ed[n * H + h]; m[h] = -1e30f; sv[h] = 0.f; }
    for (int i = lane; i < tot; i += 32) {
        int src = (i < deg) ? g_csrc[r0 + i] : n;
#pragma unroll
        for (int h = 0; h < H; h++) {
            float e = g_es[src * H + h] + edv[h];
            e = e > 0.f ? e : 0.2f * e;
            m[h] = fmaxf(m[h], e);
        }
    }
#pragma unroll
    for (int h = 0; h < H; h++)
        for (int o = 16; o; o >>= 1) m[h] = fmaxf(m[h], __shfl_xor_sync(0xffffffffu, m[h], o));
    for (int i = lane; i < tot; i += 32) {
        int src = (i < deg) ? g_csrc[r0 + i] : n;
#pragma unroll
        for (int h = 0; h < H; h++) {
            float e = g_es[src * H + h] + edv[h];
            e = e > 0.f ? e : 0.2f * e;
            sv[h] += __expf(e - m[h]);
        }
    }
#pragma unroll
    for (int h = 0; h < H; h++) {
        for (int o = 16; o; o >>= 1) sv[h] += __shfl_xor_sync(0xffffffffu, sv[h], o);
        sv[h] = 1.f / sv[h];
    }
    for (int i = lane; i < tot; i += 32) {
        int src = (i < deg) ? g_csrc[r0 + i] : n;
        float* wdst = (i < deg) ? (g_ew + (size_t)(r0 + i) * H) : (g_ewself + (size_t)n * H);
#pragma unroll
        for (int h = 0; h < H; h++) {
            float e = g_es[src * H + h] + edv[h];
            e = e > 0.f ? e : 0.2f * e;
            wdst[h] = __expf(e - m[h]) * sv[h];
        }
    }
}

// ---------------------------------------------------------------------------
// Layer-2 gather with precomputed weights; emits z2 as bf16 hi/lo
// ---------------------------------------------------------------------------
template <int H>
__global__ void aggg_kernel(const float* __restrict__ feat, int N) {
    int warp = (blockIdx.x * blockDim.x + threadIdx.x) >> 5;
    int lane = threadIdx.x & 31;
    if (warp >= N) return;
    int n   = warp;
    int r0  = g_rowptr[n];
    int deg = g_rowptr[n + 1] - r0;

    float4 acc[H];
#pragma unroll
    for (int h = 0; h < H; h++) acc[h] = make_float4(0.f, 0.f, 0.f, 0.f);
    for (int i = 0; i < deg; i++) {
        int src = g_csrc[r0 + i];
        const float* wp = g_ew + (size_t)(r0 + i) * H;
        float4 v = *(const float4*)(feat + (size_t)src * CDIM + lane * 4);
#pragma unroll
        for (int h = 0; h < H; h++) {
            float w = wp[h];
            acc[h].x += w * v.x; acc[h].y += w * v.y;
            acc[h].z += w * v.z; acc[h].w += w * v.w;
        }
    }
    {   // self loop
        const float* wp = g_ewself + (size_t)n * H;
        float4 v = *(const float4*)(feat + (size_t)n * CDIM + lane * 4);
#pragma unroll
        for (int h = 0; h < H; h++) {
            float w = wp[h];
            acc[h].x += w * v.x; acc[h].y += w * v.y;
            acc[h].z += w * v.z; acc[h].w += w * v.w;
        }
    }
#pragma unroll
    for (int h = 0; h < H; h++) {
        __nv_bfloat16 hx = __float2bfloat16(acc[h].x);
        __nv_bfloat16 hy = __float2bfloat16(acc[h].y);
        __nv_bfloat16 hz = __float2bfloat16(acc[h].z);
        __nv_bfloat16 hw = __float2bfloat16(acc[h].w);
        size_t o = (size_t)n * (H * CDIM) + h * CDIM + lane * 4;
        *(uint2*)(g_A2h + o) = make_uint2(pack_bf(hx, hy), pack_bf(hz, hw));
        *(uint2*)(g_A2l + o) = make_uint2(
            pack_bf(__float2bfloat16(acc[h].x - __bfloat162float(hx)),
                    __float2bfloat16(acc[h].y - __bfloat162float(hy))),
            pack_bf(__float2bfloat16(acc[h].z - __bfloat162float(hz)),
                    __float2bfloat16(acc[h].w - __bfloat162float(hw))));
    }
}

// ---------------------------------------------------------------------------
__global__ void readout_kernel(int N) {
    int tid = threadIdx.x;
    float a = 0.f;
    for (int n = blockIdx.x; n < N; n += gridDim.x)
        a += g_h1[(size_t)n * CDIM + tid] + g_h2[(size_t)n * CDIM + tid];
    atomicAdd(&g_hsum[tid], a);
}

__global__ void tail0_kernel(const float* __restrict__ Wfc, const float* __restrict__ bfc,
                             const float* __restrict__ Whg, const float* __restrict__ bhg,
                             const float* __restrict__ Wv,  const float* __restrict__ bv,
                             const float* __restrict__ h_mat, const float* __restrict__ h_bias,
                             int N, int HOUT) {
    __shared__ float h[128];
    __shared__ float tm[256];
    __shared__ float hg[128];
    int tid = threadIdx.x;
    if (tid < 128) h[tid] = g_hsum[tid] / (float)N;
    __syncthreads();
    if (tid < 256) {
        float a = bfc[tid];
        for (int i = 0; i < 128; i++) a += h[i] * Wfc[i * 256 + tid];
        tm[tid] = a > 0.f ? a : 0.f;
    }
    __syncthreads();
    if (tid < 128) {
        float a = bhg[tid];
        for (int i = 0; i < 256; i++) a += tm[i] * Whg[i * 128 + tid];
        hg[tid] = a;
    }
    __syncthreads();
    if (tid < 384) {
        float a = bv[tid];
        for (int i = 0; i < 128; i++) a += hg[i] * Wv[i * 384 + tid];
        g_small[tid] = a > 0.f ? a : 0.f;
        float hs = 0.f;
        for (int hh = 0; hh < HOUT; hh++) hs += h_mat[hh * 384 + tid];
        g_small[384 + tid] = hs;
    }
    if (tid == 0) {
        float hb = 0.f;
        for (int i = 0; i < HOUT; i++) hb += h_bias[i];
        g_small[768] = hb;
    }
}

__global__ void tail1_kernel(const float* __restrict__ cell,
                             const float* __restrict__ Wc, const float* __restrict__ bc,
                             const float* __restrict__ Wq, const float* __restrict__ bq,
                             int CF) {
    __shared__ float sc[1024];
    __shared__ float crow[128];
    __shared__ float qrow[384];
    __shared__ float red[128];
    int b = blockIdx.x, tid = threadIdx.x;
    for (int i = tid; i < CF; i += 128) sc[i] = cell[(size_t)b * CF + i];
    __syncthreads();
    {
        float a = bc[tid];
        for (int k = 0; k < CF; k++) a += sc[k] * Wc[k * 128 + tid];
        crow[tid] = a > 0.f ? a : 0.f;
    }
    __syncthreads();
    float part = 0.f;
    for (int mI = tid; mI < 384; mI += 128) {
        float q = bq[mI];
        for (int k = 0; k < 128; k++) q += crow[k] * Wq[k * 384 + mI];
        q = q > 0.f ? q : 0.f;
        qrow[mI] = q;
        part += g_small[384 + mI] * g_small[mI] * q;
    }
    red[tid] = part;
    __syncthreads();
    for (int o = 64; o; o >>= 1) {
        if (tid < o) red[tid] += red[tid + o];
        __syncthreads();
    }
    float att = red[0] + g_small[768];
    float l = 0.f;
#pragma unroll
    for (int j = 0; j < 3; j++) {
        int k = tid * 3 + j;
        l += g_small[k] * qrow[k];
    }
    g_logits[b * 128 + tid] = att * l;
}

__global__ void tail2_kernel(const float* __restrict__ gamma,
                             const float* __restrict__ beta,
                             float* __restrict__ out, int B) {
    __shared__ float s1[256], s2[256];
    int c = blockIdx.x, b = threadIdx.x;
    float v = g_logits[b * 128 + c];
    s1[b] = v;
    s2[b] = v * v;
    __syncthreads();
    for (int o = B >> 1; o; o >>= 1) {
        if (b < o) { s1[b] += s1[b + o]; s2[b] += s2[b + o]; }
        __syncthreads();
    }
    float mu  = s1[0] / (float)B;
    float var = s2[0] / (float)B - mu * mu;
    out[b * 128 + c] = (v - mu) * rsqrtf(var + 1e-5f) * gamma[c] + beta[c];
}

// ---------------------------------------------------------------------------
// launch
// ---------------------------------------------------------------------------
extern "C" void kernel_launch(void* const* d_in, const int* in_sizes, int n_in,
                              void* d_out, int out_size) {
    const float* cell = (const float*)d_in[0];
    const float* Wd   = (const float*)d_in[1];
    const float* bd   = (const float*)d_in[2];
    const float* W1   = (const float*)d_in[3];
    const float* a1s  = (const float*)d_in[4];
    const float* a1d  = (const float*)d_in[5];
    const float* b1   = (const float*)d_in[6];
    const float* Wl1  = (const float*)d_in[7];
    const float* bl1  = (const float*)d_in[8];
    const float* W2   = (const float*)d_in[9];
    const float* a2s  = (const float*)d_in[10];
    const float* a2d  = (const float*)d_in[11];
    const float* b2   = (const float*)d_in[12];
    const float* Wl2  = (const float*)d_in[13];
    const float* bl2  = (const float*)d_in[14];
    const float* Wfc  = (const float*)d_in[15];
    const float* bfc  = (const float*)d_in[16];
    const float* Whg  = (const float*)d_in[17];
    const float* bhg  = (const float*)d_in[18];
    const float* Wc   = (const float*)d_in[19];
    const float* bc   = (const float*)d_in[20];
    const float* Wv   = (const float*)d_in[21];
    const float* bv   = (const float*)d_in[22];
    const float* Wq   = (const float*)d_in[23];
    const float* bq   = (const float*)d_in[24];
    const float* h_mat  = (const float*)d_in[25];
    const float* h_bias = (const float*)d_in[26];
    const float* gamma  = (const float*)d_in[27];
    const float* beta   = (const float*)d_in[28];
    const int*   trip   = (const int*)d_in[29];
    const int*   ei     = (const int*)d_in[30];

    int N  = in_sizes[29] / 4;
    int E  = in_sizes[30] / 2;
    int CF = in_sizes[19] / 128;
    int B  = in_sizes[0] / CF;
    int H1 = in_sizes[4] / 128;   // 4
    int H2 = in_sizes[10] / 128;  // 5
    int HOUT = in_sizes[26];
    if (N > NMAX) N = NMAX;
    if (E > EMAX) E = EMAX;
    float* out = (float*)d_out;

    void *ph1, *ph2;
    void *pA1h, *pA1l, *pA2h, *pA2l, *pA3h, *pA3l;
    void *pb1h, *pb1l, *pb2h, *pb2l, *pb3h, *pb3l;
    cudaGetSymbolAddress(&ph1,  g_h1);
    cudaGetSymbolAddress(&ph2,  g_h2);
    cudaGetSymbolAddress(&pA1h, g_A1h);
    cudaGetSymbolAddress(&pA1l, g_A1l);
    cudaGetSymbolAddress(&pA2h, g_A2h);
    cudaGetSymbolAddress(&pA2l, g_A2l);
    cudaGetSymbolAddress(&pA3h, g_A3h);
    cudaGetSymbolAddress(&pA3l, g_A3l);
    cudaGetSymbolAddress(&pb1h, g_bt1h);
    cudaGetSymbolAddress(&pb1l, g_bt1l);
    cudaGetSymbolAddress(&pb2h, g_bt2h);
    cudaGetSymbolAddress(&pb2l, g_bt2l);
    cudaGetSymbolAddress(&pb3h, g_bt3h);
    cudaGetSymbolAddress(&pb3l, g_bt3l);

    cudaFuncSetAttribute(tgemm, cudaFuncAttributeMaxDynamicSharedMemorySize, 65536);

    int M1 = H1 * CDIM;  // 512
    int M2 = H2 * CDIM;  // 640
    int mt = (N + 127) / 128;

    // CSR build + zero
    zero_kernel<<<(N + 255) / 256, 256>>>(N);
    count_kernel<<<(E + 255) / 256, 256>>>(ei, E);
    scan_kernel<<<1, 1024>>>(N);
    fill_kernel<<<(E + 255) / 256, 256>>>(ei, E);

    // weight prep (bf16 transposed splits)
    btprep_kernel<<<dim3((128 * M1 + 255) / 256, 1), 256>>>(Wl1, 128, M1,
        (__nv_bfloat16*)pb1h, (__nv_bfloat16*)pb1l);
    btprep_kernel<<<dim3((128 * 128 + 255) / 256, H2), 256>>>(W2, M2, 128,
        (__nv_bfloat16*)pb2h, (__nv_bfloat16*)pb2l);
    btprep_kernel<<<dim3((128 * M2 + 255) / 256, 1), 256>>>(Wl2, 128, M2,
        (__nv_bfloat16*)pb3h, (__nv_bfloat16*)pb3l);

    // ---- GAT layer 1 (rank-4 until projection) ----
    wprep_kernel<<<(M1 + 127) / 128, 128>>>(Wd, bd, W1, M1);
    wfold1_kernel<<<1, 64>>>(a1s, a1d, H1, M1);
    es1_kernel<<<(N + 255) / 256, 256>>>(trip, N, H1);
    agg_rank4_kernel<4><<<(N * 32 + 255) / 256, 256>>>(trip, N);
    out1_kernel<<<(N * (M1 / 2) + 255) / 256, 256>>>(b1, N, M1);
    tgemm<<<dim3(1, mt, 1), 256, 65536>>>(
        (const __nv_bfloat16*)pA1h, (const __nv_bfloat16*)pA1l, M1, 0,
        (const __nv_bfloat16*)pb1h, (const __nv_bfloat16*)pb1l, 0,
        (float*)ph1, nullptr, nullptr, CDIM, 0, N, M1, bl1, 0, 0);

    // ---- GAT layer 2 ----
    wfold2_kernel<<<(CDIM * 2 * H2 + 127) / 128, 128>>>(W2, a2s, a2d, H2, M2);
    es2_kernel<<<(N + 7) / 8, 256>>>(N, H2);
    aggw_kernel<5><<<(N * 32 + 255) / 256, 256>>>(N);
    aggg_kernel<5><<<(N * 32 + 255) / 256, 256>>>((const float*)ph1, N);
    tgemm<<<dim3(1, mt, H2), 256, 65536>>>(
        (const __nv_bfloat16*)pA2h, (const __nv_bfloat16*)pA2l, M2, 128,
        (const __nv_bfloat16*)pb2h, (const __nv_bfloat16*)pb2l, 128 * 128,
        nullptr, (__nv_bfloat16*)pA3h, (__nv_bfloat16*)pA3l, M2, 128,
        N, 128, b2, 128, 1);
    tgemm<<<dim3(1, mt, 1), 256, 65536>>>(
        (const __nv_bfloat16*)pA3h, (const __nv_bfloat16*)pA3l, M2, 0,
        (const __nv_bfloat16*)pb3h, (const __nv_bfloat16*)pb3l, 0,
        (float*)ph2, nullptr, nullptr, CDIM, 0, N, M2, bl2, 0, 0);

    // readout + tail
    readout_kernel<<<256, 128>>>(N);
    tail0_kernel<<<1, 384>>>(Wfc, bfc, Whg, bhg, Wv, bv, h_mat, h_bias, N, HOUT);
    tail1_kernel<<<B, 128>>>(cell, Wc, bc, Wq, bq, CF);
    tail2_kernel<<<128, B>>>(gamma, beta, out, B);
}

// round 7
// speedup vs baseline: 1.6292x; 1.0403x over previous
#include <cuda_runtime.h>
#include <cuda_bf16.h>
#include <math.h>
#include <stdint.h>

#define NMAX 20000
#define EMAX 500000
#define CDIM 128
#define NPAD (NMAX + 128)

// ---------------------------------------------------------------------------
// Static device scratch
// ---------------------------------------------------------------------------
__device__ float g_h1  [NMAX * CDIM];
__device__ float g_h2  [NMAX * CDIM];
__device__ float g_es  [NMAX * 5];
__device__ float g_ed  [NMAX * 5];
__device__ float g_tt  [NMAX * 16];      // layer-1 aggregated rank-4 coords
__device__ int   g_cnt   [NMAX];
__device__ int   g_rowptr[NMAX + 1];
__device__ int   g_cursor[NMAX];
__device__ int   g_csrc  [EMAX];
__device__ float g_hsum  [CDIM];
__device__ float g_small [1024];
__device__ float g_logits[256 * CDIM];
__device__ float g_Wp  [4 * 512];
__device__ float g_bp  [512];
__device__ float g_fold1[48];
__device__ float g_fold2[128 * 10];
// bf16 hi/lo GEMM A operands (padded rows for tile overrun safety)
__device__ __nv_bfloat16 g_A1h[NPAD * 512], g_A1l[NPAD * 512];
__device__ __nv_bfloat16 g_A2h[NPAD * 640], g_A2l[NPAD * 640];
__device__ __nv_bfloat16 g_A3h[NPAD * 640], g_A3l[NPAD * 640];
// bf16 hi/lo transposed weights [128(N), K] K-major
__device__ __nv_bfloat16 g_bt1h[128 * 512], g_bt1l[128 * 512];
__device__ __nv_bfloat16 g_bt2h[5 * 128 * 128], g_bt2l[5 * 128 * 128];
__device__ __nv_bfloat16 g_bt3h[128 * 640], g_bt3l[128 * 640];

// ---------------------------------------------------------------------------
// helpers
// ---------------------------------------------------------------------------
__device__ __forceinline__ uint32_t smem_u32(const void* p) {
    uint32_t a;
    asm("{ .reg .u64 t; cvta.to.shared.u64 t, %1; cvt.u32.u64 %0, t; }" : "=r"(a) : "l"(p));
    return a;
}
__device__ __forceinline__ void ldsm4(uint32_t* r, uint32_t addr) {
    asm volatile("ldmatrix.sync.aligned.m8n8.x4.shared.b16 {%0,%1,%2,%3}, [%4];"
                 : "=r"(r[0]), "=r"(r[1]), "=r"(r[2]), "=r"(r[3]) : "r"(addr));
}
__device__ __forceinline__ void mma16816(float* d, const uint32_t* a, const uint32_t* b) {
    asm volatile(
        "mma.sync.aligned.m16n8k16.row.col.f32.bf16.bf16.f32 "
        "{%0,%1,%2,%3}, {%4,%5,%6,%7}, {%8,%9}, {%0,%1,%2,%3};"
        : "+f"(d[0]), "+f"(d[1]), "+f"(d[2]), "+f"(d[3])
        : "r"(a[0]), "r"(a[1]), "r"(a[2]), "r"(a[3]), "r"(b[0]), "r"(b[1]));
}
__device__ __forceinline__ uint32_t pack_bf(__nv_bfloat16 a, __nv_bfloat16 b) {
    __nv_bfloat162 t;
    t.x = a; t.y = b;
    return *reinterpret_cast<uint32_t*>(&t);
}
#define CPA(dst, src) \
    asm volatile("cp.async.cg.shared.global [%0], [%1], 16;" :: "r"(dst), "l"(src))

// ---------------------------------------------------------------------------
__global__ void zero_kernel(int N) {
    int i = blockIdx.x * blockDim.x + threadIdx.x;
    if (i < N)   g_cnt[i] = 0;
    if (i < CDIM) g_hsum[i] = 0.f;
}

// ---------------------------------------------------------------------------
// CSR build (2 edges/thread)
// ---------------------------------------------------------------------------
__global__ void count_kernel(const int* __restrict__ ei, int E) {
    int e = (blockIdx.x * blockDim.x + threadIdx.x) * 2;
    if (e + 1 < E) {
        int2 s = *(const int2*)(ei + e);
        int2 d = *(const int2*)(ei + E + e);
        if (s.x != d.x) atomicAdd(&g_cnt[d.x], 1);
        if (s.y != d.y) atomicAdd(&g_cnt[d.y], 1);
    } else if (e < E) {
        int s = ei[e], d = ei[E + e];
        if (s != d) atomicAdd(&g_cnt[d], 1);
    }
}

// warp-shfl scan: one block of 1024 threads, 3 syncs per 1024-tile
__global__ void scan_kernel(int N) {
    __shared__ int wsum[32];
    __shared__ int carry_s;
    int tid = threadIdx.x, lane = tid & 31, wid = tid >> 5;
    if (tid == 0) { carry_s = 0; g_rowptr[0] = 0; }
    __syncthreads();
    for (int base = 0; base < N; base += 1024) {
        int i = base + tid;
        int v = (i < N) ? g_cnt[i] : 0;
        int x = v;
#pragma unroll
        for (int o = 1; o < 32; o <<= 1) {
            int t = __shfl_up_sync(0xffffffffu, x, o);
            if (lane >= o) x += t;
        }
        if (lane == 31) wsum[wid] = x;
        __syncthreads();
        if (wid == 0) {
            int s = wsum[lane];
#pragma unroll
            for (int o = 1; o < 32; o <<= 1) {
                int t = __shfl_up_sync(0xffffffffu, s, o);
                if (lane >= o) s += t;
            }
            wsum[lane] = s;
        }
        __syncthreads();
        int inc = carry_s + (wid ? wsum[wid - 1] : 0) + x;
        if (i < N) { g_rowptr[i + 1] = inc; g_cursor[i] = inc - v; }
        __syncthreads();
        if (tid == 0) carry_s += wsum[31];
        __syncthreads();
    }
}

__global__ void fill_kernel(const int* __restrict__ ei, int E) {
    int e = (blockIdx.x * blockDim.x + threadIdx.x) * 2;
    if (e + 1 < E) {
        int2 s = *(const int2*)(ei + e);
        int2 d = *(const int2*)(ei + E + e);
        if (s.x != d.x) { int p = atomicAdd(&g_cursor[d.x], 1); g_csrc[p] = s.x; }
        if (s.y != d.y) { int p = atomicAdd(&g_cursor[d.y], 1); g_csrc[p] = s.y; }
    } else if (e < E) {
        int s = ei[e], d = ei[E + e];
        if (s != d) { int p = atomicAdd(&g_cursor[d], 1); g_csrc[p] = s; }
    }
}

// ---------------------------------------------------------------------------
// weight prep
// ---------------------------------------------------------------------------
__global__ void wprep_kernel(const float* __restrict__ Wd,
                             const float* __restrict__ bd,
                             const float* __restrict__ W1, int M1) {
    int j = blockIdx.x * blockDim.x + threadIdx.x;
    if (j >= M1) return;
    float a0 = 0.f, a1 = 0.f, a2 = 0.f, a3 = 0.f, ab = 0.f;
#pragma unroll 4
    for (int k = 0; k < CDIM; k++) {
        float w = W1[k * M1 + j];
        a0 += Wd[0 * CDIM + k] * w;
        a1 += Wd[1 * CDIM + k] * w;
        a2 += Wd[2 * CDIM + k] * w;
        a3 += Wd[3 * CDIM + k] * w;
        ab += bd[k] * w;
    }
    g_Wp[0 * M1 + j] = a0;
    g_Wp[1 * M1 + j] = a1;
    g_Wp[2 * M1 + j] = a2;
    g_Wp[3 * M1 + j] = a3;
    g_bp[j] = ab;
}

// transpose B [K, 128] -> bf16 hi/lo [128, K]
__global__ void btprep_kernel(const float* __restrict__ B, int ldb, int K,
                              __nv_bfloat16* __restrict__ oh,
                              __nv_bfloat16* __restrict__ ol) {
    int idx = blockIdx.x * blockDim.x + threadIdx.x;
    if (idx >= 128 * K) return;
    int j = idx / K, k = idx - j * K;
    float v = B[(size_t)k * ldb + blockIdx.y * 128 + j];
    __nv_bfloat16 h = __float2bfloat16(v);
    float r = v - __bfloat162float(h);
    size_t o = (size_t)blockIdx.y * 128 * K + idx;
    oh[o] = h;
    ol[o] = __float2bfloat16(r);
}

__global__ void wfold1_kernel(const float* __restrict__ a1s,
                              const float* __restrict__ a1d, int H, int M1) {
    int tid = threadIdx.x;
    int HG = H * 4;
    if (tid < HG) {
        int h = tid >> 2, i = tid & 3;
        float s = 0.f;
        for (int k = 0; k < CDIM; k++) s += g_Wp[i * M1 + h * CDIM + k] * a1s[h * CDIM + k];
        g_fold1[tid] = s;
    } else if (tid < 2 * HG) {
        int t = tid - HG;
        int h = t >> 2, i = t & 3;
        float s = 0.f;
        for (int k = 0; k < CDIM; k++) s += g_Wp[i * M1 + h * CDIM + k] * a1d[h * CDIM + k];
        g_fold1[16 + t] = s;
    } else if (tid < 2 * HG + H) {
        int h = tid - 2 * HG;
        float s = 0.f;
        for (int k = 0; k < CDIM; k++) s += g_bp[h * CDIM + k] * a1s[h * CDIM + k];
        g_fold1[32 + h] = s;
    } else if (tid < 2 * HG + 2 * H) {
        int h = tid - 2 * HG - H;
        float s = 0.f;
        for (int k = 0; k < CDIM; k++) s += g_bp[h * CDIM + k] * a1d[h * CDIM + k];
        g_fold1[36 + h] = s;
    }
}

__global__ void es1_kernel(const int* __restrict__ trip, int N, int H) {
    int n = blockIdx.x * blockDim.x + threadIdx.x;
    if (n >= N) return;
    int4 tv = *(const int4*)(trip + n * 4);
    float t0 = (float)tv.x, t1 = (float)tv.y, t2 = (float)tv.z, t3 = (float)tv.w;
#pragma unroll
    for (int h = 0; h < 4; h++) {
        float s = g_fold1[32 + h] + t0 * g_fold1[h * 4 + 0] + t1 * g_fold1[h * 4 + 1]
                + t2 * g_fold1[h * 4 + 2] + t3 * g_fold1[h * 4 + 3];
        float d = g_fold1[36 + h] + t0 * g_fold1[16 + h * 4 + 0] + t1 * g_fold1[16 + h * 4 + 1]
                + t2 * g_fold1[16 + h * 4 + 2] + t3 * g_fold1[16 + h * 4 + 3];
        g_es[n * H + h] = s;
        g_ed[n * H + h] = d;
    }
}

// ---------------------------------------------------------------------------
// Layer-1 aggregation in rank-4 space
// ---------------------------------------------------------------------------
template <int H>
__global__ void agg_rank4_kernel(const int* __restrict__ trip, int N) {
    int warp = (blockIdx.x * blockDim.x + threadIdx.x) >> 5;
    int lane = threadIdx.x & 31;
    if (warp >= N) return;
    int n   = warp;
    int r0  = g_rowptr[n];
    int deg = g_rowptr[n + 1] - r0;
    int tot = deg + 1;

    float edv[H], m[H], sv[H];
#pragma unroll
    for (int h = 0; h < H; h++) { edv[h] = g_ed[n * H + h]; m[h] = -1e30f; sv[h] = 0.f; }
    for (int i = lane; i < tot; i += 32) {
        int src = (i < deg) ? g_csrc[r0 + i] : n;
#pragma unroll
        for (int h = 0; h < H; h++) {
            float e = g_es[src * H + h] + edv[h];
            e = e > 0.f ? e : 0.2f * e;
            m[h] = fmaxf(m[h], e);
        }
    }
#pragma unroll
    for (int h = 0; h < H; h++)
        for (int o = 16; o; o >>= 1) m[h] = fmaxf(m[h], __shfl_xor_sync(0xffffffffu, m[h], o));
    for (int i = lane; i < tot; i += 32) {
        int src = (i < deg) ? g_csrc[r0 + i] : n;
#pragma unroll
        for (int h = 0; h < H; h++) {
            float e = g_es[src * H + h] + edv[h];
            e = e > 0.f ? e : 0.2f * e;
            sv[h] += __expf(e - m[h]);
        }
    }
#pragma unroll
    for (int h = 0; h < H; h++) {
        for (int o = 16; o; o >>= 1) sv[h] += __shfl_xor_sync(0xffffffffu, sv[h], o);
        sv[h] = 1.f / sv[h];
    }
    float4 acc[H];
#pragma unroll
    for (int h = 0; h < H; h++) acc[h] = make_float4(0.f, 0.f, 0.f, 0.f);
    for (int i = lane; i < tot; i += 32) {
        int src = (i < deg) ? g_csrc[r0 + i] : n;
        int4 tv = *(const int4*)(trip + src * 4);
        float4 tf = make_float4((float)tv.x, (float)tv.y, (float)tv.z, (float)tv.w);
#pragma unroll
        for (int h = 0; h < H; h++) {
            float e = g_es[src * H + h] + edv[h];
            e = e > 0.f ? e : 0.2f * e;
            float w = __expf(e - m[h]) * sv[h];
            acc[h].x += w * tf.x; acc[h].y += w * tf.y;
            acc[h].z += w * tf.z; acc[h].w += w * tf.w;
        }
    }
#pragma unroll
    for (int h = 0; h < H; h++) {
        for (int o = 16; o; o >>= 1) {
            acc[h].x += __shfl_xor_sync(0xffffffffu, acc[h].x, o);
            acc[h].y += __shfl_xor_sync(0xffffffffu, acc[h].y, o);
            acc[h].z += __shfl_xor_sync(0xffffffffu, acc[h].z, o);
            acc[h].w += __shfl_xor_sync(0xffffffffu, acc[h].w, o);
        }
    }
    if (lane == 0) {
#pragma unroll
        for (int h = 0; h < H; h++)
            *(float4*)(g_tt + n * 16 + h * 4) = acc[h];
    }
}

// out1: A1 = elu(tt@Wp + bp + b1), emitted as bf16 hi/lo. 2 elems/thread.
__global__ void out1_kernel(const float* __restrict__ b1, int N, int M1) {
    int half = M1 >> 1;
    int idx = blockIdx.x * blockDim.x + threadIdx.x;
    if (idx >= N * half) return;
    int n = idx / half, j = (idx - n * half) * 2;
    int h = j >> 7;
    float4 t = *(const float4*)(g_tt + n * 16 + h * 4);
    float v0 = g_bp[j] + b1[j] + t.x * g_Wp[0 * M1 + j] + t.y * g_Wp[1 * M1 + j]
             + t.z * g_Wp[2 * M1 + j] + t.w * g_Wp[3 * M1 + j];
    int j1 = j + 1;
    float v1 = g_bp[j1] + b1[j1] + t.x * g_Wp[0 * M1 + j1] + t.y * g_Wp[1 * M1 + j1]
             + t.z * g_Wp[2 * M1 + j1] + t.w * g_Wp[3 * M1 + j1];
    v0 = v0 > 0.f ? v0 : __expf(v0) - 1.f;
    v1 = v1 > 0.f ? v1 : __expf(v1) - 1.f;
    __nv_bfloat16 h0 = __float2bfloat16(v0);
    __nv_bfloat16 h1 = __float2bfloat16(v1);
    size_t o = (size_t)n * M1 + j;
    *(uint32_t*)(g_A1h + o) = pack_bf(h0, h1);
    *(uint32_t*)(g_A1l + o) = pack_bf(__float2bfloat16(v0 - __bfloat162float(h0)),
                                      __float2bfloat16(v1 - __bfloat162float(h1)));
}

// ---------------------------------------------------------------------------
// cp.async double-buffered warp-MMA bf16 split GEMM (unchanged from R6)
// ---------------------------------------------------------------------------
__global__ void __launch_bounds__(256)
tgemm(const __nv_bfloat16* __restrict__ Ah, const __nv_bfloat16* __restrict__ Al,
      int lda, int boa,
      const __nv_bfloat16* __restrict__ Bh, const __nv_bfloat16* __restrict__ Bl, int bob,
      float* __restrict__ Cf, __nv_bfloat16* __restrict__ Ch, __nv_bfloat16* __restrict__ Cl,
      int ldc, int boc,
      int M, int K, const float* __restrict__ cbias, int bocb, int celu) {
    Ah += (size_t)blockIdx.z * boa;
    Al += (size_t)blockIdx.z * boa;
    Bh += (size_t)blockIdx.z * bob;
    Bl += (size_t)blockIdx.z * bob;
    if (Cf) Cf += (size_t)blockIdx.z * boc;
    if (Ch) { Ch += (size_t)blockIdx.z * boc; Cl += (size_t)blockIdx.z * boc; }
    cbias += (size_t)blockIdx.z * bocb;

    extern __shared__ __align__(16) char dsm[];
    uint32_t sAu = smem_u32(dsm);
    uint32_t sBu = sAu + 32768;

    int tid  = threadIdx.x;
    int wid  = tid >> 5;
    int lane = tid & 31;
    int m0   = blockIdx.y * 128;
    int wm   = wid & 3;
    int wn   = wid >> 2;

    float acc[2][8][4];
#pragma unroll
    for (int i = 0; i < 2; i++)
#pragma unroll
        for (int j = 0; j < 8; j++)
#pragma unroll
            for (int l = 0; l < 4; l++) acc[i][j][l] = 0.f;

#define STAGE(BUF, KC)                                                         \
    {                                                                          \
        int _kc = (KC);                                                        \
        _Pragma("unroll")                                                      \
        for (int it = 0; it < 4; it++) {                                       \
            int idx = it * 256 + tid;                                          \
            int row = idx >> 3, ch = idx & 7;                                  \
            const __nv_bfloat16* gs = ((ch < 4) ? Ah : Al)                     \
                + (size_t)(m0 + row) * lda + _kc + (ch & 3) * 8;               \
            uint32_t dst = sAu + (BUF) * 16384 + row * 128                     \
                + ((ch ^ (row & 7)) << 4);                                     \
            CPA(dst, gs);                                                      \
        }                                                                      \
        _Pragma("unroll")                                                      \
        for (int it = 0; it < 4; it++) {                                       \
            int idx = it * 256 + tid;                                          \
            int row = idx >> 3, ch = idx & 7;                                  \
            const __nv_bfloat16* gs = ((ch < 4) ? Bh : Bl)                     \
                + (size_t)row * K + _kc + (ch & 3) * 8;                        \
            uint32_t dst = sBu + (BUF) * 16384 + row * 128                     \
                + ((ch ^ (row & 7)) << 4);                                     \
            CPA(dst, gs);                                                      \
        }                                                                      \
    }

    int nk = K >> 5;
    STAGE(0, 0)
    asm volatile("cp.async.commit_group;");

    for (int i = 0; i < nk; i++) {
        int buf = i & 1;
        if (i + 1 < nk) {
            STAGE(buf ^ 1, (i + 1) * 32)
            asm volatile("cp.async.commit_group;");
            asm volatile("cp.async.wait_group 1;");
        } else {
            asm volatile("cp.async.wait_group 0;");
        }
        __syncthreads();

        uint32_t a_base = sAu + buf * 16384;
        uint32_t b_base = sBu + buf * 16384;
#pragma unroll
        for (int ks = 0; ks < 2; ks++) {
            uint32_t ah[2][4], al[2][4], bh[4][4], bl[4][4];
            int arow = (lane & 7) + ((lane >> 3) & 1) * 8;
            int akg  = 2 * ks + (lane >> 4);
#pragma unroll
            for (int mf = 0; mf < 2; mf++) {
                int r = 32 * wm + 16 * mf + arow;
                ldsm4(ah[mf], a_base + r * 128 + (((akg)     ^ (r & 7)) << 4));
                ldsm4(al[mf], a_base + r * 128 + (((akg + 4) ^ (r & 7)) << 4));
            }
            int brow = (lane & 7) + (lane >> 4) * 8;
            int bkg  = 2 * ks + ((lane >> 3) & 1);
#pragma unroll
            for (int q = 0; q < 4; q++) {
                int r = 64 * wn + 16 * q + brow;
                ldsm4(bh[q], b_base + r * 128 + (((bkg)     ^ (r & 7)) << 4));
                ldsm4(bl[q], b_base + r * 128 + (((bkg + 4) ^ (r & 7)) << 4));
            }
#pragma unroll
            for (int mf = 0; mf < 2; mf++) {
#pragma unroll
                for (int q = 0; q < 4; q++) {
                    mma16816(acc[mf][2 * q + 0], ah[mf], &bh[q][0]);
                    mma16816(acc[mf][2 * q + 1], ah[mf], &bh[q][2]);
                    mma16816(acc[mf][2 * q + 0], al[mf], &bh[q][0]);
                    mma16816(acc[mf][2 * q + 1], al[mf], &bh[q][2]);
                    mma16816(acc[mf][2 * q + 0], ah[mf], &bl[q][0]);
                    mma16816(acc[mf][2 * q + 1], ah[mf], &bl[q][2]);
                }
            }
        }
        __syncthreads();
    }
#undef STAGE

#pragma unroll
    for (int mf = 0; mf < 2; mf++) {
        int r0 = m0 + 32 * wm + 16 * mf + (lane >> 2);
#pragma unroll
        for (int nf = 0; nf < 8; nf++) {
            int col = 64 * wn + 8 * nf + 2 * (lane & 3);
            float cb0 = cbias[col], cb1 = cbias[col + 1];
#pragma unroll
            for (int rr = 0; rr < 2; rr++) {
                int r = r0 + rr * 8;
                if (r >= M) continue;
                float v0 = acc[mf][nf][2 * rr + 0] + cb0;
                float v1 = acc[mf][nf][2 * rr + 1] + cb1;
                if (Cf) {
                    *(float2*)(Cf + (size_t)r * ldc + col) = make_float2(v0, v1);
                } else {
                    if (celu) {
                        v0 = v0 > 0.f ? v0 : __expf(v0) - 1.f;
                        v1 = v1 > 0.f ? v1 : __expf(v1) - 1.f;
                    }
                    __nv_bfloat16 h0 = __float2bfloat16(v0);
                    __nv_bfloat16 h1 = __float2bfloat16(v1);
                    size_t o = (size_t)r * ldc + col;
                    *(uint32_t*)(Ch + o) = pack_bf(h0, h1);
                    *(uint32_t*)(Cl + o) =
                        pack_bf(__float2bfloat16(v0 - __bfloat162float(h0)),
                                __float2bfloat16(v1 - __bfloat162float(h1)));
                }
            }
        }
    }
}

// ---------------------------------------------------------------------------
// Layer-2 folded attention weights + logits
// ---------------------------------------------------------------------------
__global__ void wfold2_kernel(const float* __restrict__ W2,
                              const float* __restrict__ a2s,
                              const float* __restrict__ a2d, int H, int M2) {
    int tid = blockIdx.x * blockDim.x + threadIdx.x;
    if (tid >= CDIM * 2 * H) return;
    int c = tid / (2 * H), o = tid - c * (2 * H);
    int h = o % H;
    const float* av = (o < H) ? a2s : a2d;
    float s = 0.f;
    for (int k = 0; k < CDIM; k++) s += W2[c * M2 + h * CDIM + k] * av[h * CDIM + k];
    g_fold2[c * (2 * H) + o] = s;
}

__global__ void es2_kernel(int N, int H) {
    __shared__ float wt[CDIM * 10];
    int tid = threadIdx.x;
    int TW = CDIM * 2 * H;
    for (int i = tid; i < TW; i += blockDim.x) wt[i] = g_fold2[i];
    __syncthreads();
    int warp = blockIdx.x * (blockDim.x >> 5) + (tid >> 5);
    int lane = tid & 31;
    if (warp >= N) return;
    float4 hv = *(const float4*)(g_h1 + (size_t)warp * CDIM + lane * 4);
    float s[10];
#pragma unroll
    for (int o = 0; o < 10; o++) s[o] = 0.f;
    float hvv[4] = {hv.x, hv.y, hv.z, hv.w};
#pragma unroll
    for (int j = 0; j < 4; j++) {
        int c = lane * 4 + j;
        for (int o = 0; o < 2 * H; o++) s[o] += hvv[j] * wt[c * (2 * H) + o];
    }
    for (int o = 0; o < 2 * H; o++)
        for (int off = 16; off; off >>= 1) s[o] += __shfl_xor_sync(0xffffffffu, s[o], off);
    if (lane < H)          g_es[warp * H + lane] = s[lane];
    else if (lane < 2 * H) g_ed[warp * H + lane - H] = s[lane];
}

// ---------------------------------------------------------------------------
// Layer-2 fused aggregation: softmax stats, then tiled gather with
// shfl-broadcast weights (lane i computes weights for edge t+i; all lanes
// then act as channels). Emits z2 as bf16 hi/lo.
// ---------------------------------------------------------------------------
template <int H>
__global__ void agg2_kernel(const float* __restrict__ feat, int N) {
    int warp = (blockIdx.x * blockDim.x + threadIdx.x) >> 5;
    int lane = threadIdx.x & 31;
    if (warp >= N) return;
    int n   = warp;
    int r0  = g_rowptr[n];
    int deg = g_rowptr[n + 1] - r0;
    int tot = deg + 1;

    float edv[H], m[H], sv[H];
#pragma unroll
    for (int h = 0; h < H; h++) { edv[h] = g_ed[n * H + h]; m[h] = -1e30f; sv[h] = 0.f; }
    for (int i = lane; i < tot; i += 32) {
        int src = (i < deg) ? g_csrc[r0 + i] : n;
#pragma unroll
        for (int h = 0; h < H; h++) {
            float e = g_es[src * H + h] + edv[h];
            e = e > 0.f ? e : 0.2f * e;
            m[h] = fmaxf(m[h], e);
        }
    }
#pragma unroll
    for (int h = 0; h < H; h++)
        for (int o = 16; o; o >>= 1) m[h] = fmaxf(m[h], __shfl_xor_sync(0xffffffffu, m[h], o));
    for (int i = lane; i < tot; i += 32) {
        int src = (i < deg) ? g_csrc[r0 + i] : n;
#pragma unroll
        for (int h = 0; h < H; h++) {
            float e = g_es[src * H + h] + edv[h];
            e = e > 0.f ? e : 0.2f * e;
            sv[h] += __expf(e - m[h]);
        }
    }
#pragma unroll
    for (int h = 0; h < H; h++) {
        for (int o = 16; o; o >>= 1) sv[h] += __shfl_xor_sync(0xffffffffu, sv[h], o);
        sv[h] = 1.f / sv[h];
    }

    float4 acc[H];
#pragma unroll
    for (int h = 0; h < H; h++) acc[h] = make_float4(0.f, 0.f, 0.f, 0.f);

    for (int t = 0; t < tot; t += 32) {
        int i = t + lane;
        int src = n;
        float w[H];
        if (i < tot) {
            src = (i < deg) ? g_csrc[r0 + i] : n;
#pragma unroll
            for (int h = 0; h < H; h++) {
                float e = g_es[src * H + h] + edv[h];
                e = e > 0.f ? e : 0.2f * e;
                w[h] = __expf(e - m[h]) * sv[h];
            }
        } else {
#pragma unroll
            for (int h = 0; h < H; h++) w[h] = 0.f;
        }
        int cnt = tot - t;
        if (cnt > 32) cnt = 32;
#pragma unroll 4
        for (int j = 0; j < cnt; j++) {
            int s = __shfl_sync(0xffffffffu, src, j);
            float wj[H];
#pragma unroll
            for (int h = 0; h < H; h++) wj[h] = __shfl_sync(0xffffffffu, w[h], j);
            float4 v = *(const float4*)(feat + (size_t)s * CDIM + lane * 4);
#pragma unroll
            for (int h = 0; h < H; h++) {
                acc[h].x += wj[h] * v.x; acc[h].y += wj[h] * v.y;
                acc[h].z += wj[h] * v.z; acc[h].w += wj[h] * v.w;
            }
        }
    }

#pragma unroll
    for (int h = 0; h < H; h++) {
        __nv_bfloat16 hx = __float2bfloat16(acc[h].x);
        __nv_bfloat16 hy = __float2bfloat16(acc[h].y);
        __nv_bfloat16 hz = __float2bfloat16(acc[h].z);
        __nv_bfloat16 hw = __float2bfloat16(acc[h].w);
        size_t o = (size_t)n * (H * CDIM) + h * CDIM + lane * 4;
        *(uint2*)(g_A2h + o) = make_uint2(pack_bf(hx, hy), pack_bf(hz, hw));
        *(uint2*)(g_A2l + o) = make_uint2(
            pack_bf(__float2bfloat16(acc[h].x - __bfloat162float(hx)),
                    __float2bfloat16(acc[h].y - __bfloat162float(hy))),
            pack_bf(__float2bfloat16(acc[h].z - __bfloat162float(hz)),
                    __float2bfloat16(acc[h].w - __bfloat162float(hw))));
    }
}

// ---------------------------------------------------------------------------
__global__ void readout_kernel(int N) {
    int tid = threadIdx.x;
    float a = 0.f;
    for (int n = blockIdx.x; n < N; n += gridDim.x)
        a += g_h1[(size_t)n * CDIM + tid] + g_h2[(size_t)n * CDIM + tid];
    atomicAdd(&g_hsum[tid], a);
}

__global__ void tail0_kernel(const float* __restrict__ Wfc, const float* __restrict__ bfc,
                             const float* __restrict__ Whg, const float* __restrict__ bhg,
                             const float* __restrict__ Wv,  const float* __restrict__ bv,
                             const float* __restrict__ h_mat, const float* __restrict__ h_bias,
                             int N, int HOUT) {
    __shared__ float h[128];
    __shared__ float tm[256];
    __shared__ float hg[128];
    int tid = threadIdx.x;
    if (tid < 128) h[tid] = g_hsum[tid] / (float)N;
    __syncthreads();
    if (tid < 256) {
        float a = bfc[tid];
        for (int i = 0; i < 128; i++) a += h[i] * Wfc[i * 256 + tid];
        tm[tid] = a > 0.f ? a : 0.f;
    }
    __syncthreads();
    if (tid < 128) {
        float a = bhg[tid];
        for (int i = 0; i < 256; i++) a += tm[i] * Whg[i * 128 + tid];
        hg[tid] = a;
    }
    __syncthreads();
    if (tid < 384) {
        float a = bv[tid];
        for (int i = 0; i < 128; i++) a += hg[i] * Wv[i * 384 + tid];
        g_small[tid] = a > 0.f ? a : 0.f;
        float hs = 0.f;
        for (int hh = 0; hh < HOUT; hh++) hs += h_mat[hh * 384 + tid];
        g_small[384 + tid] = hs;
    }
    if (tid == 0) {
        float hb = 0.f;
        for (int i = 0; i < HOUT; i++) hb += h_bias[i];
        g_small[768] = hb;
    }
}

__global__ void tail1_kernel(const float* __restrict__ cell,
                             const float* __restrict__ Wc, const float* __restrict__ bc,
                             const float* __restrict__ Wq, const float* __restrict__ bq,
                             int CF) {
    __shared__ float sc[1024];
    __shared__ float crow[128];
    __shared__ float qrow[384];
    __shared__ float red[128];
    int b = blockIdx.x, tid = threadIdx.x;
    for (int i = tid; i < CF; i += 128) sc[i] = cell[(size_t)b * CF + i];
    __syncthreads();
    {
        float a = bc[tid];
        for (int k = 0; k < CF; k++) a += sc[k] * Wc[k * 128 + tid];
        crow[tid] = a > 0.f ? a : 0.f;
    }
    __syncthreads();
    float part = 0.f;
    for (int mI = tid; mI < 384; mI += 128) {
        float q = bq[mI];
        for (int k = 0; k < 128; k++) q += crow[k] * Wq[k * 384 + mI];
        q = q > 0.f ? q : 0.f;
        qrow[mI] = q;
        part += g_small[384 + mI] * g_small[mI] * q;
    }
    red[tid] = part;
    __syncthreads();
    for (int o = 64; o; o >>= 1) {
        if (tid < o) red[tid] += red[tid + o];
        __syncthreads();
    }
    float att = red[0] + g_small[768];
    float l = 0.f;
#pragma unroll
    for (int j = 0; j < 3; j++) {
        int k = tid * 3 + j;
        l += g_small[k] * qrow[k];
    }
    g_logits[b * 128 + tid] = att * l;
}

__global__ void tail2_kernel(const float* __restrict__ gamma,
                             const float* __restrict__ beta,
                             float* __restrict__ out, int B) {
    __shared__ float s1[256], s2[256];
    int c = blockIdx.x, b = threadIdx.x;
    float v = g_logits[b * 128 + c];
    s1[b] = v;
    s2[b] = v * v;
    __syncthreads();
    for (int o = B >> 1; o; o >>= 1) {
        if (b < o) { s1[b] += s1[b + o]; s2[b] += s2[b + o]; }
        __syncthreads();
    }
    float mu  = s1[0] / (float)B;
    float var = s2[0] / (float)B - mu * mu;
    out[b * 128 + c] = (v - mu) * rsqrtf(var + 1e-5f) * gamma[c] + beta[c];
}

// ---------------------------------------------------------------------------
// launch
// ---------------------------------------------------------------------------
extern "C" void kernel_launch(void* const* d_in, const int* in_sizes, int n_in,
                              void* d_out, int out_size) {
    const float* cell = (const float*)d_in[0];
    const float* Wd   = (const float*)d_in[1];
    const float* bd   = (const float*)d_in[2];
    const float* W1   = (const float*)d_in[3];
    const float* a1s  = (const float*)d_in[4];
    const float* a1d  = (const float*)d_in[5];
    const float* b1   = (const float*)d_in[6];
    const float* Wl1  = (const float*)d_in[7];
    const float* bl1  = (const float*)d_in[8];
    const float* W2   = (const float*)d_in[9];
    const float* a2s  = (const float*)d_in[10];
    const float* a2d  = (const float*)d_in[11];
    const float* b2   = (const float*)d_in[12];
    const float* Wl2  = (const float*)d_in[13];
    const float* bl2  = (const float*)d_in[14];
    const float* Wfc  = (const float*)d_in[15];
    const float* bfc  = (const float*)d_in[16];
    const float* Whg  = (const float*)d_in[17];
    const float* bhg  = (const float*)d_in[18];
    const float* Wc   = (const float*)d_in[19];
    const float* bc   = (const float*)d_in[20];
    const float* Wv   = (const float*)d_in[21];
    const float* bv   = (const float*)d_in[22];
    const float* Wq   = (const float*)d_in[23];
    const float* bq   = (const float*)d_in[24];
    const float* h_mat  = (const float*)d_in[25];
    const float* h_bias = (const float*)d_in[26];
    const float* gamma  = (const float*)d_in[27];
    const float* beta   = (const float*)d_in[28];
    const int*   trip   = (const int*)d_in[29];
    const int*   ei     = (const int*)d_in[30];

    int N  = in_sizes[29] / 4;
    int E  = in_sizes[30] / 2;
    int CF = in_sizes[19] / 128;
    int B  = in_sizes[0] / CF;
    int H1 = in_sizes[4] / 128;   // 4
    int H2 = in_sizes[10] / 128;  // 5
    int HOUT = in_sizes[26];
    if (N > NMAX) N = NMAX;
    if (E > EMAX) E = EMAX;
    float* out = (float*)d_out;

    void *ph1, *ph2;
    void *pA1h, *pA1l, *pA2h, *pA2l, *pA3h, *pA3l;
    void *pb1h, *pb1l, *pb2h, *pb2l, *pb3h, *pb3l;
    cudaGetSymbolAddress(&ph1,  g_h1);
    cudaGetSymbolAddress(&ph2,  g_h2);
    cudaGetSymbolAddress(&pA1h, g_A1h);
    cudaGetSymbolAddress(&pA1l, g_A1l);
    cudaGetSymbolAddress(&pA2h, g_A2h);
    cudaGetSymbolAddress(&pA2l, g_A2l);
    cudaGetSymbolAddress(&pA3h, g_A3h);
    cudaGetSymbolAddress(&pA3l, g_A3l);
    cudaGetSymbolAddress(&pb1h, g_bt1h);
    cudaGetSymbolAddress(&pb1l, g_bt1l);
    cudaGetSymbolAddress(&pb2h, g_bt2h);
    cudaGetSymbolAddress(&pb2l, g_bt2l);
    cudaGetSymbolAddress(&pb3h, g_bt3h);
    cudaGetSymbolAddress(&pb3l, g_bt3l);

    cudaFuncSetAttribute(tgemm, cudaFuncAttributeMaxDynamicSharedMemorySize, 65536);

    int M1 = H1 * CDIM;  // 512
    int M2 = H2 * CDIM;  // 640
    int mt = (N + 127) / 128;

    // CSR build + zero
    zero_kernel<<<(N + 255) / 256, 256>>>(N);
    count_kernel<<<(E / 2 + 255) / 256, 256>>>(ei, E);
    scan_kernel<<<1, 1024>>>(N);
    fill_kernel<<<(E / 2 + 255) / 256, 256>>>(ei, E);

    // weight prep (bf16 transposed splits)
    btprep_kernel<<<dim3((128 * M1 + 255) / 256, 1), 256>>>(Wl1, 128, M1,
        (__nv_bfloat16*)pb1h, (__nv_bfloat16*)pb1l);
    btprep_kernel<<<dim3((128 * 128 + 255) / 256, H2), 256>>>(W2, M2, 128,
        (__nv_bfloat16*)pb2h, (__nv_bfloat16*)pb2l);
    btprep_kernel<<<dim3((128 * M2 + 255) / 256, 1), 256>>>(Wl2, 128, M2,
        (__nv_bfloat16*)pb3h, (__nv_bfloat16*)pb3l);

    // ---- GAT layer 1 (rank-4 until projection) ----
    wprep_kernel<<<(M1 + 127) / 128, 128>>>(Wd, bd, W1, M1);
    wfold1_kernel<<<1, 64>>>(a1s, a1d, H1, M1);
    es1_kernel<<<(N + 255) / 256, 256>>>(trip, N, H1);
    agg_rank4_kernel<4><<<(N * 32 + 255) / 256, 256>>>(trip, N);
    out1_kernel<<<(N * (M1 / 2) + 255) / 256, 256>>>(b1, N, M1);
    tgemm<<<dim3(1, mt, 1), 256, 65536>>>(
        (const __nv_bfloat16*)pA1h, (const __nv_bfloat16*)pA1l, M1, 0,
        (const __nv_bfloat16*)pb1h, (const __nv_bfloat16*)pb1l, 0,
        (float*)ph1, nullptr, nullptr, CDIM, 0, N, M1, bl1, 0, 0);

    // ---- GAT layer 2 ----
    wfold2_kernel<<<(CDIM * 2 * H2 + 127) / 128, 128>>>(W2, a2s, a2d, H2, M2);
    es2_kernel<<<(N + 7) / 8, 256>>>(N, H2);
    agg2_kernel<5><<<(N * 32 + 255) / 256, 256>>>((const float*)ph1, N);
    tgemm<<<dim3(1, mt, H2), 256, 65536>>>(
        (const __nv_bfloat16*)pA2h, (const __nv_bfloat16*)pA2l, M2, 128,
        (const __nv_bfloat16*)pb2h, (const __nv_bfloat16*)pb2l, 128 * 128,
        nullptr, (__nv_bfloat16*)pA3h, (__nv_bfloat16*)pA3l, M2, 128,
        N, 128, b2, 128, 1);
    tgemm<<<dim3(1, mt, 1), 256, 65536>>>(
        (const __nv_bfloat16*)pA3h, (const __nv_bfloat16*)pA3l, M2, 0,
        (const __nv_bfloat16*)pb3h, (const __nv_bfloat16*)pb3l, 0,
        (float*)ph2, nullptr, nullptr, CDIM, 0, N, M2, bl2, 0, 0);

    // readout + tail
    readout_kernel<<<256, 128>>>(N);
    tail0_kernel<<<1, 384>>>(Wfc, bfc, Whg, bhg, Wv, bv, h_mat, h_bias, N, HOUT);
    tail1_kernel<<<B, 128>>>(cell, Wc, bc, Wq, bq, CF);
    tail2_kernel<<<128, B>>>(gamma, beta, out, B);
}

// round 8
// speedup vs baseline: 1.6379x; 1.0054x over previous
#include <cuda_runtime.h>
#include <cuda_bf16.h>
#include <math.h>
#include <stdint.h>

#define NMAX 20000
#define EMAX 500000
#define CDIM 128
#define NPAD (NMAX + 128)

// ---------------------------------------------------------------------------
// Static device scratch
// ---------------------------------------------------------------------------
__device__ float g_h1  [NMAX * CDIM];
__device__ float g_h2  [NMAX * CDIM];
__device__ float g_es  [NMAX * 4];       // layer-1 logits, stride 4 (float4)
__device__ float g_ed  [NMAX * 4];
__device__ float g_es2p[NMAX * 8];       // layer-2 logits, stride 8 padded
__device__ float g_ed2p[NMAX * 8];
__device__ float g_tt  [NMAX * 16];      // layer-1 aggregated rank-4 coords
__device__ int   g_cnt   [NMAX];
__device__ int   g_rowptr[NMAX + 1];
__device__ int   g_cursor[NMAX];
__device__ int   g_csrc  [EMAX];
__device__ float g_hsum  [CDIM];
__device__ float g_small [1024];
__device__ float g_logits[256 * CDIM];
__device__ float g_Wp  [4 * 512];
__device__ float g_bp  [512];
__device__ float g_fold1[48];
__device__ float g_fold2[128 * 10];
// bf16 hi/lo GEMM A operands (padded rows for tile overrun safety)
__device__ __nv_bfloat16 g_A2h[NPAD * 640], g_A2l[NPAD * 640];
__device__ __nv_bfloat16 g_A3h[NPAD * 640], g_A3l[NPAD * 640];
// bf16 hi/lo transposed weights [128(N), K] K-major
__device__ __nv_bfloat16 g_bt1h[128 * 512], g_bt1l[128 * 512];
__device__ __nv_bfloat16 g_bt2h[5 * 128 * 128], g_bt2l[5 * 128 * 128];
__device__ __nv_bfloat16 g_bt3h[128 * 640], g_bt3l[128 * 640];

// ---------------------------------------------------------------------------
// helpers
// ---------------------------------------------------------------------------
__device__ __forceinline__ uint32_t smem_u32(const void* p) {
    uint32_t a;
    asm("{ .reg .u64 t; cvta.to.shared.u64 t, %1; cvt.u32.u64 %0, t; }" : "=r"(a) : "l"(p));
    return a;
}
__device__ __forceinline__ void ldsm4(uint32_t* r, uint32_t addr) {
    asm volatile("ldmatrix.sync.aligned.m8n8.x4.shared.b16 {%0,%1,%2,%3}, [%4];"
                 : "=r"(r[0]), "=r"(r[1]), "=r"(r[2]), "=r"(r[3]) : "r"(addr));
}
__device__ __forceinline__ void mma16816(float* d, const uint32_t* a, const uint32_t* b) {
    asm volatile(
        "mma.sync.aligned.m16n8k16.row.col.f32.bf16.bf16.f32 "
        "{%0,%1,%2,%3}, {%4,%5,%6,%7}, {%8,%9}, {%0,%1,%2,%3};"
        : "+f"(d[0]), "+f"(d[1]), "+f"(d[2]), "+f"(d[3])
        : "r"(a[0]), "r"(a[1]), "r"(a[2]), "r"(a[3]), "r"(b[0]), "r"(b[1]));
}
__device__ __forceinline__ uint32_t pack_bf(__nv_bfloat16 a, __nv_bfloat16 b) {
    __nv_bfloat162 t;
    t.x = a; t.y = b;
    return *reinterpret_cast<uint32_t*>(&t);
}
#define CPA(dst, src) \
    asm volatile("cp.async.cg.shared.global [%0], [%1], 16;" :: "r"(dst), "l"(src))

// ---------------------------------------------------------------------------
__global__ void zero_kernel(int N) {
    int i = blockIdx.x * blockDim.x + threadIdx.x;
    if (i < N)   g_cnt[i] = 0;
    if (i < CDIM) g_hsum[i] = 0.f;
}

// ---------------------------------------------------------------------------
// CSR build (2 edges/thread)
// ---------------------------------------------------------------------------
__global__ void count_kernel(const int* __restrict__ ei, int E) {
    int e = (blockIdx.x * blockDim.x + threadIdx.x) * 2;
    if (e + 1 < E) {
        int2 s = *(const int2*)(ei + e);
        int2 d = *(const int2*)(ei + E + e);
        if (s.x != d.x) atomicAdd(&g_cnt[d.x], 1);
        if (s.y != d.y) atomicAdd(&g_cnt[d.y], 1);
    } else if (e < E) {
        int s = ei[e], d = ei[E + e];
        if (s != d) atomicAdd(&g_cnt[d], 1);
    }
}

__global__ void scan_kernel(int N) {
    __shared__ int wsum[32];
    __shared__ int carry_s;
    int tid = threadIdx.x, lane = tid & 31, wid = tid >> 5;
    if (tid == 0) { carry_s = 0; g_rowptr[0] = 0; }
    __syncthreads();
    for (int base = 0; base < N; base += 1024) {
        int i = base + tid;
        int v = (i < N) ? g_cnt[i] : 0;
        int x = v;
#pragma unroll
        for (int o = 1; o < 32; o <<= 1) {
            int t = __shfl_up_sync(0xffffffffu, x, o);
            if (lane >= o) x += t;
        }
        if (lane == 31) wsum[wid] = x;
        __syncthreads();
        if (wid == 0) {
            int s = wsum[lane];
#pragma unroll
            for (int o = 1; o < 32; o <<= 1) {
                int t = __shfl_up_sync(0xffffffffu, s, o);
                if (lane >= o) s += t;
            }
            wsum[lane] = s;
        }
        __syncthreads();
        int inc = carry_s + (wid ? wsum[wid - 1] : 0) + x;
        if (i < N) { g_rowptr[i + 1] = inc; g_cursor[i] = inc - v; }
        __syncthreads();
        if (tid == 0) carry_s += wsum[31];
        __syncthreads();
    }
}

__global__ void fill_kernel(const int* __restrict__ ei, int E) {
    int e = (blockIdx.x * blockDim.x + threadIdx.x) * 2;
    if (e + 1 < E) {
        int2 s = *(const int2*)(ei + e);
        int2 d = *(const int2*)(ei + E + e);
        if (s.x != d.x) { int p = atomicAdd(&g_cursor[d.x], 1); g_csrc[p] = s.x; }
        if (s.y != d.y) { int p = atomicAdd(&g_cursor[d.y], 1); g_csrc[p] = s.y; }
    } else if (e < E) {
        int s = ei[e], d = ei[E + e];
        if (s != d) { int p = atomicAdd(&g_cursor[d], 1); g_csrc[p] = s; }
    }
}

// ---------------------------------------------------------------------------
// weight prep
// ---------------------------------------------------------------------------
__global__ void wprep_kernel(const float* __restrict__ Wd,
                             const float* __restrict__ bd,
                             const float* __restrict__ W1, int M1) {
    int j = blockIdx.x * blockDim.x + threadIdx.x;
    if (j >= M1) return;
    float a0 = 0.f, a1 = 0.f, a2 = 0.f, a3 = 0.f, ab = 0.f;
#pragma unroll 4
    for (int k = 0; k < CDIM; k++) {
        float w = W1[k * M1 + j];
        a0 += Wd[0 * CDIM + k] * w;
        a1 += Wd[1 * CDIM + k] * w;
        a2 += Wd[2 * CDIM + k] * w;
        a3 += Wd[3 * CDIM + k] * w;
        ab += bd[k] * w;
    }
    g_Wp[0 * M1 + j] = a0;
    g_Wp[1 * M1 + j] = a1;
    g_Wp[2 * M1 + j] = a2;
    g_Wp[3 * M1 + j] = a3;
    g_bp[j] = ab;
}

// transpose B [K, 128] -> bf16 hi/lo [128, K]
__global__ void btprep_kernel(const float* __restrict__ B, int ldb, int K,
                              __nv_bfloat16* __restrict__ oh,
                              __nv_bfloat16* __restrict__ ol) {
    int idx = blockIdx.x * blockDim.x + threadIdx.x;
    if (idx >= 128 * K) return;
    int j = idx / K, k = idx - j * K;
    float v = B[(size_t)k * ldb + blockIdx.y * 128 + j];
    __nv_bfloat16 h = __float2bfloat16(v);
    float r = v - __bfloat162float(h);
    size_t o = (size_t)blockIdx.y * 128 * K + idx;
    oh[o] = h;
    ol[o] = __float2bfloat16(r);
}

__global__ void wfold1_kernel(const float* __restrict__ a1s,
                              const float* __restrict__ a1d, int H, int M1) {
    int tid = threadIdx.x;
    int HG = H * 4;
    if (tid < HG) {
        int h = tid >> 2, i = tid & 3;
        float s = 0.f;
        for (int k = 0; k < CDIM; k++) s += g_Wp[i * M1 + h * CDIM + k] * a1s[h * CDIM + k];
        g_fold1[tid] = s;
    } else if (tid < 2 * HG) {
        int t = tid - HG;
        int h = t >> 2, i = t & 3;
        float s = 0.f;
        for (int k = 0; k < CDIM; k++) s += g_Wp[i * M1 + h * CDIM + k] * a1d[h * CDIM + k];
        g_fold1[16 + t] = s;
    } else if (tid < 2 * HG + H) {
        int h = tid - 2 * HG;
        float s = 0.f;
        for (int k = 0; k < CDIM; k++) s += g_bp[h * CDIM + k] * a1s[h * CDIM + k];
        g_fold1[32 + h] = s;
    } else if (tid < 2 * HG + 2 * H) {
        int h = tid - 2 * HG - H;
        float s = 0.f;
        for (int k = 0; k < CDIM; k++) s += g_bp[h * CDIM + k] * a1d[h * CDIM + k];
        g_fold1[36 + h] = s;
    }
}

__global__ void es1_kernel(const int* __restrict__ trip, int N) {
    int n = blockIdx.x * blockDim.x + threadIdx.x;
    if (n >= N) return;
    int4 tv = *(const int4*)(trip + n * 4);
    float t0 = (float)tv.x, t1 = (float)tv.y, t2 = (float)tv.z, t3 = (float)tv.w;
    float4 es, ed;
    float* esp = &es.x;
    float* edp = &ed.x;
#pragma unroll
    for (int h = 0; h < 4; h++) {
        esp[h] = g_fold1[32 + h] + t0 * g_fold1[h * 4 + 0] + t1 * g_fold1[h * 4 + 1]
               + t2 * g_fold1[h * 4 + 2] + t3 * g_fold1[h * 4 + 3];
        edp[h] = g_fold1[36 + h] + t0 * g_fold1[16 + h * 4 + 0] + t1 * g_fold1[16 + h * 4 + 1]
               + t2 * g_fold1[16 + h * 4 + 2] + t3 * g_fold1[16 + h * 4 + 3];
    }
    *(float4*)(g_es + n * 4) = es;
    *(float4*)(g_ed + n * 4) = ed;
}

// ---------------------------------------------------------------------------
// Layer-1 aggregation (2 passes: max, fused exp-sum + weighted accumulate)
// ---------------------------------------------------------------------------
__global__ void agg_rank4_kernel(const int* __restrict__ trip, int N) {
    const int H = 4;
    int warp = (blockIdx.x * blockDim.x + threadIdx.x) >> 5;
    int lane = threadIdx.x & 31;
    if (warp >= N) return;
    int n   = warp;
    int r0  = g_rowptr[n];
    int deg = g_rowptr[n + 1] - r0;
    int tot = deg + 1;

    float4 edv4 = *(const float4*)(g_ed + n * 4);
    float edv[H] = {edv4.x, edv4.y, edv4.z, edv4.w};
    float m[H] = {-1e30f, -1e30f, -1e30f, -1e30f};
    // pass 1: max
    for (int i = lane; i < tot; i += 32) {
        int src = (i < deg) ? g_csrc[r0 + i] : n;
        float4 es = *(const float4*)(g_es + src * 4);
        float ev[H] = {es.x, es.y, es.z, es.w};
#pragma unroll
        for (int h = 0; h < H; h++) {
            float e = ev[h] + edv[h];
            e = e > 0.f ? e : 0.2f * e;
            m[h] = fmaxf(m[h], e);
        }
    }
#pragma unroll
    for (int h = 0; h < H; h++)
        for (int o = 16; o; o >>= 1) m[h] = fmaxf(m[h], __shfl_xor_sync(0xffffffffu, m[h], o));
    // pass 2: unnormalized accumulate + Z
    float4 acc[H];
    float z[H];
#pragma unroll
    for (int h = 0; h < H; h++) { acc[h] = make_float4(0.f, 0.f, 0.f, 0.f); z[h] = 0.f; }
    for (int i = lane; i < tot; i += 32) {
        int src = (i < deg) ? g_csrc[r0 + i] : n;
        float4 es = *(const float4*)(g_es + src * 4);
        float ev[H] = {es.x, es.y, es.z, es.w};
        int4 tv = *(const int4*)(trip + src * 4);
        float4 tf = make_float4((float)tv.x, (float)tv.y, (float)tv.z, (float)tv.w);
#pragma unroll
        for (int h = 0; h < H; h++) {
            float e = ev[h] + edv[h];
            e = e > 0.f ? e : 0.2f * e;
            float w = __expf(e - m[h]);
            z[h] += w;
            acc[h].x += w * tf.x; acc[h].y += w * tf.y;
            acc[h].z += w * tf.z; acc[h].w += w * tf.w;
        }
    }
#pragma unroll
    for (int h = 0; h < H; h++) {
        for (int o = 16; o; o >>= 1) {
            acc[h].x += __shfl_xor_sync(0xffffffffu, acc[h].x, o);
            acc[h].y += __shfl_xor_sync(0xffffffffu, acc[h].y, o);
            acc[h].z += __shfl_xor_sync(0xffffffffu, acc[h].z, o);
            acc[h].w += __shfl_xor_sync(0xffffffffu, acc[h].w, o);
            z[h]     += __shfl_xor_sync(0xffffffffu, z[h], o);
        }
    }
    if (lane == 0) {
#pragma unroll
        for (int h = 0; h < H; h++) {
            float iz = 1.f / z[h];
            float4 r = make_float4(acc[h].x * iz, acc[h].y * iz, acc[h].z * iz, acc[h].w * iz);
            *(float4*)(g_tt + n * 16 + h * 4) = r;
        }
    }
}

// ---------------------------------------------------------------------------
// tgemm_r4: GEMM1 with A generated on the fly from g_tt (rank-4 + elu + split).
// C[M,128] = elu(tt@Wp + bp + b1) @ B (+bl1), B bf16 hi/lo [128,512] K-major.
// ---------------------------------------------------------------------------
__global__ void __launch_bounds__(256)
tgemm_r4(const float* __restrict__ b1,
         const __nv_bfloat16* __restrict__ Bh, const __nv_bfloat16* __restrict__ Bl,
         float* __restrict__ Cf, int M, const float* __restrict__ cbias) {
    const int K = 512;
    extern __shared__ __align__(16) char dsm[];
    char*    sAc = dsm;                     // A: 2 x 16KB
    uint32_t sAu = smem_u32(dsm);
    uint32_t sBu = sAu + 32768;             // B: 2 x 16KB

    int tid  = threadIdx.x;
    int wid  = tid >> 5;
    int lane = tid & 31;
    int m0   = blockIdx.y * 128;
    int wm   = wid & 3;
    int wn   = wid >> 2;

    float acc[2][8][4];
#pragma unroll
    for (int i = 0; i < 2; i++)
#pragma unroll
        for (int j = 0; j < 8; j++)
#pragma unroll
            for (int l = 0; l < 4; l++) acc[i][j][l] = 0.f;

#define STAGEB(BUF, KC)                                                        \
    {                                                                          \
        int _kc = (KC);                                                        \
        _Pragma("unroll")                                                      \
        for (int it = 0; it < 4; it++) {                                       \
            int idx = it * 256 + tid;                                          \
            int row = idx >> 3, ch = idx & 7;                                  \
            const __nv_bfloat16* gs = ((ch < 4) ? Bh : Bl)                     \
                + (size_t)row * K + _kc + (ch & 3) * 8;                        \
            uint32_t dst = sBu + (BUF) * 16384 + row * 128                     \
                + ((ch ^ (row & 7)) << 4);                                     \
            CPA(dst, gs);                                                      \
        }                                                                      \
    }

#define STAGEA(BUF, KC)                                                        \
    {                                                                          \
        int _kc = (KC);                                                        \
        int _h  = _kc >> 7;                                                    \
        _Pragma("unroll")                                                      \
        for (int it = 0; it < 4; it++) {                                       \
            int idx = it * 256 + tid;                                          \
            int row = idx >> 3, cg = idx & 7;                                  \
            int gr = m0 + row; if (gr >= M) gr = M - 1;                        \
            float4 t = *(const float4*)(g_tt + gr * 16 + _h * 4);              \
            int j = _kc + cg * 4;                                              \
            float4 w0 = *(const float4*)(g_Wp + 0 * 512 + j);                  \
            float4 w1 = *(const float4*)(g_Wp + 1 * 512 + j);                  \
            float4 w2 = *(const float4*)(g_Wp + 2 * 512 + j);                  \
            float4 w3 = *(const float4*)(g_Wp + 3 * 512 + j);                  \
            float4 bb = *(const float4*)(g_bp + j);                            \
            float4 b2v = *(const float4*)(b1 + j);                             \
            float v0 = bb.x + b2v.x + t.x * w0.x + t.y * w1.x + t.z * w2.x + t.w * w3.x; \
            float v1 = bb.y + b2v.y + t.x * w0.y + t.y * w1.y + t.z * w2.y + t.w * w3.y; \
            float v2 = bb.z + b2v.z + t.x * w0.z + t.y * w1.z + t.z * w2.z + t.w * w3.z; \
            float v3 = bb.w + b2v.w + t.x * w0.w + t.y * w1.w + t.z * w2.w + t.w * w3.w; \
            v0 = v0 > 0.f ? v0 : __expf(v0) - 1.f;                             \
            v1 = v1 > 0.f ? v1 : __expf(v1) - 1.f;                             \
            v2 = v2 > 0.f ? v2 : __expf(v2) - 1.f;                             \
            v3 = v3 > 0.f ? v3 : __expf(v3) - 1.f;                             \
            __nv_bfloat16 h0 = __float2bfloat16(v0);                           \
            __nv_bfloat16 h1 = __float2bfloat16(v1);                           \
            __nv_bfloat16 h2 = __float2bfloat16(v2);                           \
            __nv_bfloat16 h3 = __float2bfloat16(v3);                           \
            uint2 hi2 = make_uint2(pack_bf(h0, h1), pack_bf(h2, h3));          \
            uint2 lo2 = make_uint2(                                            \
                pack_bf(__float2bfloat16(v0 - __bfloat162float(h0)),           \
                        __float2bfloat16(v1 - __bfloat162float(h1))),          \
                pack_bf(__float2bfloat16(v2 - __bfloat162float(h2)),           \
                        __float2bfloat16(v3 - __bfloat162float(h3))));         \
            int ch = cg >> 1, rem = (cg & 1) * 8;                              \
            char* base = sAc + (BUF) * 16384 + row * 128;                      \
            *(uint2*)(base + (((ch)     ^ (row & 7)) << 4) + rem) = hi2;       \
            *(uint2*)(base + (((ch + 4) ^ (row & 7)) << 4) + rem) = lo2;       \
        }                                                                      \
    }

    int nk = K >> 5;  // 16
    STAGEB(0, 0)
    asm volatile("cp.async.commit_group;");
    STAGEA(0, 0)

    for (int i = 0; i < nk; i++) {
        int buf = i & 1;
        if (i + 1 < nk) {
            STAGEB(buf ^ 1, (i + 1) * 32)
            asm volatile("cp.async.commit_group;");
            STAGEA(buf ^ 1, (i + 1) * 32)
            asm volatile("cp.async.wait_group 1;");
        } else {
            asm volatile("cp.async.wait_group 0;");
        }
        __syncthreads();

        uint32_t a_base = sAu + buf * 16384;
        uint32_t b_base = sBu + buf * 16384;
#pragma unroll
        for (int ks = 0; ks < 2; ks++) {
            uint32_t ah[2][4], al[2][4], bh[4][4], bl[4][4];
            int arow = (lane & 7) + ((lane >> 3) & 1) * 8;
            int akg  = 2 * ks + (lane >> 4);
#pragma unroll
            for (int mf = 0; mf < 2; mf++) {
                int r = 32 * wm + 16 * mf + arow;
                ldsm4(ah[mf], a_base + r * 128 + (((akg)     ^ (r & 7)) << 4));
                ldsm4(al[mf], a_base + r * 128 + (((akg + 4) ^ (r & 7)) << 4));
            }
            int brow = (lane & 7) + (lane >> 4) * 8;
            int bkg  = 2 * ks + ((lane >> 3) & 1);
#pragma unroll
            for (int q = 0; q < 4; q++) {
                int r = 64 * wn + 16 * q + brow;
                ldsm4(bh[q], b_base + r * 128 + (((bkg)     ^ (r & 7)) << 4));
                ldsm4(bl[q], b_base + r * 128 + (((bkg + 4) ^ (r & 7)) << 4));
            }
#pragma unroll
            for (int mf = 0; mf < 2; mf++) {
#pragma unroll
                for (int q = 0; q < 4; q++) {
                    mma16816(acc[mf][2 * q + 0], ah[mf], &bh[q][0]);
                    mma16816(acc[mf][2 * q + 1], ah[mf], &bh[q][2]);
                    mma16816(acc[mf][2 * q + 0], al[mf], &bh[q][0]);
                    mma16816(acc[mf][2 * q + 1], al[mf], &bh[q][2]);
                    mma16816(acc[mf][2 * q + 0], ah[mf], &bl[q][0]);
                    mma16816(acc[mf][2 * q + 1], ah[mf], &bl[q][2]);
                }
            }
        }
        __syncthreads();
    }
#undef STAGEA
#undef STAGEB

#pragma unroll
    for (int mf = 0; mf < 2; mf++) {
        int r0 = m0 + 32 * wm + 16 * mf + (lane >> 2);
#pragma unroll
        for (int nf = 0; nf < 8; nf++) {
            int col = 64 * wn + 8 * nf + 2 * (lane & 3);
            float cb0 = cbias[col], cb1 = cbias[col + 1];
#pragma unroll
            for (int rr = 0; rr < 2; rr++) {
                int r = r0 + rr * 8;
                if (r >= M) continue;
                *(float2*)(Cf + (size_t)r * CDIM + col) =
                    make_float2(acc[mf][nf][2 * rr + 0] + cb0,
                                acc[mf][nf][2 * rr + 1] + cb1);
            }
        }
    }
}

// ---------------------------------------------------------------------------
// generic cp.async double-buffered warp-MMA bf16 split GEMM (as R7)
// ---------------------------------------------------------------------------
__global__ void __launch_bounds__(256)
tgemm(const __nv_bfloat16* __restrict__ Ah, const __nv_bfloat16* __restrict__ Al,
      int lda, int boa,
      const __nv_bfloat16* __restrict__ Bh, const __nv_bfloat16* __restrict__ Bl, int bob,
      float* __restrict__ Cf, __nv_bfloat16* __restrict__ Ch, __nv_bfloat16* __restrict__ Cl,
      int ldc, int boc,
      int M, int K, const float* __restrict__ cbias, int bocb, int celu) {
    Ah += (size_t)blockIdx.z * boa;
    Al += (size_t)blockIdx.z * boa;
    Bh += (size_t)blockIdx.z * bob;
    Bl += (size_t)blockIdx.z * bob;
    if (Cf) Cf += (size_t)blockIdx.z * boc;
    if (Ch) { Ch += (size_t)blockIdx.z * boc; Cl += (size_t)blockIdx.z * boc; }
    cbias += (size_t)blockIdx.z * bocb;

    extern __shared__ __align__(16) char dsm[];
    uint32_t sAu = smem_u32(dsm);
    uint32_t sBu = sAu + 32768;

    int tid  = threadIdx.x;
    int wid  = tid >> 5;
    int lane = tid & 31;
    int m0   = blockIdx.y * 128;
    int wm   = wid & 3;
    int wn   = wid >> 2;

    float acc[2][8][4];
#pragma unroll
    for (int i = 0; i < 2; i++)
#pragma unroll
        for (int j = 0; j < 8; j++)
#pragma unroll
            for (int l = 0; l < 4; l++) acc[i][j][l] = 0.f;

#define STAGE(BUF, KC)                                                         \
    {                                                                          \
        int _kc = (KC);                                                        \
        _Pragma("unroll")                                                      \
        for (int it = 0; it < 4; it++) {                                       \
            int idx = it * 256 + tid;                                          \
            int row = idx >> 3, ch = idx & 7;                                  \
            const __nv_bfloat16* gs = ((ch < 4) ? Ah : Al)                     \
                + (size_t)(m0 + row) * lda + _kc + (ch & 3) * 8;               \
            uint32_t dst = sAu + (BUF) * 16384 + row * 128                     \
                + ((ch ^ (row & 7)) << 4);                                     \
            CPA(dst, gs);                                                      \
        }                                                                      \
        _Pragma("unroll")                                                      \
        for (int it = 0; it < 4; it++) {                                       \
            int idx = it * 256 + tid;                                          \
            int row = idx >> 3, ch = idx & 7;                                  \
            const __nv_bfloat16* gs = ((ch < 4) ? Bh : Bl)                     \
                + (size_t)row * K + _kc + (ch & 3) * 8;                        \
            uint32_t dst = sBu + (BUF) * 16384 + row * 128                     \
                + ((ch ^ (row & 7)) << 4);                                     \
            CPA(dst, gs);                                                      \
        }                                                                      \
    }

    int nk = K >> 5;
    STAGE(0, 0)
    asm volatile("cp.async.commit_group;");

    for (int i = 0; i < nk; i++) {
        int buf = i & 1;
        if (i + 1 < nk) {
            STAGE(buf ^ 1, (i + 1) * 32)
            asm volatile("cp.async.commit_group;");
            asm volatile("cp.async.wait_group 1;");
        } else {
            asm volatile("cp.async.wait_group 0;");
        }
        __syncthreads();

        uint32_t a_base = sAu + buf * 16384;
        uint32_t b_base = sBu + buf * 16384;
#pragma unroll
        for (int ks = 0; ks < 2; ks++) {
            uint32_t ah[2][4], al[2][4], bh[4][4], bl[4][4];
            int arow = (lane & 7) + ((lane >> 3) & 1) * 8;
            int akg  = 2 * ks + (lane >> 4);
#pragma unroll
            for (int mf = 0; mf < 2; mf++) {
                int r = 32 * wm + 16 * mf + arow;
                ldsm4(ah[mf], a_base + r * 128 + (((akg)     ^ (r & 7)) << 4));
                ldsm4(al[mf], a_base + r * 128 + (((akg + 4) ^ (r & 7)) << 4));
            }
            int brow = (lane & 7) + (lane >> 4) * 8;
            int bkg  = 2 * ks + ((lane >> 3) & 1);
#pragma unroll
            for (int q = 0; q < 4; q++) {
                int r = 64 * wn + 16 * q + brow;
                ldsm4(bh[q], b_base + r * 128 + (((bkg)     ^ (r & 7)) << 4));
                ldsm4(bl[q], b_base + r * 128 + (((bkg + 4) ^ (r & 7)) << 4));
            }
#pragma unroll
            for (int mf = 0; mf < 2; mf++) {
#pragma unroll
                for (int q = 0; q < 4; q++) {
                    mma16816(acc[mf][2 * q + 0], ah[mf], &bh[q][0]);
                    mma16816(acc[mf][2 * q + 1], ah[mf], &bh[q][2]);
                    mma16816(acc[mf][2 * q + 0], al[mf], &bh[q][0]);
                    mma16816(acc[mf][2 * q + 1], al[mf], &bh[q][2]);
                    mma16816(acc[mf][2 * q + 0], ah[mf], &bl[q][0]);
                    mma16816(acc[mf][2 * q + 1], ah[mf], &bl[q][2]);
                }
            }
        }
        __syncthreads();
    }
#undef STAGE

#pragma unroll
    for (int mf = 0; mf < 2; mf++) {
        int r0 = m0 + 32 * wm + 16 * mf + (lane >> 2);
#pragma unroll
        for (int nf = 0; nf < 8; nf++) {
            int col = 64 * wn + 8 * nf + 2 * (lane & 3);
            float cb0 = cbias[col], cb1 = cbias[col + 1];
#pragma unroll
            for (int rr = 0; rr < 2; rr++) {
                int r = r0 + rr * 8;
                if (r >= M) continue;
                float v0 = acc[mf][nf][2 * rr + 0] + cb0;
                float v1 = acc[mf][nf][2 * rr + 1] + cb1;
                if (Cf) {
                    *(float2*)(Cf + (size_t)r * ldc + col) = make_float2(v0, v1);
                } else {
                    if (celu) {
                        v0 = v0 > 0.f ? v0 : __expf(v0) - 1.f;
                        v1 = v1 > 0.f ? v1 : __expf(v1) - 1.f;
                    }
                    __nv_bfloat16 h0 = __float2bfloat16(v0);
                    __nv_bfloat16 h1 = __float2bfloat16(v1);
                    size_t o = (size_t)r * ldc + col;
                    *(uint32_t*)(Ch + o) = pack_bf(h0, h1);
                    *(uint32_t*)(Cl + o) =
                        pack_bf(__float2bfloat16(v0 - __bfloat162float(h0)),
                                __float2bfloat16(v1 - __bfloat162float(h1)));
                }
            }
        }
    }
}

// ---------------------------------------------------------------------------
// Layer-2 folded attention weights + logits (padded stride-8 output)
// ---------------------------------------------------------------------------
__global__ void wfold2_kernel(const float* __restrict__ W2,
                              const float* __restrict__ a2s,
                              const float* __restrict__ a2d, int H, int M2) {
    int tid = blockIdx.x * blockDim.x + threadIdx.x;
    if (tid >= CDIM * 2 * H) return;
    int c = tid / (2 * H), o = tid - c * (2 * H);
    int h = o % H;
    const float* av = (o < H) ? a2s : a2d;
    float s = 0.f;
    for (int k = 0; k < CDIM; k++) s += W2[c * M2 + h * CDIM + k] * av[h * CDIM + k];
    g_fold2[c * (2 * H) + o] = s;
}

__global__ void es2_kernel(int N, int H) {
    __shared__ float wt[CDIM * 10];
    int tid = threadIdx.x;
    int TW = CDIM * 2 * H;
    for (int i = tid; i < TW; i += blockDim.x) wt[i] = g_fold2[i];
    __syncthreads();
    int warp = blockIdx.x * (blockDim.x >> 5) + (tid >> 5);
    int lane = tid & 31;
    if (warp >= N) return;
    float4 hv = *(const float4*)(g_h1 + (size_t)warp * CDIM + lane * 4);
    float s[10];
#pragma unroll
    for (int o = 0; o < 10; o++) s[o] = 0.f;
    float hvv[4] = {hv.x, hv.y, hv.z, hv.w};
#pragma unroll
    for (int j = 0; j < 4; j++) {
        int c = lane * 4 + j;
        for (int o = 0; o < 2 * H; o++) s[o] += hvv[j] * wt[c * (2 * H) + o];
    }
    for (int o = 0; o < 2 * H; o++)
        for (int off = 16; off; off >>= 1) s[o] += __shfl_xor_sync(0xffffffffu, s[o], off);
    if (lane < H)          g_es2p[warp * 8 + lane] = s[lane];
    else if (lane < 2 * H) g_ed2p[warp * 8 + lane - H] = s[lane];
}

// ---------------------------------------------------------------------------
// Layer-2 aggregation: max pass + single gather pass (unnormalized + Z)
// ---------------------------------------------------------------------------
__global__ void agg2_kernel(const float* __restrict__ feat, int N) {
    const int H = 5;
    int warp = (blockIdx.x * blockDim.x + threadIdx.x) >> 5;
    int lane = threadIdx.x & 31;
    if (warp >= N) return;
    int n   = warp;
    int r0  = g_rowptr[n];
    int deg = g_rowptr[n + 1] - r0;
    int tot = deg + 1;

    float edv[H], m[H];
    {
        float4 e4 = *(const float4*)(g_ed2p + n * 8);
        edv[0] = e4.x; edv[1] = e4.y; edv[2] = e4.z; edv[3] = e4.w;
        edv[4] = g_ed2p[n * 8 + 4];
    }
#pragma unroll
    for (int h = 0; h < H; h++) m[h] = -1e30f;
    // pass 1: max
    for (int i = lane; i < tot; i += 32) {
        int src = (i < deg) ? g_csrc[r0 + i] : n;
        float4 e4 = *(const float4*)(g_es2p + src * 8);
        float ev[H] = {e4.x, e4.y, e4.z, e4.w, g_es2p[src * 8 + 4]};
#pragma unroll
        for (int h = 0; h < H; h++) {
            float e = ev[h] + edv[h];
            e = e > 0.f ? e : 0.2f * e;
            m[h] = fmaxf(m[h], e);
        }
    }
#pragma unroll
    for (int h = 0; h < H; h++)
        for (int o = 16; o; o >>= 1) m[h] = fmaxf(m[h], __shfl_xor_sync(0xffffffffu, m[h], o));

    // pass 2: tiled gather, unnormalized + per-lane partial Z
    float4 acc[H];
    float zp[H];
#pragma unroll
    for (int h = 0; h < H; h++) { acc[h] = make_float4(0.f, 0.f, 0.f, 0.f); zp[h] = 0.f; }

    for (int t = 0; t < tot; t += 32) {
        int i = t + lane;
        int src = n;
        float w[H];
        if (i < tot) {
            src = (i < deg) ? g_csrc[r0 + i] : n;
            float4 e4 = *(const float4*)(g_es2p + src * 8);
            float ev[H] = {e4.x, e4.y, e4.z, e4.w, g_es2p[src * 8 + 4]};
#pragma unroll
            for (int h = 0; h < H; h++) {
                float e = ev[h] + edv[h];
                e = e > 0.f ? e : 0.2f * e;
                w[h] = __expf(e - m[h]);
                zp[h] += w[h];
            }
        } else {
#pragma unroll
            for (int h = 0; h < H; h++) w[h] = 0.f;
        }
        int cnt = tot - t;
        if (cnt > 32) cnt = 32;
#pragma unroll 4
        for (int j = 0; j < cnt; j++) {
            int s = __shfl_sync(0xffffffffu, src, j);
            float wj[H];
#pragma unroll
            for (int h = 0; h < H; h++) wj[h] = __shfl_sync(0xffffffffu, w[h], j);
            float4 v = *(const float4*)(feat + (size_t)s * CDIM + lane * 4);
#pragma unroll
            for (int h = 0; h < H; h++) {
                acc[h].x += wj[h] * v.x; acc[h].y += wj[h] * v.y;
                acc[h].z += wj[h] * v.z; acc[h].w += wj[h] * v.w;
            }
        }
    }
#pragma unroll
    for (int h = 0; h < H; h++)
        for (int o = 16; o; o >>= 1) zp[h] += __shfl_xor_sync(0xffffffffu, zp[h], o);

#pragma unroll
    for (int h = 0; h < H; h++) {
        float iz = 1.f / zp[h];
        float ax = acc[h].x * iz, ay = acc[h].y * iz;
        float az = acc[h].z * iz, aw = acc[h].w * iz;
        __nv_bfloat16 hx = __float2bfloat16(ax);
        __nv_bfloat16 hy = __float2bfloat16(ay);
        __nv_bfloat16 hz = __float2bfloat16(az);
        __nv_bfloat16 hw = __float2bfloat16(aw);
        size_t o = (size_t)n * (H * CDIM) + h * CDIM + lane * 4;
        *(uint2*)(g_A2h + o) = make_uint2(pack_bf(hx, hy), pack_bf(hz, hw));
        *(uint2*)(g_A2l + o) = make_uint2(
            pack_bf(__float2bfloat16(ax - __bfloat162float(hx)),
                    __float2bfloat16(ay - __bfloat162float(hy))),
            pack_bf(__float2bfloat16(az - __bfloat162float(hz)),
                    __float2bfloat16(aw - __bfloat162float(hw))));
    }
}

// ---------------------------------------------------------------------------
__global__ void readout_kernel(int N) {
    int tid = threadIdx.x;
    float a = 0.f;
    for (int n = blockIdx.x; n < N; n += gridDim.x)
        a += g_h1[(size_t)n * CDIM + tid] + g_h2[(size_t)n * CDIM + tid];
    atomicAdd(&g_hsum[tid], a);
}

__global__ void tail0_kernel(const float* __restrict__ Wfc, const float* __restrict__ bfc,
                             const float* __restrict__ Whg, const float* __restrict__ bhg,
                             const float* __restrict__ Wv,  const float* __restrict__ bv,
                             const float* __restrict__ h_mat, const float* __restrict__ h_bias,
                             int N, int HOUT) {
    __shared__ float h[128];
    __shared__ float tm[256];
    __shared__ float hg[128];
    int tid = threadIdx.x;
    if (tid < 128) h[tid] = g_hsum[tid] / (float)N;
    __syncthreads();
    if (tid < 256) {
        float a = bfc[tid];
        for (int i = 0; i < 128; i++) a += h[i] * Wfc[i * 256 + tid];
        tm[tid] = a > 0.f ? a : 0.f;
    }
    __syncthreads();
    if (tid < 128) {
        float a = bhg[tid];
        for (int i = 0; i < 256; i++) a += tm[i] * Whg[i * 128 + tid];
        hg[tid] = a;
    }
    __syncthreads();
    if (tid < 384) {
        float a = bv[tid];
        for (int i = 0; i < 128; i++) a += hg[i] * Wv[i * 384 + tid];
        g_small[tid] = a > 0.f ? a : 0.f;
        float hs = 0.f;
        for (int hh = 0; hh < HOUT; hh++) hs += h_mat[hh * 384 + tid];
        g_small[384 + tid] = hs;
    }
    if (tid == 0) {
        float hb = 0.f;
        for (int i = 0; i < HOUT; i++) hb += h_bias[i];
        g_small[768] = hb;
    }
}

__global__ void tail1_kernel(const float* __restrict__ cell,
                             const float* __restrict__ Wc, const float* __restrict__ bc,
                             const float* __restrict__ Wq, const float* __restrict__ bq,
                             int CF) {
    __shared__ float sc[1024];
    __shared__ float crow[128];
    __shared__ float qrow[384];
    __shared__ float red[128];
    int b = blockIdx.x, tid = threadIdx.x;
    for (int i = tid; i < CF; i += 128) sc[i] = cell[(size_t)b * CF + i];
    __syncthreads();
    {
        float a = bc[tid];
        for (int k = 0; k < CF; k++) a += sc[k] * Wc[k * 128 + tid];
        crow[tid] = a > 0.f ? a : 0.f;
    }
    __syncthreads();
    float part = 0.f;
    for (int mI = tid; mI < 384; mI += 128) {
        float q = bq[mI];
        for (int k = 0; k < 128; k++) q += crow[k] * Wq[k * 384 + mI];
        q = q > 0.f ? q : 0.f;
        qrow[mI] = q;
        part += g_small[384 + mI] * g_small[mI] * q;
    }
    red[tid] = part;
    __syncthreads();
    for (int o = 64; o; o >>= 1) {
        if (tid < o) red[tid] += red[tid + o];
        __syncthreads();
    }
    float att = red[0] + g_small[768];
    float l = 0.f;
#pragma unroll
    for (int j = 0; j < 3; j++) {
        int k = tid * 3 + j;
        l += g_small[k] * qrow[k];
    }
    g_logits[b * 128 + tid] = att * l;
}

__global__ void tail2_kernel(const float* __restrict__ gamma,
                             const float* __restrict__ beta,
                             float* __restrict__ out, int B) {
    __shared__ float s1[256], s2[256];
    int c = blockIdx.x, b = threadIdx.x;
    float v = g_logits[b * 128 + c];
    s1[b] = v;
    s2[b] = v * v;
    __syncthreads();
    for (int o = B >> 1; o; o >>= 1) {
        if (b < o) { s1[b] += s1[b + o]; s2[b] += s2[b + o]; }
        __syncthreads();
    }
    float mu  = s1[0] / (float)B;
    float var = s2[0] / (float)B - mu * mu;
    out[b * 128 + c] = (v - mu) * rsqrtf(var + 1e-5f) * gamma[c] + beta[c];
}

// ---------------------------------------------------------------------------
// launch
// ---------------------------------------------------------------------------
extern "C" void kernel_launch(void* const* d_in, const int* in_sizes, int n_in,
                              void* d_out, int out_size) {
    const float* cell = (const float*)d_in[0];
    const float* Wd   = (const float*)d_in[1];
    const float* bd   = (const float*)d_in[2];
    const float* W1   = (const float*)d_in[3];
    const float* a1s  = (const float*)d_in[4];
    const float* a1d  = (const float*)d_in[5];
    const float* b1   = (const float*)d_in[6];
    const float* Wl1  = (const float*)d_in[7];
    const float* bl1  = (const float*)d_in[8];
    const float* W2   = (const float*)d_in[9];
    const float* a2s  = (const float*)d_in[10];
    const float* a2d  = (const float*)d_in[11];
    const float* b2   = (const float*)d_in[12];
    const float* Wl2  = (const float*)d_in[13];
    const float* bl2  = (const float*)d_in[14];
    const float* Wfc  = (const float*)d_in[15];
    const float* bfc  = (const float*)d_in[16];
    const float* Whg  = (const float*)d_in[17];
    const float* bhg  = (const float*)d_in[18];
    const float* Wc   = (const float*)d_in[19];
    const float* bc   = (const float*)d_in[20];
    const float* Wv   = (const float*)d_in[21];
    const float* bv   = (const float*)d_in[22];
    const float* Wq   = (const float*)d_in[23];
    const float* bq   = (const float*)d_in[24];
    const float* h_mat  = (const float*)d_in[25];
    const float* h_bias = (const float*)d_in[26];
    const float* gamma  = (const float*)d_in[27];
    const float* beta   = (const float*)d_in[28];
    const int*   trip   = (const int*)d_in[29];
    const int*   ei     = (const int*)d_in[30];

    int N  = in_sizes[29] / 4;
    int E  = in_sizes[30] / 2;
    int CF = in_sizes[19] / 128;
    int B  = in_sizes[0] / CF;
    int H1 = in_sizes[4] / 128;   // 4
    int H2 = in_sizes[10] / 128;  // 5
    int HOUT = in_sizes[26];
    if (N > NMAX) N = NMAX;
    if (E > EMAX) E = EMAX;
    float* out = (float*)d_out;

    void *ph1, *ph2;
    void *pA2h, *pA2l, *pA3h, *pA3l;
    void *pb1h, *pb1l, *pb2h, *pb2l, *pb3h, *pb3l;
    cudaGetSymbolAddress(&ph1,  g_h1);
    cudaGetSymbolAddress(&ph2,  g_h2);
    cudaGetSymbolAddress(&pA2h, g_A2h);
    cudaGetSymbolAddress(&pA2l, g_A2l);
    cudaGetSymbolAddress(&pA3h, g_A3h);
    cudaGetSymbolAddress(&pA3l, g_A3l);
    cudaGetSymbolAddress(&pb1h, g_bt1h);
    cudaGetSymbolAddress(&pb1l, g_bt1l);
    cudaGetSymbolAddress(&pb2h, g_bt2h);
    cudaGetSymbolAddress(&pb2l, g_bt2l);
    cudaGetSymbolAddress(&pb3h, g_bt3h);
    cudaGetSymbolAddress(&pb3l, g_bt3l);

    cudaFuncSetAttribute(tgemm,    cudaFuncAttributeMaxDynamicSharedMemorySize, 65536);
    cudaFuncSetAttribute(tgemm_r4, cudaFuncAttributeMaxDynamicSharedMemorySize, 65536);

    int M1 = H1 * CDIM;  // 512
    int M2 = H2 * CDIM;  // 640
    int mt = (N + 127) / 128;

    // CSR build + zero
    zero_kernel<<<(N + 255) / 256, 256>>>(N);
    count_kernel<<<(E / 2 + 255) / 256, 256>>>(ei, E);
    scan_kernel<<<1, 1024>>>(N);
    fill_kernel<<<(E / 2 + 255) / 256, 256>>>(ei, E);

    // weight prep (bf16 transposed splits)
    btprep_kernel<<<dim3((128 * M1 + 255) / 256, 1), 256>>>(Wl1, 128, M1,
        (__nv_bfloat16*)pb1h, (__nv_bfloat16*)pb1l);
    btprep_kernel<<<dim3((128 * 128 + 255) / 256, H2), 256>>>(W2, M2, 128,
        (__nv_bfloat16*)pb2h, (__nv_bfloat16*)pb2l);
    btprep_kernel<<<dim3((128 * M2 + 255) / 256, 1), 256>>>(Wl2, 128, M2,
        (__nv_bfloat16*)pb3h, (__nv_bfloat16*)pb3l);

    // ---- GAT layer 1 (rank-4 until projection; GEMM generates A on the fly) ----
    wprep_kernel<<<(M1 + 127) / 128, 128>>>(Wd, bd, W1, M1);
    wfold1_kernel<<<1, 64>>>(a1s, a1d, H1, M1);
    es1_kernel<<<(N + 255) / 256, 256>>>(trip, N);
    agg_rank4_kernel<<<(N * 32 + 255) / 256, 256>>>(trip, N);
    tgemm_r4<<<dim3(1, mt, 1), 256, 65536>>>(
        b1, (const __nv_bfloat16*)pb1h, (const __nv_bfloat16*)pb1l,
        (float*)ph1, N, bl1);

    // ---- GAT layer 2 ----
    wfold2_kernel<<<(CDIM * 2 * H2 + 127) / 128, 128>>>(W2, a2s, a2d, H2, M2);
    es2_kernel<<<(N + 7) / 8, 256>>>(N, H2);
    agg2_kernel<<<(N * 32 + 255) / 256, 256>>>((const float*)ph1, N);
    tgemm<<<dim3(1, mt, H2), 256, 65536>>>(
        (const __nv_bfloat16*)pA2h, (const __nv_bfloat16*)pA2l, M2, 128,
        (const __nv_bfloat16*)pb2h, (const __nv_bfloat16*)pb2l, 128 * 128,
        nullptr, (__nv_bfloat16*)pA3h, (__nv_bfloat16*)pA3l, M2, 128,
        N, 128, b2, 128, 1);
    tgemm<<<dim3(1, mt, 1), 256, 65536>>>(
        (const __nv_bfloat16*)pA3h, (const __nv_bfloat16*)pA3l, M2, 0,
        (const __nv_bfloat16*)pb3h, (const __nv_bfloat16*)pb3l, 0,
        (float*)ph2, nullptr, nullptr, CDIM, 0, N, M2, bl2, 0, 0);

    // readout + tail
    readout_kernel<<<256, 128>>>(N);
    tail0_kernel<<<1, 384>>>(Wfc, bfc, Whg, bhg, Wv, bv, h_mat, h_bias, N, HOUT);
    tail1_kernel<<<B, 128>>>(cell, Wc, bc, Wq, bq, CF);
    tail2_kernel<<<128, B>>>(gamma, beta, out, B);
}

// round 9
// speedup vs baseline: 1.6607x; 1.0139x over previous
#include <cuda_runtime.h>
#include <cuda_bf16.h>
#include <math.h>
#include <stdint.h>

#define NMAX 20000
#define EMAX 500000
#define CDIM 128
#define NPAD (NMAX + 128)

// ---------------------------------------------------------------------------
// Static device scratch
// ---------------------------------------------------------------------------
__device__ float g_h1  [NMAX * CDIM];
__device__ float g_es  [NMAX * 4];       // layer-1 logits, stride 4 (float4)
__device__ float g_ed  [NMAX * 4];
__device__ float g_es2p[NMAX * 8];       // layer-2 logits, stride 8 padded
__device__ float g_ed2p[NMAX * 8];
__device__ float g_tt  [NMAX * 16];      // layer-1 aggregated rank-4 coords
__device__ int   g_cnt   [NMAX];
__device__ int   g_rowptr[NMAX + 1];
__device__ int   g_cursor[NMAX];
__device__ int   g_csrc  [EMAX];
__device__ float g_hsum  [CDIM];
__device__ float g_small [1024];
__device__ float g_logits[256 * CDIM];
__device__ float g_Wp  [4 * 512];
__device__ float g_bp  [512];
__device__ float g_fold1[48];
__device__ float g_fold2[128 * 10];
// bf16 hi/lo GEMM A operands (padded rows for tile overrun safety)
__device__ __nv_bfloat16 g_A2h[NPAD * 640], g_A2l[NPAD * 640];
__device__ __nv_bfloat16 g_A3h[NPAD * 640], g_A3l[NPAD * 640];
// bf16 hi/lo transposed weights [128(N), K] K-major
__device__ __nv_bfloat16 g_bt1h[128 * 512], g_bt1l[128 * 512];
__device__ __nv_bfloat16 g_bt2h[5 * 128 * 128], g_bt2l[5 * 128 * 128];
__device__ __nv_bfloat16 g_bt3h[128 * 640], g_bt3l[128 * 640];

// ---------------------------------------------------------------------------
// helpers
// ---------------------------------------------------------------------------
__device__ __forceinline__ uint32_t smem_u32(const void* p) {
    uint32_t a;
    asm("{ .reg .u64 t; cvta.to.shared.u64 t, %1; cvt.u32.u64 %0, t; }" : "=r"(a) : "l"(p));
    return a;
}
__device__ __forceinline__ void ldsm4(uint32_t* r, uint32_t addr) {
    asm volatile("ldmatrix.sync.aligned.m8n8.x4.shared.b16 {%0,%1,%2,%3}, [%4];"
                 : "=r"(r[0]), "=r"(r[1]), "=r"(r[2]), "=r"(r[3]) : "r"(addr));
}
__device__ __forceinline__ void mma16816(float* d, const uint32_t* a, const uint32_t* b) {
    asm volatile(
        "mma.sync.aligned.m16n8k16.row.col.f32.bf16.bf16.f32 "
        "{%0,%1,%2,%3}, {%4,%5,%6,%7}, {%8,%9}, {%0,%1,%2,%3};"
        : "+f"(d[0]), "+f"(d[1]), "+f"(d[2]), "+f"(d[3])
        : "r"(a[0]), "r"(a[1]), "r"(a[2]), "r"(a[3]), "r"(b[0]), "r"(b[1]));
}
__device__ __forceinline__ uint32_t pack_bf(__nv_bfloat16 a, __nv_bfloat16 b) {
    __nv_bfloat162 t;
    t.x = a; t.y = b;
    return *reinterpret_cast<uint32_t*>(&t);
}
#define CPA(dst, src) \
    asm volatile("cp.async.cg.shared.global [%0], [%1], 16;" :: "r"(dst), "l"(src))

// ---------------------------------------------------------------------------
__global__ void zero_kernel(int N) {
    int i = blockIdx.x * blockDim.x + threadIdx.x;
    if (i < N)   g_cnt[i] = 0;
    if (i < CDIM) g_hsum[i] = 0.f;
}

// ---------------------------------------------------------------------------
// CSR build (2 edges/thread)
// ---------------------------------------------------------------------------
__global__ void count_kernel(const int* __restrict__ ei, int E) {
    int e = (blockIdx.x * blockDim.x + threadIdx.x) * 2;
    if (e + 1 < E) {
        int2 s = *(const int2*)(ei + e);
        int2 d = *(const int2*)(ei + E + e);
        if (s.x != d.x) atomicAdd(&g_cnt[d.x], 1);
        if (s.y != d.y) atomicAdd(&g_cnt[d.y], 1);
    } else if (e < E) {
        int s = ei[e], d = ei[E + e];
        if (s != d) atomicAdd(&g_cnt[d], 1);
    }
}

__global__ void scan_kernel(int N) {
    __shared__ int wsum[32];
    __shared__ int carry_s;
    int tid = threadIdx.x, lane = tid & 31, wid = tid >> 5;
    if (tid == 0) { carry_s = 0; g_rowptr[0] = 0; }
    __syncthreads();
    for (int base = 0; base < N; base += 1024) {
        int i = base + tid;
        int v = (i < N) ? g_cnt[i] : 0;
        int x = v;
#pragma unroll
        for (int o = 1; o < 32; o <<= 1) {
            int t = __shfl_up_sync(0xffffffffu, x, o);
            if (lane >= o) x += t;
        }
        if (lane == 31) wsum[wid] = x;
        __syncthreads();
        if (wid == 0) {
            int s = wsum[lane];
#pragma unroll
            for (int o = 1; o < 32; o <<= 1) {
                int t = __shfl_up_sync(0xffffffffu, s, o);
                if (lane >= o) s += t;
            }
            wsum[lane] = s;
        }
        __syncthreads();
        int inc = carry_s + (wid ? wsum[wid - 1] : 0) + x;
        if (i < N) { g_rowptr[i + 1] = inc; g_cursor[i] = inc - v; }
        __syncthreads();
        if (tid == 0) carry_s += wsum[31];
        __syncthreads();
    }
}

__global__ void fill_kernel(const int* __restrict__ ei, int E) {
    int e = (blockIdx.x * blockDim.x + threadIdx.x) * 2;
    if (e + 1 < E) {
        int2 s = *(const int2*)(ei + e);
        int2 d = *(const int2*)(ei + E + e);
        if (s.x != d.x) { int p = atomicAdd(&g_cursor[d.x], 1); g_csrc[p] = s.x; }
        if (s.y != d.y) { int p = atomicAdd(&g_cursor[d.y], 1); g_csrc[p] = s.y; }
    } else if (e < E) {
        int s = ei[e], d = ei[E + e];
        if (s != d) { int p = atomicAdd(&g_cursor[d], 1); g_csrc[p] = s; }
    }
}

// ---------------------------------------------------------------------------
// weight prep
// ---------------------------------------------------------------------------
__global__ void wprep_kernel(const float* __restrict__ Wd,
                             const float* __restrict__ bd,
                             const float* __restrict__ W1, int M1) {
    int j = blockIdx.x * blockDim.x + threadIdx.x;
    if (j >= M1) return;
    float a0 = 0.f, a1 = 0.f, a2 = 0.f, a3 = 0.f, ab = 0.f;
#pragma unroll 4
    for (int k = 0; k < CDIM; k++) {
        float w = W1[k * M1 + j];
        a0 += Wd[0 * CDIM + k] * w;
        a1 += Wd[1 * CDIM + k] * w;
        a2 += Wd[2 * CDIM + k] * w;
        a3 += Wd[3 * CDIM + k] * w;
        ab += bd[k] * w;
    }
    g_Wp[0 * M1 + j] = a0;
    g_Wp[1 * M1 + j] = a1;
    g_Wp[2 * M1 + j] = a2;
    g_Wp[3 * M1 + j] = a3;
    g_bp[j] = ab;
}

// transpose B [K, 128] -> bf16 hi/lo [128, K]
__global__ void btprep_kernel(const float* __restrict__ B, int ldb, int K,
                              __nv_bfloat16* __restrict__ oh,
                              __nv_bfloat16* __restrict__ ol) {
    int idx = blockIdx.x * blockDim.x + threadIdx.x;
    if (idx >= 128 * K) return;
    int j = idx / K, k = idx - j * K;
    float v = B[(size_t)k * ldb + blockIdx.y * 128 + j];
    __nv_bfloat16 h = __float2bfloat16(v);
    float r = v - __bfloat162float(h);
    size_t o = (size_t)blockIdx.y * 128 * K + idx;
    oh[o] = h;
    ol[o] = __float2bfloat16(r);
}

__global__ void wfold1_kernel(const float* __restrict__ a1s,
                              const float* __restrict__ a1d, int H, int M1) {
    int tid = threadIdx.x;
    int HG = H * 4;
    if (tid < HG) {
        int h = tid >> 2, i = tid & 3;
        float s = 0.f;
        for (int k = 0; k < CDIM; k++) s += g_Wp[i * M1 + h * CDIM + k] * a1s[h * CDIM + k];
        g_fold1[tid] = s;
    } else if (tid < 2 * HG) {
        int t = tid - HG;
        int h = t >> 2, i = t & 3;
        float s = 0.f;
        for (int k = 0; k < CDIM; k++) s += g_Wp[i * M1 + h * CDIM + k] * a1d[h * CDIM + k];
        g_fold1[16 + t] = s;
    } else if (tid < 2 * HG + H) {
        int h = tid - 2 * HG;
        float s = 0.f;
        for (int k = 0; k < CDIM; k++) s += g_bp[h * CDIM + k] * a1s[h * CDIM + k];
        g_fold1[32 + h] = s;
    } else if (tid < 2 * HG + 2 * H) {
        int h = tid - 2 * HG - H;
        float s = 0.f;
        for (int k = 0; k < CDIM; k++) s += g_bp[h * CDIM + k] * a1d[h * CDIM + k];
        g_fold1[36 + h] = s;
    }
}

__global__ void es1_kernel(const int* __restrict__ trip, int N) {
    int n = blockIdx.x * blockDim.x + threadIdx.x;
    if (n >= N) return;
    int4 tv = *(const int4*)(trip + n * 4);
    float t0 = (float)tv.x, t1 = (float)tv.y, t2 = (float)tv.z, t3 = (float)tv.w;
    float4 es, ed;
    float* esp = &es.x;
    float* edp = &ed.x;
#pragma unroll
    for (int h = 0; h < 4; h++) {
        esp[h] = g_fold1[32 + h] + t0 * g_fold1[h * 4 + 0] + t1 * g_fold1[h * 4 + 1]
               + t2 * g_fold1[h * 4 + 2] + t3 * g_fold1[h * 4 + 3];
        edp[h] = g_fold1[36 + h] + t0 * g_fold1[16 + h * 4 + 0] + t1 * g_fold1[16 + h * 4 + 1]
               + t2 * g_fold1[16 + h * 4 + 2] + t3 * g_fold1[16 + h * 4 + 3];
    }
    *(float4*)(g_es + n * 4) = es;
    *(float4*)(g_ed + n * 4) = ed;
}

// ---------------------------------------------------------------------------
// Layer-1 aggregation (2 passes: max, fused exp-sum + weighted accumulate)
// ---------------------------------------------------------------------------
__global__ void agg_rank4_kernel(const int* __restrict__ trip, int N) {
    const int H = 4;
    int warp = (blockIdx.x * blockDim.x + threadIdx.x) >> 5;
    int lane = threadIdx.x & 31;
    if (warp >= N) return;
    int n   = warp;
    int r0  = g_rowptr[n];
    int deg = g_rowptr[n + 1] - r0;
    int tot = deg + 1;

    float4 edv4 = *(const float4*)(g_ed + n * 4);
    float edv[H] = {edv4.x, edv4.y, edv4.z, edv4.w};
    float m[H] = {-1e30f, -1e30f, -1e30f, -1e30f};
    for (int i = lane; i < tot; i += 32) {
        int src = (i < deg) ? g_csrc[r0 + i] : n;
        float4 es = *(const float4*)(g_es + src * 4);
        float ev[H] = {es.x, es.y, es.z, es.w};
#pragma unroll
        for (int h = 0; h < H; h++) {
            float e = ev[h] + edv[h];
            e = e > 0.f ? e : 0.2f * e;
            m[h] = fmaxf(m[h], e);
        }
    }
#pragma unroll
    for (int h = 0; h < H; h++)
        for (int o = 16; o; o >>= 1) m[h] = fmaxf(m[h], __shfl_xor_sync(0xffffffffu, m[h], o));
    float4 acc[H];
    float z[H];
#pragma unroll
    for (int h = 0; h < H; h++) { acc[h] = make_float4(0.f, 0.f, 0.f, 0.f); z[h] = 0.f; }
    for (int i = lane; i < tot; i += 32) {
        int src = (i < deg) ? g_csrc[r0 + i] : n;
        float4 es = *(const float4*)(g_es + src * 4);
        float ev[H] = {es.x, es.y, es.z, es.w};
        int4 tv = *(const int4*)(trip + src * 4);
        float4 tf = make_float4((float)tv.x, (float)tv.y, (float)tv.z, (float)tv.w);
#pragma unroll
        for (int h = 0; h < H; h++) {
            float e = ev[h] + edv[h];
            e = e > 0.f ? e : 0.2f * e;
            float w = __expf(e - m[h]);
            z[h] += w;
            acc[h].x += w * tf.x; acc[h].y += w * tf.y;
            acc[h].z += w * tf.z; acc[h].w += w * tf.w;
        }
    }
#pragma unroll
    for (int h = 0; h < H; h++) {
        for (int o = 16; o; o >>= 1) {
            acc[h].x += __shfl_xor_sync(0xffffffffu, acc[h].x, o);
            acc[h].y += __shfl_xor_sync(0xffffffffu, acc[h].y, o);
            acc[h].z += __shfl_xor_sync(0xffffffffu, acc[h].z, o);
            acc[h].w += __shfl_xor_sync(0xffffffffu, acc[h].w, o);
            z[h]     += __shfl_xor_sync(0xffffffffu, z[h], o);
        }
    }
    if (lane == 0) {
#pragma unroll
        for (int h = 0; h < H; h++) {
            float iz = 1.f / z[h];
            float4 r = make_float4(acc[h].x * iz, acc[h].y * iz, acc[h].z * iz, acc[h].w * iz);
            *(float4*)(g_tt + n * 16 + h * 4) = r;
        }
    }
}

// ---------------------------------------------------------------------------
// tgemm_r4: GEMM1 with A generated on the fly from g_tt. 3-stage pipeline.
// C[M,128] = elu(tt@Wp + bp + b1) @ B (+bl1). Also accumulates column sums
// of C into g_hsum (graph readout contribution of h1).
// ---------------------------------------------------------------------------
__global__ void __launch_bounds__(256)
tgemm_r4(const float* __restrict__ b1,
         const __nv_bfloat16* __restrict__ Bh, const __nv_bfloat16* __restrict__ Bl,
         float* __restrict__ Cf, int M, const float* __restrict__ cbias) {
    const int K = 512;
    extern __shared__ __align__(16) char dsm[];
    char*    sAc = dsm;                     // A: 3 x 16KB
    uint32_t sAu = smem_u32(dsm);
    uint32_t sBu = sAu + 49152;             // B: 3 x 16KB

    int tid  = threadIdx.x;
    int wid  = tid >> 5;
    int lane = tid & 31;
    int m0   = blockIdx.y * 128;
    int wm   = wid & 3;
    int wn   = wid >> 2;

    float acc[2][8][4];
#pragma unroll
    for (int i = 0; i < 2; i++)
#pragma unroll
        for (int j = 0; j < 8; j++)
#pragma unroll
            for (int l = 0; l < 4; l++) acc[i][j][l] = 0.f;

#define STAGEB(BUF, KC)                                                        \
    {                                                                          \
        int _kc = (KC);                                                        \
        _Pragma("unroll")                                                      \
        for (int it = 0; it < 4; it++) {                                       \
            int idx = it * 256 + tid;                                          \
            int row = idx >> 3, ch = idx & 7;                                  \
            const __nv_bfloat16* gs = ((ch < 4) ? Bh : Bl)                     \
                + (size_t)row * K + _kc + (ch & 3) * 8;                        \
            uint32_t dst = sBu + (BUF) * 16384 + row * 128                     \
                + ((ch ^ (row & 7)) << 4);                                     \
            CPA(dst, gs);                                                      \
        }                                                                      \
    }

#define STAGEA(BUF, KC)                                                        \
    {                                                                          \
        int _kc = (KC);                                                        \
        int _h  = _kc >> 7;                                                    \
        _Pragma("unroll")                                                      \
        for (int it = 0; it < 4; it++) {                                       \
            int idx = it * 256 + tid;                                          \
            int row = idx >> 3, cg = idx & 7;                                  \
            int gr = m0 + row; if (gr >= M) gr = M - 1;                        \
            float4 t = *(const float4*)(g_tt + gr * 16 + _h * 4);              \
            int j = _kc + cg * 4;                                              \
            float4 w0 = *(const float4*)(g_Wp + 0 * 512 + j);                  \
            float4 w1 = *(const float4*)(g_Wp + 1 * 512 + j);                  \
            float4 w2 = *(const float4*)(g_Wp + 2 * 512 + j);                  \
            float4 w3 = *(const float4*)(g_Wp + 3 * 512 + j);                  \
            float4 bb = *(const float4*)(g_bp + j);                            \
            float4 b2v = *(const float4*)(b1 + j);                             \
            float v0 = bb.x + b2v.x + t.x * w0.x + t.y * w1.x + t.z * w2.x + t.w * w3.x; \
            float v1 = bb.y + b2v.y + t.x * w0.y + t.y * w1.y + t.z * w2.y + t.w * w3.y; \
            float v2 = bb.z + b2v.z + t.x * w0.z + t.y * w1.z + t.z * w2.z + t.w * w3.z; \
            float v3 = bb.w + b2v.w + t.x * w0.w + t.y * w1.w + t.z * w2.w + t.w * w3.w; \
            v0 = v0 > 0.f ? v0 : __expf(v0) - 1.f;                             \
            v1 = v1 > 0.f ? v1 : __expf(v1) - 1.f;                             \
            v2 = v2 > 0.f ? v2 : __expf(v2) - 1.f;                             \
            v3 = v3 > 0.f ? v3 : __expf(v3) - 1.f;                             \
            __nv_bfloat16 h0 = __float2bfloat16(v0);                           \
            __nv_bfloat16 h1 = __float2bfloat16(v1);                           \
            __nv_bfloat16 h2 = __float2bfloat16(v2);                           \
            __nv_bfloat16 h3 = __float2bfloat16(v3);                           \
            uint2 hi2 = make_uint2(pack_bf(h0, h1), pack_bf(h2, h3));          \
            uint2 lo2 = make_uint2(                                            \
                pack_bf(__float2bfloat16(v0 - __bfloat162float(h0)),           \
                        __float2bfloat16(v1 - __bfloat162float(h1))),          \
                pack_bf(__float2bfloat16(v2 - __bfloat162float(h2)),           \
                        __float2bfloat16(v3 - __bfloat162float(h3))));         \
            int ch = cg >> 1, rem = (cg & 1) * 8;                              \
            char* base = sAc + (BUF) * 16384 + row * 128;                      \
            *(uint2*)(base + (((ch)     ^ (row & 7)) << 4) + rem) = hi2;       \
            *(uint2*)(base + (((ch + 4) ^ (row & 7)) << 4) + rem) = lo2;       \
        }                                                                      \
    }

    int nk = K >> 5;  // 16
    STAGEB(0, 0)
    asm volatile("cp.async.commit_group;");
    STAGEA(0, 0)
    STAGEB(1, 32)
    asm volatile("cp.async.commit_group;");
    STAGEA(1, 32)

    for (int i = 0; i < nk; i++) {
        if (i + 1 < nk) asm volatile("cp.async.wait_group 1;");
        else            asm volatile("cp.async.wait_group 0;");
        __syncthreads();
        int buf = i % 3;
        int nb  = (i + 2) % 3;
        if (i + 2 < nk) {
            STAGEB(nb, (i + 2) * 32)
            asm volatile("cp.async.commit_group;");
        }

        uint32_t a_base = sAu + buf * 16384;
        uint32_t b_base = sBu + buf * 16384;
#pragma unroll
        for (int ks = 0; ks < 2; ks++) {
            uint32_t ah[2][4], al[2][4], bh[4][4], bl[4][4];
            int arow = (lane & 7) + ((lane >> 3) & 1) * 8;
            int akg  = 2 * ks + (lane >> 4);
#pragma unroll
            for (int mf = 0; mf < 2; mf++) {
                int r = 32 * wm + 16 * mf + arow;
                ldsm4(ah[mf], a_base + r * 128 + (((akg)     ^ (r & 7)) << 4));
                ldsm4(al[mf], a_base + r * 128 + (((akg + 4) ^ (r & 7)) << 4));
            }
            int brow = (lane & 7) + (lane >> 4) * 8;
            int bkg  = 2 * ks + ((lane >> 3) & 1);
#pragma unroll
            for (int q = 0; q < 4; q++) {
                int r = 64 * wn + 16 * q + brow;
                ldsm4(bh[q], b_base + r * 128 + (((bkg)     ^ (r & 7)) << 4));
                ldsm4(bl[q], b_base + r * 128 + (((bkg + 4) ^ (r & 7)) << 4));
            }
#pragma unroll
            for (int mf = 0; mf < 2; mf++) {
#pragma unroll
                for (int q = 0; q < 4; q++) {
                    mma16816(acc[mf][2 * q + 0], ah[mf], &bh[q][0]);
                    mma16816(acc[mf][2 * q + 1], ah[mf], &bh[q][2]);
                    mma16816(acc[mf][2 * q + 0], al[mf], &bh[q][0]);
                    mma16816(acc[mf][2 * q + 1], al[mf], &bh[q][2]);
                    mma16816(acc[mf][2 * q + 0], ah[mf], &bl[q][0]);
                    mma16816(acc[mf][2 * q + 1], ah[mf], &bl[q][2]);
                }
            }
        }
        if (i + 2 < nk) STAGEA(nb, (i + 2) * 32)
    }
#undef STAGEA
#undef STAGEB

    // epilogue: store h1 + accumulate column sums into g_hsum
    __syncthreads();
    float* colsum = (float*)dsm;
    if (tid < 128) colsum[tid] = 0.f;
    __syncthreads();
#pragma unroll
    for (int mf = 0; mf < 2; mf++) {
        int r0 = m0 + 32 * wm + 16 * mf + (lane >> 2);
#pragma unroll
        for (int nf = 0; nf < 8; nf++) {
            int col = 64 * wn + 8 * nf + 2 * (lane & 3);
            float cb0 = cbias[col], cb1 = cbias[col + 1];
            float s0 = 0.f, s1 = 0.f;
#pragma unroll
            for (int rr = 0; rr < 2; rr++) {
                int r = r0 + rr * 8;
                if (r >= M) continue;
                float v0 = acc[mf][nf][2 * rr + 0] + cb0;
                float v1 = acc[mf][nf][2 * rr + 1] + cb1;
                *(float2*)(Cf + (size_t)r * CDIM + col) = make_float2(v0, v1);
                s0 += v0; s1 += v1;
            }
            atomicAdd(&colsum[col], s0);
            atomicAdd(&colsum[col + 1], s1);
        }
    }
    __syncthreads();
    if (tid < 128) atomicAdd(&g_hsum[tid], colsum[tid]);
}

// ---------------------------------------------------------------------------
// generic 3-stage cp.async warp-MMA bf16 split GEMM.
// Out modes: fp32 store (Cf), bias+elu+bf16 split (Ch/Cl), or sum-only
// (both null) which accumulates column sums (+cbias) into g_hsum.
// ---------------------------------------------------------------------------
__global__ void __launch_bounds__(256)
tgemm(const __nv_bfloat16* __restrict__ Ah, const __nv_bfloat16* __restrict__ Al,
      int lda, int boa,
      const __nv_bfloat16* __restrict__ Bh, const __nv_bfloat16* __restrict__ Bl, int bob,
      float* __restrict__ Cf, __nv_bfloat16* __restrict__ Ch, __nv_bfloat16* __restrict__ Cl,
      int ldc, int boc,
      int M, int K, const float* __restrict__ cbias, int bocb, int celu) {
    Ah += (size_t)blockIdx.z * boa;
    Al += (size_t)blockIdx.z * boa;
    Bh += (size_t)blockIdx.z * bob;
    Bl += (size_t)blockIdx.z * bob;
    if (Cf) Cf += (size_t)blockIdx.z * boc;
    if (Ch) { Ch += (size_t)blockIdx.z * boc; Cl += (size_t)blockIdx.z * boc; }
    cbias += (size_t)blockIdx.z * bocb;
    int sum_only = (Cf == nullptr) && (Ch == nullptr);

    extern __shared__ __align__(16) char dsm[];
    uint32_t sAu = smem_u32(dsm);     // stage s: A at s*32768, B at s*32768+16384

    int tid  = threadIdx.x;
    int wid  = tid >> 5;
    int lane = tid & 31;
    int m0   = blockIdx.y * 128;
    int wm   = wid & 3;
    int wn   = wid >> 2;

    float acc[2][8][4];
#pragma unroll
    for (int i = 0; i < 2; i++)
#pragma unroll
        for (int j = 0; j < 8; j++)
#pragma unroll
            for (int l = 0; l < 4; l++) acc[i][j][l] = 0.f;

#define STAGE(BUF, KC)                                                         \
    {                                                                          \
        int _kc = (KC);                                                        \
        _Pragma("unroll")                                                      \
        for (int it = 0; it < 4; it++) {                                       \
            int idx = it * 256 + tid;                                          \
            int row = idx >> 3, ch = idx & 7;                                  \
            const __nv_bfloat16* gs = ((ch < 4) ? Ah : Al)                     \
                + (size_t)(m0 + row) * lda + _kc + (ch & 3) * 8;               \
            uint32_t dst = sAu + (BUF) * 32768 + row * 128                     \
                + ((ch ^ (row & 7)) << 4);                                     \
            CPA(dst, gs);                                                      \
        }                                                                      \
        _Pragma("unroll")                                                      \
        for (int it = 0; it < 4; it++) {                                       \
            int idx = it * 256 + tid;                                          \
            int row = idx >> 3, ch = idx & 7;                                  \
            const __nv_bfloat16* gs = ((ch < 4) ? Bh : Bl)                     \
                + (size_t)row * K + _kc + (ch & 3) * 8;                        \
            uint32_t dst = sAu + (BUF) * 32768 + 16384 + row * 128             \
                + ((ch ^ (row & 7)) << 4);                                     \
            CPA(dst, gs);                                                      \
        }                                                                      \
    }

    int nk = K >> 5;
    STAGE(0, 0)
    asm volatile("cp.async.commit_group;");
    STAGE(1, 32)
    asm volatile("cp.async.commit_group;");

    for (int i = 0; i < nk; i++) {
        if (i + 1 < nk) asm volatile("cp.async.wait_group 1;");
        else            asm volatile("cp.async.wait_group 0;");
        __syncthreads();
        int buf = i % 3;
        if (i + 2 < nk) {
            STAGE((i + 2) % 3, (i + 2) * 32)
            asm volatile("cp.async.commit_group;");
        }

        uint32_t a_base = sAu + buf * 32768;
        uint32_t b_base = a_base + 16384;
#pragma unroll
        for (int ks = 0; ks < 2; ks++) {
            uint32_t ah[2][4], al[2][4], bh[4][4], bl[4][4];
            int arow = (lane & 7) + ((lane >> 3) & 1) * 8;
            int akg  = 2 * ks + (lane >> 4);
#pragma unroll
            for (int mf = 0; mf < 2; mf++) {
                int r = 32 * wm + 16 * mf + arow;
                ldsm4(ah[mf], a_base + r * 128 + (((akg)     ^ (r & 7)) << 4));
                ldsm4(al[mf], a_base + r * 128 + (((akg + 4) ^ (r & 7)) << 4));
            }
            int brow = (lane & 7) + (lane >> 4) * 8;
            int bkg  = 2 * ks + ((lane >> 3) & 1);
#pragma unroll
            for (int q = 0; q < 4; q++) {
                int r = 64 * wn + 16 * q + brow;
                ldsm4(bh[q], b_base + r * 128 + (((bkg)     ^ (r & 7)) << 4));
                ldsm4(bl[q], b_base + r * 128 + (((bkg + 4) ^ (r & 7)) << 4));
            }
#pragma unroll
            for (int mf = 0; mf < 2; mf++) {
#pragma unroll
                for (int q = 0; q < 4; q++) {
                    mma16816(acc[mf][2 * q + 0], ah[mf], &bh[q][0]);
                    mma16816(acc[mf][2 * q + 1], ah[mf], &bh[q][2]);
                    mma16816(acc[mf][2 * q + 0], al[mf], &bh[q][0]);
                    mma16816(acc[mf][2 * q + 1], al[mf], &bh[q][2]);
                    mma16816(acc[mf][2 * q + 0], ah[mf], &bl[q][0]);
                    mma16816(acc[mf][2 * q + 1], ah[mf], &bl[q][2]);
                }
            }
        }
    }
#undef STAGE

    float* colsum = (float*)dsm;
    if (sum_only) {
        __syncthreads();
        if (tid < 128) colsum[tid] = 0.f;
        __syncthreads();
    }
#pragma unroll
    for (int mf = 0; mf < 2; mf++) {
        int r0 = m0 + 32 * wm + 16 * mf + (lane >> 2);
#pragma unroll
        for (int nf = 0; nf < 8; nf++) {
            int col = 64 * wn + 8 * nf + 2 * (lane & 3);
            float cb0 = cbias[col], cb1 = cbias[col + 1];
            float s0 = 0.f, s1 = 0.f;
#pragma unroll
            for (int rr = 0; rr < 2; rr++) {
                int r = r0 + rr * 8;
                if (r >= M) continue;
                float v0 = acc[mf][nf][2 * rr + 0] + cb0;
                float v1 = acc[mf][nf][2 * rr + 1] + cb1;
                if (Cf) {
                    *(float2*)(Cf + (size_t)r * ldc + col) = make_float2(v0, v1);
                } else if (Ch) {
                    if (celu) {
                        v0 = v0 > 0.f ? v0 : __expf(v0) - 1.f;
                        v1 = v1 > 0.f ? v1 : __expf(v1) - 1.f;
                    }
                    __nv_bfloat16 h0 = __float2bfloat16(v0);
                    __nv_bfloat16 h1 = __float2bfloat16(v1);
                    size_t o = (size_t)r * ldc + col;
                    *(uint32_t*)(Ch + o) = pack_bf(h0, h1);
                    *(uint32_t*)(Cl + o) =
                        pack_bf(__float2bfloat16(v0 - __bfloat162float(h0)),
                                __float2bfloat16(v1 - __bfloat162float(h1)));
                } else {
                    s0 += v0; s1 += v1;
                }
            }
            if (sum_only) {
                atomicAdd(&colsum[col], s0);
                atomicAdd(&colsum[col + 1], s1);
            }
        }
    }
    if (sum_only) {
        __syncthreads();
        if (tid < 128) atomicAdd(&g_hsum[tid], colsum[tid]);
    }
}

// ---------------------------------------------------------------------------
// Layer-2 folded attention weights + logits (padded stride-8 output)
// ---------------------------------------------------------------------------
__global__ void wfold2_kernel(const float* __restrict__ W2,
                              const float* __restrict__ a2s,
                              const float* __restrict__ a2d, int H, int M2) {
    int tid = blockIdx.x * blockDim.x + threadIdx.x;
    if (tid >= CDIM * 2 * H) return;
    int c = tid / (2 * H), o = tid - c * (2 * H);
    int h = o % H;
    const float* av = (o < H) ? a2s : a2d;
    float s = 0.f;
    for (int k = 0; k < CDIM; k++) s += W2[c * M2 + h * CDIM + k] * av[h * CDIM + k];
    g_fold2[c * (2 * H) + o] = s;
}

__global__ void es2_kernel(int N, int H) {
    __shared__ float wt[CDIM * 10];
    int tid = threadIdx.x;
    int TW = CDIM * 2 * H;
    for (int i = tid; i < TW; i += blockDim.x) wt[i] = g_fold2[i];
    __syncthreads();
    int warp = blockIdx.x * (blockDim.x >> 5) + (tid >> 5);
    int lane = tid & 31;
    if (warp >= N) return;
    float4 hv = *(const float4*)(g_h1 + (size_t)warp * CDIM + lane * 4);
    float s[10];
#pragma unroll
    for (int o = 0; o < 10; o++) s[o] = 0.f;
    float hvv[4] = {hv.x, hv.y, hv.z, hv.w};
#pragma unroll
    for (int j = 0; j < 4; j++) {
        int c = lane * 4 + j;
        for (int o = 0; o < 2 * H; o++) s[o] += hvv[j] * wt[c * (2 * H) + o];
    }
    for (int o = 0; o < 2 * H; o++)
        for (int off = 16; off; off >>= 1) s[o] += __shfl_xor_sync(0xffffffffu, s[o], off);
    if (lane < H)          g_es2p[warp * 8 + lane] = s[lane];
    else if (lane < 2 * H) g_ed2p[warp * 8 + lane - H] = s[lane];
}

// ---------------------------------------------------------------------------
// Layer-2 aggregation: max pass + single gather pass (unnormalized + Z)
// ---------------------------------------------------------------------------
__global__ void agg2_kernel(const float* __restrict__ feat, int N) {
    const int H = 5;
    int warp = (blockIdx.x * blockDim.x + threadIdx.x) >> 5;
    int lane = threadIdx.x & 31;
    if (warp >= N) return;
    int n   = warp;
    int r0  = g_rowptr[n];
    int deg = g_rowptr[n + 1] - r0;
    int tot = deg + 1;

    float edv[H], m[H];
    {
        float4 e4 = *(const float4*)(g_ed2p + n * 8);
        edv[0] = e4.x; edv[1] = e4.y; edv[2] = e4.z; edv[3] = e4.w;
        edv[4] = g_ed2p[n * 8 + 4];
    }
#pragma unroll
    for (int h = 0; h < H; h++) m[h] = -1e30f;
    for (int i = lane; i < tot; i += 32) {
        int src = (i < deg) ? g_csrc[r0 + i] : n;
        float4 e4 = *(const float4*)(g_es2p + src * 8);
        float ev[H] = {e4.x, e4.y, e4.z, e4.w, g_es2p[src * 8 + 4]};
#pragma unroll
        for (int h = 0; h < H; h++) {
            float e = ev[h] + edv[h];
            e = e > 0.f ? e : 0.2f * e;
            m[h] = fmaxf(m[h], e);
        }
    }
#pragma unroll
    for (int h = 0; h < H; h++)
        for (int o = 16; o; o >>= 1) m[h] = fmaxf(m[h], __shfl_xor_sync(0xffffffffu, m[h], o));

    float4 acc[H];
    float zp[H];
#pragma unroll
    for (int h = 0; h < H; h++) { acc[h] = make_float4(0.f, 0.f, 0.f, 0.f); zp[h] = 0.f; }

    for (int t = 0; t < tot; t += 32) {
        int i = t + lane;
        int src = n;
        float w[H];
        if (i < tot) {
            src = (i < deg) ? g_csrc[r0 + i] : n;
            float4 e4 = *(const float4*)(g_es2p + src * 8);
            float ev[H] = {e4.x, e4.y, e4.z, e4.w, g_es2p[src * 8 + 4]};
#pragma unroll
            for (int h = 0; h < H; h++) {
                float e = ev[h] + edv[h];
                e = e > 0.f ? e : 0.2f * e;
                w[h] = __expf(e - m[h]);
                zp[h] += w[h];
            }
        } else {
#pragma unroll
            for (int h = 0; h < H; h++) w[h] = 0.f;
        }
        int cnt = tot - t;
        if (cnt > 32) cnt = 32;
#pragma unroll 4
        for (int j = 0; j < cnt; j++) {
            int s = __shfl_sync(0xffffffffu, src, j);
            float wj[H];
#pragma unroll
            for (int h = 0; h < H; h++) wj[h] = __shfl_sync(0xffffffffu, w[h], j);
            float4 v = *(const float4*)(feat + (size_t)s * CDIM + lane * 4);
#pragma unroll
            for (int h = 0; h < H; h++) {
                acc[h].x += wj[h] * v.x; acc[h].y += wj[h] * v.y;
                acc[h].z += wj[h] * v.z; acc[h].w += wj[h] * v.w;
            }
        }
    }
#pragma unroll
    for (int h = 0; h < H; h++)
        for (int o = 16; o; o >>= 1) zp[h] += __shfl_xor_sync(0xffffffffu, zp[h], o);

#pragma unroll
    for (int h = 0; h < H; h++) {
        float iz = 1.f / zp[h];
        float ax = acc[h].x * iz, ay = acc[h].y * iz;
        float az = acc[h].z * iz, aw = acc[h].w * iz;
        __nv_bfloat16 hx = __float2bfloat16(ax);
        __nv_bfloat16 hy = __float2bfloat16(ay);
        __nv_bfloat16 hz = __float2bfloat16(az);
        __nv_bfloat16 hw = __float2bfloat16(aw);
        size_t o = (size_t)n * (H * CDIM) + h * CDIM + lane * 4;
        *(uint2*)(g_A2h + o) = make_uint2(pack_bf(hx, hy), pack_bf(hz, hw));
        *(uint2*)(g_A2l + o) = make_uint2(
            pack_bf(__float2bfloat16(ax - __bfloat162float(hx)),
                    __float2bfloat16(ay - __bfloat162float(hy))),
            pack_bf(__float2bfloat16(az - __bfloat162float(hz)),
                    __float2bfloat16(aw - __bfloat162float(hw))));
    }
}

// ---------------------------------------------------------------------------
__global__ void tail0_kernel(const float* __restrict__ Wfc, const float* __restrict__ bfc,
                             const float* __restrict__ Whg, const float* __restrict__ bhg,
                             const float* __restrict__ Wv,  const float* __restrict__ bv,
                             const float* __restrict__ h_mat, const float* __restrict__ h_bias,
                             int N, int HOUT) {
    __shared__ float h[128];
    __shared__ float tm[256];
    __shared__ float hg[128];
    int tid = threadIdx.x;
    if (tid < 128) h[tid] = g_hsum[tid] / (float)N;
    __syncthreads();
    if (tid < 256) {
        float a = bfc[tid];
        for (int i = 0; i < 128; i++) a += h[i] * Wfc[i * 256 + tid];
        tm[tid] = a > 0.f ? a : 0.f;
    }
    __syncthreads();
    if (tid < 128) {
        float a = bhg[tid];
        for (int i = 0; i < 256; i++) a += tm[i] * Whg[i * 128 + tid];
        hg[tid] = a;
    }
    __syncthreads();
    if (tid < 384) {
        float a = bv[tid];
        for (int i = 0; i < 128; i++) a += hg[i] * Wv[i * 384 + tid];
        g_small[tid] = a > 0.f ? a : 0.f;
        float hs = 0.f;
        for (int hh = 0; hh < HOUT; hh++) hs += h_mat[hh * 384 + tid];
        g_small[384 + tid] = hs;
    }
    if (tid == 0) {
        float hb = 0.f;
        for (int i = 0; i < HOUT; i++) hb += h_bias[i];
        g_small[768] = hb;
    }
}

__global__ void tail1_kernel(const float* __restrict__ cell,
                             const float* __restrict__ Wc, const float* __restrict__ bc,
                             const float* __restrict__ Wq, const float* __restrict__ bq,
                             int CF) {
    __shared__ float sc[1024];
    __shared__ float crow[128];
    __shared__ float qrow[384];
    __shared__ float red[128];
    int b = blockIdx.x, tid = threadIdx.x;
    for (int i = tid; i < CF; i += 128) sc[i] = cell[(size_t)b * CF + i];
    __syncthreads();
    {
        float a = bc[tid];
        for (int k = 0; k < CF; k++) a += sc[k] * Wc[k * 128 + tid];
        crow[tid] = a > 0.f ? a : 0.f;
    }
    __syncthreads();
    float part = 0.f;
    for (int mI = tid; mI < 384; mI += 128) {
        float q = bq[mI];
        for (int k = 0; k < 128; k++) q += crow[k] * Wq[k * 384 + mI];
        q = q > 0.f ? q : 0.f;
        qrow[mI] = q;
        part += g_small[384 + mI] * g_small[mI] * q;
    }
    red[tid] = part;
    __syncthreads();
    for (int o = 64; o; o >>= 1) {
        if (tid < o) red[tid] += red[tid + o];
        __syncthreads();
    }
    float att = red[0] + g_small[768];
    float l = 0.f;
#pragma unroll
    for (int j = 0; j < 3; j++) {
        int k = tid * 3 + j;
        l += g_small[k] * qrow[k];
    }
    g_logits[b * 128 + tid] = att * l;
}

__global__ void tail2_kernel(const float* __restrict__ gamma,
                             const float* __restrict__ beta,
                             float* __restrict__ out, int B) {
    __shared__ float s1[256], s2[256];
    int c = blockIdx.x, b = threadIdx.x;
    float v = g_logits[b * 128 + c];
    s1[b] = v;
    s2[b] = v * v;
    __syncthreads();
    for (int o = B >> 1; o; o >>= 1) {
        if (b < o) { s1[b] += s1[b + o]; s2[b] += s2[b + o]; }
        __syncthreads();
    }
    float mu  = s1[0] / (float)B;
    float var = s2[0] / (float)B - mu * mu;
    out[b * 128 + c] = (v - mu) * rsqrtf(var + 1e-5f) * gamma[c] + beta[c];
}

// ---------------------------------------------------------------------------
// launch
// ---------------------------------------------------------------------------
extern "C" void kernel_launch(void* const* d_in, const int* in_sizes, int n_in,
                              void* d_out, int out_size) {
    const float* cell = (const float*)d_in[0];
    const float* Wd   = (const float*)d_in[1];
    const float* bd   = (const float*)d_in[2];
    const float* W1   = (const float*)d_in[3];
    const float* a1s  = (const float*)d_in[4];
    const float* a1d  = (const float*)d_in[5];
    const float* b1   = (const float*)d_in[6];
    const float* Wl1  = (const float*)d_in[7];
    const float* bl1  = (const float*)d_in[8];
    const float* W2   = (const float*)d_in[9];
    const float* a2s  = (const float*)d_in[10];
    const float* a2d  = (const float*)d_in[11];
    const float* b2   = (const float*)d_in[12];
    const float* Wl2  = (const float*)d_in[13];
    const float* bl2  = (const float*)d_in[14];
    const float* Wfc  = (const float*)d_in[15];
    const float* bfc  = (const float*)d_in[16];
    const float* Whg  = (const float*)d_in[17];
    const float* bhg  = (const float*)d_in[18];
    const float* Wc   = (const float*)d_in[19];
    const float* bc   = (const float*)d_in[20];
    const float* Wv   = (const float*)d_in[21];
    const float* bv   = (const float*)d_in[22];
    const float* Wq   = (const float*)d_in[23];
    const float* bq   = (const float*)d_in[24];
    const float* h_mat  = (const float*)d_in[25];
    const float* h_bias = (const float*)d_in[26];
    const float* gamma  = (const float*)d_in[27];
    const float* beta   = (const float*)d_in[28];
    const int*   trip   = (const int*)d_in[29];
    const int*   ei     = (const int*)d_in[30];

    int N  = in_sizes[29] / 4;
    int E  = in_sizes[30] / 2;
    int CF = in_sizes[19] / 128;
    int B  = in_sizes[0] / CF;
    int H1 = in_sizes[4] / 128;   // 4
    int H2 = in_sizes[10] / 128;  // 5
    int HOUT = in_sizes[26];
    if (N > NMAX) N = NMAX;
    if (E > EMAX) E = EMAX;
    float* out = (float*)d_out;

    void *ph1;
    void *pA2h, *pA2l, *pA3h, *pA3l;
    void *pb1h, *pb1l, *pb2h, *pb2l, *pb3h, *pb3l;
    cudaGetSymbolAddress(&ph1,  g_h1);
    cudaGetSymbolAddress(&pA2h, g_A2h);
    cudaGetSymbolAddress(&pA2l, g_A2l);
    cudaGetSymbolAddress(&pA3h, g_A3h);
    cudaGetSymbolAddress(&pA3l, g_A3l);
    cudaGetSymbolAddress(&pb1h, g_bt1h);
    cudaGetSymbolAddress(&pb1l, g_bt1l);
    cudaGetSymbolAddress(&pb2h, g_bt2h);
    cudaGetSymbolAddress(&pb2l, g_bt2l);
    cudaGetSymbolAddress(&pb3h, g_bt3h);
    cudaGetSymbolAddress(&pb3l, g_bt3l);

    cudaFuncSetAttribute(tgemm,    cudaFuncAttributeMaxDynamicSharedMemorySize, 98304);
    cudaFuncSetAttribute(tgemm_r4, cudaFuncAttributeMaxDynamicSharedMemorySize, 98304);

    int M1 = H1 * CDIM;  // 512
    int M2 = H2 * CDIM;  // 640
    int mt = (N + 127) / 128;

    // CSR build + zero
    zero_kernel<<<(N + 255) / 256, 256>>>(N);
    count_kernel<<<(E / 2 + 255) / 256, 256>>>(ei, E);
    scan_kernel<<<1, 1024>>>(N);
    fill_kernel<<<(E / 2 + 255) / 256, 256>>>(ei, E);

    // weight prep (bf16 transposed splits)
    btprep_kernel<<<dim3((128 * M1 + 255) / 256, 1), 256>>>(Wl1, 128, M1,
        (__nv_bfloat16*)pb1h, (__nv_bfloat16*)pb1l);
    btprep_kernel<<<dim3((128 * 128 + 255) / 256, H2), 256>>>(W2, M2, 128,
        (__nv_bfloat16*)pb2h, (__nv_bfloat16*)pb2l);
    btprep_kernel<<<dim3((128 * M2 + 255) / 256, 1), 256>>>(Wl2, 128, M2,
        (__nv_bfloat16*)pb3h, (__nv_bfloat16*)pb3l);

    // ---- GAT layer 1 (rank-4 until projection; GEMM generates A on the fly) ----
    wprep_kernel<<<(M1 + 127) / 128, 128>>>(Wd, bd, W1, M1);
    wfold1_kernel<<<1, 64>>>(a1s, a1d, H1, M1);
    es1_kernel<<<(N + 255) / 256, 256>>>(trip, N);
    agg_rank4_kernel<<<(N * 32 + 255) / 256, 256>>>(trip, N);
    tgemm_r4<<<dim3(1, mt, 1), 256, 98304>>>(
        b1, (const __nv_bfloat16*)pb1h, (const __nv_bfloat16*)pb1l,
        (float*)ph1, N, bl1);

    // ---- GAT layer 2 ----
    wfold2_kernel<<<(CDIM * 2 * H2 + 127) / 128, 128>>>(W2, a2s, a2d, H2, M2);
    es2_kernel<<<(N + 7) / 8, 256>>>(N, H2);
    agg2_kernel<<<(N * 32 + 255) / 256, 256>>>((const float*)ph1, N);
    tgemm<<<dim3(1, mt, H2), 256, 98304>>>(
        (const __nv_bfloat16*)pA2h, (const __nv_bfloat16*)pA2l, M2, 128,
        (const __nv_bfloat16*)pb2h, (const __nv_bfloat16*)pb2l, 128 * 128,
        nullptr, (__nv_bfloat16*)pA3h, (__nv_bfloat16*)pA3l, M2, 128,
        N, 128, b2, 128, 1);
    // GEMM3: h2 feeds only the graph readout -> sum-only epilogue into g_hsum
    tgemm<<<dim3(1, mt, 1), 256, 98304>>>(
        (const __nv_bfloat16*)pA3h, (const __nv_bfloat16*)pA3l, M2, 0,
        (const __nv_bfloat16*)pb3h, (const __nv_bfloat16*)pb3l, 0,
        nullptr, nullptr, nullptr, CDIM, 0, N, M2, bl2, 0, 0);

    // tail
    tail0_kernel<<<1, 384>>>(Wfc, bfc, Whg, bhg, Wv, bv, h_mat, h_bias, N, HOUT);
    tail1_kernel<<<B, 128>>>(cell, Wc, bc, Wq, bq, CF);
    tail2_kernel<<<128, B>>>(gamma, beta, out, B);
}

// round 10
// speedup vs baseline: 1.6885x; 1.0167x over previous
#include <cuda_runtime.h>
#include <cuda_bf16.h>
#include <math.h>
#include <stdint.h>

#define NMAX 20000
#define EMAX 500000
#define CDIM 128
#define NPAD (NMAX + 128)

// ---------------------------------------------------------------------------
// Static device scratch
// ---------------------------------------------------------------------------
__device__ float g_h1  [NMAX * CDIM];
__device__ float g_es  [NMAX * 4];
__device__ float g_ed  [NMAX * 4];
__device__ float g_es2p[NMAX * 8];
__device__ float g_ed2p[NMAX * 8];
__device__ float g_tt  [NMAX * 16];
__device__ int   g_cnt   [NMAX];
__device__ int   g_rowptr[NMAX + 1];
__device__ int   g_cursor[NMAX];
__device__ int   g_csrc  [EMAX];
__device__ float g_hsum  [CDIM];
__device__ float g_small [1024];
__device__ float g_logits[256 * CDIM];
__device__ float g_Wp  [4 * 512];
__device__ float g_bp  [512];
__device__ float g_fold2[128 * 10];
__device__ __nv_bfloat16 g_A2h[NPAD * 640], g_A2l[NPAD * 640];
__device__ __nv_bfloat16 g_A3h[NPAD * 640], g_A3l[NPAD * 640];
__device__ __nv_bfloat16 g_bt1h[128 * 512], g_bt1l[128 * 512];
__device__ __nv_bfloat16 g_bt2h[5 * 128 * 128], g_bt2l[5 * 128 * 128];
__device__ __nv_bfloat16 g_bt3h[128 * 640], g_bt3l[128 * 640];

// ---------------------------------------------------------------------------
// helpers
// ---------------------------------------------------------------------------
__device__ __forceinline__ uint32_t smem_u32(const void* p) {
    uint32_t a;
    asm("{ .reg .u64 t; cvta.to.shared.u64 t, %1; cvt.u32.u64 %0, t; }" : "=r"(a) : "l"(p));
    return a;
}
__device__ __forceinline__ void ldsm4(uint32_t* r, uint32_t addr) {
    asm volatile("ldmatrix.sync.aligned.m8n8.x4.shared.b16 {%0,%1,%2,%3}, [%4];"
                 : "=r"(r[0]), "=r"(r[1]), "=r"(r[2]), "=r"(r[3]) : "r"(addr));
}
__device__ __forceinline__ void mma16816(float* d, const uint32_t* a, const uint32_t* b) {
    asm volatile(
        "mma.sync.aligned.m16n8k16.row.col.f32.bf16.bf16.f32 "
        "{%0,%1,%2,%3}, {%4,%5,%6,%7}, {%8,%9}, {%0,%1,%2,%3};"
        : "+f"(d[0]), "+f"(d[1]), "+f"(d[2]), "+f"(d[3])
        : "r"(a[0]), "r"(a[1]), "r"(a[2]), "r"(a[3]), "r"(b[0]), "r"(b[1]));
}
__device__ __forceinline__ uint32_t pack_bf(__nv_bfloat16 a, __nv_bfloat16 b) {
    __nv_bfloat162 t;
    t.x = a; t.y = b;
    return *reinterpret_cast<uint32_t*>(&t);
}
#define CPA(dst, src) \
    asm volatile("cp.async.cg.shared.global [%0], [%1], 16;" :: "r"(dst), "l"(src))

// ---------------------------------------------------------------------------
// prep: zero counters + 3x bf16 weight transpose/split + drug-linear fold
// (one launch, blockIdx-partitioned)
// ---------------------------------------------------------------------------
__global__ void prep_kernel(const float* __restrict__ Wl1, const float* __restrict__ W2,
                            const float* __restrict__ Wl2, const float* __restrict__ Wd,
                            const float* __restrict__ bd,  const float* __restrict__ W1,
                            int N, int M1, int M2, int H2,
                            int s0, int s1, int s2, int s3) {
    int b = blockIdx.x, tid = threadIdx.x;
    if (b < s0) {                       // zero g_cnt + g_hsum
        int i = b * 256 + tid;
        if (i < N) g_cnt[i] = 0;
        if (b == 0 && tid < CDIM) g_hsum[tid] = 0.f;
        return;
    }
    b -= s0;
    if (b < s1) {                       // Wl1 -> bt1 [128, M1]
        int idx = b * 256 + tid;
        if (idx < 128 * M1) {
            int j = idx / M1, k = idx - j * M1;
            float v = Wl1[(size_t)k * 128 + j];
            __nv_bfloat16 h = __float2bfloat16(v);
            g_bt1h[idx] = h;
            g_bt1l[idx] = __float2bfloat16(v - __bfloat162float(h));
        }
        return;
    }
    b -= s1;
    if (b < s2) {                       // W2 per head -> bt2 [H2][128,128]
        int idx = b * 256 + tid;
        if (idx < 128 * 128 * H2) {
            int z = idx / 16384, r = idx - z * 16384;
            int j = r / 128, k = r - j * 128;
            float v = W2[(size_t)k * M2 + z * 128 + j];
            __nv_bfloat16 h = __float2bfloat16(v);
            g_bt2h[idx] = h;
            g_bt2l[idx] = __float2bfloat16(v - __bfloat162float(h));
        }
        return;
    }
    b -= s2;
    if (b < s3) {                       // Wl2 -> bt3 [128, M2]
        int idx = b * 256 + tid;
        if (idx < 128 * M2) {
            int j = idx / M2, k = idx - j * M2;
            float v = Wl2[(size_t)k * 128 + j];
            __nv_bfloat16 h = __float2bfloat16(v);
            g_bt3h[idx] = h;
            g_bt3l[idx] = __float2bfloat16(v - __bfloat162float(h));
        }
        return;
    }
    b -= s3;
    {                                   // wprep: Wp = Wd@W1, bp = bd@W1
        int j = b * 256 + tid;
        if (j < M1) {
            float a0 = 0.f, a1 = 0.f, a2 = 0.f, a3 = 0.f, ab = 0.f;
#pragma unroll 4
            for (int k = 0; k < CDIM; k++) {
                float w = W1[k * M1 + j];
                a0 += Wd[0 * CDIM + k] * w;
                a1 += Wd[1 * CDIM + k] * w;
                a2 += Wd[2 * CDIM + k] * w;
                a3 += Wd[3 * CDIM + k] * w;
                ab += bd[k] * w;
            }
            g_Wp[0 * M1 + j] = a0;
            g_Wp[1 * M1 + j] = a1;
            g_Wp[2 * M1 + j] = a2;
            g_Wp[3 * M1 + j] = a3;
            g_bp[j] = ab;
        }
    }
}

// ---------------------------------------------------------------------------
// CSR build
// ---------------------------------------------------------------------------
__global__ void count_kernel(const int* __restrict__ ei, int E) {
    int e = (blockIdx.x * blockDim.x + threadIdx.x) * 2;
    if (e + 1 < E) {
        int2 s = *(const int2*)(ei + e);
        int2 d = *(const int2*)(ei + E + e);
        if (s.x != d.x) atomicAdd(&g_cnt[d.x], 1);
        if (s.y != d.y) atomicAdd(&g_cnt[d.y], 1);
    } else if (e < E) {
        int s = ei[e], d = ei[E + e];
        if (s != d) atomicAdd(&g_cnt[d], 1);
    }
}

// vectorized single-block scan: 4 elems/thread, warp-shfl
__global__ void scan_kernel(int N) {
    __shared__ int wsum[32];
    __shared__ int carry_s;
    int tid = threadIdx.x, lane = tid & 31, wid = tid >> 5;
    if (tid == 0) { carry_s = 0; g_rowptr[0] = 0; }
    __syncthreads();
    int NT = (N + 3) >> 2;
    for (int base = 0; base < NT; base += 1024) {
        int i4 = base + tid;
        int b0 = i4 * 4;
        int4 v = make_int4(0, 0, 0, 0);
        if (b0 + 3 < N) {
            v = *(const int4*)(g_cnt + b0);
        } else if (b0 < N) {
            v.x = g_cnt[b0];
            if (b0 + 1 < N) v.y = g_cnt[b0 + 1];
            if (b0 + 2 < N) v.z = g_cnt[b0 + 2];
        }
        int p1 = v.x, p2 = p1 + v.y, p3 = p2 + v.z, p4 = p3 + v.w;
        int x = p4;
#pragma unroll
        for (int o = 1; o < 32; o <<= 1) {
            int t = __shfl_up_sync(0xffffffffu, x, o);
            if (lane >= o) x += t;
        }
        if (lane == 31) wsum[wid] = x;
        __syncthreads();
        if (wid == 0) {
            int s = wsum[lane];
#pragma unroll
            for (int o = 1; o < 32; o <<= 1) {
                int t = __shfl_up_sync(0xffffffffu, s, o);
                if (lane >= o) s += t;
            }
            wsum[lane] = s;
        }
        __syncthreads();
        int pre = carry_s + (wid ? wsum[wid - 1] : 0) + (x - p4);
        if (b0 < N)     { g_rowptr[b0 + 1] = pre + p1; g_cursor[b0]     = pre; }
        if (b0 + 1 < N) { g_rowptr[b0 + 2] = pre + p2; g_cursor[b0 + 1] = pre + p1; }
        if (b0 + 2 < N) { g_rowptr[b0 + 3] = pre + p3; g_cursor[b0 + 2] = pre + p2; }
        if (b0 + 3 < N) { g_rowptr[b0 + 4] = pre + p4; g_cursor[b0 + 3] = pre + p3; }
        __syncthreads();
        if (tid == 0) carry_s += wsum[31];
        __syncthreads();
    }
}

__global__ void fill_kernel(const int* __restrict__ ei, int E) {
    int e = (blockIdx.x * blockDim.x + threadIdx.x) * 2;
    if (e + 1 < E) {
        int2 s = *(const int2*)(ei + e);
        int2 d = *(const int2*)(ei + E + e);
        if (s.x != d.x) { int p = atomicAdd(&g_cursor[d.x], 1); g_csrc[p] = s.x; }
        if (s.y != d.y) { int p = atomicAdd(&g_cursor[d.y], 1); g_csrc[p] = s.y; }
    } else if (e < E) {
        int s = ei[e], d = ei[E + e];
        if (s != d) { int p = atomicAdd(&g_cursor[d], 1); g_csrc[p] = s; }
    }
}

// ---------------------------------------------------------------------------
// es1: fold attention vectors through Wp/bp in-block, then per-node logits
// ---------------------------------------------------------------------------
__global__ void es1_kernel(const int* __restrict__ trip,
                           const float* __restrict__ a1s,
                           const float* __restrict__ a1d, int N, int M1) {
    __shared__ float f1[48];
    int tid = threadIdx.x;
    if (tid < 16) {
        int h = tid >> 2, i = tid & 3;
        float s = 0.f;
        for (int k = 0; k < CDIM; k++) s += g_Wp[i * M1 + h * CDIM + k] * a1s[h * CDIM + k];
        f1[tid] = s;
    } else if (tid < 32) {
        int t = tid - 16;
        int h = t >> 2, i = t & 3;
        float s = 0.f;
        for (int k = 0; k < CDIM; k++) s += g_Wp[i * M1 + h * CDIM + k] * a1d[h * CDIM + k];
        f1[tid] = s;
    } else if (tid < 36) {
        int h = tid - 32;
        float s = 0.f;
        for (int k = 0; k < CDIM; k++) s += g_bp[h * CDIM + k] * a1s[h * CDIM + k];
        f1[tid] = s;
    } else if (tid < 40) {
        int h = tid - 36;
        float s = 0.f;
        for (int k = 0; k < CDIM; k++) s += g_bp[h * CDIM + k] * a1d[h * CDIM + k];
        f1[tid] = s;
    }
    __syncthreads();
    int n = blockIdx.x * blockDim.x + tid;
    if (n >= N) return;
    int4 tv = *(const int4*)(trip + n * 4);
    float t0 = (float)tv.x, t1 = (float)tv.y, t2 = (float)tv.z, t3 = (float)tv.w;
    float4 es, ed;
    float* esp = &es.x;
    float* edp = &ed.x;
#pragma unroll
    for (int h = 0; h < 4; h++) {
        esp[h] = f1[32 + h] + t0 * f1[h * 4 + 0] + t1 * f1[h * 4 + 1]
               + t2 * f1[h * 4 + 2] + t3 * f1[h * 4 + 3];
        edp[h] = f1[36 + h] + t0 * f1[16 + h * 4 + 0] + t1 * f1[16 + h * 4 + 1]
               + t2 * f1[16 + h * 4 + 2] + t3 * f1[16 + h * 4 + 3];
    }
    *(float4*)(g_es + n * 4) = es;
    *(float4*)(g_ed + n * 4) = ed;
}

// ---------------------------------------------------------------------------
// Layer-1 aggregation (max pass + fused exp/accumulate pass)
// ---------------------------------------------------------------------------
__global__ void agg_rank4_kernel(const int* __restrict__ trip, int N) {
    const int H = 4;
    int warp = (blockIdx.x * blockDim.x + threadIdx.x) >> 5;
    int lane = threadIdx.x & 31;
    if (warp >= N) return;
    int n   = warp;
    int r0  = g_rowptr[n];
    int deg = g_rowptr[n + 1] - r0;
    int tot = deg + 1;

    float4 edv4 = *(const float4*)(g_ed + n * 4);
    float edv[H] = {edv4.x, edv4.y, edv4.z, edv4.w};
    float m[H] = {-1e30f, -1e30f, -1e30f, -1e30f};
    for (int i = lane; i < tot; i += 32) {
        int src = (i < deg) ? g_csrc[r0 + i] : n;
        float4 es = *(const float4*)(g_es + src * 4);
        float ev[H] = {es.x, es.y, es.z, es.w};
#pragma unroll
        for (int h = 0; h < H; h++) {
            float e = ev[h] + edv[h];
            e = e > 0.f ? e : 0.2f * e;
            m[h] = fmaxf(m[h], e);
        }
    }
#pragma unroll
    for (int h = 0; h < H; h++)
        for (int o = 16; o; o >>= 1) m[h] = fmaxf(m[h], __shfl_xor_sync(0xffffffffu, m[h], o));
    float4 acc[H];
    float z[H];
#pragma unroll
    for (int h = 0; h < H; h++) { acc[h] = make_float4(0.f, 0.f, 0.f, 0.f); z[h] = 0.f; }
    for (int i = lane; i < tot; i += 32) {
        int src = (i < deg) ? g_csrc[r0 + i] : n;
        float4 es = *(const float4*)(g_es + src * 4);
        float ev[H] = {es.x, es.y, es.z, es.w};
        int4 tv = *(const int4*)(trip + src * 4);
        float4 tf = make_float4((float)tv.x, (float)tv.y, (float)tv.z, (float)tv.w);
#pragma unroll
        for (int h = 0; h < H; h++) {
            float e = ev[h] + edv[h];
            e = e > 0.f ? e : 0.2f * e;
            float w = __expf(e - m[h]);
            z[h] += w;
            acc[h].x += w * tf.x; acc[h].y += w * tf.y;
            acc[h].z += w * tf.z; acc[h].w += w * tf.w;
        }
    }
#pragma unroll
    for (int h = 0; h < H; h++) {
        for (int o = 16; o; o >>= 1) {
            acc[h].x += __shfl_xor_sync(0xffffffffu, acc[h].x, o);
            acc[h].y += __shfl_xor_sync(0xffffffffu, acc[h].y, o);
            acc[h].z += __shfl_xor_sync(0xffffffffu, acc[h].z, o);
            acc[h].w += __shfl_xor_sync(0xffffffffu, acc[h].w, o);
            z[h]     += __shfl_xor_sync(0xffffffffu, z[h], o);
        }
    }
    if (lane == 0) {
#pragma unroll
        for (int h = 0; h < H; h++) {
            float iz = 1.f / z[h];
            float4 r = make_float4(acc[h].x * iz, acc[h].y * iz, acc[h].z * iz, acc[h].w * iz);
            *(float4*)(g_tt + n * 16 + h * 4) = r;
        }
    }
}

// ---------------------------------------------------------------------------
// tgemm_r4: GEMM1, A generated on the fly from g_tt; 3-stage pipeline;
// epilogue stores h1 and accumulates column sums into g_hsum.
// ---------------------------------------------------------------------------
__global__ void __launch_bounds__(256)
tgemm_r4(const float* __restrict__ b1,
         const __nv_bfloat16* __restrict__ Bh, const __nv_bfloat16* __restrict__ Bl,
         float* __restrict__ Cf, int M, const float* __restrict__ cbias) {
    const int K = 512;
    extern __shared__ __align__(16) char dsm[];
    char*    sAc = dsm;
    uint32_t sAu = smem_u32(dsm);
    uint32_t sBu = sAu + 49152;

    int tid  = threadIdx.x;
    int wid  = tid >> 5;
    int lane = tid & 31;
    int m0   = blockIdx.y * 128;
    int wm   = wid & 3;
    int wn   = wid >> 2;

    float acc[2][8][4];
#pragma unroll
    for (int i = 0; i < 2; i++)
#pragma unroll
        for (int j = 0; j < 8; j++)
#pragma unroll
            for (int l = 0; l < 4; l++) acc[i][j][l] = 0.f;

#define STAGEB(BUF, KC)                                                        \
    {                                                                          \
        int _kc = (KC);                                                        \
        _Pragma("unroll")                                                      \
        for (int it = 0; it < 4; it++) {                                       \
            int idx = it * 256 + tid;                                          \
            int row = idx >> 3, ch = idx & 7;                                  \
            const __nv_bfloat16* gs = ((ch < 4) ? Bh : Bl)                     \
                + (size_t)row * K + _kc + (ch & 3) * 8;                        \
            uint32_t dst = sBu + (BUF) * 16384 + row * 128                     \
                + ((ch ^ (row & 7)) << 4);                                     \
            CPA(dst, gs);                                                      \
        }                                                                      \
    }

#define STAGEA(BUF, KC)                                                        \
    {                                                                          \
        int _kc = (KC);                                                        \
        int _h  = _kc >> 7;                                                    \
        _Pragma("unroll")                                                      \
        for (int it = 0; it < 4; it++) {                                       \
            int idx = it * 256 + tid;                                          \
            int row = idx >> 3, cg = idx & 7;                                  \
            int gr = m0 + row; if (gr >= M) gr = M - 1;                        \
            float4 t = *(const float4*)(g_tt + gr * 16 + _h * 4);              \
            int j = _kc + cg * 4;                                              \
            float4 w0 = *(const float4*)(g_Wp + 0 * 512 + j);                  \
            float4 w1 = *(const float4*)(g_Wp + 1 * 512 + j);                  \
            float4 w2 = *(const float4*)(g_Wp + 2 * 512 + j);                  \
            float4 w3 = *(const float4*)(g_Wp + 3 * 512 + j);                  \
            float4 bb = *(const float4*)(g_bp + j);                            \
            float4 b2v = *(const float4*)(b1 + j);                             \
            float v0 = bb.x + b2v.x + t.x * w0.x + t.y * w1.x + t.z * w2.x + t.w * w3.x; \
            float v1 = bb.y + b2v.y + t.x * w0.y + t.y * w1.y + t.z * w2.y + t.w * w3.y; \
            float v2 = bb.z + b2v.z + t.x * w0.z + t.y * w1.z + t.z * w2.z + t.w * w3.z; \
            float v3 = bb.w + b2v.w + t.x * w0.w + t.y * w1.w + t.z * w2.w + t.w * w3.w; \
            v0 = v0 > 0.f ? v0 : __expf(v0) - 1.f;                             \
            v1 = v1 > 0.f ? v1 : __expf(v1) - 1.f;                             \
            v2 = v2 > 0.f ? v2 : __expf(v2) - 1.f;                             \
            v3 = v3 > 0.f ? v3 : __expf(v3) - 1.f;                             \
            __nv_bfloat16 h0 = __float2bfloat16(v0);                           \
            __nv_bfloat16 h1 = __float2bfloat16(v1);                           \
            __nv_bfloat16 h2 = __float2bfloat16(v2);                           \
            __nv_bfloat16 h3 = __float2bfloat16(v3);                           \
            uint2 hi2 = make_uint2(pack_bf(h0, h1), pack_bf(h2, h3));          \
            uint2 lo2 = make_uint2(                                            \
                pack_bf(__float2bfloat16(v0 - __bfloat162float(h0)),           \
                        __float2bfloat16(v1 - __bfloat162float(h1))),          \
                pack_bf(__float2bfloat16(v2 - __bfloat162float(h2)),           \
                        __float2bfloat16(v3 - __bfloat162float(h3))));         \
            int ch = cg >> 1, rem = (cg & 1) * 8;                              \
            char* base = sAc + (BUF) * 16384 + row * 128;                      \
            *(uint2*)(base + (((ch)     ^ (row & 7)) << 4) + rem) = hi2;       \
            *(uint2*)(base + (((ch + 4) ^ (row & 7)) << 4) + rem) = lo2;       \
        }                                                                      \
    }

    int nk = K >> 5;
    STAGEB(0, 0)
    asm volatile("cp.async.commit_group;");
    STAGEA(0, 0)
    STAGEB(1, 32)
    asm volatile("cp.async.commit_group;");
    STAGEA(1, 32)

    for (int i = 0; i < nk; i++) {
        if (i + 1 < nk) asm volatile("cp.async.wait_group 1;");
        else            asm volatile("cp.async.wait_group 0;");
        __syncthreads();
        int buf = i % 3;
        int nb  = (i + 2) % 3;
        if (i + 2 < nk) {
            STAGEB(nb, (i + 2) * 32)
            asm volatile("cp.async.commit_group;");
        }

        uint32_t a_base = sAu + buf * 16384;
        uint32_t b_base = sBu + buf * 16384;
#pragma unroll
        for (int ks = 0; ks < 2; ks++) {
            uint32_t ah[2][4], al[2][4], bh[4][4], bl[4][4];
            int arow = (lane & 7) + ((lane >> 3) & 1) * 8;
            int akg  = 2 * ks + (lane >> 4);
#pragma unroll
            for (int mf = 0; mf < 2; mf++) {
                int r = 32 * wm + 16 * mf + arow;
                ldsm4(ah[mf], a_base + r * 128 + (((akg)     ^ (r & 7)) << 4));
                ldsm4(al[mf], a_base + r * 128 + (((akg + 4) ^ (r & 7)) << 4));
            }
            int brow = (lane & 7) + (lane >> 4) * 8;
            int bkg  = 2 * ks + ((lane >> 3) & 1);
#pragma unroll
            for (int q = 0; q < 4; q++) {
                int r = 64 * wn + 16 * q + brow;
                ldsm4(bh[q], b_base + r * 128 + (((bkg)     ^ (r & 7)) << 4));
                ldsm4(bl[q], b_base + r * 128 + (((bkg + 4) ^ (r & 7)) << 4));
            }
#pragma unroll
            for (int mf = 0; mf < 2; mf++) {
#pragma unroll
                for (int q = 0; q < 4; q++) {
                    mma16816(acc[mf][2 * q + 0], ah[mf], &bh[q][0]);
                    mma16816(acc[mf][2 * q + 1], ah[mf], &bh[q][2]);
                    mma16816(acc[mf][2 * q + 0], al[mf], &bh[q][0]);
                    mma16816(acc[mf][2 * q + 1], al[mf], &bh[q][2]);
                    mma16816(acc[mf][2 * q + 0], ah[mf], &bl[q][0]);
                    mma16816(acc[mf][2 * q + 1], ah[mf], &bl[q][2]);
                }
            }
        }
        if (i + 2 < nk) STAGEA(nb, (i + 2) * 32)
    }
#undef STAGEA
#undef STAGEB

    __syncthreads();
    float* colsum = (float*)dsm;
    if (tid < 128) colsum[tid] = 0.f;
    __syncthreads();
#pragma unroll
    for (int mf = 0; mf < 2; mf++) {
        int r0 = m0 + 32 * wm + 16 * mf + (lane >> 2);
#pragma unroll
        for (int nf = 0; nf < 8; nf++) {
            int col = 64 * wn + 8 * nf + 2 * (lane & 3);
            float cb0 = cbias[col], cb1 = cbias[col + 1];
            float s0 = 0.f, s1 = 0.f;
#pragma unroll
            for (int rr = 0; rr < 2; rr++) {
                int r = r0 + rr * 8;
                if (r >= M) continue;
                float v0 = acc[mf][nf][2 * rr + 0] + cb0;
                float v1 = acc[mf][nf][2 * rr + 1] + cb1;
                *(float2*)(Cf + (size_t)r * CDIM + col) = make_float2(v0, v1);
                s0 += v0; s1 += v1;
            }
            atomicAdd(&colsum[col], s0);
            atomicAdd(&colsum[col + 1], s1);
        }
    }
    __syncthreads();
    if (tid < 128) atomicAdd(&g_hsum[tid], colsum[tid]);
}

// ---------------------------------------------------------------------------
// generic 3-stage cp.async warp-MMA bf16 split GEMM (fp32 out / bf16-split out
// / sum-only into g_hsum)
// ---------------------------------------------------------------------------
__global__ void __launch_bounds__(256)
tgemm(const __nv_bfloat16* __restrict__ Ah, const __nv_bfloat16* __restrict__ Al,
      int lda, int boa,
      const __nv_bfloat16* __restrict__ Bh, const __nv_bfloat16* __restrict__ Bl, int bob,
      float* __restrict__ Cf, __nv_bfloat16* __restrict__ Ch, __nv_bfloat16* __restrict__ Cl,
      int ldc, int boc,
      int M, int K, const float* __restrict__ cbias, int bocb, int celu) {
    Ah += (size_t)blockIdx.z * boa;
    Al += (size_t)blockIdx.z * boa;
    Bh += (size_t)blockIdx.z * bob;
    Bl += (size_t)blockIdx.z * bob;
    if (Cf) Cf += (size_t)blockIdx.z * boc;
    if (Ch) { Ch += (size_t)blockIdx.z * boc; Cl += (size_t)blockIdx.z * boc; }
    cbias += (size_t)blockIdx.z * bocb;
    int sum_only = (Cf == nullptr) && (Ch == nullptr);

    extern __shared__ __align__(16) char dsm[];
    uint32_t sAu = smem_u32(dsm);

    int tid  = threadIdx.x;
    int wid  = tid >> 5;
    int lane = tid & 31;
    int m0   = blockIdx.y * 128;
    int wm   = wid & 3;
    int wn   = wid >> 2;

    float acc[2][8][4];
#pragma unroll
    for (int i = 0; i < 2; i++)
#pragma unroll
        for (int j = 0; j < 8; j++)
#pragma unroll
            for (int l = 0; l < 4; l++) acc[i][j][l] = 0.f;

#define STAGE(BUF, KC)                                                         \
    {                                                                          \
        int _kc = (KC);                                                        \
        _Pragma("unroll")                                                      \
        for (int it = 0; it < 4; it++) {                                       \
            int idx = it * 256 + tid;                                          \
            int row = idx >> 3, ch = idx & 7;                                  \
            const __nv_bfloat16* gs = ((ch < 4) ? Ah : Al)                     \
                + (size_t)(m0 + row) * lda + _kc + (ch & 3) * 8;               \
            uint32_t dst = sAu + (BUF) * 32768 + row * 128                     \
                + ((ch ^ (row & 7)) << 4);                                     \
            CPA(dst, gs);                                                      \
        }                                                                      \
        _Pragma("unroll")                                                      \
        for (int it = 0; it < 4; it++) {                                       \
            int idx = it * 256 + tid;                                          \
            int row = idx >> 3, ch = idx & 7;                                  \
            const __nv_bfloat16* gs = ((ch < 4) ? Bh : Bl)                     \
                + (size_t)row * K + _kc + (ch & 3) * 8;                        \
            uint32_t dst = sAu + (BUF) * 32768 + 16384 + row * 128             \
                + ((ch ^ (row & 7)) << 4);                                     \
            CPA(dst, gs);                                                      \
        }                                                                      \
    }

    int nk = K >> 5;
    STAGE(0, 0)
    asm volatile("cp.async.commit_group;");
    STAGE(1, 32)
    asm volatile("cp.async.commit_group;");

    for (int i = 0; i < nk; i++) {
        if (i + 1 < nk) asm volatile("cp.async.wait_group 1;");
        else            asm volatile("cp.async.wait_group 0;");
        __syncthreads();
        int buf = i % 3;
        if (i + 2 < nk) {
            STAGE((i + 2) % 3, (i + 2) * 32)
            asm volatile("cp.async.commit_group;");
        }

        uint32_t a_base = sAu + buf * 32768;
        uint32_t b_base = a_base + 16384;
#pragma unroll
        for (int ks = 0; ks < 2; ks++) {
            uint32_t ah[2][4], al[2][4], bh[4][4], bl[4][4];
            int arow = (lane & 7) + ((lane >> 3) & 1) * 8;
            int akg  = 2 * ks + (lane >> 4);
#pragma unroll
            for (int mf = 0; mf < 2; mf++) {
                int r = 32 * wm + 16 * mf + arow;
                ldsm4(ah[mf], a_base + r * 128 + (((akg)     ^ (r & 7)) << 4));
                ldsm4(al[mf], a_base + r * 128 + (((akg + 4) ^ (r & 7)) << 4));
            }
            int brow = (lane & 7) + (lane >> 4) * 8;
            int bkg  = 2 * ks + ((lane >> 3) & 1);
#pragma unroll
            for (int q = 0; q < 4; q++) {
                int r = 64 * wn + 16 * q + brow;
                ldsm4(bh[q], b_base + r * 128 + (((bkg)     ^ (r & 7)) << 4));
                ldsm4(bl[q], b_base + r * 128 + (((bkg + 4) ^ (r & 7)) << 4));
            }
#pragma unroll
            for (int mf = 0; mf < 2; mf++) {
#pragma unroll
                for (int q = 0; q < 4; q++) {
                    mma16816(acc[mf][2 * q + 0], ah[mf], &bh[q][0]);
                    mma16816(acc[mf][2 * q + 1], ah[mf], &bh[q][2]);
                    mma16816(acc[mf][2 * q + 0], al[mf], &bh[q][0]);
                    mma16816(acc[mf][2 * q + 1], al[mf], &bh[q][2]);
                    mma16816(acc[mf][2 * q + 0], ah[mf], &bl[q][0]);
                    mma16816(acc[mf][2 * q + 1], ah[mf], &bl[q][2]);
                }
            }
        }
    }
#undef STAGE

    float* colsum = (float*)dsm;
    if (sum_only) {
        __syncthreads();
        if (tid < 128) colsum[tid] = 0.f;
        __syncthreads();
    }
#pragma unroll
    for (int mf = 0; mf < 2; mf++) {
        int r0 = m0 + 32 * wm + 16 * mf + (lane >> 2);
#pragma unroll
        for (int nf = 0; nf < 8; nf++) {
            int col = 64 * wn + 8 * nf + 2 * (lane & 3);
            float cb0 = cbias[col], cb1 = cbias[col + 1];
            float s0 = 0.f, s1 = 0.f;
#pragma unroll
            for (int rr = 0; rr < 2; rr++) {
                int r = r0 + rr * 8;
                if (r >= M) continue;
                float v0 = acc[mf][nf][2 * rr + 0] + cb0;
                float v1 = acc[mf][nf][2 * rr + 1] + cb1;
                if (Cf) {
                    *(float2*)(Cf + (size_t)r * ldc + col) = make_float2(v0, v1);
                } else if (Ch) {
                    if (celu) {
                        v0 = v0 > 0.f ? v0 : __expf(v0) - 1.f;
                        v1 = v1 > 0.f ? v1 : __expf(v1) - 1.f;
                    }
                    __nv_bfloat16 h0 = __float2bfloat16(v0);
                    __nv_bfloat16 h1 = __float2bfloat16(v1);
                    size_t o = (size_t)r * ldc + col;
                    *(uint32_t*)(Ch + o) = pack_bf(h0, h1);
                    *(uint32_t*)(Cl + o) =
                        pack_bf(__float2bfloat16(v0 - __bfloat162float(h0)),
                                __float2bfloat16(v1 - __bfloat162float(h1)));
                } else {
                    s0 += v0; s1 += v1;
                }
            }
            if (sum_only) {
                atomicAdd(&colsum[col], s0);
                atomicAdd(&colsum[col + 1], s1);
            }
        }
    }
    if (sum_only) {
        __syncthreads();
        if (tid < 128) atomicAdd(&g_hsum[tid], colsum[tid]);
    }
}

// ---------------------------------------------------------------------------
// Layer-2 folded attention weights + logits
// ---------------------------------------------------------------------------
__global__ void wfold2_kernel(const float* __restrict__ W2,
                              const float* __restrict__ a2s,
                              const float* __restrict__ a2d, int H, int M2) {
    int tid = blockIdx.x * blockDim.x + threadIdx.x;
    if (tid >= CDIM * 2 * H) return;
    int c = tid / (2 * H), o = tid - c * (2 * H);
    int h = o % H;
    const float* av = (o < H) ? a2s : a2d;
    float s = 0.f;
    for (int k = 0; k < CDIM; k++) s += W2[c * M2 + h * CDIM + k] * av[h * CDIM + k];
    g_fold2[c * (2 * H) + o] = s;
}

__global__ void es2_kernel(int N, int H) {
    __shared__ float wt[CDIM * 10];
    int tid = threadIdx.x;
    int TW = CDIM * 2 * H;
    for (int i = tid; i < TW; i += blockDim.x) wt[i] = g_fold2[i];
    __syncthreads();
    int warp = blockIdx.x * (blockDim.x >> 5) + (tid >> 5);
    int lane = tid & 31;
    if (warp >= N) return;
    float4 hv = *(const float4*)(g_h1 + (size_t)warp * CDIM + lane * 4);
    float s[10];
#pragma unroll
    for (int o = 0; o < 10; o++) s[o] = 0.f;
    float hvv[4] = {hv.x, hv.y, hv.z, hv.w};
#pragma unroll
    for (int j = 0; j < 4; j++) {
        int c = lane * 4 + j;
        for (int o = 0; o < 2 * H; o++) s[o] += hvv[j] * wt[c * (2 * H) + o];
    }
    for (int o = 0; o < 2 * H; o++)
        for (int off = 16; off; off >>= 1) s[o] += __shfl_xor_sync(0xffffffffu, s[o], off);
    if (lane < H)          g_es2p[warp * 8 + lane] = s[lane];
    else if (lane < 2 * H) g_ed2p[warp * 8 + lane - H] = s[lane];
}

// ---------------------------------------------------------------------------
// Layer-2 aggregation
// ---------------------------------------------------------------------------
__global__ void agg2_kernel(const float* __restrict__ feat, int N) {
    const int H = 5;
    int warp = (blockIdx.x * blockDim.x + threadIdx.x) >> 5;
    int lane = threadIdx.x & 31;
    if (warp >= N) return;
    int n   = warp;
    int r0  = g_rowptr[n];
    int deg = g_rowptr[n + 1] - r0;
    int tot = deg + 1;

    float edv[H], m[H];
    {
        float4 e4 = *(const float4*)(g_ed2p + n * 8);
        edv[0] = e4.x; edv[1] = e4.y; edv[2] = e4.z; edv[3] = e4.w;
        edv[4] = g_ed2p[n * 8 + 4];
    }
#pragma unroll
    for (int h = 0; h < H; h++) m[h] = -1e30f;
    for (int i = lane; i < tot; i += 32) {
        int src = (i < deg) ? g_csrc[r0 + i] : n;
        float4 e4 = *(const float4*)(g_es2p + src * 8);
        float ev[H] = {e4.x, e4.y, e4.z, e4.w, g_es2p[src * 8 + 4]};
#pragma unroll
        for (int h = 0; h < H; h++) {
            float e = ev[h] + edv[h];
            e = e > 0.f ? e : 0.2f * e;
            m[h] = fmaxf(m[h], e);
        }
    }
#pragma unroll
    for (int h = 0; h < H; h++)
        for (int o = 16; o; o >>= 1) m[h] = fmaxf(m[h], __shfl_xor_sync(0xffffffffu, m[h], o));

    float4 acc[H];
    float zp[H];
#pragma unroll
    for (int h = 0; h < H; h++) { acc[h] = make_float4(0.f, 0.f, 0.f, 0.f); zp[h] = 0.f; }

    for (int t = 0; t < tot; t += 32) {
        int i = t + lane;
        int src = n;
        float w[H];
        if (i < tot) {
            src = (i < deg) ? g_csrc[r0 + i] : n;
            float4 e4 = *(const float4*)(g_es2p + src * 8);
            float ev[H] = {e4.x, e4.y, e4.z, e4.w, g_es2p[src * 8 + 4]};
#pragma unroll
            for (int h = 0; h < H; h++) {
                float e = ev[h] + edv[h];
                e = e > 0.f ? e : 0.2f * e;
                w[h] = __expf(e - m[h]);
                zp[h] += w[h];
            }
        } else {
#pragma unroll
            for (int h = 0; h < H; h++) w[h] = 0.f;
        }
        int cnt = tot - t;
        if (cnt > 32) cnt = 32;
#pragma unroll 4
        for (int j = 0; j < cnt; j++) {
            int s = __shfl_sync(0xffffffffu, src, j);
            float wj[H];
#pragma unroll
            for (int h = 0; h < H; h++) wj[h] = __shfl_sync(0xffffffffu, w[h], j);
            float4 v = *(const float4*)(feat + (size_t)s * CDIM + lane * 4);
#pragma unroll
            for (int h = 0; h < H; h++) {
                acc[h].x += wj[h] * v.x; acc[h].y += wj[h] * v.y;
                acc[h].z += wj[h] * v.z; acc[h].w += wj[h] * v.w;
            }
        }
    }
#pragma unroll
    for (int h = 0; h < H; h++)
        for (int o = 16; o; o >>= 1) zp[h] += __shfl_xor_sync(0xffffffffu, zp[h], o);

#pragma unroll
    for (int h = 0; h < H; h++) {
        float iz = 1.f / zp[h];
        float ax = acc[h].x * iz, ay = acc[h].y * iz;
        float az = acc[h].z * iz, aw = acc[h].w * iz;
        __nv_bfloat16 hx = __float2bfloat16(ax);
        __nv_bfloat16 hy = __float2bfloat16(ay);
        __nv_bfloat16 hz = __float2bfloat16(az);
        __nv_bfloat16 hw = __float2bfloat16(aw);
        size_t o = (size_t)n * (H * CDIM) + h * CDIM + lane * 4;
        *(uint2*)(g_A2h + o) = make_uint2(pack_bf(hx, hy), pack_bf(hz, hw));
        *(uint2*)(g_A2l + o) = make_uint2(
            pack_bf(__float2bfloat16(ax - __bfloat162float(hx)),
                    __float2bfloat16(ay - __bfloat162float(hy))),
            pack_bf(__float2bfloat16(az - __bfloat162float(hz)),
                    __float2bfloat16(aw - __bfloat162float(hw))));
    }
}

// ---------------------------------------------------------------------------
__global__ void tail0_kernel(const float* __restrict__ Wfc, const float* __restrict__ bfc,
                             const float* __restrict__ Whg, const float* __restrict__ bhg,
                             const float* __restrict__ Wv,  const float* __restrict__ bv,
                             const float* __restrict__ h_mat, const float* __restrict__ h_bias,
                             int N, int HOUT) {
    __shared__ float h[128];
    __shared__ float tm[256];
    __shared__ float hg[128];
    int tid = threadIdx.x;
    if (tid < 128) h[tid] = g_hsum[tid] / (float)N;
    __syncthreads();
    if (tid < 256) {
        float a = bfc[tid];
        for (int i = 0; i < 128; i++) a += h[i] * Wfc[i * 256 + tid];
        tm[tid] = a > 0.f ? a : 0.f;
    }
    __syncthreads();
    if (tid < 128) {
        float a = bhg[tid];
        for (int i = 0; i < 256; i++) a += tm[i] * Whg[i * 128 + tid];
        hg[tid] = a;
    }
    __syncthreads();
    if (tid < 384) {
        float a = bv[tid];
        for (int i = 0; i < 128; i++) a += hg[i] * Wv[i * 384 + tid];
        g_small[tid] = a > 0.f ? a : 0.f;
        float hs = 0.f;
        for (int hh = 0; hh < HOUT; hh++) hs += h_mat[hh * 384 + tid];
        g_small[384 + tid] = hs;
    }
    if (tid == 0) {
        float hb = 0.f;
        for (int i = 0; i < HOUT; i++) hb += h_bias[i];
        g_small[768] = hb;
    }
}

__global__ void tail1_kernel(const float* __restrict__ cell,
                             const float* __restrict__ Wc, const float* __restrict__ bc,
                             const float* __restrict__ Wq, const float* __restrict__ bq,
                             int CF) {
    __shared__ float sc[1024];
    __shared__ float crow[128];
    __shared__ float qrow[384];
    __shared__ float red[128];
    int b = blockIdx.x, tid = threadIdx.x;
    for (int i = tid; i < CF; i += 128) sc[i] = cell[(size_t)b * CF + i];
    __syncthreads();
    {
        float a = bc[tid];
        for (int k = 0; k < CF; k++) a += sc[k] * Wc[k * 128 + tid];
        crow[tid] = a > 0.f ? a : 0.f;
    }
    __syncthreads();
    float part = 0.f;
    for (int mI = tid; mI < 384; mI += 128) {
        float q = bq[mI];
        for (int k = 0; k < 128; k++) q += crow[k] * Wq[k * 384 + mI];
        q = q > 0.f ? q : 0.f;
        qrow[mI] = q;
        part += g_small[384 + mI] * g_small[mI] * q;
    }
    red[tid] = part;
    __syncthreads();
    for (int o = 64; o; o >>= 1) {
        if (tid < o) red[tid] += red[tid + o];
        __syncthreads();
    }
    float att = red[0] + g_small[768];
    float l = 0.f;
#pragma unroll
    for (int j = 0; j < 3; j++) {
        int k = tid * 3 + j;
        l += g_small[k] * qrow[k];
    }
    g_logits[b * 128 + tid] = att * l;
}

__global__ void tail2_kernel(const float* __restrict__ gamma,
                             const float* __restrict__ beta,
                             float* __restrict__ out, int B) {
    __shared__ float s1[256], s2[256];
    int c = blockIdx.x, b = threadIdx.x;
    float v = g_logits[b * 128 + c];
    s1[b] = v;
    s2[b] = v * v;
    __syncthreads();
    for (int o = B >> 1; o; o >>= 1) {
        if (b < o) { s1[b] += s1[b + o]; s2[b] += s2[b + o]; }
        __syncthreads();
    }
    float mu  = s1[0] / (float)B;
    float var = s2[0] / (float)B - mu * mu;
    out[b * 128 + c] = (v - mu) * rsqrtf(var + 1e-5f) * gamma[c] + beta[c];
}

// ---------------------------------------------------------------------------
// launch
// ---------------------------------------------------------------------------
extern "C" void kernel_launch(void* const* d_in, const int* in_sizes, int n_in,
                              void* d_out, int out_size) {
    const float* cell = (const float*)d_in[0];
    const float* Wd   = (const float*)d_in[1];
    const float* bd   = (const float*)d_in[2];
    const float* W1   = (const float*)d_in[3];
    const float* a1s  = (const float*)d_in[4];
    const float* a1d  = (const float*)d_in[5];
    const float* b1   = (const float*)d_in[6];
    const float* Wl1  = (const float*)d_in[7];
    const float* bl1  = (const float*)d_in[8];
    const float* W2   = (const float*)d_in[9];
    const float* a2s  = (const float*)d_in[10];
    const float* a2d  = (const float*)d_in[11];
    const float* b2   = (const float*)d_in[12];
    const float* Wl2  = (const float*)d_in[13];
    const float* bl2  = (const float*)d_in[14];
    const float* Wfc  = (const float*)d_in[15];
    const float* bfc  = (const float*)d_in[16];
    const float* Whg  = (const float*)d_in[17];
    const float* bhg  = (const float*)d_in[18];
    const float* Wc   = (const float*)d_in[19];
    const float* bc   = (const float*)d_in[20];
    const float* Wv   = (const float*)d_in[21];
    const float* bv   = (const float*)d_in[22];
    const float* Wq   = (const float*)d_in[23];
    const float* bq   = (const float*)d_in[24];
    const float* h_mat  = (const float*)d_in[25];
    const float* h_bias = (const float*)d_in[26];
    const float* gamma  = (const float*)d_in[27];
    const float* beta   = (const float*)d_in[28];
    const int*   trip   = (const int*)d_in[29];
    const int*   ei     = (const int*)d_in[30];

    int N  = in_sizes[29] / 4;
    int E  = in_sizes[30] / 2;
    int CF = in_sizes[19] / 128;
    int B  = in_sizes[0] / CF;
    int H1 = in_sizes[4] / 128;   // 4
    int H2 = in_sizes[10] / 128;  // 5
    int HOUT = in_sizes[26];
    if (N > NMAX) N = NMAX;
    if (E > EMAX) E = EMAX;
    float* out = (float*)d_out;

    void *ph1;
    void *pA2h, *pA2l, *pA3h, *pA3l;
    void *pb1h, *pb1l, *pb2h, *pb2l, *pb3h, *pb3l;
    cudaGetSymbolAddress(&ph1,  g_h1);
    cudaGetSymbolAddress(&pA2h, g_A2h);
    cudaGetSymbolAddress(&pA2l, g_A2l);
    cudaGetSymbolAddress(&pA3h, g_A3h);
    cudaGetSymbolAddress(&pA3l, g_A3l);
    cudaGetSymbolAddress(&pb1h, g_bt1h);
    cudaGetSymbolAddress(&pb1l, g_bt1l);
    cudaGetSymbolAddress(&pb2h, g_bt2h);
    cudaGetSymbolAddress(&pb2l, g_bt2l);
    cudaGetSymbolAddress(&pb3h, g_bt3h);
    cudaGetSymbolAddress(&pb3l, g_bt3l);

    cudaFuncSetAttribute(tgemm,    cudaFuncAttributeMaxDynamicSharedMemorySize, 98304);
    cudaFuncSetAttribute(tgemm_r4, cudaFuncAttributeMaxDynamicSharedMemorySize, 98304);

    int M1 = H1 * CDIM;  // 512
    int M2 = H2 * CDIM;  // 640
    int mt = (N + 127) / 128;

    // ---- prep (zero + weight splits + drug-linear fold), one launch ----
    int s0 = (N + 255) / 256;
    int s1 = (128 * M1 + 255) / 256;
    int s2 = (128 * 128 * H2 + 255) / 256;
    int s3 = (128 * M2 + 255) / 256;
    int s4 = (M1 + 255) / 256;
    prep_kernel<<<s0 + s1 + s2 + s3 + s4, 256>>>(Wl1, W2, Wl2, Wd, bd, W1,
                                                 N, M1, M2, H2, s0, s1, s2, s3);

    // ---- CSR build ----
    count_kernel<<<(E / 2 + 255) / 256, 256>>>(ei, E);
    scan_kernel<<<1, 1024>>>(N);
    fill_kernel<<<(E / 2 + 255) / 256, 256>>>(ei, E);

    // ---- GAT layer 1 ----
    es1_kernel<<<(N + 255) / 256, 256>>>(trip, a1s, a1d, N, M1);
    agg_rank4_kernel<<<(N * 32 + 255) / 256, 256>>>(trip, N);
    tgemm_r4<<<dim3(1, mt, 1), 256, 98304>>>(
        b1, (const __nv_bfloat16*)pb1h, (const __nv_bfloat16*)pb1l,
        (float*)ph1, N, bl1);

    // ---- GAT layer 2 ----
    wfold2_kernel<<<(CDIM * 2 * H2 + 127) / 128, 128>>>(W2, a2s, a2d, H2, M2);
    es2_kernel<<<(N + 7) / 8, 256>>>(N, H2);
    agg2_kernel<<<(N * 32 + 255) / 256, 256>>>((const float*)ph1, N);
    tgemm<<<dim3(1, mt, H2), 256, 98304>>>(
        (const __nv_bfloat16*)pA2h, (const __nv_bfloat16*)pA2l, M2, 128,
        (const __nv_bfloat16*)pb2h, (const __nv_bfloat16*)pb2l, 128 * 128,
        nullptr, (__nv_bfloat16*)pA3h, (__nv_bfloat16*)pA3l, M2, 128,
        N, 128, b2, 128, 1);
    tgemm<<<dim3(1, mt, 1), 256, 98304>>>(
        (const __nv_bfloat16*)pA3h, (const __nv_bfloat16*)pA3l, M2, 0,
        (const __nv_bfloat16*)pb3h, (const __nv_bfloat16*)pb3l, 0,
        nullptr, nullptr, nullptr, CDIM, 0, N, M2, bl2, 0, 0);

    // ---- tail ----
    tail0_kernel<<<1, 384>>>(Wfc, bfc, Whg, bhg, Wv, bv, h_mat, h_bias, N, HOUT);
    tail1_kernel<<<B, 128>>>(cell, Wc, bc, Wq, bq, CF);
    tail2_kernel<<<128, B>>>(gamma, beta, out, B);
}

// round 11
// speedup vs baseline: 1.9047x; 1.1281x over previous
#include <cuda_runtime.h>
#include <cuda_bf16.h>
#include <math.h>
#include <stdint.h>

#define NMAX 20000
#define EMAX 500000
#define CDIM 128
#define NPAD (NMAX + 128)

// ---------------------------------------------------------------------------
// Static device scratch
// ---------------------------------------------------------------------------
__device__ float g_h1  [NMAX * CDIM];
__device__ float g_es  [NMAX * 4];
__device__ float g_ed  [NMAX * 4];
__device__ float g_es2p[NMAX * 8];
__device__ float g_ed2p[NMAX * 8];
__device__ float g_tt  [NMAX * 16];
__device__ int   g_cnt   [NMAX];
__device__ int   g_rowptr[NMAX + 1];
__device__ int   g_cursor[NMAX];
__device__ int   g_csrc  [EMAX];
__device__ float g_hsum  [CDIM];
__device__ float g_small [1024];
__device__ float g_logits[256 * CDIM];
__device__ float g_Wp  [4 * 512];
__device__ float g_bp  [512];
__device__ float g_fold2[128 * 10];
__device__ __nv_bfloat16 g_A2h[NPAD * 640], g_A2l[NPAD * 640];
__device__ __nv_bfloat16 g_A3h[NPAD * 640], g_A3l[NPAD * 640];
__device__ __nv_bfloat16 g_bt1h[128 * 512], g_bt1l[128 * 512];
__device__ __nv_bfloat16 g_bt2h[5 * 128 * 128], g_bt2l[5 * 128 * 128];
__device__ __nv_bfloat16 g_bt3h[128 * 640], g_bt3l[128 * 640];

// ---------------------------------------------------------------------------
// helpers
// ---------------------------------------------------------------------------
__device__ __forceinline__ uint32_t smem_u32(const void* p) {
    uint32_t a;
    asm("{ .reg .u64 t; cvta.to.shared.u64 t, %1; cvt.u32.u64 %0, t; }" : "=r"(a) : "l"(p));
    return a;
}
__device__ __forceinline__ void ldsm4(uint32_t* r, uint32_t addr) {
    asm volatile("ldmatrix.sync.aligned.m8n8.x4.shared.b16 {%0,%1,%2,%3}, [%4];"
                 : "=r"(r[0]), "=r"(r[1]), "=r"(r[2]), "=r"(r[3]) : "r"(addr));
}
__device__ __forceinline__ void mma16816(float* d, const uint32_t* a, const uint32_t* b) {
    asm volatile(
        "mma.sync.aligned.m16n8k16.row.col.f32.bf16.bf16.f32 "
        "{%0,%1,%2,%3}, {%4,%5,%6,%7}, {%8,%9}, {%0,%1,%2,%3};"
        : "+f"(d[0]), "+f"(d[1]), "+f"(d[2]), "+f"(d[3])
        : "r"(a[0]), "r"(a[1]), "r"(a[2]), "r"(a[3]), "r"(b[0]), "r"(b[1]));
}
__device__ __forceinline__ uint32_t pack_bf(__nv_bfloat16 a, __nv_bfloat16 b) {
    __nv_bfloat162 t;
    t.x = a; t.y = b;
    return *reinterpret_cast<uint32_t*>(&t);
}
#define CPA(dst, src) \
    asm volatile("cp.async.cg.shared.global [%0], [%1], 16;" :: "r"(dst), "l"(src))

// ---------------------------------------------------------------------------
// prep: zero counters + 3x bf16 weight transpose/split + drug-linear fold
// ---------------------------------------------------------------------------
__global__ void prep_kernel(const float* __restrict__ Wl1, const float* __restrict__ W2,
                            const float* __restrict__ Wl2, const float* __restrict__ Wd,
                            const float* __restrict__ bd,  const float* __restrict__ W1,
                            int N, int M1, int M2, int H2,
                            int s0, int s1, int s2, int s3) {
    int b = blockIdx.x, tid = threadIdx.x;
    if (b < s0) {
        int i = b * 256 + tid;
        if (i < N) g_cnt[i] = 0;
        if (b == 0 && tid < CDIM) g_hsum[tid] = 0.f;
        return;
    }
    b -= s0;
    if (b < s1) {
        int idx = b * 256 + tid;
        if (idx < 128 * M1) {
            int j = idx / M1, k = idx - j * M1;
            float v = Wl1[(size_t)k * 128 + j];
            __nv_bfloat16 h = __float2bfloat16(v);
            g_bt1h[idx] = h;
            g_bt1l[idx] = __float2bfloat16(v - __bfloat162float(h));
        }
        return;
    }
    b -= s1;
    if (b < s2) {
        int idx = b * 256 + tid;
        if (idx < 128 * 128 * H2) {
            int z = idx / 16384, r = idx - z * 16384;
            int j = r / 128, k = r - j * 128;
            float v = W2[(size_t)k * M2 + z * 128 + j];
            __nv_bfloat16 h = __float2bfloat16(v);
            g_bt2h[idx] = h;
            g_bt2l[idx] = __float2bfloat16(v - __bfloat162float(h));
        }
        return;
    }
    b -= s2;
    if (b < s3) {
        int idx = b * 256 + tid;
        if (idx < 128 * M2) {
            int j = idx / M2, k = idx - j * M2;
            float v = Wl2[(size_t)k * 128 + j];
            __nv_bfloat16 h = __float2bfloat16(v);
            g_bt3h[idx] = h;
            g_bt3l[idx] = __float2bfloat16(v - __bfloat162float(h));
        }
        return;
    }
    b -= s3;
    {
        int j = b * 256 + tid;
        if (j < M1) {
            float a0 = 0.f, a1 = 0.f, a2 = 0.f, a3 = 0.f, ab = 0.f;
#pragma unroll 4
            for (int k = 0; k < CDIM; k++) {
                float w = W1[k * M1 + j];
                a0 += Wd[0 * CDIM + k] * w;
                a1 += Wd[1 * CDIM + k] * w;
                a2 += Wd[2 * CDIM + k] * w;
                a3 += Wd[3 * CDIM + k] * w;
                ab += bd[k] * w;
            }
            g_Wp[0 * M1 + j] = a0;
            g_Wp[1 * M1 + j] = a1;
            g_Wp[2 * M1 + j] = a2;
            g_Wp[3 * M1 + j] = a3;
            g_bp[j] = ab;
        }
    }
}

// ---------------------------------------------------------------------------
// CSR build
// ---------------------------------------------------------------------------
__global__ void count_kernel(const int* __restrict__ ei, int E) {
    int e = (blockIdx.x * blockDim.x + threadIdx.x) * 2;
    if (e + 1 < E) {
        int2 s = *(const int2*)(ei + e);
        int2 d = *(const int2*)(ei + E + e);
        if (s.x != d.x) atomicAdd(&g_cnt[d.x], 1);
        if (s.y != d.y) atomicAdd(&g_cnt[d.y], 1);
    } else if (e < E) {
        int s = ei[e], d = ei[E + e];
        if (s != d) atomicAdd(&g_cnt[d], 1);
    }
}

__global__ void scan_kernel(int N) {
    __shared__ int wsum[32];
    __shared__ int carry_s;
    int tid = threadIdx.x, lane = tid & 31, wid = tid >> 5;
    if (tid == 0) { carry_s = 0; g_rowptr[0] = 0; }
    __syncthreads();
    int NT = (N + 3) >> 2;
    for (int base = 0; base < NT; base += 1024) {
        int i4 = base + tid;
        int b0 = i4 * 4;
        int4 v = make_int4(0, 0, 0, 0);
        if (b0 + 3 < N) {
            v = *(const int4*)(g_cnt + b0);
        } else if (b0 < N) {
            v.x = g_cnt[b0];
            if (b0 + 1 < N) v.y = g_cnt[b0 + 1];
            if (b0 + 2 < N) v.z = g_cnt[b0 + 2];
        }
        int p1 = v.x, p2 = p1 + v.y, p3 = p2 + v.z, p4 = p3 + v.w;
        int x = p4;
#pragma unroll
        for (int o = 1; o < 32; o <<= 1) {
            int t = __shfl_up_sync(0xffffffffu, x, o);
            if (lane >= o) x += t;
        }
        if (lane == 31) wsum[wid] = x;
        __syncthreads();
        if (wid == 0) {
            int s = wsum[lane];
#pragma unroll
            for (int o = 1; o < 32; o <<= 1) {
                int t = __shfl_up_sync(0xffffffffu, s, o);
                if (lane >= o) s += t;
            }
            wsum[lane] = s;
        }
        __syncthreads();
        int pre = carry_s + (wid ? wsum[wid - 1] : 0) + (x - p4);
        if (b0 < N)     { g_rowptr[b0 + 1] = pre + p1; g_cursor[b0]     = pre; }
        if (b0 + 1 < N) { g_rowptr[b0 + 2] = pre + p2; g_cursor[b0 + 1] = pre + p1; }
        if (b0 + 2 < N) { g_rowptr[b0 + 3] = pre + p3; g_cursor[b0 + 2] = pre + p2; }
        if (b0 + 3 < N) { g_rowptr[b0 + 4] = pre + p4; g_cursor[b0 + 3] = pre + p3; }
        __syncthreads();
        if (tid == 0) carry_s += wsum[31];
        __syncthreads();
    }
}

__global__ void fill_kernel(const int* __restrict__ ei, int E) {
    int e = (blockIdx.x * blockDim.x + threadIdx.x) * 2;
    if (e + 1 < E) {
        int2 s = *(const int2*)(ei + e);
        int2 d = *(const int2*)(ei + E + e);
        if (s.x != d.x) { int p = atomicAdd(&g_cursor[d.x], 1); g_csrc[p] = s.x; }
        if (s.y != d.y) { int p = atomicAdd(&g_cursor[d.y], 1); g_csrc[p] = s.y; }
    } else if (e < E) {
        int s = ei[e], d = ei[E + e];
        if (s != d) { int p = atomicAdd(&g_cursor[d], 1); g_csrc[p] = s; }
    }
}

// ---------------------------------------------------------------------------
// es1
// ---------------------------------------------------------------------------
__global__ void es1_kernel(const int* __restrict__ trip,
                           const float* __restrict__ a1s,
                           const float* __restrict__ a1d, int N, int M1) {
    __shared__ float f1[48];
    int tid = threadIdx.x;
    if (tid < 16) {
        int h = tid >> 2, i = tid & 3;
        float s = 0.f;
        for (int k = 0; k < CDIM; k++) s += g_Wp[i * M1 + h * CDIM + k] * a1s[h * CDIM + k];
        f1[tid] = s;
    } else if (tid < 32) {
        int t = tid - 16;
        int h = t >> 2, i = t & 3;
        float s = 0.f;
        for (int k = 0; k < CDIM; k++) s += g_Wp[i * M1 + h * CDIM + k] * a1d[h * CDIM + k];
        f1[tid] = s;
    } else if (tid < 36) {
        int h = tid - 32;
        float s = 0.f;
        for (int k = 0; k < CDIM; k++) s += g_bp[h * CDIM + k] * a1s[h * CDIM + k];
        f1[tid] = s;
    } else if (tid < 40) {
        int h = tid - 36;
        float s = 0.f;
        for (int k = 0; k < CDIM; k++) s += g_bp[h * CDIM + k] * a1d[h * CDIM + k];
        f1[tid] = s;
    }
    __syncthreads();
    int n = blockIdx.x * blockDim.x + tid;
    if (n >= N) return;
    int4 tv = *(const int4*)(trip + n * 4);
    float t0 = (float)tv.x, t1 = (float)tv.y, t2 = (float)tv.z, t3 = (float)tv.w;
    float4 es, ed;
    float* esp = &es.x;
    float* edp = &ed.x;
#pragma unroll
    for (int h = 0; h < 4; h++) {
        esp[h] = f1[32 + h] + t0 * f1[h * 4 + 0] + t1 * f1[h * 4 + 1]
               + t2 * f1[h * 4 + 2] + t3 * f1[h * 4 + 3];
        edp[h] = f1[36 + h] + t0 * f1[16 + h * 4 + 0] + t1 * f1[16 + h * 4 + 1]
               + t2 * f1[16 + h * 4 + 2] + t3 * f1[16 + h * 4 + 3];
    }
    *(float4*)(g_es + n * 4) = es;
    *(float4*)(g_ed + n * 4) = ed;
}

// ---------------------------------------------------------------------------
// Layer-1 aggregation
// ---------------------------------------------------------------------------
__global__ void agg_rank4_kernel(const int* __restrict__ trip, int N) {
    const int H = 4;
    int warp = (blockIdx.x * blockDim.x + threadIdx.x) >> 5;
    int lane = threadIdx.x & 31;
    if (warp >= N) return;
    int n   = warp;
    int r0  = g_rowptr[n];
    int deg = g_rowptr[n + 1] - r0;
    int tot = deg + 1;

    float4 edv4 = *(const float4*)(g_ed + n * 4);
    float edv[H] = {edv4.x, edv4.y, edv4.z, edv4.w};
    float m[H] = {-1e30f, -1e30f, -1e30f, -1e30f};
    for (int i = lane; i < tot; i += 32) {
        int src = (i < deg) ? g_csrc[r0 + i] : n;
        float4 es = *(const float4*)(g_es + src * 4);
        float ev[H] = {es.x, es.y, es.z, es.w};
#pragma unroll
        for (int h = 0; h < H; h++) {
            float e = ev[h] + edv[h];
            e = e > 0.f ? e : 0.2f * e;
            m[h] = fmaxf(m[h], e);
        }
    }
#pragma unroll
    for (int h = 0; h < H; h++)
        for (int o = 16; o; o >>= 1) m[h] = fmaxf(m[h], __shfl_xor_sync(0xffffffffu, m[h], o));
    float4 acc[H];
    float z[H];
#pragma unroll
    for (int h = 0; h < H; h++) { acc[h] = make_float4(0.f, 0.f, 0.f, 0.f); z[h] = 0.f; }
    for (int i = lane; i < tot; i += 32) {
        int src = (i < deg) ? g_csrc[r0 + i] : n;
        float4 es = *(const float4*)(g_es + src * 4);
        float ev[H] = {es.x, es.y, es.z, es.w};
        int4 tv = *(const int4*)(trip + src * 4);
        float4 tf = make_float4((float)tv.x, (float)tv.y, (float)tv.z, (float)tv.w);
#pragma unroll
        for (int h = 0; h < H; h++) {
            float e = ev[h] + edv[h];
            e = e > 0.f ? e : 0.2f * e;
            float w = __expf(e - m[h]);
            z[h] += w;
            acc[h].x += w * tf.x; acc[h].y += w * tf.y;
            acc[h].z += w * tf.z; acc[h].w += w * tf.w;
        }
    }
#pragma unroll
    for (int h = 0; h < H; h++) {
        for (int o = 16; o; o >>= 1) {
            acc[h].x += __shfl_xor_sync(0xffffffffu, acc[h].x, o);
            acc[h].y += __shfl_xor_sync(0xffffffffu, acc[h].y, o);
            acc[h].z += __shfl_xor_sync(0xffffffffu, acc[h].z, o);
            acc[h].w += __shfl_xor_sync(0xffffffffu, acc[h].w, o);
            z[h]     += __shfl_xor_sync(0xffffffffu, z[h], o);
        }
    }
    if (lane == 0) {
#pragma unroll
        for (int h = 0; h < H; h++) {
            float iz = 1.f / z[h];
            float4 r = make_float4(acc[h].x * iz, acc[h].y * iz, acc[h].z * iz, acc[h].w * iz);
            *(float4*)(g_tt + n * 16 + h * 4) = r;
        }
    }
}

// ---------------------------------------------------------------------------
// tgemm_r4: GEMM1, A generated from g_tt. 64-row CTA tile, 2 CTA/SM,
// 3-stage pipeline; epilogue stores h1 + colsums into g_hsum.
// smem: A 3x8KB @0, B 3x16KB @24576 -> 73728 B.
// ---------------------------------------------------------------------------
__global__ void __launch_bounds__(256, 2)
tgemm_r4(const float* __restrict__ b1,
         const __nv_bfloat16* __restrict__ Bh, const __nv_bfloat16* __restrict__ Bl,
         float* __restrict__ Cf, int M, const float* __restrict__ cbias) {
    const int K = 512;
    extern __shared__ __align__(16) char dsm[];
    char*    sAc = dsm;
    uint32_t sAu = smem_u32(dsm);
    uint32_t sBu = sAu + 24576;

    int tid  = threadIdx.x;
    int wid  = tid >> 5;
    int lane = tid & 31;
    int m0   = blockIdx.y * 64;
    int wm   = wid & 1;
    int wn   = wid >> 1;

    float acc[2][4][4];
#pragma unroll
    for (int i = 0; i < 2; i++)
#pragma unroll
        for (int j = 0; j < 4; j++)
#pragma unroll
            for (int l = 0; l < 4; l++) acc[i][j][l] = 0.f;

#define STAGEB(BUF, KC)                                                        \
    {                                                                          \
        int _kc = (KC);                                                        \
        _Pragma("unroll")                                                      \
        for (int it = 0; it < 4; it++) {                                       \
            int idx = it * 256 + tid;                                          \
            int row = idx >> 3, ch = idx & 7;                                  \
            const __nv_bfloat16* gs = ((ch < 4) ? Bh : Bl)                     \
                + (size_t)row * K + _kc + (ch & 3) * 8;                        \
            uint32_t dst = sBu + (BUF) * 16384 + row * 128                     \
                + ((ch ^ (row & 7)) << 4);                                     \
            CPA(dst, gs);                                                      \
        }                                                                      \
    }

#define STAGEA(BUF, KC)                                                        \
    {                                                                          \
        int _kc = (KC);                                                        \
        int _h  = _kc >> 7;                                                    \
        _Pragma("unroll")                                                      \
        for (int it = 0; it < 2; it++) {                                       \
            int idx = it * 256 + tid;                                          \
            int row = idx >> 3, cg = idx & 7;                                  \
            int gr = m0 + row; if (gr >= M) gr = M - 1;                        \
            float4 t = *(const float4*)(g_tt + gr * 16 + _h * 4);              \
            int j = _kc + cg * 4;                                              \
            float4 w0 = *(const float4*)(g_Wp + 0 * 512 + j);                  \
            float4 w1 = *(const float4*)(g_Wp + 1 * 512 + j);                  \
            float4 w2 = *(const float4*)(g_Wp + 2 * 512 + j);                  \
            float4 w3 = *(const float4*)(g_Wp + 3 * 512 + j);                  \
            float4 bb = *(const float4*)(g_bp + j);                            \
            float4 b2v = *(const float4*)(b1 + j);                             \
            float v0 = bb.x + b2v.x + t.x * w0.x + t.y * w1.x + t.z * w2.x + t.w * w3.x; \
            float v1 = bb.y + b2v.y + t.x * w0.y + t.y * w1.y + t.z * w2.y + t.w * w3.y; \
            float v2 = bb.z + b2v.z + t.x * w0.z + t.y * w1.z + t.z * w2.z + t.w * w3.z; \
            float v3 = bb.w + b2v.w + t.x * w0.w + t.y * w1.w + t.z * w2.w + t.w * w3.w; \
            v0 = v0 > 0.f ? v0 : __expf(v0) - 1.f;                             \
            v1 = v1 > 0.f ? v1 : __expf(v1) - 1.f;                             \
            v2 = v2 > 0.f ? v2 : __expf(v2) - 1.f;                             \
            v3 = v3 > 0.f ? v3 : __expf(v3) - 1.f;                             \
            __nv_bfloat16 h0 = __float2bfloat16(v0);                           \
            __nv_bfloat16 h1 = __float2bfloat16(v1);                           \
            __nv_bfloat16 h2 = __float2bfloat16(v2);                           \
            __nv_bfloat16 h3 = __float2bfloat16(v3);                           \
            uint2 hi2 = make_uint2(pack_bf(h0, h1), pack_bf(h2, h3));          \
            uint2 lo2 = make_uint2(                                            \
                pack_bf(__float2bfloat16(v0 - __bfloat162float(h0)),           \
                        __float2bfloat16(v1 - __bfloat162float(h1))),          \
                pack_bf(__float2bfloat16(v2 - __bfloat162float(h2)),           \
                        __float2bfloat16(v3 - __bfloat162float(h3))));         \
            int ch = cg >> 1, rem = (cg & 1) * 8;                              \
            char* base = sAc + (BUF) * 8192 + row * 128;                       \
            *(uint2*)(base + (((ch)     ^ (row & 7)) << 4) + rem) = hi2;       \
            *(uint2*)(base + (((ch + 4) ^ (row & 7)) << 4) + rem) = lo2;       \
        }                                                                      \
    }

    int nk = K >> 5;
    STAGEB(0, 0)
    asm volatile("cp.async.commit_group;");
    STAGEA(0, 0)
    STAGEB(1, 32)
    asm volatile("cp.async.commit_group;");
    STAGEA(1, 32)

    for (int i = 0; i < nk; i++) {
        if (i + 1 < nk) asm volatile("cp.async.wait_group 1;");
        else            asm volatile("cp.async.wait_group 0;");
        __syncthreads();
        int buf = i % 3;
        int nb  = (i + 2) % 3;
        if (i + 2 < nk) {
            STAGEB(nb, (i + 2) * 32)
            asm volatile("cp.async.commit_group;");
        }

        uint32_t a_base = sAu + buf * 8192;
        uint32_t b_base = sBu + buf * 16384;
#pragma unroll
        for (int ks = 0; ks < 2; ks++) {
            uint32_t ah[2][4], al[2][4], bh[2][4], bl[2][4];
            int arow = (lane & 7) + ((lane >> 3) & 1) * 8;
            int akg  = 2 * ks + (lane >> 4);
#pragma unroll
            for (int mf = 0; mf < 2; mf++) {
                int r = 32 * wm + 16 * mf + arow;
                ldsm4(ah[mf], a_base + r * 128 + (((akg)     ^ (r & 7)) << 4));
                ldsm4(al[mf], a_base + r * 128 + (((akg + 4) ^ (r & 7)) << 4));
            }
            int brow = (lane & 7) + (lane >> 4) * 8;
            int bkg  = 2 * ks + ((lane >> 3) & 1);
#pragma unroll
            for (int q = 0; q < 2; q++) {
                int r = 32 * wn + 16 * q + brow;
                ldsm4(bh[q], b_base + r * 128 + (((bkg)     ^ (r & 7)) << 4));
                ldsm4(bl[q], b_base + r * 128 + (((bkg + 4) ^ (r & 7)) << 4));
            }
#pragma unroll
            for (int mf = 0; mf < 2; mf++) {
#pragma unroll
                for (int q = 0; q < 2; q++) {
                    mma16816(acc[mf][2 * q + 0], ah[mf], &bh[q][0]);
                    mma16816(acc[mf][2 * q + 1], ah[mf], &bh[q][2]);
                    mma16816(acc[mf][2 * q + 0], al[mf], &bh[q][0]);
                    mma16816(acc[mf][2 * q + 1], al[mf], &bh[q][2]);
                    mma16816(acc[mf][2 * q + 0], ah[mf], &bl[q][0]);
                    mma16816(acc[mf][2 * q + 1], ah[mf], &bl[q][2]);
                }
            }
        }
        if (i + 2 < nk) STAGEA(nb, (i + 2) * 32)
    }
#undef STAGEA
#undef STAGEB

    __syncthreads();
    float* colsum = (float*)dsm;
    if (tid < 128) colsum[tid] = 0.f;
    __syncthreads();
#pragma unroll
    for (int mf = 0; mf < 2; mf++) {
        int r0 = m0 + 32 * wm + 16 * mf + (lane >> 2);
#pragma unroll
        for (int nf = 0; nf < 4; nf++) {
            int col = 32 * wn + 8 * nf + 2 * (lane & 3);
            float cb0 = cbias[col], cb1 = cbias[col + 1];
            float s0 = 0.f, s1 = 0.f;
#pragma unroll
            for (int rr = 0; rr < 2; rr++) {
                int r = r0 + rr * 8;
                if (r >= M) continue;
                float v0 = acc[mf][nf][2 * rr + 0] + cb0;
                float v1 = acc[mf][nf][2 * rr + 1] + cb1;
                *(float2*)(Cf + (size_t)r * CDIM + col) = make_float2(v0, v1);
                s0 += v0; s1 += v1;
            }
            atomicAdd(&colsum[col], s0);
            atomicAdd(&colsum[col + 1], s1);
        }
    }
    __syncthreads();
    if (tid < 128) atomicAdd(&g_hsum[tid], colsum[tid]);
}

// ---------------------------------------------------------------------------
// generic tgemm: 64-row CTA tile, N=128, 2 CTA/SM, 3-stage pipeline.
// Out modes: fp32 / bias+elu+bf16-split / sum-only into g_hsum.
// smem: A 3x8KB @0, B 3x16KB @24576 -> 73728 B.
// ---------------------------------------------------------------------------
__global__ void __launch_bounds__(256, 2)
tgemm(const __nv_bfloat16* __restrict__ Ah, const __nv_bfloat16* __restrict__ Al,
      int lda, int boa,
      const __nv_bfloat16* __restrict__ Bh, const __nv_bfloat16* __restrict__ Bl, int bob,
      float* __restrict__ Cf, __nv_bfloat16* __restrict__ Ch, __nv_bfloat16* __restrict__ Cl,
      int ldc, int boc,
      int M, int K, const float* __restrict__ cbias, int bocb, int celu) {
    Ah += (size_t)blockIdx.z * boa;
    Al += (size_t)blockIdx.z * boa;
    Bh += (size_t)blockIdx.z * bob;
    Bl += (size_t)blockIdx.z * bob;
    if (Cf) Cf += (size_t)blockIdx.z * boc;
    if (Ch) { Ch += (size_t)blockIdx.z * boc; Cl += (size_t)blockIdx.z * boc; }
    cbias += (size_t)blockIdx.z * bocb;
    int sum_only = (Cf == nullptr) && (Ch == nullptr);

    extern __shared__ __align__(16) char dsm[];
    uint32_t sAu = smem_u32(dsm);
    uint32_t sBu = sAu + 24576;

    int tid  = threadIdx.x;
    int wid  = tid >> 5;
    int lane = tid & 31;
    int m0   = blockIdx.y * 64;
    int wm   = wid & 1;
    int wn   = wid >> 1;

    float acc[2][4][4];
#pragma unroll
    for (int i = 0; i < 2; i++)
#pragma unroll
        for (int j = 0; j < 4; j++)
#pragma unroll
            for (int l = 0; l < 4; l++) acc[i][j][l] = 0.f;

#define STAGE(BUF, KC)                                                         \
    {                                                                          \
        int _kc = (KC);                                                        \
        _Pragma("unroll")                                                      \
        for (int it = 0; it < 2; it++) {                                       \
            int idx = it * 256 + tid;                                          \
            int row = idx >> 3, ch = idx & 7;                                  \
            const __nv_bfloat16* gs = ((ch < 4) ? Ah : Al)                     \
                + (size_t)(m0 + row) * lda + _kc + (ch & 3) * 8;               \
            uint32_t dst = sAu + (BUF) * 8192 + row * 128                      \
                + ((ch ^ (row & 7)) << 4);                                     \
            CPA(dst, gs);                                                      \
        }                                                                      \
        _Pragma("unroll")                                                      \
        for (int it = 0; it < 4; it++) {                                       \
            int idx = it * 256 + tid;                                          \
            int row = idx >> 3, ch = idx & 7;                                  \
            const __nv_bfloat16* gs = ((ch < 4) ? Bh : Bl)                     \
                + (size_t)row * K + _kc + (ch & 3) * 8;                        \
            uint32_t dst = sBu + (BUF) * 16384 + row * 128                     \
                + ((ch ^ (row & 7)) << 4);                                     \
            CPA(dst, gs);                                                      \
        }                                                                      \
    }

    int nk = K >> 5;
    STAGE(0, 0)
    asm volatile("cp.async.commit_group;");
    STAGE(1, 32)
    asm volatile("cp.async.commit_group;");

    for (int i = 0; i < nk; i++) {
        if (i + 1 < nk) asm volatile("cp.async.wait_group 1;");
        else            asm volatile("cp.async.wait_group 0;");
        __syncthreads();
        int buf = i % 3;
        if (i + 2 < nk) {
            STAGE((i + 2) % 3, (i + 2) * 32)
            asm volatile("cp.async.commit_group;");
        }

        uint32_t a_base = sAu + buf * 8192;
        uint32_t b_base = sBu + buf * 16384;
#pragma unroll
        for (int ks = 0; ks < 2; ks++) {
            uint32_t ah[2][4], al[2][4], bh[2][4], bl[2][4];
            int arow = (lane & 7) + ((lane >> 3) & 1) * 8;
            int akg  = 2 * ks + (lane >> 4);
#pragma unroll
            for (int mf = 0; mf < 2; mf++) {
                int r = 32 * wm + 16 * mf + arow;
                ldsm4(ah[mf], a_base + r * 128 + (((akg)     ^ (r & 7)) << 4));
                ldsm4(al[mf], a_base + r * 128 + (((akg + 4) ^ (r & 7)) << 4));
            }
            int brow = (lane & 7) + (lane >> 4) * 8;
            int bkg  = 2 * ks + ((lane >> 3) & 1);
#pragma unroll
            for (int q = 0; q < 2; q++) {
                int r = 32 * wn + 16 * q + brow;
                ldsm4(bh[q], b_base + r * 128 + (((bkg)     ^ (r & 7)) << 4));
                ldsm4(bl[q], b_base + r * 128 + (((bkg + 4) ^ (r & 7)) << 4));
            }
#pragma unroll
            for (int mf = 0; mf < 2; mf++) {
#pragma unroll
                for (int q = 0; q < 2; q++) {
                    mma16816(acc[mf][2 * q + 0], ah[mf], &bh[q][0]);
                    mma16816(acc[mf][2 * q + 1], ah[mf], &bh[q][2]);
                    mma16816(acc[mf][2 * q + 0], al[mf], &bh[q][0]);
                    mma16816(acc[mf][2 * q + 1], al[mf], &bh[q][2]);
                    mma16816(acc[mf][2 * q + 0], ah[mf], &bl[q][0]);
                    mma16816(acc[mf][2 * q + 1], ah[mf], &bl[q][2]);
                }
            }
        }
    }
#undef STAGE

    float* colsum = (float*)dsm;
    if (sum_only) {
        __syncthreads();
        if (tid < 128) colsum[tid] = 0.f;
        __syncthreads();
    }
#pragma unroll
    for (int mf = 0; mf < 2; mf++) {
        int r0 = m0 + 32 * wm + 16 * mf + (lane >> 2);
#pragma unroll
        for (int nf = 0; nf < 4; nf++) {
            int col = 32 * wn + 8 * nf + 2 * (lane & 3);
            float cb0 = cbias[col], cb1 = cbias[col + 1];
            float s0 = 0.f, s1 = 0.f;
#pragma unroll
            for (int rr = 0; rr < 2; rr++) {
                int r = r0 + rr * 8;
                if (r >= M) continue;
                float v0 = acc[mf][nf][2 * rr + 0] + cb0;
                float v1 = acc[mf][nf][2 * rr + 1] + cb1;
                if (Cf) {
                    *(float2*)(Cf + (size_t)r * ldc + col) = make_float2(v0, v1);
                } else if (Ch) {
                    if (celu) {
                        v0 = v0 > 0.f ? v0 : __expf(v0) - 1.f;
                        v1 = v1 > 0.f ? v1 : __expf(v1) - 1.f;
                    }
                    __nv_bfloat16 h0 = __float2bfloat16(v0);
                    __nv_bfloat16 h1 = __float2bfloat16(v1);
                    size_t o = (size_t)r * ldc + col;
                    *(uint32_t*)(Ch + o) = pack_bf(h0, h1);
                    *(uint32_t*)(Cl + o) =
                        pack_bf(__float2bfloat16(v0 - __bfloat162float(h0)),
                                __float2bfloat16(v1 - __bfloat162float(h1)));
                } else {
                    s0 += v0; s1 += v1;
                }
            }
            if (sum_only) {
                atomicAdd(&colsum[col], s0);
                atomicAdd(&colsum[col + 1], s1);
            }
        }
    }
    if (sum_only) {
        __syncthreads();
        if (tid < 128) atomicAdd(&g_hsum[tid], colsum[tid]);
    }
}

// ---------------------------------------------------------------------------
// Layer-2 folded attention weights + logits
// ---------------------------------------------------------------------------
__global__ void wfold2_kernel(const float* __restrict__ W2,
                              const float* __restrict__ a2s,
                              const float* __restrict__ a2d, int H, int M2) {
    int tid = blockIdx.x * blockDim.x + threadIdx.x;
    if (tid >= CDIM * 2 * H) return;
    int c = tid / (2 * H), o = tid - c * (2 * H);
    int h = o % H;
    const float* av = (o < H) ? a2s : a2d;
    float s = 0.f;
    for (int k = 0; k < CDIM; k++) s += W2[c * M2 + h * CDIM + k] * av[h * CDIM + k];
    g_fold2[c * (2 * H) + o] = s;
}

__global__ void es2_kernel(int N, int H) {
    __shared__ float wt[CDIM * 10];
    int tid = threadIdx.x;
    int TW = CDIM * 2 * H;
    for (int i = tid; i < TW; i += blockDim.x) wt[i] = g_fold2[i];
    __syncthreads();
    int warp = blockIdx.x * (blockDim.x >> 5) + (tid >> 5);
    int lane = tid & 31;
    if (warp >= N) return;
    float4 hv = *(const float4*)(g_h1 + (size_t)warp * CDIM + lane * 4);
    float s[10];
#pragma unroll
    for (int o = 0; o < 10; o++) s[o] = 0.f;
    float hvv[4] = {hv.x, hv.y, hv.z, hv.w};
#pragma unroll
    for (int j = 0; j < 4; j++) {
        int c = lane * 4 + j;
        for (int o = 0; o < 2 * H; o++) s[o] += hvv[j] * wt[c * (2 * H) + o];
    }
    for (int o = 0; o < 2 * H; o++)
        for (int off = 16; off; off >>= 1) s[o] += __shfl_xor_sync(0xffffffffu, s[o], off);
    if (lane < H)          g_es2p[warp * 8 + lane] = s[lane];
    else if (lane < 2 * H) g_ed2p[warp * 8 + lane - H] = s[lane];
}

// ---------------------------------------------------------------------------
// Layer-2 aggregation
// ---------------------------------------------------------------------------
__global__ void agg2_kernel(const float* __restrict__ feat, int N) {
    const int H = 5;
    int warp = (blockIdx.x * blockDim.x + threadIdx.x) >> 5;
    int lane = threadIdx.x & 31;
    if (warp >= N) return;
    int n   = warp;
    int r0  = g_rowptr[n];
    int deg = g_rowptr[n + 1] - r0;
    int tot = deg + 1;

    float edv[H], m[H];
    {
        float4 e4 = *(const float4*)(g_ed2p + n * 8);
        edv[0] = e4.x; edv[1] = e4.y; edv[2] = e4.z; edv[3] = e4.w;
        edv[4] = g_ed2p[n * 8 + 4];
    }
#pragma unroll
    for (int h = 0; h < H; h++) m[h] = -1e30f;
    for (int i = lane; i < tot; i += 32) {
        int src = (i < deg) ? g_csrc[r0 + i] : n;
        float4 e4 = *(const float4*)(g_es2p + src * 8);
        float ev[H] = {e4.x, e4.y, e4.z, e4.w, g_es2p[src * 8 + 4]};
#pragma unroll
        for (int h = 0; h < H; h++) {
            float e = ev[h] + edv[h];
            e = e > 0.f ? e : 0.2f * e;
            m[h] = fmaxf(m[h], e);
        }
    }
#pragma unroll
    for (int h = 0; h < H; h++)
        for (int o = 16; o; o >>= 1) m[h] = fmaxf(m[h], __shfl_xor_sync(0xffffffffu, m[h], o));

    float4 acc[H];
    float zp[H];
#pragma unroll
    for (int h = 0; h < H; h++) { acc[h] = make_float4(0.f, 0.f, 0.f, 0.f); zp[h] = 0.f; }

    for (int t = 0; t < tot; t += 32) {
        int i = t + lane;
        int src = n;
        float w[H];
        if (i < tot) {
            src = (i < deg) ? g_csrc[r0 + i] : n;
            float4 e4 = *(const float4*)(g_es2p + src * 8);
            float ev[H] = {e4.x, e4.y, e4.z, e4.w, g_es2p[src * 8 + 4]};
#pragma unroll
            for (int h = 0; h < H; h++) {
                float e = ev[h] + edv[h];
                e = e > 0.f ? e : 0.2f * e;
                w[h] = __expf(e - m[h]);
                zp[h] += w[h];
            }
        } else {
#pragma unroll
            for (int h = 0; h < H; h++) w[h] = 0.f;
        }
        int cnt = tot - t;
        if (cnt > 32) cnt = 32;
#pragma unroll 4
        for (int j = 0; j < cnt; j++) {
            int s = __shfl_sync(0xffffffffu, src, j);
            float wj[H];
#pragma unroll
            for (int h = 0; h < H; h++) wj[h] = __shfl_sync(0xffffffffu, w[h], j);
            float4 v = *(const float4*)(feat + (size_t)s * CDIM + lane * 4);
#pragma unroll
            for (int h = 0; h < H; h++) {
                acc[h].x += wj[h] * v.x; acc[h].y += wj[h] * v.y;
                acc[h].z += wj[h] * v.z; acc[h].w += wj[h] * v.w;
            }
        }
    }
#pragma unroll
    for (int h = 0; h < H; h++)
        for (int o = 16; o; o >>= 1) zp[h] += __shfl_xor_sync(0xffffffffu, zp[h], o);

#pragma unroll
    for (int h = 0; h < H; h++) {
        float iz = 1.f / zp[h];
        float ax = acc[h].x * iz, ay = acc[h].y * iz;
        float az = acc[h].z * iz, aw = acc[h].w * iz;
        __nv_bfloat16 hx = __float2bfloat16(ax);
        __nv_bfloat16 hy = __float2bfloat16(ay);
        __nv_bfloat16 hz = __float2bfloat16(az);
        __nv_bfloat16 hw = __float2bfloat16(aw);
        size_t o = (size_t)n * (H * CDIM) + h * CDIM + lane * 4;
        *(uint2*)(g_A2h + o) = make_uint2(pack_bf(hx, hy), pack_bf(hz, hw));
        *(uint2*)(g_A2l + o) = make_uint2(
            pack_bf(__float2bfloat16(ax - __bfloat162float(hx)),
                    __float2bfloat16(ay - __bfloat162float(hy))),
            pack_bf(__float2bfloat16(az - __bfloat162float(hz)),
                    __float2bfloat16(aw - __bfloat162float(hw))));
    }
}

// ---------------------------------------------------------------------------
__global__ void tail0_kernel(const float* __restrict__ Wfc, const float* __restrict__ bfc,
                             const float* __restrict__ Whg, const float* __restrict__ bhg,
                             const float* __restrict__ Wv,  const float* __restrict__ bv,
                             const float* __restrict__ h_mat, const float* __restrict__ h_bias,
                             int N, int HOUT) {
    __shared__ float h[128];
    __shared__ float tm[256];
    __shared__ float hg[128];
    int tid = threadIdx.x;
    if (tid < 128) h[tid] = g_hsum[tid] / (float)N;
    __syncthreads();
    if (tid < 256) {
        float a = bfc[tid];
        for (int i = 0; i < 128; i++) a += h[i] * Wfc[i * 256 + tid];
        tm[tid] = a > 0.f ? a : 0.f;
    }
    __syncthreads();
    if (tid < 128) {
        float a = bhg[tid];
        for (int i = 0; i < 256; i++) a += tm[i] * Whg[i * 128 + tid];
        hg[tid] = a;
    }
    __syncthreads();
    if (tid < 384) {
        float a = bv[tid];
        for (int i = 0; i < 128; i++) a += hg[i] * Wv[i * 384 + tid];
        g_small[tid] = a > 0.f ? a : 0.f;
        float hs = 0.f;
        for (int hh = 0; hh < HOUT; hh++) hs += h_mat[hh * 384 + tid];
        g_small[384 + tid] = hs;
    }
    if (tid == 0) {
        float hb = 0.f;
        for (int i = 0; i < HOUT; i++) hb += h_bias[i];
        g_small[768] = hb;
    }
}

__global__ void tail1_kernel(const float* __restrict__ cell,
                             const float* __restrict__ Wc, const float* __restrict__ bc,
                             const float* __restrict__ Wq, const float* __restrict__ bq,
                             int CF) {
    __shared__ float sc[1024];
    __shared__ float crow[128];
    __shared__ float qrow[384];
    __shared__ float red[128];
    int b = blockIdx.x, tid = threadIdx.x;
    for (int i = tid; i < CF; i += 128) sc[i] = cell[(size_t)b * CF + i];
    __syncthreads();
    {
        float a = bc[tid];
        for (int k = 0; k < CF; k++) a += sc[k] * Wc[k * 128 + tid];
        crow[tid] = a > 0.f ? a : 0.f;
    }
    __syncthreads();
    float part = 0.f;
    for (int mI = tid; mI < 384; mI += 128) {
        float q = bq[mI];
        for (int k = 0; k < 128; k++) q += crow[k] * Wq[k * 384 + mI];
        q = q > 0.f ? q : 0.f;
        qrow[mI] = q;
        part += g_small[384 + mI] * g_small[mI] * q;
    }
    red[tid] = part;
    __syncthreads();
    for (int o = 64; o; o >>= 1) {
        if (tid < o) red[tid] += red[tid + o];
        __syncthreads();
    }
    float att = red[0] + g_small[768];
    float l = 0.f;
#pragma unroll
    for (int j = 0; j < 3; j++) {
        int k = tid * 3 + j;
        l += g_small[k] * qrow[k];
    }
    g_logits[b * 128 + tid] = att * l;
}

__global__ void tail2_kernel(const float* __restrict__ gamma,
                             const float* __restrict__ beta,
                             float* __restrict__ out, int B) {
    __shared__ float s1[256], s2[256];
    int c = blockIdx.x, b = threadIdx.x;
    float v = g_logits[b * 128 + c];
    s1[b] = v;
    s2[b] = v * v;
    __syncthreads();
    for (int o = B >> 1; o; o >>= 1) {
        if (b < o) { s1[b] += s1[b + o]; s2[b] += s2[b + o]; }
        __syncthreads();
    }
    float mu  = s1[0] / (float)B;
    float var = s2[0] / (float)B - mu * mu;
    out[b * 128 + c] = (v - mu) * rsqrtf(var + 1e-5f) * gamma[c] + beta[c];
}

// ---------------------------------------------------------------------------
// launch
// ---------------------------------------------------------------------------
extern "C" void kernel_launch(void* const* d_in, const int* in_sizes, int n_in,
                              void* d_out, int out_size) {
    const float* cell = (const float*)d_in[0];
    const float* Wd   = (const float*)d_in[1];
    const float* bd   = (const float*)d_in[2];
    const float* W1   = (const float*)d_in[3];
    const float* a1s  = (const float*)d_in[4];
    const float* a1d  = (const float*)d_in[5];
    const float* b1   = (const float*)d_in[6];
    const float* Wl1  = (const float*)d_in[7];
    const float* bl1  = (const float*)d_in[8];
    const float* W2   = (const float*)d_in[9];
    const float* a2s  = (const float*)d_in[10];
    const float* a2d  = (const float*)d_in[11];
    const float* b2   = (const float*)d_in[12];
    const float* Wl2  = (const float*)d_in[13];
    const float* bl2  = (const float*)d_in[14];
    const float* Wfc  = (const float*)d_in[15];
    const float* bfc  = (const float*)d_in[16];
    const float* Whg  = (const float*)d_in[17];
    const float* bhg  = (const float*)d_in[18];
    const float* Wc   = (const float*)d_in[19];
    const float* bc   = (const float*)d_in[20];
    const float* Wv   = (const float*)d_in[21];
    const float* bv   = (const float*)d_in[22];
    const float* Wq   = (const float*)d_in[23];
    const float* bq   = (const float*)d_in[24];
    const float* h_mat  = (const float*)d_in[25];
    const float* h_bias = (const float*)d_in[26];
    const float* gamma  = (const float*)d_in[27];
    const float* beta   = (const float*)d_in[28];
    const int*   trip   = (const int*)d_in[29];
    const int*   ei     = (const int*)d_in[30];

    int N  = in_sizes[29] / 4;
    int E  = in_sizes[30] / 2;
    int CF = in_sizes[19] / 128;
    int B  = in_sizes[0] / CF;
    int H1 = in_sizes[4] / 128;   // 4
    int H2 = in_sizes[10] / 128;  // 5
    int HOUT = in_sizes[26];
    if (N > NMAX) N = NMAX;
    if (E > EMAX) E = EMAX;
    float* out = (float*)d_out;

    void *ph1;
    void *pA2h, *pA2l, *pA3h, *pA3l;
    void *pb1h, *pb1l, *pb2h, *pb2l, *pb3h, *pb3l;
    cudaGetSymbolAddress(&ph1,  g_h1);
    cudaGetSymbolAddress(&pA2h, g_A2h);
    cudaGetSymbolAddress(&pA2l, g_A2l);
    cudaGetSymbolAddress(&pA3h, g_A3h);
    cudaGetSymbolAddress(&pA3l, g_A3l);
    cudaGetSymbolAddress(&pb1h, g_bt1h);
    cudaGetSymbolAddress(&pb1l, g_bt1l);
    cudaGetSymbolAddress(&pb2h, g_bt2h);
    cudaGetSymbolAddress(&pb2l, g_bt2l);
    cudaGetSymbolAddress(&pb3h, g_bt3h);
    cudaGetSymbolAddress(&pb3l, g_bt3l);

    cudaFuncSetAttribute(tgemm,    cudaFuncAttributeMaxDynamicSharedMemorySize, 73728);
    cudaFuncSetAttribute(tgemm_r4, cudaFuncAttributeMaxDynamicSharedMemorySize, 73728);

    int M1 = H1 * CDIM;  // 512
    int M2 = H2 * CDIM;  // 640
    int mt = (N + 63) / 64;

    // ---- prep ----
    int s0 = (N + 255) / 256;
    int s1 = (128 * M1 + 255) / 256;
    int s2 = (128 * 128 * H2 + 255) / 256;
    int s3 = (128 * M2 + 255) / 256;
    int s4 = (M1 + 255) / 256;
    prep_kernel<<<s0 + s1 + s2 + s3 + s4, 256>>>(Wl1, W2, Wl2, Wd, bd, W1,
                                                 N, M1, M2, H2, s0, s1, s2, s3);

    // ---- CSR build ----
    count_kernel<<<(E / 2 + 255) / 256, 256>>>(ei, E);
    scan_kernel<<<1, 1024>>>(N);
    fill_kernel<<<(E / 2 + 255) / 256, 256>>>(ei, E);

    // ---- GAT layer 1 ----
    es1_kernel<<<(N + 255) / 256, 256>>>(trip, a1s, a1d, N, M1);
    agg_rank4_kernel<<<(N * 32 + 255) / 256, 256>>>(trip, N);
    tgemm_r4<<<dim3(1, mt, 1), 256, 73728>>>(
        b1, (const __nv_bfloat16*)pb1h, (const __nv_bfloat16*)pb1l,
        (float*)ph1, N, bl1);

    // ---- GAT layer 2 ----
    wfold2_kernel<<<(CDIM * 2 * H2 + 127) / 128, 128>>>(W2, a2s, a2d, H2, M2);
    es2_kernel<<<(N + 7) / 8, 256>>>(N, H2);
    agg2_kernel<<<(N * 32 + 255) / 256, 256>>>((const float*)ph1, N);
    tgemm<<<dim3(1, mt, H2), 256, 73728>>>(
        (const __nv_bfloat16*)pA2h, (const __nv_bfloat16*)pA2l, M2, 128,
        (const __nv_bfloat16*)pb2h, (const __nv_bfloat16*)pb2l, 128 * 128,
        nullptr, (__nv_bfloat16*)pA3h, (__nv_bfloat16*)pA3l, M2, 128,
        N, 128, b2, 128, 1);
    tgemm<<<dim3(1, mt, 1), 256, 73728>>>(
        (const __nv_bfloat16*)pA3h, (const __nv_bfloat16*)pA3l, M2, 0,
        (const __nv_bfloat16*)pb3h, (const __nv_bfloat16*)pb3l, 0,
        nullptr, nullptr, nullptr, CDIM, 0, N, M2, bl2, 0, 0);

    // ---- tail ----
    tail0_kernel<<<1, 384>>>(Wfc, bfc, Whg, bhg, Wv, bv, h_mat, h_bias, N, HOUT);
    tail1_kernel<<<B, 128>>>(cell, Wc, bc, Wq, bq, CF);
    tail2_kernel<<<128, B>>>(gamma, beta, out, B);
}

// round 12
// speedup vs baseline: 1.9570x; 1.0275x over previous
#include <cuda_runtime.h>
#include <cuda_bf16.h>
#include <math.h>
#include <stdint.h>

#define NMAX 20000
#define EMAX 500000
#define CDIM 128
#define NPAD (NMAX + 128)

// ---------------------------------------------------------------------------
// Static device scratch
// ---------------------------------------------------------------------------
__device__ float g_h1  [NMAX * CDIM];
__device__ float g_es  [NMAX * 4];
__device__ float g_ed  [NMAX * 4];
__device__ float g_es2p[NMAX * 8];
__device__ float g_ed2p[NMAX * 8];
__device__ float g_tt  [NMAX * 16];
__device__ int   g_cnt   [NMAX];
__device__ int   g_rowptr[NMAX + 1];
__device__ int   g_cursor[NMAX];
__device__ int   g_csrc  [EMAX];
__device__ float g_hsum  [CDIM];
__device__ float g_small [1024];
__device__ float g_logits[256 * CDIM];
__device__ float g_Wp  [4 * 512];
__device__ float g_bp  [512];
__device__ float g_fold2[128 * 10];
__device__ __nv_bfloat16 g_A2h[NPAD * 640], g_A2l[NPAD * 640];
__device__ __nv_bfloat16 g_A3h[NPAD * 640], g_A3l[NPAD * 640];
__device__ __nv_bfloat16 g_bt1h[128 * 512], g_bt1l[128 * 512];
__device__ __nv_bfloat16 g_bt2h[5 * 128 * 128], g_bt2l[5 * 128 * 128];
__device__ __nv_bfloat16 g_bt3h[128 * 640], g_bt3l[128 * 640];

// ---------------------------------------------------------------------------
// helpers
// ---------------------------------------------------------------------------
__device__ __forceinline__ uint32_t smem_u32(const void* p) {
    uint32_t a;
    asm("{ .reg .u64 t; cvta.to.shared.u64 t, %1; cvt.u32.u64 %0, t; }" : "=r"(a) : "l"(p));
    return a;
}
__device__ __forceinline__ void ldsm4(uint32_t* r, uint32_t addr) {
    asm volatile("ldmatrix.sync.aligned.m8n8.x4.shared.b16 {%0,%1,%2,%3}, [%4];"
                 : "=r"(r[0]), "=r"(r[1]), "=r"(r[2]), "=r"(r[3]) : "r"(addr));
}
__device__ __forceinline__ void mma16816(float* d, const uint32_t* a, const uint32_t* b) {
    asm volatile(
        "mma.sync.aligned.m16n8k16.row.col.f32.bf16.bf16.f32 "
        "{%0,%1,%2,%3}, {%4,%5,%6,%7}, {%8,%9}, {%0,%1,%2,%3};"
        : "+f"(d[0]), "+f"(d[1]), "+f"(d[2]), "+f"(d[3])
        : "r"(a[0]), "r"(a[1]), "r"(a[2]), "r"(a[3]), "r"(b[0]), "r"(b[1]));
}
__device__ __forceinline__ uint32_t pack_bf(__nv_bfloat16 a, __nv_bfloat16 b) {
    __nv_bfloat162 t;
    t.x = a; t.y = b;
    return *reinterpret_cast<uint32_t*>(&t);
}
#define CPA(dst, src) \
    asm volatile("cp.async.cg.shared.global [%0], [%1], 16;" :: "r"(dst), "l"(src))

// ---------------------------------------------------------------------------
// prep: zero counters + 3x bf16 weight transpose/split + drug-linear fold
// ---------------------------------------------------------------------------
__global__ void prep_kernel(const float* __restrict__ Wl1, const float* __restrict__ W2,
                            const float* __restrict__ Wl2, const float* __restrict__ Wd,
                            const float* __restrict__ bd,  const float* __restrict__ W1,
                            int N, int M1, int M2, int H2,
                            int s0, int s1, int s2, int s3) {
    int b = blockIdx.x, tid = threadIdx.x;
    if (b < s0) {
        int i = b * 256 + tid;
        if (i < N) g_cnt[i] = 0;
        if (b == 0 && tid < CDIM) g_hsum[tid] = 0.f;
        return;
    }
    b -= s0;
    if (b < s1) {
        int idx = b * 256 + tid;
        if (idx < 128 * M1) {
            int j = idx / M1, k = idx - j * M1;
            float v = Wl1[(size_t)k * 128 + j];
            __nv_bfloat16 h = __float2bfloat16(v);
            g_bt1h[idx] = h;
            g_bt1l[idx] = __float2bfloat16(v - __bfloat162float(h));
        }
        return;
    }
    b -= s1;
    if (b < s2) {
        int idx = b * 256 + tid;
        if (idx < 128 * 128 * H2) {
            int z = idx / 16384, r = idx - z * 16384;
            int j = r / 128, k = r - j * 128;
            float v = W2[(size_t)k * M2 + z * 128 + j];
            __nv_bfloat16 h = __float2bfloat16(v);
            g_bt2h[idx] = h;
            g_bt2l[idx] = __float2bfloat16(v - __bfloat162float(h));
        }
        return;
    }
    b -= s2;
    if (b < s3) {
        int idx = b * 256 + tid;
        if (idx < 128 * M2) {
            int j = idx / M2, k = idx - j * M2;
            float v = Wl2[(size_t)k * 128 + j];
            __nv_bfloat16 h = __float2bfloat16(v);
            g_bt3h[idx] = h;
            g_bt3l[idx] = __float2bfloat16(v - __bfloat162float(h));
        }
        return;
    }
    b -= s3;
    {
        int j = b * 256 + tid;
        if (j < M1) {
            float a0 = 0.f, a1 = 0.f, a2 = 0.f, a3 = 0.f, ab = 0.f;
#pragma unroll 4
            for (int k = 0; k < CDIM; k++) {
                float w = W1[k * M1 + j];
                a0 += Wd[0 * CDIM + k] * w;
                a1 += Wd[1 * CDIM + k] * w;
                a2 += Wd[2 * CDIM + k] * w;
                a3 += Wd[3 * CDIM + k] * w;
                ab += bd[k] * w;
            }
            g_Wp[0 * M1 + j] = a0;
            g_Wp[1 * M1 + j] = a1;
            g_Wp[2 * M1 + j] = a2;
            g_Wp[3 * M1 + j] = a3;
            g_bp[j] = ab;
        }
    }
}

// ---------------------------------------------------------------------------
// CSR build
// ---------------------------------------------------------------------------
__global__ void count_kernel(const int* __restrict__ ei, int E) {
    int e = (blockIdx.x * blockDim.x + threadIdx.x) * 2;
    if (e + 1 < E) {
        int2 s = *(const int2*)(ei + e);
        int2 d = *(const int2*)(ei + E + e);
        if (s.x != d.x) atomicAdd(&g_cnt[d.x], 1);
        if (s.y != d.y) atomicAdd(&g_cnt[d.y], 1);
    } else if (e < E) {
        int s = ei[e], d = ei[E + e];
        if (s != d) atomicAdd(&g_cnt[d], 1);
    }
}

__global__ void scan_kernel(int N) {
    __shared__ int wsum[32];
    __shared__ int carry_s;
    int tid = threadIdx.x, lane = tid & 31, wid = tid >> 5;
    if (tid == 0) { carry_s = 0; g_rowptr[0] = 0; }
    __syncthreads();
    int NT = (N + 3) >> 2;
    for (int base = 0; base < NT; base += 1024) {
        int i4 = base + tid;
        int b0 = i4 * 4;
        int4 v = make_int4(0, 0, 0, 0);
        if (b0 + 3 < N) {
            v = *(const int4*)(g_cnt + b0);
        } else if (b0 < N) {
            v.x = g_cnt[b0];
            if (b0 + 1 < N) v.y = g_cnt[b0 + 1];
            if (b0 + 2 < N) v.z = g_cnt[b0 + 2];
        }
        int p1 = v.x, p2 = p1 + v.y, p3 = p2 + v.z, p4 = p3 + v.w;
        int x = p4;
#pragma unroll
        for (int o = 1; o < 32; o <<= 1) {
            int t = __shfl_up_sync(0xffffffffu, x, o);
            if (lane >= o) x += t;
        }
        if (lane == 31) wsum[wid] = x;
        __syncthreads();
        if (wid == 0) {
            int s = wsum[lane];
#pragma unroll
            for (int o = 1; o < 32; o <<= 1) {
                int t = __shfl_up_sync(0xffffffffu, s, o);
                if (lane >= o) s += t;
            }
            wsum[lane] = s;
        }
        __syncthreads();
        int pre = carry_s + (wid ? wsum[wid - 1] : 0) + (x - p4);
        if (b0 < N)     { g_rowptr[b0 + 1] = pre + p1; g_cursor[b0]     = pre; }
        if (b0 + 1 < N) { g_rowptr[b0 + 2] = pre + p2; g_cursor[b0 + 1] = pre + p1; }
        if (b0 + 2 < N) { g_rowptr[b0 + 3] = pre + p3; g_cursor[b0 + 2] = pre + p2; }
        if (b0 + 3 < N) { g_rowptr[b0 + 4] = pre + p4; g_cursor[b0 + 3] = pre + p3; }
        __syncthreads();
        if (tid == 0) carry_s += wsum[31];
        __syncthreads();
    }
}

__global__ void fill_kernel(const int* __restrict__ ei, int E) {
    int e = (blockIdx.x * blockDim.x + threadIdx.x) * 2;
    if (e + 1 < E) {
        int2 s = *(const int2*)(ei + e);
        int2 d = *(const int2*)(ei + E + e);
        if (s.x != d.x) { int p = atomicAdd(&g_cursor[d.x], 1); g_csrc[p] = s.x; }
        if (s.y != d.y) { int p = atomicAdd(&g_cursor[d.y], 1); g_csrc[p] = s.y; }
    } else if (e < E) {
        int s = ei[e], d = ei[E + e];
        if (s != d) { int p = atomicAdd(&g_cursor[d], 1); g_csrc[p] = s; }
    }
}

// ---------------------------------------------------------------------------
// es1
// ---------------------------------------------------------------------------
__global__ void es1_kernel(const int* __restrict__ trip,
                           const float* __restrict__ a1s,
                           const float* __restrict__ a1d, int N, int M1) {
    __shared__ float f1[48];
    int tid = threadIdx.x;
    if (tid < 16) {
        int h = tid >> 2, i = tid & 3;
        float s = 0.f;
        for (int k = 0; k < CDIM; k++) s += g_Wp[i * M1 + h * CDIM + k] * a1s[h * CDIM + k];
        f1[tid] = s;
    } else if (tid < 32) {
        int t = tid - 16;
        int h = t >> 2, i = t & 3;
        float s = 0.f;
        for (int k = 0; k < CDIM; k++) s += g_Wp[i * M1 + h * CDIM + k] * a1d[h * CDIM + k];
        f1[tid] = s;
    } else if (tid < 36) {
        int h = tid - 32;
        float s = 0.f;
        for (int k = 0; k < CDIM; k++) s += g_bp[h * CDIM + k] * a1s[h * CDIM + k];
        f1[tid] = s;
    } else if (tid < 40) {
        int h = tid - 36;
        float s = 0.f;
        for (int k = 0; k < CDIM; k++) s += g_bp[h * CDIM + k] * a1d[h * CDIM + k];
        f1[tid] = s;
    }
    __syncthreads();
    int n = blockIdx.x * blockDim.x + tid;
    if (n >= N) return;
    int4 tv = *(const int4*)(trip + n * 4);
    float t0 = (float)tv.x, t1 = (float)tv.y, t2 = (float)tv.z, t3 = (float)tv.w;
    float4 es, ed;
    float* esp = &es.x;
    float* edp = &ed.x;
#pragma unroll
    for (int h = 0; h < 4; h++) {
        esp[h] = f1[32 + h] + t0 * f1[h * 4 + 0] + t1 * f1[h * 4 + 1]
               + t2 * f1[h * 4 + 2] + t3 * f1[h * 4 + 3];
        edp[h] = f1[36 + h] + t0 * f1[16 + h * 4 + 0] + t1 * f1[16 + h * 4 + 1]
               + t2 * f1[16 + h * 4 + 2] + t3 * f1[16 + h * 4 + 3];
    }
    *(float4*)(g_es + n * 4) = es;
    *(float4*)(g_ed + n * 4) = ed;
}

// ---------------------------------------------------------------------------
// Layer-1 aggregation
// ---------------------------------------------------------------------------
__global__ void agg_rank4_kernel(const int* __restrict__ trip, int N) {
    const int H = 4;
    int warp = (blockIdx.x * blockDim.x + threadIdx.x) >> 5;
    int lane = threadIdx.x & 31;
    if (warp >= N) return;
    int n   = warp;
    int r0  = g_rowptr[n];
    int deg = g_rowptr[n + 1] - r0;
    int tot = deg + 1;

    float4 edv4 = *(const float4*)(g_ed + n * 4);
    float edv[H] = {edv4.x, edv4.y, edv4.z, edv4.w};
    float m[H] = {-1e30f, -1e30f, -1e30f, -1e30f};
    for (int i = lane; i < tot; i += 32) {
        int src = (i < deg) ? g_csrc[r0 + i] : n;
        float4 es = *(const float4*)(g_es + src * 4);
        float ev[H] = {es.x, es.y, es.z, es.w};
#pragma unroll
        for (int h = 0; h < H; h++) {
            float e = ev[h] + edv[h];
            e = e > 0.f ? e : 0.2f * e;
            m[h] = fmaxf(m[h], e);
        }
    }
#pragma unroll
    for (int h = 0; h < H; h++)
        for (int o = 16; o; o >>= 1) m[h] = fmaxf(m[h], __shfl_xor_sync(0xffffffffu, m[h], o));
    float4 acc[H];
    float z[H];
#pragma unroll
    for (int h = 0; h < H; h++) { acc[h] = make_float4(0.f, 0.f, 0.f, 0.f); z[h] = 0.f; }
    for (int i = lane; i < tot; i += 32) {
        int src = (i < deg) ? g_csrc[r0 + i] : n;
        float4 es = *(const float4*)(g_es + src * 4);
        float ev[H] = {es.x, es.y, es.z, es.w};
        int4 tv = *(const int4*)(trip + src * 4);
        float4 tf = make_float4((float)tv.x, (float)tv.y, (float)tv.z, (float)tv.w);
#pragma unroll
        for (int h = 0; h < H; h++) {
            float e = ev[h] + edv[h];
            e = e > 0.f ? e : 0.2f * e;
            float w = __expf(e - m[h]);
            z[h] += w;
            acc[h].x += w * tf.x; acc[h].y += w * tf.y;
            acc[h].z += w * tf.z; acc[h].w += w * tf.w;
        }
    }
#pragma unroll
    for (int h = 0; h < H; h++) {
        for (int o = 16; o; o >>= 1) {
            acc[h].x += __shfl_xor_sync(0xffffffffu, acc[h].x, o);
            acc[h].y += __shfl_xor_sync(0xffffffffu, acc[h].y, o);
            acc[h].z += __shfl_xor_sync(0xffffffffu, acc[h].z, o);
            acc[h].w += __shfl_xor_sync(0xffffffffu, acc[h].w, o);
            z[h]     += __shfl_xor_sync(0xffffffffu, z[h], o);
        }
    }
    if (lane == 0) {
#pragma unroll
        for (int h = 0; h < H; h++) {
            float iz = 1.f / z[h];
            float4 r = make_float4(acc[h].x * iz, acc[h].y * iz, acc[h].z * iz, acc[h].w * iz);
            *(float4*)(g_tt + n * 16 + h * 4) = r;
        }
    }
}

// ---------------------------------------------------------------------------
// tgemm_r4: GEMM1, A generated from g_tt. 64-row CTA tile, 2-stage pipeline,
// 3 CTAs/SM; epilogue stores h1 + colsums into g_hsum.
// smem: A 2x8KB @0, B 2x16KB @16384 -> 49152 B.
// ---------------------------------------------------------------------------
__global__ void __launch_bounds__(256, 3)
tgemm_r4(const float* __restrict__ b1,
         const __nv_bfloat16* __restrict__ Bh, const __nv_bfloat16* __restrict__ Bl,
         float* __restrict__ Cf, int M, const float* __restrict__ cbias) {
    const int K = 512;
    extern __shared__ __align__(16) char dsm[];
    char*    sAc = dsm;
    uint32_t sAu = smem_u32(dsm);
    uint32_t sBu = sAu + 16384;

    int tid  = threadIdx.x;
    int wid  = tid >> 5;
    int lane = tid & 31;
    int m0   = blockIdx.y * 64;
    int wm   = wid & 1;
    int wn   = wid >> 1;

    float acc[2][4][4];
#pragma unroll
    for (int i = 0; i < 2; i++)
#pragma unroll
        for (int j = 0; j < 4; j++)
#pragma unroll
            for (int l = 0; l < 4; l++) acc[i][j][l] = 0.f;

#define STAGEB(BUF, KC)                                                        \
    {                                                                          \
        int _kc = (KC);                                                        \
        _Pragma("unroll")                                                      \
        for (int it = 0; it < 4; it++) {                                       \
            int idx = it * 256 + tid;                                          \
            int row = idx >> 3, ch = idx & 7;                                  \
            const __nv_bfloat16* gs = ((ch < 4) ? Bh : Bl)                     \
                + (size_t)row * K + _kc + (ch & 3) * 8;                        \
            uint32_t dst = sBu + (BUF) * 16384 + row * 128                     \
                + ((ch ^ (row & 7)) << 4);                                     \
            CPA(dst, gs);                                                      \
        }                                                                      \
    }

#define STAGEA(BUF, KC)                                                        \
    {                                                                          \
        int _kc = (KC);                                                        \
        int _h  = _kc >> 7;                                                    \
        _Pragma("unroll")                                                      \
        for (int it = 0; it < 2; it++) {                                       \
            int idx = it * 256 + tid;                                          \
            int row = idx >> 3, cg = idx & 7;                                  \
            int gr = m0 + row; if (gr >= M) gr = M - 1;                        \
            float4 t = *(const float4*)(g_tt + gr * 16 + _h * 4);              \
            int j = _kc + cg * 4;                                              \
            float4 w0 = *(const float4*)(g_Wp + 0 * 512 + j);                  \
            float4 w1 = *(const float4*)(g_Wp + 1 * 512 + j);                  \
            float4 w2 = *(const float4*)(g_Wp + 2 * 512 + j);                  \
            float4 w3 = *(const float4*)(g_Wp + 3 * 512 + j);                  \
            float4 bb = *(const float4*)(g_bp + j);                            \
            float4 b2v = *(const float4*)(b1 + j);                             \
            float v0 = bb.x + b2v.x + t.x * w0.x + t.y * w1.x + t.z * w2.x + t.w * w3.x; \
            float v1 = bb.y + b2v.y + t.x * w0.y + t.y * w1.y + t.z * w2.y + t.w * w3.y; \
            float v2 = bb.z + b2v.z + t.x * w0.z + t.y * w1.z + t.z * w2.z + t.w * w3.z; \
            float v3 = bb.w + b2v.w + t.x * w0.w + t.y * w1.w + t.z * w2.w + t.w * w3.w; \
            v0 = v0 > 0.f ? v0 : __expf(v0) - 1.f;                             \
            v1 = v1 > 0.f ? v1 : __expf(v1) - 1.f;                             \
            v2 = v2 > 0.f ? v2 : __expf(v2) - 1.f;                             \
            v3 = v3 > 0.f ? v3 : __expf(v3) - 1.f;                             \
            __nv_bfloat16 h0 = __float2bfloat16(v0);                           \
            __nv_bfloat16 h1 = __float2bfloat16(v1);                           \
            __nv_bfloat16 h2 = __float2bfloat16(v2);                           \
            __nv_bfloat16 h3 = __float2bfloat16(v3);                           \
            uint2 hi2 = make_uint2(pack_bf(h0, h1), pack_bf(h2, h3));          \
            uint2 lo2 = make_uint2(                                            \
                pack_bf(__float2bfloat16(v0 - __bfloat162float(h0)),           \
                        __float2bfloat16(v1 - __bfloat162float(h1))),          \
                pack_bf(__float2bfloat16(v2 - __bfloat162float(h2)),           \
                        __float2bfloat16(v3 - __bfloat162float(h3))));         \
            int ch = cg >> 1, rem = (cg & 1) * 8;                              \
            char* base = sAc + (BUF) * 8192 + row * 128;                       \
            *(uint2*)(base + (((ch)     ^ (row & 7)) << 4) + rem) = hi2;       \
            *(uint2*)(base + (((ch + 4) ^ (row & 7)) << 4) + rem) = lo2;       \
        }                                                                      \
    }

    int nk = K >> 5;
    STAGEB(0, 0)
    asm volatile("cp.async.commit_group;");
    STAGEA(0, 0)

    for (int i = 0; i < nk; i++) {
        int buf = i & 1;
        if (i + 1 < nk) {
            STAGEB(buf ^ 1, (i + 1) * 32)
            asm volatile("cp.async.commit_group;");
            STAGEA(buf ^ 1, (i + 1) * 32)
            asm volatile("cp.async.wait_group 1;");
        } else {
            asm volatile("cp.async.wait_group 0;");
        }
        __syncthreads();

        uint32_t a_base = sAu + buf * 8192;
        uint32_t b_base = sBu + buf * 16384;
#pragma unroll
        for (int ks = 0; ks < 2; ks++) {
            uint32_t ah[2][4], al[2][4], bh[2][4], bl[2][4];
            int arow = (lane & 7) + ((lane >> 3) & 1) * 8;
            int akg  = 2 * ks + (lane >> 4);
#pragma unroll
            for (int mf = 0; mf < 2; mf++) {
                int r = 32 * wm + 16 * mf + arow;
                ldsm4(ah[mf], a_base + r * 128 + (((akg)     ^ (r & 7)) << 4));
                ldsm4(al[mf], a_base + r * 128 + (((akg + 4) ^ (r & 7)) << 4));
            }
            int brow = (lane & 7) + (lane >> 4) * 8;
            int bkg  = 2 * ks + ((lane >> 3) & 1);
#pragma unroll
            for (int q = 0; q < 2; q++) {
                int r = 32 * wn + 16 * q + brow;
                ldsm4(bh[q], b_base + r * 128 + (((bkg)     ^ (r & 7)) << 4));
                ldsm4(bl[q], b_base + r * 128 + (((bkg + 4) ^ (r & 7)) << 4));
            }
#pragma unroll
            for (int mf = 0; mf < 2; mf++) {
#pragma unroll
                for (int q = 0; q < 2; q++) {
                    mma16816(acc[mf][2 * q + 0], ah[mf], &bh[q][0]);
                    mma16816(acc[mf][2 * q + 1], ah[mf], &bh[q][2]);
                    mma16816(acc[mf][2 * q + 0], al[mf], &bh[q][0]);
                    mma16816(acc[mf][2 * q + 1], al[mf], &bh[q][2]);
                    mma16816(acc[mf][2 * q + 0], ah[mf], &bl[q][0]);
                    mma16816(acc[mf][2 * q + 1], ah[mf], &bl[q][2]);
                }
            }
        }
        __syncthreads();
    }
#undef STAGEA
#undef STAGEB

    float* colsum = (float*)dsm;
    if (tid < 128) colsum[tid] = 0.f;
    __syncthreads();
#pragma unroll
    for (int mf = 0; mf < 2; mf++) {
        int r0 = m0 + 32 * wm + 16 * mf + (lane >> 2);
#pragma unroll
        for (int nf = 0; nf < 4; nf++) {
            int col = 32 * wn + 8 * nf + 2 * (lane & 3);
            float cb0 = cbias[col], cb1 = cbias[col + 1];
            float s0 = 0.f, s1 = 0.f;
#pragma unroll
            for (int rr = 0; rr < 2; rr++) {
                int r = r0 + rr * 8;
                if (r >= M) continue;
                float v0 = acc[mf][nf][2 * rr + 0] + cb0;
                float v1 = acc[mf][nf][2 * rr + 1] + cb1;
                *(float2*)(Cf + (size_t)r * CDIM + col) = make_float2(v0, v1);
                s0 += v0; s1 += v1;
            }
            atomicAdd(&colsum[col], s0);
            atomicAdd(&colsum[col + 1], s1);
        }
    }
    __syncthreads();
    if (tid < 128) atomicAdd(&g_hsum[tid], colsum[tid]);
}

// ---------------------------------------------------------------------------
// generic tgemm: 64-row CTA tile, N=128, 2-stage pipeline, 3 CTAs/SM.
// Out modes: fp32 / bias+elu+bf16-split / sum-only into g_hsum.
// smem: A 2x8KB @0, B 2x16KB @16384 -> 49152 B.
// ---------------------------------------------------------------------------
__global__ void __launch_bounds__(256, 3)
tgemm(const __nv_bfloat16* __restrict__ Ah, const __nv_bfloat16* __restrict__ Al,
      int lda, int boa,
      const __nv_bfloat16* __restrict__ Bh, const __nv_bfloat16* __restrict__ Bl, int bob,
      float* __restrict__ Cf, __nv_bfloat16* __restrict__ Ch, __nv_bfloat16* __restrict__ Cl,
      int ldc, int boc,
      int M, int K, const float* __restrict__ cbias, int bocb, int celu) {
    Ah += (size_t)blockIdx.z * boa;
    Al += (size_t)blockIdx.z * boa;
    Bh += (size_t)blockIdx.z * bob;
    Bl += (size_t)blockIdx.z * bob;
    if (Cf) Cf += (size_t)blockIdx.z * boc;
    if (Ch) { Ch += (size_t)blockIdx.z * boc; Cl += (size_t)blockIdx.z * boc; }
    cbias += (size_t)blockIdx.z * bocb;
    int sum_only = (Cf == nullptr) && (Ch == nullptr);

    extern __shared__ __align__(16) char dsm[];
    uint32_t sAu = smem_u32(dsm);
    uint32_t sBu = sAu + 16384;

    int tid  = threadIdx.x;
    int wid  = tid >> 5;
    int lane = tid & 31;
    int m0   = blockIdx.y * 64;
    int wm   = wid & 1;
    int wn   = wid >> 1;

    float acc[2][4][4];
#pragma unroll
    for (int i = 0; i < 2; i++)
#pragma unroll
        for (int j = 0; j < 4; j++)
#pragma unroll
            for (int l = 0; l < 4; l++) acc[i][j][l] = 0.f;

#define STAGE(BUF, KC)                                                         \
    {                                                                          \
        int _kc = (KC);                                                        \
        _Pragma("unroll")                                                      \
        for (int it = 0; it < 2; it++) {                                       \
            int idx = it * 256 + tid;                                          \
            int row = idx >> 3, ch = idx & 7;                                  \
            const __nv_bfloat16* gs = ((ch < 4) ? Ah : Al)                     \
                + (size_t)(m0 + row) * lda + _kc + (ch & 3) * 8;               \
            uint32_t dst = sAu + (BUF) * 8192 + row * 128                      \
                + ((ch ^ (row & 7)) << 4);                                     \
            CPA(dst, gs);                                                      \
        }                                                                      \
        _Pragma("unroll")                                                      \
        for (int it = 0; it < 4; it++) {                                       \
            int idx = it * 256 + tid;                                          \
            int row = idx >> 3, ch = idx & 7;                                  \
            const __nv_bfloat16* gs = ((ch < 4) ? Bh : Bl)                     \
                + (size_t)row * K + _kc + (ch & 3) * 8;                        \
            uint32_t dst = sBu + (BUF) * 16384 + row * 128                     \
                + ((ch ^ (row & 7)) << 4);                                     \
            CPA(dst, gs);                                                      \
        }                                                                      \
    }

    int nk = K >> 5;
    STAGE(0, 0)
    asm volatile("cp.async.commit_group;");

    for (int i = 0; i < nk; i++) {
        int buf = i & 1;
        if (i + 1 < nk) {
            STAGE(buf ^ 1, (i + 1) * 32)
            asm volatile("cp.async.commit_group;");
            asm volatile("cp.async.wait_group 1;");
        } else {
            asm volatile("cp.async.wait_group 0;");
        }
        __syncthreads();

        uint32_t a_base = sAu + buf * 8192;
        uint32_t b_base = sBu + buf * 16384;
#pragma unroll
        for (int ks = 0; ks < 2; ks++) {
            uint32_t ah[2][4], al[2][4], bh[2][4], bl[2][4];
            int arow = (lane & 7) + ((lane >> 3) & 1) * 8;
            int akg  = 2 * ks + (lane >> 4);
#pragma unroll
            for (int mf = 0; mf < 2; mf++) {
                int r = 32 * wm + 16 * mf + arow;
                ldsm4(ah[mf], a_base + r * 128 + (((akg)     ^ (r & 7)) << 4));
                ldsm4(al[mf], a_base + r * 128 + (((akg + 4) ^ (r & 7)) << 4));
            }
            int brow = (lane & 7) + (lane >> 4) * 8;
            int bkg  = 2 * ks + ((lane >> 3) & 1);
#pragma unroll
            for (int q = 0; q < 2; q++) {
                int r = 32 * wn + 16 * q + brow;
                ldsm4(bh[q], b_base + r * 128 + (((bkg)     ^ (r & 7)) << 4));
                ldsm4(bl[q], b_base + r * 128 + (((bkg + 4) ^ (r & 7)) << 4));
            }
#pragma unroll
            for (int mf = 0; mf < 2; mf++) {
#pragma unroll
                for (int q = 0; q < 2; q++) {
                    mma16816(acc[mf][2 * q + 0], ah[mf], &bh[q][0]);
                    mma16816(acc[mf][2 * q + 1], ah[mf], &bh[q][2]);
                    mma16816(acc[mf][2 * q + 0], al[mf], &bh[q][0]);
                    mma16816(acc[mf][2 * q + 1], al[mf], &bh[q][2]);
                    mma16816(acc[mf][2 * q + 0], ah[mf], &bl[q][0]);
                    mma16816(acc[mf][2 * q + 1], ah[mf], &bl[q][2]);
                }
            }
        }
        __syncthreads();
    }
#undef STAGE

    float* colsum = (float*)dsm;
    if (sum_only) {
        if (tid < 128) colsum[tid] = 0.f;
        __syncthreads();
    }
#pragma unroll
    for (int mf = 0; mf < 2; mf++) {
        int r0 = m0 + 32 * wm + 16 * mf + (lane >> 2);
#pragma unroll
        for (int nf = 0; nf < 4; nf++) {
            int col = 32 * wn + 8 * nf + 2 * (lane & 3);
            float cb0 = cbias[col], cb1 = cbias[col + 1];
            float s0 = 0.f, s1 = 0.f;
#pragma unroll
            for (int rr = 0; rr < 2; rr++) {
                int r = r0 + rr * 8;
                if (r >= M) continue;
                float v0 = acc[mf][nf][2 * rr + 0] + cb0;
                float v1 = acc[mf][nf][2 * rr + 1] + cb1;
                if (Cf) {
                    *(float2*)(Cf + (size_t)r * ldc + col) = make_float2(v0, v1);
                } else if (Ch) {
                    if (celu) {
                        v0 = v0 > 0.f ? v0 : __expf(v0) - 1.f;
                        v1 = v1 > 0.f ? v1 : __expf(v1) - 1.f;
                    }
                    __nv_bfloat16 h0 = __float2bfloat16(v0);
                    __nv_bfloat16 h1 = __float2bfloat16(v1);
                    size_t o = (size_t)r * ldc + col;
                    *(uint32_t*)(Ch + o) = pack_bf(h0, h1);
                    *(uint32_t*)(Cl + o) =
                        pack_bf(__float2bfloat16(v0 - __bfloat162float(h0)),
                                __float2bfloat16(v1 - __bfloat162float(h1)));
                } else {
                    s0 += v0; s1 += v1;
                }
            }
            if (sum_only) {
                atomicAdd(&colsum[col], s0);
                atomicAdd(&colsum[col + 1], s1);
            }
        }
    }
    if (sum_only) {
        __syncthreads();
        if (tid < 128) atomicAdd(&g_hsum[tid], colsum[tid]);
    }
}

// ---------------------------------------------------------------------------
// Layer-2 folded attention weights + logits
// ---------------------------------------------------------------------------
__global__ void wfold2_kernel(const float* __restrict__ W2,
                              const float* __restrict__ a2s,
                              const float* __restrict__ a2d, int H, int M2) {
    int tid = blockIdx.x * blockDim.x + threadIdx.x;
    if (tid >= CDIM * 2 * H) return;
    int c = tid / (2 * H), o = tid - c * (2 * H);
    int h = o % H;
    const float* av = (o < H) ? a2s : a2d;
    float s = 0.f;
    for (int k = 0; k < CDIM; k++) s += W2[c * M2 + h * CDIM + k] * av[h * CDIM + k];
    g_fold2[c * (2 * H) + o] = s;
}

__global__ void es2_kernel(int N, int H) {
    __shared__ float wt[CDIM * 10];
    int tid = threadIdx.x;
    int TW = CDIM * 2 * H;
    for (int i = tid; i < TW; i += blockDim.x) wt[i] = g_fold2[i];
    __syncthreads();
    int warp = blockIdx.x * (blockDim.x >> 5) + (tid >> 5);
    int lane = tid & 31;
    if (warp >= N) return;
    float4 hv = *(const float4*)(g_h1 + (size_t)warp * CDIM + lane * 4);
    float s[10];
#pragma unroll
    for (int o = 0; o < 10; o++) s[o] = 0.f;
    float hvv[4] = {hv.x, hv.y, hv.z, hv.w};
#pragma unroll
    for (int j = 0; j < 4; j++) {
        int c = lane * 4 + j;
        for (int o = 0; o < 2 * H; o++) s[o] += hvv[j] * wt[c * (2 * H) + o];
    }
    for (int o = 0; o < 2 * H; o++)
        for (int off = 16; off; off >>= 1) s[o] += __shfl_xor_sync(0xffffffffu, s[o], off);
    if (lane < H)          g_es2p[warp * 8 + lane] = s[lane];
    else if (lane < 2 * H) g_ed2p[warp * 8 + lane - H] = s[lane];
}

// ---------------------------------------------------------------------------
// Layer-2 aggregation
// ---------------------------------------------------------------------------
__global__ void agg2_kernel(const float* __restrict__ feat, int N) {
    const int H = 5;
    int warp = (blockIdx.x * blockDim.x + threadIdx.x) >> 5;
    int lane = threadIdx.x & 31;
    if (warp >= N) return;
    int n   = warp;
    int r0  = g_rowptr[n];
    int deg = g_rowptr[n + 1] - r0;
    int tot = deg + 1;

    float edv[H], m[H];
    {
        float4 e4 = *(const float4*)(g_ed2p + n * 8);
        edv[0] = e4.x; edv[1] = e4.y; edv[2] = e4.z; edv[3] = e4.w;
        edv[4] = g_ed2p[n * 8 + 4];
    }
#pragma unroll
    for (int h = 0; h < H; h++) m[h] = -1e30f;
    for (int i = lane; i < tot; i += 32) {
        int src = (i < deg) ? g_csrc[r0 + i] : n;
        float4 e4 = *(const float4*)(g_es2p + src * 8);
        float ev[H] = {e4.x, e4.y, e4.z, e4.w, g_es2p[src * 8 + 4]};
#pragma unroll
        for (int h = 0; h < H; h++) {
            float e = ev[h] + edv[h];
            e = e > 0.f ? e : 0.2f * e;
            m[h] = fmaxf(m[h], e);
        }
    }
#pragma unroll
    for (int h = 0; h < H; h++)
        for (int o = 16; o; o >>= 1) m[h] = fmaxf(m[h], __shfl_xor_sync(0xffffffffu, m[h], o));

    float4 acc[H];
    float zp[H];
#pragma unroll
    for (int h = 0; h < H; h++) { acc[h] = make_float4(0.f, 0.f, 0.f, 0.f); zp[h] = 0.f; }

    for (int t = 0; t < tot; t += 32) {
        int i = t + lane;
        int src = n;
        float w[H];
        if (i < tot) {
            src = (i < deg) ? g_csrc[r0 + i] : n;
            float4 e4 = *(const float4*)(g_es2p + src * 8);
            float ev[H] = {e4.x, e4.y, e4.z, e4.w, g_es2p[src * 8 + 4]};
#pragma unroll
            for (int h = 0; h < H; h++) {
                float e = ev[h] + edv[h];
                e = e > 0.f ? e : 0.2f * e;
                w[h] = __expf(e - m[h]);
                zp[h] += w[h];
            }
        } else {
#pragma unroll
            for (int h = 0; h < H; h++) w[h] = 0.f;
        }
        int cnt = tot - t;
        if (cnt > 32) cnt = 32;
#pragma unroll 4
        for (int j = 0; j < cnt; j++) {
            int s = __shfl_sync(0xffffffffu, src, j);
            float wj[H];
#pragma unroll
            for (int h = 0; h < H; h++) wj[h] = __shfl_sync(0xffffffffu, w[h], j);
            float4 v = *(const float4*)(feat + (size_t)s * CDIM + lane * 4);
#pragma unroll
            for (int h = 0; h < H; h++) {
                acc[h].x += wj[h] * v.x; acc[h].y += wj[h] * v.y;
                acc[h].z += wj[h] * v.z; acc[h].w += wj[h] * v.w;
            }
        }
    }
#pragma unroll
    for (int h = 0; h < H; h++)
        for (int o = 16; o; o >>= 1) zp[h] += __shfl_xor_sync(0xffffffffu, zp[h], o);

#pragma unroll
    for (int h = 0; h < H; h++) {
        float iz = 1.f / zp[h];
        float ax = acc[h].x * iz, ay = acc[h].y * iz;
        float az = acc[h].z * iz, aw = acc[h].w * iz;
        __nv_bfloat16 hx = __float2bfloat16(ax);
        __nv_bfloat16 hy = __float2bfloat16(ay);
        __nv_bfloat16 hz = __float2bfloat16(az);
        __nv_bfloat16 hw = __float2bfloat16(aw);
        size_t o = (size_t)n * (H * CDIM) + h * CDIM + lane * 4;
        *(uint2*)(g_A2h + o) = make_uint2(pack_bf(hx, hy), pack_bf(hz, hw));
        *(uint2*)(g_A2l + o) = make_uint2(
            pack_bf(__float2bfloat16(ax - __bfloat162float(hx)),
                    __float2bfloat16(ay - __bfloat162float(hy))),
            pack_bf(__float2bfloat16(az - __bfloat162float(hz)),
                    __float2bfloat16(aw - __bfloat162float(hw))));
    }
}

// ---------------------------------------------------------------------------
__global__ void tail0_kernel(const float* __restrict__ Wfc, const float* __restrict__ bfc,
                             const float* __restrict__ Whg, const float* __restrict__ bhg,
                             const float* __restrict__ Wv,  const float* __restrict__ bv,
                             const float* __restrict__ h_mat, const float* __restrict__ h_bias,
                             int N, int HOUT) {
    __shared__ float h[128];
    __shared__ float tm[256];
    __shared__ float hg[128];
    int tid = threadIdx.x;
    if (tid < 128) h[tid] = g_hsum[tid] / (float)N;
    __syncthreads();
    if (tid < 256) {
        float a = bfc[tid];
        for (int i = 0; i < 128; i++) a += h[i] * Wfc[i * 256 + tid];
        tm[tid] = a > 0.f ? a : 0.f;
    }
    __syncthreads();
    if (tid < 128) {
        float a = bhg[tid];
        for (int i = 0; i < 256; i++) a += tm[i] * Whg[i * 128 + tid];
        hg[tid] = a;
    }
    __syncthreads();
    if (tid < 384) {
        float a = bv[tid];
        for (int i = 0; i < 128; i++) a += hg[i] * Wv[i * 384 + tid];
        g_small[tid] = a > 0.f ? a : 0.f;
        float hs = 0.f;
        for (int hh = 0; hh < HOUT; hh++) hs += h_mat[hh * 384 + tid];
        g_small[384 + tid] = hs;
    }
    if (tid == 0) {
        float hb = 0.f;
        for (int i = 0; i < HOUT; i++) hb += h_bias[i];
        g_small[768] = hb;
    }
}

__global__ void tail1_kernel(const float* __restrict__ cell,
                             const float* __restrict__ Wc, const float* __restrict__ bc,
                             const float* __restrict__ Wq, const float* __restrict__ bq,
                             int CF) {
    __shared__ float sc[1024];
    __shared__ float crow[128];
    __shared__ float qrow[384];
    __shared__ float red[128];
    int b = blockIdx.x, tid = threadIdx.x;
    for (int i = tid; i < CF; i += 128) sc[i] = cell[(size_t)b * CF + i];
    __syncthreads();
    {
        float a = bc[tid];
        for (int k = 0; k < CF; k++) a += sc[k] * Wc[k * 128 + tid];
        crow[tid] = a > 0.f ? a : 0.f;
    }
    __syncthreads();
    float part = 0.f;
    for (int mI = tid; mI < 384; mI += 128) {
        float q = bq[mI];
        for (int k = 0; k < 128; k++) q += crow[k] * Wq[k * 384 + mI];
        q = q > 0.f ? q : 0.f;
        qrow[mI] = q;
        part += g_small[384 + mI] * g_small[mI] * q;
    }
    red[tid] = part;
    __syncthreads();
    for (int o = 64; o; o >>= 1) {
        if (tid < o) red[tid] += red[tid + o];
        __syncthreads();
    }
    float att = red[0] + g_small[768];
    float l = 0.f;
#pragma unroll
    for (int j = 0; j < 3; j++) {
        int k = tid * 3 + j;
        l += g_small[k] * qrow[k];
    }
    g_logits[b * 128 + tid] = att * l;
}

__global__ void tail2_kernel(const float* __restrict__ gamma,
                             const float* __restrict__ beta,
                             float* __restrict__ out, int B) {
    __shared__ float s1[256], s2[256];
    int c = blockIdx.x, b = threadIdx.x;
    float v = g_logits[b * 128 + c];
    s1[b] = v;
    s2[b] = v * v;
    __syncthreads();
    for (int o = B >> 1; o; o >>= 1) {
        if (b < o) { s1[b] += s1[b + o]; s2[b] += s2[b + o]; }
        __syncthreads();
    }
    float mu  = s1[0] / (float)B;
    float var = s2[0] / (float)B - mu * mu;
    out[b * 128 + c] = (v - mu) * rsqrtf(var + 1e-5f) * gamma[c] + beta[c];
}

// ---------------------------------------------------------------------------
// launch
// ---------------------------------------------------------------------------
extern "C" void kernel_launch(void* const* d_in, const int* in_sizes, int n_in,
                              void* d_out, int out_size) {
    const float* cell = (const float*)d_in[0];
    const float* Wd   = (const float*)d_in[1];
    const float* bd   = (const float*)d_in[2];
    const float* W1   = (const float*)d_in[3];
    const float* a1s  = (const float*)d_in[4];
    const float* a1d  = (const float*)d_in[5];
    const float* b1   = (const float*)d_in[6];
    const float* Wl1  = (const float*)d_in[7];
    const float* bl1  = (const float*)d_in[8];
    const float* W2   = (const float*)d_in[9];
    const float* a2s  = (const float*)d_in[10];
    const float* a2d  = (const float*)d_in[11];
    const float* b2   = (const float*)d_in[12];
    const float* Wl2  = (const float*)d_in[13];
    const float* bl2  = (const float*)d_in[14];
    const float* Wfc  = (const float*)d_in[15];
    const float* bfc  = (const float*)d_in[16];
    const float* Whg  = (const float*)d_in[17];
    const float* bhg  = (const float*)d_in[18];
    const float* Wc   = (const float*)d_in[19];
    const float* bc   = (const float*)d_in[20];
    const float* Wv   = (const float*)d_in[21];
    const float* bv   = (const float*)d_in[22];
    const float* Wq   = (const float*)d_in[23];
    const float* bq   = (const float*)d_in[24];
    const float* h_mat  = (const float*)d_in[25];
    const float* h_bias = (const float*)d_in[26];
    const float* gamma  = (const float*)d_in[27];
    const float* beta   = (const float*)d_in[28];
    const int*   trip   = (const int*)d_in[29];
    const int*   ei     = (const int*)d_in[30];

    int N  = in_sizes[29] / 4;
    int E  = in_sizes[30] / 2;
    int CF = in_sizes[19] / 128;
    int B  = in_sizes[0] / CF;
    int H1 = in_sizes[4] / 128;   // 4
    int H2 = in_sizes[10] / 128;  // 5
    int HOUT = in_sizes[26];
    if (N > NMAX) N = NMAX;
    if (E > EMAX) E = EMAX;
    float* out = (float*)d_out;

    void *ph1;
    void *pA2h, *pA2l, *pA3h, *pA3l;
    void *pb1h, *pb1l, *pb2h, *pb2l, *pb3h, *pb3l;
    cudaGetSymbolAddress(&ph1,  g_h1);
    cudaGetSymbolAddress(&pA2h, g_A2h);
    cudaGetSymbolAddress(&pA2l, g_A2l);
    cudaGetSymbolAddress(&pA3h, g_A3h);
    cudaGetSymbolAddress(&pA3l, g_A3l);
    cudaGetSymbolAddress(&pb1h, g_bt1h);
    cudaGetSymbolAddress(&pb1l, g_bt1l);
    cudaGetSymbolAddress(&pb2h, g_bt2h);
    cudaGetSymbolAddress(&pb2l, g_bt2l);
    cudaGetSymbolAddress(&pb3h, g_bt3h);
    cudaGetSymbolAddress(&pb3l, g_bt3l);

    cudaFuncSetAttribute(tgemm,    cudaFuncAttributeMaxDynamicSharedMemorySize, 49152);
    cudaFuncSetAttribute(tgemm_r4, cudaFuncAttributeMaxDynamicSharedMemorySize, 49152);

    int M1 = H1 * CDIM;  // 512
    int M2 = H2 * CDIM;  // 640
    int mt = (N + 63) / 64;

    // ---- prep ----
    int s0 = (N + 255) / 256;
    int s1 = (128 * M1 + 255) / 256;
    int s2 = (128 * 128 * H2 + 255) / 256;
    int s3 = (128 * M2 + 255) / 256;
    int s4 = (M1 + 255) / 256;
    prep_kernel<<<s0 + s1 + s2 + s3 + s4, 256>>>(Wl1, W2, Wl2, Wd, bd, W1,
                                                 N, M1, M2, H2, s0, s1, s2, s3);

    // ---- CSR build ----
    count_kernel<<<(E / 2 + 255) / 256, 256>>>(ei, E);
    scan_kernel<<<1, 1024>>>(N);
    fill_kernel<<<(E / 2 + 255) / 256, 256>>>(ei, E);

    // ---- GAT layer 1 ----
    es1_kernel<<<(N + 255) / 256, 256>>>(trip, a1s, a1d, N, M1);
    agg_rank4_kernel<<<(N * 32 + 255) / 256, 256>>>(trip, N);
    tgemm_r4<<<dim3(1, mt, 1), 256, 49152>>>(
        b1, (const __nv_bfloat16*)pb1h, (const __nv_bfloat16*)pb1l,
        (float*)ph1, N, bl1);

    // ---- GAT layer 2 ----
    wfold2_kernel<<<(CDIM * 2 * H2 + 127) / 128, 128>>>(W2, a2s, a2d, H2, M2);
    es2_kernel<<<(N + 7) / 8, 256>>>(N, H2);
    agg2_kernel<<<(N * 32 + 255) / 256, 256>>>((const float*)ph1, N);
    tgemm<<<dim3(1, mt, H2), 256, 49152>>>(
        (const __nv_bfloat16*)pA2h, (const __nv_bfloat16*)pA2l, M2, 128,
        (const __nv_bfloat16*)pb2h, (const __nv_bfloat16*)pb2l, 128 * 128,
        nullptr, (__nv_bfloat16*)pA3h, (__nv_bfloat16*)pA3l, M2, 128,
        N, 128, b2, 128, 1);
    tgemm<<<dim3(1, mt, 1), 256, 49152>>>(
        (const __nv_bfloat16*)pA3h, (const __nv_bfloat16*)pA3l, M2, 0,
        (const __nv_bfloat16*)pb3h, (const __nv_bfloat16*)pb3l, 0,
        nullptr, nullptr, nullptr, CDIM, 0, N, M2, bl2, 0, 0);

    // ---- tail ----
    tail0_kernel<<<1, 384>>>(Wfc, bfc, Whg, bhg, Wv, bv, h_mat, h_bias, N, HOUT);
    tail1_kernel<<<B, 128>>>(cell, Wc, bc, Wq, bq, CF);
    tail2_kernel<<<128, B>>>(gamma, beta, out, B);
}